// round 2
// baseline (speedup 1.0000x reference)
#include <cuda_runtime.h>
#include <math.h>

#define B_  512
#define S_  200
#define D_  512
#define NH_ 8
#define DK_ 64
#define L_  4
#define CH  32

// ---------------- scratch (device globals: no allocation allowed) ----------
__device__ float g_hblk[B_*L_*D_];
__device__ float g_valid[B_*L_];
__device__ float g_T[B_*L_*D_];
__device__ float g_a[B_*L_];
__device__ float g_s1[B_*L_];
__device__ float g_bt[B_*D_];
__device__ float g_H[B_*S_*D_];     // 210 MB
__device__ float g_WkT[D_*D_];
__device__ float g_q[B_*D_];
__device__ float g_uK[B_*NH_*D_];
__device__ float g_ctx[B_*NH_*D_];
__device__ float g_psum[B_*NH_];
__device__ float g_mraw[B_*D_];
__device__ float g_mt[B_*D_];
__device__ float g_gi[B_*3*D_];
__device__ float g_gh[B_*3*D_];

// ---------------- helpers ---------------------------------------------------
__device__ __forceinline__ float warpSum(float v) {
    #pragma unroll
    for (int o = 16; o; o >>= 1) v += __shfl_down_sync(0xffffffffu, v, o);
    return v;
}
__device__ __forceinline__ float warpMax(float v) {
    #pragma unroll
    for (int o = 16; o; o >>= 1) v = fmaxf(v, __shfl_down_sync(0xffffffffu, v, o));
    return v;
}
// block-wide sum; red must hold >= 32 floats; returns to ALL threads
__device__ __forceinline__ float blockSum(float v, float* red) {
    int lane = threadIdx.x & 31, w = threadIdx.x >> 5;
    v = warpSum(v);
    if (lane == 0) red[w] = v;
    __syncthreads();
    float r = 0.f;
    if (threadIdx.x < (blockDim.x >> 5)) r = red[threadIdx.x];
    if (w == 0) r = warpSum(r);
    if (threadIdx.x == 0) red[0] = r;
    __syncthreads();
    r = red[0];
    __syncthreads();
    return r;
}
__device__ __forceinline__ float blockMax(float v, float* red) {
    int lane = threadIdx.x & 31, w = threadIdx.x >> 5;
    v = warpMax(v);
    if (lane == 0) red[w] = v;
    __syncthreads();
    float r = -3.0e38f;
    if (threadIdx.x < (blockDim.x >> 5)) r = red[threadIdx.x];
    if (w == 0) r = warpMax(r);
    if (threadIdx.x == 0) red[0] = r;
    __syncthreads();
    r = red[0];
    __syncthreads();
    return r;
}
__device__ __forceinline__ float sigm(float x) { return 1.f / (1.f + expf(-x)); }

// ---------------- generic tiled SIMT GEMM (64x64x16, 256 threads) ----------
// C[M,N] = A[M,Kd] @ B + (bias).  B normal: (Kd x N) row-major; trans: (N x Kd).
// All of M,N multiples of 64; Kd multiple of 16; all pointers 16B aligned.
template <bool TRANSB, bool BIAS>
__global__ __launch_bounds__(256) void k_gemm(
    const float* __restrict__ A, int lda, int sA,
    const float* __restrict__ B, int ldb, int sB,
    float* __restrict__ C, int ldc, int sC,
    const float* __restrict__ bias, int M, int N, int Kd)
{
    int z = blockIdx.z;
    A += (long)z * sA; B += (long)z * sB; C += (long)z * sC;
    int m0 = blockIdx.y * 64, n0 = blockIdx.x * 64;
    __shared__ float As[16][64];
    __shared__ float Bs[16][64];
    int tid = threadIdx.x;
    int tx = tid & 15, ty = tid >> 4;
    float acc[4][4] = {};
    for (int k0 = 0; k0 < Kd; k0 += 16) {
        {   // A tile: 64(m) x 16(k), store transposed As[k][m]
            int m = tid >> 2, kq = tid & 3;
            float4 v = *(const float4*)(A + (long)(m0 + m) * lda + k0 + kq * 4);
            As[kq*4+0][m] = v.x; As[kq*4+1][m] = v.y;
            As[kq*4+2][m] = v.z; As[kq*4+3][m] = v.w;
        }
        if (TRANSB) {
            int n = tid >> 2, kq = tid & 3;
            float4 v = *(const float4*)(B + (long)(n0 + n) * ldb + k0 + kq * 4);
            Bs[kq*4+0][n] = v.x; Bs[kq*4+1][n] = v.y;
            Bs[kq*4+2][n] = v.z; Bs[kq*4+3][n] = v.w;
        } else {
            int k = tid >> 4, nq = tid & 15;
            *(float4*)&Bs[k][nq*4] = *(const float4*)(B + (long)(k0 + k) * ldb + n0 + nq * 4);
        }
        __syncthreads();
        #pragma unroll
        for (int kk = 0; kk < 16; kk++) {
            float4 a4 = *(const float4*)&As[kk][ty * 4];
            float4 b4 = *(const float4*)&Bs[kk][tx * 4];
            acc[0][0] += a4.x*b4.x; acc[0][1] += a4.x*b4.y; acc[0][2] += a4.x*b4.z; acc[0][3] += a4.x*b4.w;
            acc[1][0] += a4.y*b4.x; acc[1][1] += a4.y*b4.y; acc[1][2] += a4.y*b4.z; acc[1][3] += a4.y*b4.w;
            acc[2][0] += a4.z*b4.x; acc[2][1] += a4.z*b4.y; acc[2][2] += a4.z*b4.z; acc[2][3] += a4.z*b4.w;
            acc[3][0] += a4.w*b4.x; acc[3][1] += a4.w*b4.y; acc[3][2] += a4.w*b4.z; acc[3][3] += a4.w*b4.w;
        }
        __syncthreads();
    }
    float4 bvv = make_float4(0.f, 0.f, 0.f, 0.f);
    if (BIAS) bvv = *(const float4*)(bias + n0 + tx * 4);
    #pragma unroll
    for (int i = 0; i < 4; i++) {
        float4 o;
        o.x = acc[i][0] + bvv.x; o.y = acc[i][1] + bvv.y;
        o.z = acc[i][2] + bvv.z; o.w = acc[i][3] + bvv.w;
        *(float4*)(C + (long)(m0 + ty * 4 + i) * ldc + n0 + tx * 4) = o;
    }
}

// ---------------- preamble kernels ------------------------------------------
__global__ __launch_bounds__(512) void k_transpose(const float* __restrict__ src,
                                                   float* __restrict__ dst)
{
    __shared__ float t[32][33];
    int bx = (blockIdx.x & 15) * 32, by = (blockIdx.x >> 4) * 32;
    int lx = threadIdx.x & 31, lyBase = threadIdx.x >> 5; // 16 warps -> rows stride 16
    #pragma unroll
    for (int j = lyBase; j < 32; j += 16)
        t[j][lx] = src[(long)(by + j) * D_ + bx + lx];
    __syncthreads();
    #pragma unroll
    for (int j = lyBase; j < 32; j += 16)
        dst[(long)(bx + j) * D_ + by + lx] = t[lx][j];
}

__global__ __launch_bounds__(512) void k_build_hblk(
    const float* __restrict__ emb, const int* __restrict__ stc,
    const int* __restrict__ off, const int* __restrict__ sep)
{
    int b = blockIdx.x;
    int o = off[b], len = stc[b];
    int sA = sep[b * 2], sB2 = sep[b * 2 + 1];
    int idx = (sA < o ? 1 : 0) + (sB2 < o ? 1 : 0);
    int pidx = idx - 1; pidx = pidx < 0 ? 0 : (pidx > 1 ? 1 : pidx);
    int prev = (pidx == 0) ? sA : sB2;
    int left = (idx > 0) ? prev + 1 : 0;
    int nidx = idx > 1 ? 1 : idx;
    int nxt = (nidx == 0) ? sA : sB2;
    int right = (idx < 2) ? nxt : len;
    int start = (o - 2 > left) ? o - 2 : left;
    int end = (o + 2 < right) ? o + 2 : right;
    int t = threadIdx.x;
    #pragma unroll
    for (int l = 0; l < L_; l++) {
        int ind = start + l;
        bool v = ind < end;
        int ic = ind < 0 ? 0 : (ind > S_ - 1 ? S_ - 1 : ind);
        g_hblk[(b * L_ + l) * D_ + t] = v ? emb[((long)b * S_ + ic) * D_ + t] : 0.f;
        if (t == 0) g_valid[b * L_ + l] = v ? 1.f : 0.f;
    }
}

__global__ __launch_bounds__(256) void k_a(const float* __restrict__ W2)
{
    int m = blockIdx.x, t = threadIdx.x;
    float v = tanhf(g_T[m * D_ + t]) * W2[t] + tanhf(g_T[m * D_ + t + 256]) * W2[t + 256];
    __shared__ float red[32];
    v = blockSum(v, red);
    if (t == 0) g_a[m] = v;
}

__global__ __launch_bounds__(512) void k_s1()
{
    int l = blockIdx.x, t = threadIdx.x;
    __shared__ float red[32];
    float v = g_a[t * L_ + l];
    float mx = blockMax(v, red);
    float e = expf(v - mx);
    float s = blockSum(e, red);
    g_s1[t * L_ + l] = e / s;
}

__global__ __launch_bounds__(512) void k_b0(
    const float* __restrict__ ln_g, const float* __restrict__ ln_b,
    const float* __restrict__ pe)
{
    int b = blockIdx.x, t = threadIdx.x;
    __shared__ float sc[4];
    __shared__ float red[32];
    if (t == 0) {
        float vals[4], mx = -3.0e38f;
        #pragma unroll
        for (int l = 0; l < 4; l++) {
            float v = (g_valid[b * 4 + l] > 0.5f) ? g_s1[b * 4 + l] : -1e9f;
            vals[l] = v; mx = fmaxf(mx, v);
        }
        float s = 0.f;
        #pragma unroll
        for (int l = 0; l < 4; l++) { float e = expf(vals[l] - mx); sc[l] = e; s += e; }
        #pragma unroll
        for (int l = 0; l < 4; l++) sc[l] /= s;
    }
    __syncthreads();
    float x = sc[0] * g_hblk[(b * 4 + 0) * D_ + t] + sc[1] * g_hblk[(b * 4 + 1) * D_ + t]
            + sc[2] * g_hblk[(b * 4 + 2) * D_ + t] + sc[3] * g_hblk[(b * 4 + 3) * D_ + t]
            + pe[t];
    float mean = blockSum(x, red) * (1.f / 512.f);
    float d = x - mean;
    float var = blockSum(d * d, red) * (1.f / 512.f);
    g_bt[b * D_ + t] = d * rsqrtf(var + 1e-5f) * ln_g[t] + ln_b[t];
}

__global__ __launch_bounds__(128) void k_buildH(
    const float* __restrict__ emb, const float* __restrict__ pe,
    const float* __restrict__ seg_emb, const float* __restrict__ ln_g,
    const float* __restrict__ ln_b, const int* __restrict__ stc,
    const int* __restrict__ off)
{
    int b = blockIdx.y, s = blockIdx.x;
    if (s >= stc[b]) return;
    int pos = off[b];
    int ip = (s < pos) ? (pos - s) : (s + 1 - pos);
    ip = ip < 0 ? 0 : (ip > S_ ? S_ : ip);
    int sg = (s >= pos) ? 1 : 0;
    int t = threadIdx.x;
    __shared__ float red[32];
    float4 e = *(const float4*)(emb + ((long)b * S_ + s) * D_ + t * 4);
    float4 p = *(const float4*)(pe + (long)ip * D_ + t * 4);
    float4 g = *(const float4*)(seg_emb + sg * D_ + t * 4);
    float x0 = e.x + p.x + g.x, x1 = e.y + p.y + g.y;
    float x2 = e.z + p.z + g.z, x3 = e.w + p.w + g.w;
    float mean = blockSum(x0 + x1 + x2 + x3, red) * (1.f / 512.f);
    float d0 = x0 - mean, d1 = x1 - mean, d2 = x2 - mean, d3 = x3 - mean;
    float var = blockSum(d0 * d0 + d1 * d1 + d2 * d2 + d3 * d3, red) * (1.f / 512.f);
    float inv = rsqrtf(var + 1e-5f);
    float4 gg = *(const float4*)(ln_g + t * 4);
    float4 bb = *(const float4*)(ln_b + t * 4);
    float4 o;
    o.x = d0 * inv * gg.x + bb.x; o.y = d1 * inv * gg.y + bb.y;
    o.z = d2 * inv * gg.z + bb.z; o.w = d3 * inv * gg.w + bb.w;
    *(float4*)(g_H + ((long)b * S_ + s) * D_ + t * 4) = o;
}

// ---------------- fused attention (per-batch CTA) ---------------------------
#define DOT4(u, h) ((u).x*(h).x + (u).y*(h).y + (u).z*(h).z + (u).w*(h).w)

__global__ __launch_bounds__(512) void k_attn(
    const float* __restrict__ bk, const int* __restrict__ stc)
{
    int b = blockIdx.x;
    int tid = threadIdx.x, lane = tid & 31, warp = tid >> 5;
    extern __shared__ float sm[];
    float* uKs = sm;                    // 8*512
    float* Hs  = sm + NH_ * D_;         // CH*512
    float* ps  = Hs + CH * D_;          // CH*8  [s][h]
    float* cKs = ps + CH * NH_;         // 8
    float* pss = cKs + NH_;             // 8
    int len = stc[b];
    // stage uK
    {
        const float4* src = (const float4*)(g_uK + (long)b * NH_ * D_);
        float4* dst = (float4*)uKs;
        dst[tid] = src[tid];
        dst[tid + 512] = src[tid + 512];
    }
    // cK[h] = bk_h . q_h ; init psum
    if (warp < NH_) {
        float v = bk[warp * 64 + lane] * g_q[b * D_ + warp * 64 + lane]
                + bk[warp * 64 + 32 + lane] * g_q[b * D_ + warp * 64 + 32 + lane];
        v = warpSum(v);
        if (lane == 0) { cKs[warp] = v; pss[warp] = 0.f; }
    }
    float creg[8] = {0.f,0.f,0.f,0.f,0.f,0.f,0.f,0.f};
    __syncthreads();
    int nch = (len + CH - 1) / CH;
    for (int c = 0; c < nch; c++) {
        int s0 = c * CH;
        // stage H chunk (zeros past len)
        #pragma unroll 4
        for (int r = 0; r < CH; r++) {
            int s = s0 + r;
            Hs[r * D_ + tid] = (s < len) ? g_H[((long)b * S_ + s) * D_ + tid] : 0.f;
        }
        if (tid < CH * NH_) ps[tid] = 0.f;
        __syncthreads();
        // scores: 32 tasks = 8 heads x 4 groups of 8 rows
        for (int task = warp; task < 32; task += 16) {
            int h = task >> 2, sb = (task & 3) * 8;
            const float4* uk4 = (const float4*)(uKs + h * D_) + (lane << 2);
            float4 u0 = uk4[0], u1 = uk4[1], u2 = uk4[2], u3 = uk4[3];
            float acc[8];
            #pragma unroll
            for (int j = 0; j < 8; j++) {
                const float4* h4 = (const float4*)(Hs + (sb + j) * D_) + (lane << 2);
                acc[j] = DOT4(u0, h4[0]) + DOT4(u1, h4[1]) + DOT4(u2, h4[2]) + DOT4(u3, h4[3]);
            }
            #pragma unroll
            for (int j = 0; j < 8; j++) acc[j] = warpSum(acc[j]);
            if (lane == 0) {
                #pragma unroll
                for (int j = 0; j < 8; j++) {
                    int s = s0 + sb + j;
                    if (s < len)
                        ps[(sb + j) * NH_ + h] = sigm(0.125f * (acc[j] + cKs[h]));
                }
            }
        }
        __syncthreads();
        // ctx accumulation: thread owns dim tid
        #pragma unroll 4
        for (int r = 0; r < CH; r++) {
            float hv = Hs[r * D_ + tid];
            float4 p0 = *(const float4*)(ps + r * NH_);
            float4 p1 = *(const float4*)(ps + r * NH_ + 4);
            creg[0] += p0.x * hv; creg[1] += p0.y * hv;
            creg[2] += p0.z * hv; creg[3] += p0.w * hv;
            creg[4] += p1.x * hv; creg[5] += p1.y * hv;
            creg[6] += p1.z * hv; creg[7] += p1.w * hv;
        }
        // psum
        if (warp < NH_) {
            float v = ps[lane * NH_ + warp];
            v = warpSum(v);
            if (lane == 0) pss[warp] += v;
        }
        __syncthreads();
    }
    #pragma unroll
    for (int h = 0; h < NH_; h++)
        g_ctx[((long)b * NH_ + h) * D_ + tid] = creg[h];
    if (tid < NH_) g_psum[b * NH_ + tid] = pss[tid];
}

// ---------------- per-iteration small kernels -------------------------------
__global__ __launch_bounds__(512) void k_ln_mt(
    const float* __restrict__ bv, const float* __restrict__ lng_g,
    const float* __restrict__ lng_b)
{
    int b = blockIdx.x, t = threadIdx.x;
    __shared__ float red[32];
    float x = g_mraw[b * D_ + t] + g_psum[b * NH_ + (t >> 6)] * bv[t];
    float mean = blockSum(x, red) * (1.f / 512.f);
    float d = x - mean;
    float var = blockSum(d * d, red) * (1.f / 512.f);
    g_mt[b * D_ + t] = d * rsqrtf(var + 1e-5f) * lng_g[t] + lng_b[t];
}

__global__ __launch_bounds__(512) void k_gru()
{
    int b = blockIdx.x, t = threadIdx.x;
    float ir = g_gi[b * 1536 + t];
    float iz = g_gi[b * 1536 + 512 + t];
    float in = g_gi[b * 1536 + 1024 + t];
    float hr = g_gh[b * 1536 + t];
    float hz = g_gh[b * 1536 + 512 + t];
    float hn = g_gh[b * 1536 + 1024 + t];
    float r = sigm(ir + hr);
    float z = sigm(iz + hz);
    float n = tanhf(in + r * hn);
    float old = g_bt[b * D_ + t];
    g_bt[b * D_ + t] = (1.f - z) * n + z * old;
}

__global__ __launch_bounds__(512) void k_copy(float* __restrict__ out)
{
    out[blockIdx.x * 512 + threadIdx.x] = g_bt[blockIdx.x * 512 + threadIdx.x];
}

// ---------------- launch -----------------------------------------------------
extern "C" void kernel_launch(void* const* d_in, const int* in_sizes, int n_in,
                              void* d_out, int out_size)
{
    const float* emb   = (const float*)d_in[0];
    const int*   stc   = (const int*)  d_in[1];
    const int*   off   = (const int*)  d_in[2];
    const int*   sep   = (const int*)  d_in[3];
    const float* W1    = (const float*)d_in[4];
    const float* W2    = (const float*)d_in[5];
    const float* ln_g  = (const float*)d_in[6];
    const float* ln_b  = (const float*)d_in[7];
    const float* lng_g = (const float*)d_in[8];
    const float* lng_b = (const float*)d_in[9];
    const float* Wq    = (const float*)d_in[10];
    const float* bq    = (const float*)d_in[11];
    const float* Wk    = (const float*)d_in[12];
    const float* bk    = (const float*)d_in[13];
    const float* Wv    = (const float*)d_in[14];
    const float* bv    = (const float*)d_in[15];
    const float* W_ih  = (const float*)d_in[16];
    const float* W_hh  = (const float*)d_in[17];
    const float* b_ih  = (const float*)d_in[18];
    const float* b_hh  = (const float*)d_in[19];
    const float* seg   = (const float*)d_in[20];
    const float* pe    = (const float*)d_in[21];
    float* out = (float*)d_out;

    float *pHblk, *pT, *pBt, *pWkT, *pQ, *pUK, *pCtx, *pMraw, *pMt, *pGi, *pGh;
    cudaGetSymbolAddress((void**)&pHblk, g_hblk);
    cudaGetSymbolAddress((void**)&pT,    g_T);
    cudaGetSymbolAddress((void**)&pBt,   g_bt);
    cudaGetSymbolAddress((void**)&pWkT,  g_WkT);
    cudaGetSymbolAddress((void**)&pQ,    g_q);
    cudaGetSymbolAddress((void**)&pUK,   g_uK);
    cudaGetSymbolAddress((void**)&pCtx,  g_ctx);
    cudaGetSymbolAddress((void**)&pMraw, g_mraw);
    cudaGetSymbolAddress((void**)&pMt,   g_mt);
    cudaGetSymbolAddress((void**)&pGi,   g_gi);
    cudaGetSymbolAddress((void**)&pGh,   g_gh);

    static const int ATTN_SMEM = (NH_*D_ + CH*D_ + CH*NH_ + 2*NH_) * 4;
    cudaFuncSetAttribute(k_attn, cudaFuncAttributeMaxDynamicSharedMemorySize, ATTN_SMEM);

    // ---- preamble ----
    k_transpose<<<256, 512>>>(Wk, pWkT);
    k_build_hblk<<<B_, 512>>>(emb, stc, off, sep);
    k_gemm<false,false><<<dim3(8, 32, 1), 256>>>(pHblk, 512, 0, W1, 512, 0,
                                                 pT, 512, 0, nullptr, 2048, 512, 512);
    k_a<<<2048, 256>>>(W2);
    k_s1<<<L_, 512>>>();
    k_b0<<<B_, 512>>>(ln_g, ln_b, pe);
    k_buildH<<<dim3(S_, B_), 128>>>(emb, pe, seg, ln_g, ln_b, stc, off);

    // ---- 3 GRU iterations ----
    for (int it = 0; it < 3; it++) {
        // q = bt @ Wq + bq
        k_gemm<false,true><<<dim3(8, 8, 1), 256>>>(pBt, 512, 0, Wq, 512, 0,
                                                   pQ, 512, 0, bq, 512, 512, 512);
        // gh = bt @ W_hh^T + b_hh
        k_gemm<true,true><<<dim3(24, 8, 1), 256>>>(pBt, 512, 0, W_hh, 512, 0,
                                                   pGh, 1536, 0, b_hh, 512, 1536, 512);
        // uK (per-head): uK[b,h,:] = q_h @ WkT_h
        k_gemm<false,false><<<dim3(8, 8, 8), 256>>>(pQ, 512, 64, pWkT, 512, 64*512,
                                                    pUK, 4096, 512, nullptr, 512, 512, 64);
        // fused attention: scores+sigmoid+ctx+psum
        k_attn<<<B_, 512, ATTN_SMEM>>>(bk, stc);
        // mraw (per-head): ctx_h @ Wv_h
        k_gemm<false,false><<<dim3(1, 8, 8), 256>>>(pCtx, 4096, 512, Wv + 0, 512, 64,
                                                    pMraw, 512, 64, nullptr, 512, 64, 512);
        // m_t = LN(mraw + psum*bv)
        k_ln_mt<<<B_, 512>>>(bv, lng_g, lng_b);
        // gi = m_t @ W_ih^T + b_ih
        k_gemm<true,true><<<dim3(24, 8, 1), 256>>>(pMt, 512, 0, W_ih, 512, 0,
                                                   pGi, 1536, 0, b_ih, 512, 1536, 512);
        // GRU update of b_t
        k_gru<<<B_, 512>>>();
    }
    k_copy<<<B_, 512>>>(out);
    (void)in_sizes; (void)n_in; (void)out_size;
}

// round 3
// speedup vs baseline: 1.5967x; 1.5967x over previous
#include <cuda_runtime.h>
#include <math.h>

#define B_  512
#define S_  200
#define D_  512
#define NH_ 8
#define L_  4
#define CH  32

// ---------------- scratch (device globals) ----------------------------------
__device__ float g_hblk[B_*L_*D_];
__device__ float g_valid[B_*L_];
__device__ float g_a[B_*L_];
__device__ float g_s1[B_*L_];
__device__ float g_bt[B_*D_];
__device__ float g_H[B_*S_*D_];          // 210 MB
__device__ float g_WkT[D_*D_];
__device__ float g_Wcomb[D_*2048];       // [Wq | W_hh^T]
__device__ float g_WihT[D_*1536];
__device__ float g_bcomb[2048];
__device__ float g_q[B_*D_];
__device__ float g_gh[B_*3*D_];
__device__ float g_uK[B_*NH_*D_];
__device__ float g_ctx[B_*NH_*D_];
__device__ float g_psum[B_*NH_];
__device__ float g_mraw[B_*D_];
__device__ float g_mt[B_*D_];
__device__ float g_part[2*512*2048];     // split-K partials (reused)

// ---------------- helpers ----------------------------------------------------
__device__ __forceinline__ float warpSum(float v) {
    #pragma unroll
    for (int o = 16; o; o >>= 1) v += __shfl_down_sync(0xffffffffu, v, o);
    return v;
}
__device__ __forceinline__ float warpMax(float v) {
    #pragma unroll
    for (int o = 16; o; o >>= 1) v = fmaxf(v, __shfl_down_sync(0xffffffffu, v, o));
    return v;
}
__device__ __forceinline__ float blockSum(float v, float* red) {
    int lane = threadIdx.x & 31, w = threadIdx.x >> 5;
    v = warpSum(v);
    if (lane == 0) red[w] = v;
    __syncthreads();
    float r = 0.f;
    if (threadIdx.x < (blockDim.x >> 5)) r = red[threadIdx.x];
    if (w == 0) r = warpSum(r);
    if (threadIdx.x == 0) red[0] = r;
    __syncthreads();
    r = red[0];
    __syncthreads();
    return r;
}
__device__ __forceinline__ float blockMax(float v, float* red) {
    int lane = threadIdx.x & 31, w = threadIdx.x >> 5;
    v = warpMax(v);
    if (lane == 0) red[w] = v;
    __syncthreads();
    float r = -3.0e38f;
    if (threadIdx.x < (blockDim.x >> 5)) r = red[threadIdx.x];
    if (w == 0) r = warpMax(r);
    if (threadIdx.x == 0) red[0] = r;
    __syncthreads();
    r = red[0];
    __syncthreads();
    return r;
}
__device__ __forceinline__ float sigm(float x) { return 1.f / (1.f + expf(-x)); }
#define DOT4(u, h) ((u).x*(h).x + (u).y*(h).y + (u).z*(h).z + (u).w*(h).w)

// ---------------- 128xBN SIMT GEMM (256 thr, 8x(BN/16) acc, dbuf) -----------
// C[128, BN] tile of A[M,Kd] @ B[Kd,N].  B is K-major (Kd x N row-major).
// blockIdx.z batches via (sA, sB, sC) pointer offsets (heads OR split-K).
// All dims exact multiples of tile sizes; Kd % 8 == 0.
template <int BN>
__global__ __launch_bounds__(256) void k_gemm(
    const float* __restrict__ A, int lda, int sA,
    const float* __restrict__ B, int ldb, int sB,
    float* __restrict__ C, int ldc, int sC, int Kd)
{
    const int NF = BN / 16;          // 8 or 4 accum cols
    const float* Ab = A + (long)blockIdx.z * sA;
    const float* Bb = B + (long)blockIdx.z * sB;
    float* Cb = C + (long)blockIdx.z * sC;
    int m0 = blockIdx.y * 128, n0 = blockIdx.x * BN;
    __shared__ float As[2][8][132];
    __shared__ float Bs[2][8][BN + 4];
    int tid = threadIdx.x, tx = tid & 15, ty = tid >> 4;
    // A loader: thread -> (row am, k-quad ak)
    int am = tid >> 1, ak = (tid & 1) * 4;
    const float* Aptr = Ab + (long)(m0 + am) * lda + ak;
    // B loader
    int bkr, bnc; bool bact;
    if (BN == 128) { bkr = tid >> 5; bnc = (tid & 31) * 4; bact = true; }
    else           { bkr = tid >> 4; bnc = (tid & 15) * 4; bact = (tid < 128); }
    const float* Bptr = Bb + (long)bkr * ldb + n0 + bnc;

    float acc[8][NF];
    #pragma unroll
    for (int i = 0; i < 8; i++)
        #pragma unroll
        for (int j = 0; j < NF; j++) acc[i][j] = 0.f;

    int nch = Kd >> 3;
    float4 va = *(const float4*)Aptr;
    float4 vb = bact ? *(const float4*)Bptr : make_float4(0,0,0,0);
    As[0][ak+0][am] = va.x; As[0][ak+1][am] = va.y;
    As[0][ak+2][am] = va.z; As[0][ak+3][am] = va.w;
    if (bact) *(float4*)&Bs[0][bkr][bnc] = vb;
    __syncthreads();

    for (int c = 1; c <= nch; c++) {
        if (c < nch) {
            va = *(const float4*)(Aptr + c * 8);
            if (bact) vb = *(const float4*)(Bptr + (long)c * 8 * ldb);
        }
        int st = (c - 1) & 1;
        #pragma unroll
        for (int k = 0; k < 8; k++) {
            float4 a0 = *(const float4*)&As[st][k][ty * 4];
            float4 a1 = *(const float4*)&As[st][k][64 + ty * 4];
            float4 b0 = *(const float4*)&Bs[st][k][tx * 4];
            float am_[8] = {a0.x, a0.y, a0.z, a0.w, a1.x, a1.y, a1.z, a1.w};
            #pragma unroll
            for (int i = 0; i < 8; i++) {
                acc[i][0] += am_[i] * b0.x; acc[i][1] += am_[i] * b0.y;
                acc[i][2] += am_[i] * b0.z; acc[i][3] += am_[i] * b0.w;
            }
            if (BN == 128) {
                float4 b1 = *(const float4*)&Bs[st][k][64 + tx * 4];
                #pragma unroll
                for (int i = 0; i < 8; i++) {
                    acc[i][4] += am_[i] * b1.x; acc[i][5] += am_[i] * b1.y;
                    acc[i][6] += am_[i] * b1.z; acc[i][7] += am_[i] * b1.w;
                }
            }
        }
        if (c < nch) {
            int nx = c & 1;
            As[nx][ak+0][am] = va.x; As[nx][ak+1][am] = va.y;
            As[nx][ak+2][am] = va.z; As[nx][ak+3][am] = va.w;
            if (bact) *(float4*)&Bs[nx][bkr][bnc] = vb;
        }
        __syncthreads();
    }
    #pragma unroll
    for (int i = 0; i < 8; i++) {
        int row = m0 + ((i < 4) ? (ty * 4 + i) : (64 + ty * 4 + i - 4));
        float4 o0 = make_float4(acc[i][0], acc[i][1], acc[i][2], acc[i][3]);
        *(float4*)(Cb + (long)row * ldc + n0 + tx * 4) = o0;
        if (BN == 128) {
            float4 o1 = make_float4(acc[i][4], acc[i][5], acc[i][6], acc[i][7]);
            *(float4*)(Cb + (long)row * ldc + n0 + 64 + tx * 4) = o1;
        }
    }
}

// ---------------- transpose / weight prep ------------------------------------
// dst[j, i] = src[i, j]; src is R x C (ldS), dst is C x R (ldD). Dims %32==0.
__global__ __launch_bounds__(256) void k_tr(const float* __restrict__ src, int ldS,
                                            float* __restrict__ dst, int ldD)
{
    __shared__ float t[32][33];
    int bx = blockIdx.x * 32, by = blockIdx.y * 32;
    int lx = threadIdx.x & 31, wy = threadIdx.x >> 5;
    #pragma unroll
    for (int j = wy; j < 32; j += 8)
        t[j][lx] = src[(long)(by + j) * ldS + bx + lx];
    __syncthreads();
    #pragma unroll
    for (int j = wy; j < 32; j += 8)
        dst[(long)(bx + j) * ldD + by + lx] = t[lx][j];
}

__global__ __launch_bounds__(512) void k_cpWq(const float* __restrict__ Wq)
{
    int k = blockIdx.x;
    g_Wcomb[(long)k * 2048 + threadIdx.x] = Wq[k * 512 + threadIdx.x];
}

__global__ __launch_bounds__(512) void k_bcomb(const float* __restrict__ bq,
                                               const float* __restrict__ b_hh)
{
    int j = blockIdx.x * 512 + threadIdx.x;
    g_bcomb[j] = (j < 512) ? bq[j] : b_hh[j - 512];
}

// ---------------- preamble -----------------------------------------------------
__global__ __launch_bounds__(512) void k_build_hblk(
    const float* __restrict__ emb, const int* __restrict__ stc,
    const int* __restrict__ off, const int* __restrict__ sep)
{
    int b = blockIdx.x;
    int o = off[b], len = stc[b];
    int sA = sep[b * 2], sB2 = sep[b * 2 + 1];
    int idx = (sA < o ? 1 : 0) + (sB2 < o ? 1 : 0);
    int pidx = idx - 1; pidx = pidx < 0 ? 0 : (pidx > 1 ? 1 : pidx);
    int prev = (pidx == 0) ? sA : sB2;
    int left = (idx > 0) ? prev + 1 : 0;
    int nidx = idx > 1 ? 1 : idx;
    int nxt = (nidx == 0) ? sA : sB2;
    int right = (idx < 2) ? nxt : len;
    int start = (o - 2 > left) ? o - 2 : left;
    int end = (o + 2 < right) ? o + 2 : right;
    int t = threadIdx.x;
    #pragma unroll
    for (int l = 0; l < L_; l++) {
        int ind = start + l;
        bool v = ind < end;
        int ic = ind < 0 ? 0 : (ind > S_ - 1 ? S_ - 1 : ind);
        g_hblk[(b * L_ + l) * D_ + t] = v ? emb[((long)b * S_ + ic) * D_ + t] : 0.f;
        if (t == 0) g_valid[b * L_ + l] = v ? 1.f : 0.f;
    }
}

__global__ __launch_bounds__(256) void k_a(const float* __restrict__ W2)
{
    int m = blockIdx.x, t = threadIdx.x;
    const long off = 2048L * 512;
    float t0 = tanhf(g_part[(long)m * 512 + t] + g_part[off + (long)m * 512 + t]);
    float t1 = tanhf(g_part[(long)m * 512 + t + 256] + g_part[off + (long)m * 512 + t + 256]);
    float v = t0 * W2[t] + t1 * W2[t + 256];
    __shared__ float red[32];
    v = blockSum(v, red);
    if (t == 0) g_a[m] = v;
}

__global__ __launch_bounds__(512) void k_s1()
{
    int l = blockIdx.x, t = threadIdx.x;
    __shared__ float red[32];
    float v = g_a[t * L_ + l];
    float mx = blockMax(v, red);
    float e = expf(v - mx);
    float s = blockSum(e, red);
    g_s1[t * L_ + l] = e / s;
}

__global__ __launch_bounds__(512) void k_b0(
    const float* __restrict__ ln_g, const float* __restrict__ ln_b,
    const float* __restrict__ pe)
{
    int b = blockIdx.x, t = threadIdx.x;
    __shared__ float sc[4];
    __shared__ float red[32];
    if (t == 0) {
        float vals[4], mx = -3.0e38f;
        #pragma unroll
        for (int l = 0; l < 4; l++) {
            float v = (g_valid[b * 4 + l] > 0.5f) ? g_s1[b * 4 + l] : -1e9f;
            vals[l] = v; mx = fmaxf(mx, v);
        }
        float s = 0.f;
        #pragma unroll
        for (int l = 0; l < 4; l++) { float e = expf(vals[l] - mx); sc[l] = e; s += e; }
        #pragma unroll
        for (int l = 0; l < 4; l++) sc[l] /= s;
    }
    __syncthreads();
    float x = sc[0] * g_hblk[(b * 4 + 0) * D_ + t] + sc[1] * g_hblk[(b * 4 + 1) * D_ + t]
            + sc[2] * g_hblk[(b * 4 + 2) * D_ + t] + sc[3] * g_hblk[(b * 4 + 3) * D_ + t]
            + pe[t];
    float mean = blockSum(x, red) * (1.f / 512.f);
    float d = x - mean;
    float var = blockSum(d * d, red) * (1.f / 512.f);
    g_bt[b * D_ + t] = d * rsqrtf(var + 1e-5f) * ln_g[t] + ln_b[t];
}

__global__ __launch_bounds__(128) void k_buildH(
    const float* __restrict__ emb, const float* __restrict__ pe,
    const float* __restrict__ seg_emb, const float* __restrict__ ln_g,
    const float* __restrict__ ln_b, const int* __restrict__ stc,
    const int* __restrict__ off)
{
    int b = blockIdx.y, s = blockIdx.x;
    if (s >= stc[b]) return;
    int pos = off[b];
    int ip = (s < pos) ? (pos - s) : (s + 1 - pos);
    ip = ip < 0 ? 0 : (ip > S_ ? S_ : ip);
    int sg = (s >= pos) ? 1 : 0;
    int t = threadIdx.x;
    __shared__ float red[32];
    float4 e = *(const float4*)(emb + ((long)b * S_ + s) * D_ + t * 4);
    float4 p = *(const float4*)(pe + (long)ip * D_ + t * 4);
    float4 g = *(const float4*)(seg_emb + sg * D_ + t * 4);
    float x0 = e.x + p.x + g.x, x1 = e.y + p.y + g.y;
    float x2 = e.z + p.z + g.z, x3 = e.w + p.w + g.w;
    float mean = blockSum(x0 + x1 + x2 + x3, red) * (1.f / 512.f);
    float d0 = x0 - mean, d1 = x1 - mean, d2 = x2 - mean, d3 = x3 - mean;
    float var = blockSum(d0 * d0 + d1 * d1 + d2 * d2 + d3 * d3, red) * (1.f / 512.f);
    float inv = rsqrtf(var + 1e-5f);
    float4 gg = *(const float4*)(ln_g + t * 4);
    float4 bb = *(const float4*)(ln_b + t * 4);
    float4 o;
    o.x = d0 * inv * gg.x + bb.x; o.y = d1 * inv * gg.y + bb.y;
    o.z = d2 * inv * gg.z + bb.z; o.w = d3 * inv * gg.w + bb.w;
    *(float4*)(g_H + ((long)b * S_ + s) * D_ + t * 4) = o;
}

// ---------------- per-iter epilogue kernels -----------------------------------
__global__ __launch_bounds__(512) void k_qgh()
{
    int b = blockIdx.x;
    const long off = 512L * 2048;
    #pragma unroll
    for (int jj = 0; jj < 4; jj++) {
        int j = jj * 512 + threadIdx.x;
        float v = g_part[(long)b * 2048 + j] + g_part[off + (long)b * 2048 + j] + g_bcomb[j];
        if (j < 512) g_q[b * 512 + j] = v;
        else         g_gh[b * 1536 + j - 512] = v;
    }
}

// ---------------- fused attention (256 thr, per-batch CTA) --------------------
__global__ __launch_bounds__(256) void k_attn(
    const float* __restrict__ bk, const int* __restrict__ stc)
{
    int b = blockIdx.x;
    int tid = threadIdx.x, lane = tid & 31, warp = tid >> 5;   // 8 warps
    extern __shared__ float sm[];
    float* uKs = sm;                    // 8*512
    float* Hs  = sm + NH_ * D_;         // 32*512
    float* ps  = Hs + CH * D_;          // 32*8  [s][h]
    float* cKs = ps + CH * NH_;         // 8
    float* pss = cKs + NH_;             // 8
    int len = stc[b];
    // stage uK (4096 floats = 1024 f4)
    {
        const float4* src = (const float4*)(g_uK + (long)b * NH_ * D_);
        float4* dst = (float4*)uKs;
        #pragma unroll
        for (int i = 0; i < 4; i++) dst[i * 256 + tid] = src[i * 256 + tid];
    }
    // cK[h] = bk_h . q_h
    {
        float v = bk[warp * 64 + lane] * g_q[b * D_ + warp * 64 + lane]
                + bk[warp * 64 + 32 + lane] * g_q[b * D_ + warp * 64 + 32 + lane];
        v = warpSum(v);
        if (lane == 0) { cKs[warp] = v; pss[warp] = 0.f; }
    }
    float creg[16] = {0.f,0.f,0.f,0.f,0.f,0.f,0.f,0.f,0.f,0.f,0.f,0.f,0.f,0.f,0.f,0.f};
    __syncthreads();
    int nch = (len + CH - 1) / CH;
    for (int c = 0; c < nch; c++) {
        int s0 = c * CH;
        // stage H chunk: each warp 4 rows, zeros past len
        for (int r = warp; r < CH; r += 8) {
            int s = s0 + r;
            float4* dst = (float4*)(Hs + r * D_);
            if (s < len) {
                const float4* src = (const float4*)(g_H + ((long)b * S_ + s) * D_);
                #pragma unroll
                for (int i = 0; i < 4; i++) dst[i * 32 + lane] = src[i * 32 + lane];
            } else {
                float4 z = make_float4(0,0,0,0);
                #pragma unroll
                for (int i = 0; i < 4; i++) dst[i * 32 + lane] = z;
            }
        }
        ps[tid] = 0.f;
        __syncthreads();
        // scores: two passes of 4 heads; uK slices register-resident per pass
        #pragma unroll
        for (int pass = 0; pass < 2; pass++) {
            int hb = pass * 4;
            float4 u[4][4];
            #pragma unroll
            for (int hh = 0; hh < 4; hh++)
                #pragma unroll
                for (int i = 0; i < 4; i++)
                    u[hh][i] = *(const float4*)(uKs + (hb + hh) * D_ + (i * 32 + lane) * 4);
            #pragma unroll
            for (int rr = 0; rr < 4; rr++) {
                int r = warp * 4 + rr;
                float4 h4[4];
                #pragma unroll
                for (int i = 0; i < 4; i++)
                    h4[i] = *(const float4*)(Hs + r * D_ + (i * 32 + lane) * 4);
                float acc[4];
                #pragma unroll
                for (int hh = 0; hh < 4; hh++) {
                    acc[hh] = DOT4(u[hh][0], h4[0]) + DOT4(u[hh][1], h4[1])
                            + DOT4(u[hh][2], h4[2]) + DOT4(u[hh][3], h4[3]);
                    acc[hh] = warpSum(acc[hh]);
                }
                if (lane == 0) {
                    int s = s0 + r;
                    if (s < len) {
                        #pragma unroll
                        for (int hh = 0; hh < 4; hh++)
                            ps[r * NH_ + hb + hh] = sigm(0.125f * (acc[hh] + cKs[hb + hh]));
                    }
                }
            }
        }
        __syncthreads();
        // ctx: thread owns dims tid and tid+256
        #pragma unroll 4
        for (int r = 0; r < CH; r++) {
            float hv0 = Hs[r * D_ + tid];
            float hv1 = Hs[r * D_ + tid + 256];
            float4 p0 = *(const float4*)(ps + r * NH_);
            float4 p1 = *(const float4*)(ps + r * NH_ + 4);
            creg[0] += p0.x * hv0; creg[1] += p0.y * hv0;
            creg[2] += p0.z * hv0; creg[3] += p0.w * hv0;
            creg[4] += p1.x * hv0; creg[5] += p1.y * hv0;
            creg[6] += p1.z * hv0; creg[7] += p1.w * hv0;
            creg[8]  += p0.x * hv1; creg[9]  += p0.y * hv1;
            creg[10] += p0.z * hv1; creg[11] += p0.w * hv1;
            creg[12] += p1.x * hv1; creg[13] += p1.y * hv1;
            creg[14] += p1.z * hv1; creg[15] += p1.w * hv1;
        }
        // psum
        {
            float v = ps[lane * NH_ + warp];
            v = warpSum(v);
            if (lane == 0) pss[warp] += v;
        }
        __syncthreads();
    }
    #pragma unroll
    for (int h = 0; h < NH_; h++) {
        g_ctx[((long)b * NH_ + h) * D_ + tid]       = creg[h];
        g_ctx[((long)b * NH_ + h) * D_ + tid + 256] = creg[8 + h];
    }
    if (tid < NH_) g_psum[b * NH_ + tid] = pss[tid];
}

// ---------------- small per-iter kernels --------------------------------------
__global__ __launch_bounds__(512) void k_ln_mt(
    const float* __restrict__ bv, const float* __restrict__ lng_g,
    const float* __restrict__ lng_b)
{
    int b = blockIdx.x, t = threadIdx.x;
    __shared__ float red[32];
    float x = g_mraw[b * D_ + t] + g_psum[b * NH_ + (t >> 6)] * bv[t];
    float mean = blockSum(x, red) * (1.f / 512.f);
    float d = x - mean;
    float var = blockSum(d * d, red) * (1.f / 512.f);
    g_mt[b * D_ + t] = d * rsqrtf(var + 1e-5f) * lng_g[t] + lng_b[t];
}

__global__ __launch_bounds__(512) void k_gru(const float* __restrict__ b_ih)
{
    int b = blockIdx.x, t = threadIdx.x;
    const float* P0 = g_part + (long)b * 1536;
    const float* P1 = g_part + 512L * 1536 + (long)b * 1536;
    float ir = P0[t]        + P1[t]        + b_ih[t];
    float iz = P0[t + 512]  + P1[t + 512]  + b_ih[t + 512];
    float in = P0[t + 1024] + P1[t + 1024] + b_ih[t + 1024];
    float hr = g_gh[b * 1536 + t];
    float hz = g_gh[b * 1536 + 512 + t];
    float hn = g_gh[b * 1536 + 1024 + t];
    float r = sigm(ir + hr);
    float z = sigm(iz + hz);
    float n = tanhf(in + r * hn);
    float old = g_bt[b * D_ + t];
    g_bt[b * D_ + t] = (1.f - z) * n + z * old;
}

__global__ __launch_bounds__(512) void k_copy(float* __restrict__ out)
{
    out[blockIdx.x * 512 + threadIdx.x] = g_bt[blockIdx.x * 512 + threadIdx.x];
}

// ---------------- launch --------------------------------------------------------
extern "C" void kernel_launch(void* const* d_in, const int* in_sizes, int n_in,
                              void* d_out, int out_size)
{
    const float* emb   = (const float*)d_in[0];
    const int*   stc   = (const int*)  d_in[1];
    const int*   off   = (const int*)  d_in[2];
    const int*   sep   = (const int*)  d_in[3];
    const float* W1    = (const float*)d_in[4];
    const float* W2    = (const float*)d_in[5];
    const float* ln_g  = (const float*)d_in[6];
    const float* ln_b  = (const float*)d_in[7];
    const float* lng_g = (const float*)d_in[8];
    const float* lng_b = (const float*)d_in[9];
    const float* Wq    = (const float*)d_in[10];
    const float* bq    = (const float*)d_in[11];
    const float* Wk    = (const float*)d_in[12];
    const float* bk    = (const float*)d_in[13];
    const float* Wv    = (const float*)d_in[14];
    const float* bv    = (const float*)d_in[15];
    const float* W_ih  = (const float*)d_in[16];
    const float* W_hh  = (const float*)d_in[17];
    const float* b_ih  = (const float*)d_in[18];
    const float* b_hh  = (const float*)d_in[19];
    const float* seg   = (const float*)d_in[20];
    const float* pe    = (const float*)d_in[21];
    float* out = (float*)d_out;

    float *pHblk, *pBt, *pWkT, *pWcomb, *pWihT, *pQ, *pUK, *pCtx, *pMraw, *pMt, *pPart;
    cudaGetSymbolAddress((void**)&pHblk,  g_hblk);
    cudaGetSymbolAddress((void**)&pBt,    g_bt);
    cudaGetSymbolAddress((void**)&pWkT,   g_WkT);
    cudaGetSymbolAddress((void**)&pWcomb, g_Wcomb);
    cudaGetSymbolAddress((void**)&pWihT,  g_WihT);
    cudaGetSymbolAddress((void**)&pQ,     g_q);
    cudaGetSymbolAddress((void**)&pUK,    g_uK);
    cudaGetSymbolAddress((void**)&pCtx,   g_ctx);
    cudaGetSymbolAddress((void**)&pMraw,  g_mraw);
    cudaGetSymbolAddress((void**)&pMt,    g_mt);
    cudaGetSymbolAddress((void**)&pPart,  g_part);

    static const int ATTN_SMEM = (NH_*D_ + CH*D_ + CH*NH_ + 2*NH_) * 4;
    cudaFuncSetAttribute(k_attn, cudaFuncAttributeMaxDynamicSharedMemorySize, ATTN_SMEM);

    // ---- preamble: weight prep ----
    k_tr<<<dim3(16, 16), 256>>>(Wk, 512, pWkT, 512);               // Wk^T
    k_tr<<<dim3(16, 48), 256>>>(W_hh, 512, pWcomb + 512, 2048);    // W_hh^T -> comb[:,512:]
    k_tr<<<dim3(16, 48), 256>>>(W_ih, 512, pWihT, 1536);           // W_ih^T
    k_cpWq<<<512, 512>>>(Wq);                                      // Wq -> comb[:,0:512]
    k_bcomb<<<4, 512>>>(bq, b_hh);

    // ---- preamble: b0 / H ----
    k_build_hblk<<<B_, 512>>>(emb, stc, off, sep);
    // T = hblk @ W1 (split-K=2 into parts)
    k_gemm<128><<<dim3(4, 16, 2), 256>>>(pHblk, 512, 256, W1, 512, 256*512,
                                         pPart, 512, 2048*512, 256);
    k_a<<<2048, 256>>>(W2);
    k_s1<<<L_, 512>>>();
    k_b0<<<B_, 512>>>(ln_g, ln_b, pe);
    k_buildH<<<dim3(S_, B_), 128>>>(emb, pe, seg, ln_g, ln_b, stc, off);

    // ---- 3 GRU iterations ----
    for (int it = 0; it < 3; it++) {
        // [q | gh] = bt @ Wcomb (split-K=2)
        k_gemm<128><<<dim3(16, 4, 2), 256>>>(pBt, 512, 256, pWcomb, 2048, 256*2048,
                                             pPart, 2048, 512*2048, 256);
        k_qgh<<<B_, 512>>>();
        // uK[b,h,:] = q_h @ WkT_h (z = head)
        k_gemm<128><<<dim3(4, 4, 8), 256>>>(pQ, 512, 64, pWkT, 512, 64*512,
                                            pUK, 4096, 512, 64);
        // fused attention
        k_attn<<<B_, 256, ATTN_SMEM>>>(bk, stc);
        // mraw_h = ctx_h @ Wv_h (z = head)
        k_gemm<64><<<dim3(1, 4, 8), 256>>>(pCtx, 4096, 512, Wv, 512, 64,
                                           pMraw, 512, 64, 512);
        k_ln_mt<<<B_, 512>>>(bv, lng_g, lng_b);
        // gi = mt @ W_ih^T (split-K=2)
        k_gemm<128><<<dim3(12, 4, 2), 256>>>(pMt, 512, 256, pWihT, 1536, 256*1536,
                                             pPart, 1536, 512*1536, 256);
        k_gru<<<B_, 512>>>(b_ih);
    }
    k_copy<<<B_, 512>>>(out);
    (void)in_sizes; (void)n_in; (void)out_size;
}

// round 4
// speedup vs baseline: 1.8458x; 1.1560x over previous
#include <cuda_runtime.h>
#include <math.h>

#define B_  512
#define S_  200
#define D_  512
#define NH_ 8
#define L_  4
#define CH  32

// ---------------- scratch (device globals) ----------------------------------
__device__ float g_hblk[B_*L_*D_];
__device__ float g_valid[B_*L_];
__device__ float g_a[B_*L_];
__device__ float g_s1[B_*L_];
__device__ float g_bt[B_*D_];
__device__ float g_H[B_*S_*D_];          // 210 MB
__device__ float g_WkT[D_*D_];
__device__ float g_Wcomb[D_*2048];       // [Wq | W_hh^T]
__device__ float g_WihT[D_*1536];
__device__ float g_uK[B_*NH_*D_];
__device__ float g_ctx[B_*NH_*D_];
__device__ float g_psum[B_*NH_];
__device__ float g_mt[B_*D_];
__device__ float g_partC[2*B_*2048];     // comb / W1 split-K partials
__device__ float g_partM[4*B_*D_];       // mraw split-K partials
__device__ float g_partG[2*B_*1536];     // gi split-K partials

#define PC1_OFF 1048576L   // 512*2048
#define PM_OFF  262144L    // 512*512
#define PG1_OFF 786432L    // 512*1536

// ---------------- helpers ----------------------------------------------------
__device__ __forceinline__ float warpSum(float v) {
    #pragma unroll
    for (int o = 16; o; o >>= 1) v += __shfl_down_sync(0xffffffffu, v, o);
    return v;
}
__device__ __forceinline__ float warpMax(float v) {
    #pragma unroll
    for (int o = 16; o; o >>= 1) v = fmaxf(v, __shfl_down_sync(0xffffffffu, v, o));
    return v;
}
__device__ __forceinline__ float blockSum(float v, float* red) {
    int lane = threadIdx.x & 31, w = threadIdx.x >> 5;
    v = warpSum(v);
    if (lane == 0) red[w] = v;
    __syncthreads();
    float r = 0.f;
    if (threadIdx.x < (blockDim.x >> 5)) r = red[threadIdx.x];
    if (w == 0) r = warpSum(r);
    if (threadIdx.x == 0) red[0] = r;
    __syncthreads();
    r = red[0];
    __syncthreads();
    return r;
}
__device__ __forceinline__ float blockMax(float v, float* red) {
    int lane = threadIdx.x & 31, w = threadIdx.x >> 5;
    v = warpMax(v);
    if (lane == 0) red[w] = v;
    __syncthreads();
    float r = -3.0e38f;
    if (threadIdx.x < (blockDim.x >> 5)) r = red[threadIdx.x];
    if (w == 0) r = warpMax(r);
    if (threadIdx.x == 0) red[0] = r;
    __syncthreads();
    r = red[0];
    __syncthreads();
    return r;
}
__device__ __forceinline__ float sigm(float x) { return 1.f / (1.f + expf(-x)); }
#define DOT4(u, h) ((u).x*(h).x + (u).y*(h).y + (u).z*(h).z + (u).w*(h).w)

// ---------------- GEMM core: 128xBN tile, 256 thr, dbuf ---------------------
// C tile of A[M,Kd] @ B[Kd,N], B K-major. If COMPOSE, A = A0 + A1 + bias[k].
template <int BN, bool COMPOSE>
__device__ __forceinline__ void gemm_core(
    const float* __restrict__ A0, const float* __restrict__ A1,
    const float* __restrict__ Abias, int lda,
    const float* __restrict__ Bb, int ldb,
    float* __restrict__ Cb, int ldc, int Kd, int m0, int n0)
{
    const int NF = BN / 16;
    __shared__ float As[2][8][132];
    __shared__ float Bs[2][8][BN + 4];
    int tid = threadIdx.x, tx = tid & 15, ty = tid >> 4;
    int am = tid >> 1, ak = (tid & 1) * 4;
    const float* Aptr0 = A0 + (long)(m0 + am) * lda + ak;
    const float* Aptr1 = COMPOSE ? (A1 + (long)(m0 + am) * lda + ak) : nullptr;
    int bkr, bnc; bool bact;
    if (BN == 128) { bkr = tid >> 5; bnc = (tid & 31) * 4; bact = true; }
    else           { bkr = tid >> 4; bnc = (tid & 15) * 4; bact = (tid < 128); }
    const float* Bptr = Bb + (long)bkr * ldb + n0 + bnc;

    float acc[8][NF];
    #pragma unroll
    for (int i = 0; i < 8; i++)
        #pragma unroll
        for (int j = 0; j < NF; j++) acc[i][j] = 0.f;

    int nch = Kd >> 3;
    float4 va = *(const float4*)Aptr0;
    if (COMPOSE) {
        float4 v1 = *(const float4*)Aptr1;
        float4 bi = *(const float4*)(Abias + ak);
        va.x += v1.x + bi.x; va.y += v1.y + bi.y;
        va.z += v1.z + bi.z; va.w += v1.w + bi.w;
    }
    float4 vb = bact ? *(const float4*)Bptr : make_float4(0,0,0,0);
    As[0][ak+0][am] = va.x; As[0][ak+1][am] = va.y;
    As[0][ak+2][am] = va.z; As[0][ak+3][am] = va.w;
    if (bact) *(float4*)&Bs[0][bkr][bnc] = vb;
    __syncthreads();

    for (int c = 1; c <= nch; c++) {
        if (c < nch) {
            va = *(const float4*)(Aptr0 + c * 8);
            if (COMPOSE) {
                float4 v1 = *(const float4*)(Aptr1 + c * 8);
                float4 bi = *(const float4*)(Abias + c * 8 + ak);
                va.x += v1.x + bi.x; va.y += v1.y + bi.y;
                va.z += v1.z + bi.z; va.w += v1.w + bi.w;
            }
            if (bact) vb = *(const float4*)(Bptr + (long)c * 8 * ldb);
        }
        int st = (c - 1) & 1;
        #pragma unroll
        for (int k = 0; k < 8; k++) {
            float4 a0 = *(const float4*)&As[st][k][ty * 4];
            float4 a1 = *(const float4*)&As[st][k][64 + ty * 4];
            float4 b0 = *(const float4*)&Bs[st][k][tx * 4];
            float am_[8] = {a0.x, a0.y, a0.z, a0.w, a1.x, a1.y, a1.z, a1.w};
            #pragma unroll
            for (int i = 0; i < 8; i++) {
                acc[i][0] += am_[i] * b0.x; acc[i][1] += am_[i] * b0.y;
                acc[i][2] += am_[i] * b0.z; acc[i][3] += am_[i] * b0.w;
            }
            if (BN == 128) {
                float4 b1 = *(const float4*)&Bs[st][k][64 + tx * 4];
                #pragma unroll
                for (int i = 0; i < 8; i++) {
                    acc[i][4] += am_[i] * b1.x; acc[i][5] += am_[i] * b1.y;
                    acc[i][6] += am_[i] * b1.z; acc[i][7] += am_[i] * b1.w;
                }
            }
        }
        if (c < nch) {
            int nx = c & 1;
            As[nx][ak+0][am] = va.x; As[nx][ak+1][am] = va.y;
            As[nx][ak+2][am] = va.z; As[nx][ak+3][am] = va.w;
            if (bact) *(float4*)&Bs[nx][bkr][bnc] = vb;
        }
        __syncthreads();
    }
    #pragma unroll
    for (int i = 0; i < 8; i++) {
        int row = m0 + ((i < 4) ? (ty * 4 + i) : (64 + ty * 4 + i - 4));
        float4 o0 = make_float4(acc[i][0], acc[i][1], acc[i][2], acc[i][3]);
        *(float4*)(Cb + (long)row * ldc + n0 + tx * 4) = o0;
        if (BN == 128) {
            float4 o1 = make_float4(acc[i][4], acc[i][5], acc[i][6], acc[i][7]);
            *(float4*)(Cb + (long)row * ldc + n0 + 64 + tx * 4) = o1;
        }
    }
}

// generic wrapper (z-batched via strides)
template <int BN>
__global__ __launch_bounds__(256) void k_gemm(
    const float* __restrict__ A, int lda, int sA,
    const float* __restrict__ B, int ldb, int sB,
    float* __restrict__ C, int ldc, int sC, int Kd)
{
    int z = blockIdx.z;
    gemm_core<BN, false>(A + (long)z * sA, nullptr, nullptr, lda,
                         B + (long)z * sB, ldb, C + (long)z * sC, ldc, Kd,
                         blockIdx.y * 128, blockIdx.x * BN);
}

// uK GEMM: per head h, A = q_h composed from comb partials + bq
__global__ __launch_bounds__(256) void k_gemm_uk(const float* __restrict__ bq)
{
    int h = blockIdx.z;
    gemm_core<128, true>(g_partC + h * 64, g_partC + PC1_OFF + h * 64, bq + h * 64,
                         2048, g_WkT + (long)h * 64 * 512, 512,
                         g_uK + h * 512, 4096, 64,
                         blockIdx.y * 128, blockIdx.x * 128);
}

// mraw GEMM: z = h*4 + ksplit; per head M=512,N=64,K=512 split into 4
__global__ __launch_bounds__(256) void k_gemm_mraw(const float* __restrict__ Wv)
{
    int z = blockIdx.z, h = z >> 2, ks = z & 3;
    gemm_core<64, false>(g_ctx + h * 512 + ks * 128, nullptr, nullptr, 4096,
                         Wv + (long)(ks * 128) * 512 + h * 64, 512,
                         g_partM + ks * PM_OFF + h * 64, 512, 128,
                         blockIdx.y * 128, 0);
}

// ---------------- fused weight prep ------------------------------------------
__global__ __launch_bounds__(256) void k_prep(
    const float* __restrict__ Wk, const float* __restrict__ W_hh,
    const float* __restrict__ W_ih, const float* __restrict__ Wq)
{
    __shared__ float t[32][33];
    int job = blockIdx.z;
    int bx = blockIdx.x * 32, by = blockIdx.y * 32;
    int lx = threadIdx.x & 31, wy = threadIdx.x >> 5;
    const float* src = nullptr; float* dst = nullptr; int ldS = 512, ldD = 0;
    if (job == 0) { if (blockIdx.y >= 16) return; src = Wk;  dst = g_WkT;       ldD = 512;  }
    else if (job == 1) { src = W_hh; dst = g_Wcomb + 512; ldD = 2048; }
    else if (job == 2) { src = W_ih; dst = g_WihT;       ldD = 1536; }
    else {
        if (blockIdx.y >= 16) return;
        #pragma unroll
        for (int j = wy; j < 32; j += 8)
            g_Wcomb[(long)(by + j) * 2048 + bx + lx] = Wq[(by + j) * 512 + bx + lx];
        return;
    }
    #pragma unroll
    for (int j = wy; j < 32; j += 8)
        t[j][lx] = src[(long)(by + j) * ldS + bx + lx];
    __syncthreads();
    #pragma unroll
    for (int j = wy; j < 32; j += 8)
        dst[(long)(bx + j) * ldD + by + lx] = t[lx][j];
}

// ---------------- preamble -----------------------------------------------------
__global__ __launch_bounds__(512) void k_build_hblk(
    const float* __restrict__ emb, const int* __restrict__ stc,
    const int* __restrict__ off, const int* __restrict__ sep)
{
    int b = blockIdx.x;
    int o = off[b], len = stc[b];
    int sA = sep[b * 2], sB2 = sep[b * 2 + 1];
    int idx = (sA < o ? 1 : 0) + (sB2 < o ? 1 : 0);
    int pidx = idx - 1; pidx = pidx < 0 ? 0 : (pidx > 1 ? 1 : pidx);
    int prev = (pidx == 0) ? sA : sB2;
    int left = (idx > 0) ? prev + 1 : 0;
    int nidx = idx > 1 ? 1 : idx;
    int nxt = (nidx == 0) ? sA : sB2;
    int right = (idx < 2) ? nxt : len;
    int start = (o - 2 > left) ? o - 2 : left;
    int end = (o + 2 < right) ? o + 2 : right;
    int t = threadIdx.x;
    #pragma unroll
    for (int l = 0; l < L_; l++) {
        int ind = start + l;
        bool v = ind < end;
        int ic = ind < 0 ? 0 : (ind > S_ - 1 ? S_ - 1 : ind);
        g_hblk[(b * L_ + l) * D_ + t] = v ? emb[((long)b * S_ + ic) * D_ + t] : 0.f;
        if (t == 0) g_valid[b * L_ + l] = v ? 1.f : 0.f;
    }
}

__global__ __launch_bounds__(256) void k_a(const float* __restrict__ W2)
{
    int m = blockIdx.x, t = threadIdx.x;
    float t0 = tanhf(g_partC[(long)m * 512 + t] + g_partC[PC1_OFF + (long)m * 512 + t]);
    float t1 = tanhf(g_partC[(long)m * 512 + t + 256] + g_partC[PC1_OFF + (long)m * 512 + t + 256]);
    float v = t0 * W2[t] + t1 * W2[t + 256];
    __shared__ float red[32];
    v = blockSum(v, red);
    if (t == 0) g_a[m] = v;
}

__global__ __launch_bounds__(512) void k_s1()
{
    int l = blockIdx.x, t = threadIdx.x;
    __shared__ float red[32];
    float v = g_a[t * L_ + l];
    float mx = blockMax(v, red);
    float e = expf(v - mx);
    float s = blockSum(e, red);
    g_s1[t * L_ + l] = e / s;
}

__global__ __launch_bounds__(512) void k_b0(
    const float* __restrict__ ln_g, const float* __restrict__ ln_b,
    const float* __restrict__ pe)
{
    int b = blockIdx.x, t = threadIdx.x;
    __shared__ float sc[4];
    __shared__ float red[32];
    if (t == 0) {
        float vals[4], mx = -3.0e38f;
        #pragma unroll
        for (int l = 0; l < 4; l++) {
            float v = (g_valid[b * 4 + l] > 0.5f) ? g_s1[b * 4 + l] : -1e9f;
            vals[l] = v; mx = fmaxf(mx, v);
        }
        float s = 0.f;
        #pragma unroll
        for (int l = 0; l < 4; l++) { float e = expf(vals[l] - mx); sc[l] = e; s += e; }
        #pragma unroll
        for (int l = 0; l < 4; l++) sc[l] /= s;
    }
    __syncthreads();
    float x = sc[0] * g_hblk[(b * 4 + 0) * D_ + t] + sc[1] * g_hblk[(b * 4 + 1) * D_ + t]
            + sc[2] * g_hblk[(b * 4 + 2) * D_ + t] + sc[3] * g_hblk[(b * 4 + 3) * D_ + t]
            + pe[t];
    float mean = blockSum(x, red) * (1.f / 512.f);
    float d = x - mean;
    float var = blockSum(d * d, red) * (1.f / 512.f);
    g_bt[b * D_ + t] = d * rsqrtf(var + 1e-5f) * ln_g[t] + ln_b[t];
}

__global__ __launch_bounds__(128) void k_buildH(
    const float* __restrict__ emb, const float* __restrict__ pe,
    const float* __restrict__ seg_emb, const float* __restrict__ ln_g,
    const float* __restrict__ ln_b, const int* __restrict__ stc,
    const int* __restrict__ off)
{
    int b = blockIdx.y, s = blockIdx.x;
    if (s >= stc[b]) return;
    int pos = off[b];
    int ip = (s < pos) ? (pos - s) : (s + 1 - pos);
    ip = ip < 0 ? 0 : (ip > S_ ? S_ : ip);
    int sg = (s >= pos) ? 1 : 0;
    int t = threadIdx.x;
    __shared__ float red[32];
    float4 e = *(const float4*)(emb + ((long)b * S_ + s) * D_ + t * 4);
    float4 p = *(const float4*)(pe + (long)ip * D_ + t * 4);
    float4 g = *(const float4*)(seg_emb + sg * D_ + t * 4);
    float x0 = e.x + p.x + g.x, x1 = e.y + p.y + g.y;
    float x2 = e.z + p.z + g.z, x3 = e.w + p.w + g.w;
    float mean = blockSum(x0 + x1 + x2 + x3, red) * (1.f / 512.f);
    float d0 = x0 - mean, d1 = x1 - mean, d2 = x2 - mean, d3 = x3 - mean;
    float var = blockSum(d0 * d0 + d1 * d1 + d2 * d2 + d3 * d3, red) * (1.f / 512.f);
    float inv = rsqrtf(var + 1e-5f);
    float4 gg = *(const float4*)(ln_g + t * 4);
    float4 bb = *(const float4*)(ln_b + t * 4);
    float4 o;
    o.x = d0 * inv * gg.x + bb.x; o.y = d1 * inv * gg.y + bb.y;
    o.z = d2 * inv * gg.z + bb.z; o.w = d3 * inv * gg.w + bb.w;
    *(float4*)(g_H + ((long)b * S_ + s) * D_ + t * 4) = o;
}

// ---------------- fused attention (256 thr, per-batch CTA) --------------------
__global__ __launch_bounds__(256) void k_attn(
    const float* __restrict__ bk, const float* __restrict__ bq,
    const int* __restrict__ stc)
{
    int b = blockIdx.x;
    int tid = threadIdx.x, lane = tid & 31, warp = tid >> 5;   // 8 warps
    extern __shared__ float sm[];
    float* uKs = sm;                    // 8*512
    float* Hs  = sm + NH_ * D_;         // 32*512
    float* ps  = Hs + CH * D_;          // 32*8  [s][h]
    float* cKs = ps + CH * NH_;         // 8
    float* pss = cKs + NH_;             // 8
    int len = stc[b];
    // stage uK
    {
        const float4* src = (const float4*)(g_uK + (long)b * NH_ * D_);
        float4* dst = (float4*)uKs;
        #pragma unroll
        for (int i = 0; i < 4; i++) dst[i * 256 + tid] = src[i * 256 + tid];
    }
    // cK[h] = bk_h . q_h  (q composed from comb partials + bq)
    {
        int j0 = warp * 64 + lane, j1 = j0 + 32;
        float q0 = g_partC[(long)b * 2048 + j0] + g_partC[PC1_OFF + (long)b * 2048 + j0] + bq[j0];
        float q1 = g_partC[(long)b * 2048 + j1] + g_partC[PC1_OFF + (long)b * 2048 + j1] + bq[j1];
        float v = bk[j0] * q0 + bk[j1] * q1;
        v = warpSum(v);
        if (lane == 0) { cKs[warp] = v; pss[warp] = 0.f; }
    }
    float creg[16] = {0.f,0.f,0.f,0.f,0.f,0.f,0.f,0.f,0.f,0.f,0.f,0.f,0.f,0.f,0.f,0.f};
    __syncthreads();
    int nch = (len + CH - 1) / CH;
    for (int c = 0; c < nch; c++) {
        int s0 = c * CH;
        for (int r = warp; r < CH; r += 8) {
            int s = s0 + r;
            float4* dst = (float4*)(Hs + r * D_);
            if (s < len) {
                const float4* src = (const float4*)(g_H + ((long)b * S_ + s) * D_);
                #pragma unroll
                for (int i = 0; i < 4; i++) dst[i * 32 + lane] = src[i * 32 + lane];
            } else {
                float4 z = make_float4(0,0,0,0);
                #pragma unroll
                for (int i = 0; i < 4; i++) dst[i * 32 + lane] = z;
            }
        }
        ps[tid] = 0.f;
        __syncthreads();
        #pragma unroll
        for (int pass = 0; pass < 2; pass++) {
            int hb = pass * 4;
            float4 u[4][4];
            #pragma unroll
            for (int hh = 0; hh < 4; hh++)
                #pragma unroll
                for (int i = 0; i < 4; i++)
                    u[hh][i] = *(const float4*)(uKs + (hb + hh) * D_ + (i * 32 + lane) * 4);
            #pragma unroll
            for (int rr = 0; rr < 4; rr++) {
                int r = warp * 4 + rr;
                float4 h4[4];
                #pragma unroll
                for (int i = 0; i < 4; i++)
                    h4[i] = *(const float4*)(Hs + r * D_ + (i * 32 + lane) * 4);
                float acc[4];
                #pragma unroll
                for (int hh = 0; hh < 4; hh++) {
                    acc[hh] = DOT4(u[hh][0], h4[0]) + DOT4(u[hh][1], h4[1])
                            + DOT4(u[hh][2], h4[2]) + DOT4(u[hh][3], h4[3]);
                    acc[hh] = warpSum(acc[hh]);
                }
                if (lane == 0) {
                    int s = s0 + r;
                    if (s < len) {
                        #pragma unroll
                        for (int hh = 0; hh < 4; hh++)
                            ps[r * NH_ + hb + hh] = sigm(0.125f * (acc[hh] + cKs[hb + hh]));
                    }
                }
            }
        }
        __syncthreads();
        #pragma unroll 4
        for (int r = 0; r < CH; r++) {
            float hv0 = Hs[r * D_ + tid];
            float hv1 = Hs[r * D_ + tid + 256];
            float4 p0 = *(const float4*)(ps + r * NH_);
            float4 p1 = *(const float4*)(ps + r * NH_ + 4);
            creg[0] += p0.x * hv0; creg[1] += p0.y * hv0;
            creg[2] += p0.z * hv0; creg[3] += p0.w * hv0;
            creg[4] += p1.x * hv0; creg[5] += p1.y * hv0;
            creg[6] += p1.z * hv0; creg[7] += p1.w * hv0;
            creg[8]  += p0.x * hv1; creg[9]  += p0.y * hv1;
            creg[10] += p0.z * hv1; creg[11] += p0.w * hv1;
            creg[12] += p1.x * hv1; creg[13] += p1.y * hv1;
            creg[14] += p1.z * hv1; creg[15] += p1.w * hv1;
        }
        {
            float v = ps[lane * NH_ + warp];
            v = warpSum(v);
            if (lane == 0) pss[warp] += v;
        }
        __syncthreads();
    }
    #pragma unroll
    for (int h = 0; h < NH_; h++) {
        g_ctx[((long)b * NH_ + h) * D_ + tid]       = creg[h];
        g_ctx[((long)b * NH_ + h) * D_ + tid + 256] = creg[8 + h];
    }
    if (tid < NH_) g_psum[b * NH_ + tid] = pss[tid];
}

// ---------------- small per-iter kernels --------------------------------------
__global__ __launch_bounds__(512) void k_ln_mt(
    const float* __restrict__ bv, const float* __restrict__ lng_g,
    const float* __restrict__ lng_b)
{
    int b = blockIdx.x, t = threadIdx.x;
    __shared__ float red[32];
    long o = (long)b * 512 + t;
    float x = g_partM[o] + g_partM[PM_OFF + o] + g_partM[2 * PM_OFF + o]
            + g_partM[3 * PM_OFF + o] + g_psum[b * NH_ + (t >> 6)] * bv[t];
    float mean = blockSum(x, red) * (1.f / 512.f);
    float d = x - mean;
    float var = blockSum(d * d, red) * (1.f / 512.f);
    g_mt[b * D_ + t] = d * rsqrtf(var + 1e-5f) * lng_g[t] + lng_b[t];
}

__global__ __launch_bounds__(512) void k_gru(
    const float* __restrict__ b_ih, const float* __restrict__ b_hh,
    float* __restrict__ out, int last)
{
    int b = blockIdx.x, t = threadIdx.x;
    const float* G0 = g_partG + (long)b * 1536;
    const float* G1 = g_partG + PG1_OFF + (long)b * 1536;
    const float* C0 = g_partC + (long)b * 2048 + 512;
    const float* C1 = g_partC + PC1_OFF + (long)b * 2048 + 512;
    float ir = G0[t]        + G1[t]        + b_ih[t];
    float iz = G0[t + 512]  + G1[t + 512]  + b_ih[t + 512];
    float in = G0[t + 1024] + G1[t + 1024] + b_ih[t + 1024];
    float hr = C0[t]        + C1[t]        + b_hh[t];
    float hz = C0[t + 512]  + C1[t + 512]  + b_hh[t + 512];
    float hn = C0[t + 1024] + C1[t + 1024] + b_hh[t + 1024];
    float r = sigm(ir + hr);
    float z = sigm(iz + hz);
    float n = tanhf(in + r * hn);
    float old = g_bt[b * D_ + t];
    float nv = (1.f - z) * n + z * old;
    g_bt[b * D_ + t] = nv;
    if (last) out[b * 512 + t] = nv;
}

// ---------------- launch --------------------------------------------------------
extern "C" void kernel_launch(void* const* d_in, const int* in_sizes, int n_in,
                              void* d_out, int out_size)
{
    const float* emb   = (const float*)d_in[0];
    const int*   stc   = (const int*)  d_in[1];
    const int*   off   = (const int*)  d_in[2];
    const int*   sep   = (const int*)  d_in[3];
    const float* W1    = (const float*)d_in[4];
    const float* W2    = (const float*)d_in[5];
    const float* ln_g  = (const float*)d_in[6];
    const float* ln_b  = (const float*)d_in[7];
    const float* lng_g = (const float*)d_in[8];
    const float* lng_b = (const float*)d_in[9];
    const float* Wq    = (const float*)d_in[10];
    const float* bq    = (const float*)d_in[11];
    const float* Wk    = (const float*)d_in[12];
    const float* bk    = (const float*)d_in[13];
    const float* Wv    = (const float*)d_in[14];
    const float* bv    = (const float*)d_in[15];
    const float* W_ih  = (const float*)d_in[16];
    const float* W_hh  = (const float*)d_in[17];
    const float* b_ih  = (const float*)d_in[18];
    const float* b_hh  = (const float*)d_in[19];
    const float* seg   = (const float*)d_in[20];
    const float* pe    = (const float*)d_in[21];
    float* out = (float*)d_out;

    float *pHblk, *pBt, *pWcomb, *pWihT, *pMt, *pPartC, *pPartG;
    cudaGetSymbolAddress((void**)&pHblk,  g_hblk);
    cudaGetSymbolAddress((void**)&pBt,    g_bt);
    cudaGetSymbolAddress((void**)&pWcomb, g_Wcomb);
    cudaGetSymbolAddress((void**)&pWihT,  g_WihT);
    cudaGetSymbolAddress((void**)&pMt,    g_mt);
    cudaGetSymbolAddress((void**)&pPartC, g_partC);
    cudaGetSymbolAddress((void**)&pPartG, g_partG);

    static const int ATTN_SMEM = (NH_*D_ + CH*D_ + CH*NH_ + 2*NH_) * 4;
    cudaFuncSetAttribute(k_attn, cudaFuncAttributeMaxDynamicSharedMemorySize, ATTN_SMEM);

    // ---- preamble ----
    k_prep<<<dim3(16, 48, 4), 256>>>(Wk, W_hh, W_ih, Wq);
    k_build_hblk<<<B_, 512>>>(emb, stc, off, sep);
    // T = hblk @ W1 (split-K=2 into partC)
    k_gemm<128><<<dim3(4, 16, 2), 256>>>(pHblk, 512, 256, W1, 512, 256*512,
                                         pPartC, 512, 2048*512, 256);
    k_a<<<2048, 256>>>(W2);
    k_s1<<<L_, 512>>>();
    k_b0<<<B_, 512>>>(ln_g, ln_b, pe);
    k_buildH<<<dim3(S_, B_), 128>>>(emb, pe, seg, ln_g, ln_b, stc, off);

    // ---- 3 GRU iterations ----
    for (int it = 0; it < 3; it++) {
        // [q | gh] partials = bt @ Wcomb (split-K=2)
        k_gemm<128><<<dim3(16, 4, 2), 256>>>(pBt, 512, 256, pWcomb, 2048, 256*2048,
                                             pPartC, 2048, 512*2048, 256);
        // uK[b,h,:] = (q composed) @ WkT_h  (z = head)
        k_gemm_uk<<<dim3(4, 4, 8), 256>>>(bq);
        // fused attention
        k_attn<<<B_, 256, ATTN_SMEM>>>(bk, bq, stc);
        // mraw partials = ctx_h @ Wv_h  (z = head*4 + ksplit)
        k_gemm_mraw<<<dim3(1, 4, 32), 256>>>(Wv);
        // m_t = LN(sum partials + psum*bv)
        k_ln_mt<<<B_, 512>>>(bv, lng_g, lng_b);
        // gi partials = mt @ W_ih^T (split-K=2)
        k_gemm<128><<<dim3(12, 4, 2), 256>>>(pMt, 512, 256, pWihT, 1536, 256*1536,
                                             pPartG, 1536, 512*1536, 256);
        // GRU update (writes out on last iter)
        k_gru<<<B_, 512>>>(b_ih, b_hh, out, it == 2 ? 1 : 0);
    }
    (void)in_sizes; (void)n_in; (void)out_size;
}

// round 7
// speedup vs baseline: 2.2276x; 1.2069x over previous
#include <cuda_runtime.h>
#include <cuda_bf16.h>
#include <mma.h>
#include <math.h>

#define B_  512
#define S_  200
#define D_  512
#define NH_ 8
#define L_  4
#define CH  32

// ---------------- scratch (device globals) ----------------------------------
__device__ float g_hblk[B_*L_*D_];
__device__ float g_valid[B_*L_];
__device__ float g_a[B_*L_];
__device__ float g_s1[B_*L_];
__device__ float g_bt[B_*D_];
__device__ float g_H[B_*S_*D_];          // 210 MB
__device__ float g_uK[B_*NH_*D_];
__device__ float g_ctx[B_*NH_*D_];
__device__ float g_psum[B_*NH_];
__device__ float g_mt[B_*D_];
__device__ float g_partC[2*B_*2048];     // comb / W1 split-K partials
__device__ float g_partM[4*B_*D_];       // mraw split-K partials
__device__ float g_partG[2*B_*1536];     // gi split-K partials

// bf16 hi/lo split weights, [N][K] layout (K contiguous)
__device__ __nv_bfloat16 g_combT_h[2048*512];
__device__ __nv_bfloat16 g_combT_l[2048*512];
__device__ __nv_bfloat16 g_Wih_h[1536*512];
__device__ __nv_bfloat16 g_Wih_l[1536*512];
__device__ __nv_bfloat16 g_Wk_h[512*512];
__device__ __nv_bfloat16 g_Wk_l[512*512];
__device__ __nv_bfloat16 g_WvT_h[512*512];
__device__ __nv_bfloat16 g_WvT_l[512*512];
__device__ __nv_bfloat16 g_W1T_h[512*512];
__device__ __nv_bfloat16 g_W1T_l[512*512];

#define PC1_OFF 1048576L   // 512*2048
#define PM_OFF  262144L    // 512*512
#define PG1_OFF 786432L    // 512*1536

// ---------------- helpers ----------------------------------------------------
__device__ __forceinline__ float warpSum(float v) {
    #pragma unroll
    for (int o = 16; o; o >>= 1) v += __shfl_down_sync(0xffffffffu, v, o);
    return v;
}
__device__ __forceinline__ float warpMax(float v) {
    #pragma unroll
    for (int o = 16; o; o >>= 1) v = fmaxf(v, __shfl_down_sync(0xffffffffu, v, o));
    return v;
}
__device__ __forceinline__ float blockSum(float v, float* red) {
    int lane = threadIdx.x & 31, w = threadIdx.x >> 5;
    v = warpSum(v);
    if (lane == 0) red[w] = v;
    __syncthreads();
    float r = 0.f;
    if (threadIdx.x < (blockDim.x >> 5)) r = red[threadIdx.x];
    if (w == 0) r = warpSum(r);
    if (threadIdx.x == 0) red[0] = r;
    __syncthreads();
    r = red[0];
    __syncthreads();
    return r;
}
__device__ __forceinline__ float blockMax(float v, float* red) {
    int lane = threadIdx.x & 31, w = threadIdx.x >> 5;
    v = warpMax(v);
    if (lane == 0) red[w] = v;
    __syncthreads();
    float r = -3.0e38f;
    if (threadIdx.x < (blockDim.x >> 5)) r = red[threadIdx.x];
    if (w == 0) r = warpMax(r);
    if (threadIdx.x == 0) red[0] = r;
    __syncthreads();
    r = red[0];
    __syncthreads();
    return r;
}
__device__ __forceinline__ float sigm(float x) { return 1.f / (1.f + expf(-x)); }
#define DOT4(u, h) ((u).x*(h).x + (u).y*(h).y + (u).z*(h).z + (u).w*(h).w)

// ---------------- WMMA tensor GEMM core ---------------------------------------
// C[128 x BN] tile of A[M,Kd](fp32) @ B^T where B is bf16 hi/lo in [N][K] layout.
// 3-product bf16 split: AhBh + AhBl + AlBh, fp32 accumulate.
// If COMPOSE: A = A0 + A1 + Abias[k].
// 256 threads = 8 warps: wm = warp & 3 (32 rows each), wn = warp >> 2 (BN/2 cols).
template <int BN, bool COMPOSE>
__device__ __forceinline__ void tc_core(
    const float* A0, const float* A1, const float* Ab, int lda,
    const __nv_bfloat16* Bh, const __nv_bfloat16* Bl, int ldb,
    float* C, int ldc, int Kd, int m0, int n0)
{
    const int RS = 40;        // smem row stride in bf16 elems (80 B)
    const int NT = BN / 32;   // 16-wide n tiles per warp (4 or 2)

    __shared__ __align__(32) __nv_bfloat16 sAh[128 * RS];
    __shared__ __align__(32) __nv_bfloat16 sAl[128 * RS];
    __shared__ __align__(32) __nv_bfloat16 sBh[BN * RS];
    __shared__ __align__(32) __nv_bfloat16 sBl[BN * RS];

    int tid = threadIdx.x;
    int warp = tid >> 5;
    int wm = warp & 3;
    int wn = warp >> 2;

    nvcuda::wmma::fragment<nvcuda::wmma::accumulator, 16, 16, 16, float> acc[2][NT];
    #pragma unroll
    for (int i = 0; i < 2; i++) {
        #pragma unroll
        for (int j = 0; j < NT; j++) {
            nvcuda::wmma::fill_fragment(acc[i][j], 0.0f);
        }
    }

    for (int kc = 0; kc < Kd; kc += 32) {
        // stage A: 128 rows x 32 k, fp32 -> bf16 hi/lo
        #pragma unroll
        for (int i = 0; i < 4; i++) {
            int idx = tid + i * 256;
            int row = idx >> 3;
            int q = idx & 7;
            float4 v = *(const float4*)(A0 + (long)(m0 + row) * lda + kc + q * 4);
            if (COMPOSE) {
                float4 v1 = *(const float4*)(A1 + (long)(m0 + row) * lda + kc + q * 4);
                float4 bi = *(const float4*)(Ab + kc + q * 4);
                v.x += v1.x + bi.x; v.y += v1.y + bi.y;
                v.z += v1.z + bi.z; v.w += v1.w + bi.w;
            }
            __nv_bfloat16 h0 = __float2bfloat16(v.x);
            __nv_bfloat16 h1 = __float2bfloat16(v.y);
            __nv_bfloat16 h2 = __float2bfloat16(v.z);
            __nv_bfloat16 h3 = __float2bfloat16(v.w);
            int o = row * RS + q * 4;
            sAh[o + 0] = h0; sAh[o + 1] = h1; sAh[o + 2] = h2; sAh[o + 3] = h3;
            sAl[o + 0] = __float2bfloat16(v.x - __bfloat162float(h0));
            sAl[o + 1] = __float2bfloat16(v.y - __bfloat162float(h1));
            sAl[o + 2] = __float2bfloat16(v.z - __bfloat162float(h2));
            sAl[o + 3] = __float2bfloat16(v.w - __bfloat162float(h3));
        }
        // stage B: BN rows x 32 k, straight bf16 copies (16 B chunks)
        for (int c = tid; c < BN * 4; c += 256) {
            int row = c >> 2;
            int q = c & 3;
            *(uint4*)(sBh + row * RS + q * 8) =
                *(const uint4*)(Bh + (long)(n0 + row) * ldb + kc + q * 8);
            *(uint4*)(sBl + row * RS + q * 8) =
                *(const uint4*)(Bl + (long)(n0 + row) * ldb + kc + q * 8);
        }
        __syncthreads();
        #pragma unroll
        for (int ks = 0; ks < 2; ks++) {
            nvcuda::wmma::fragment<nvcuda::wmma::matrix_a, 16, 16, 16,
                                   __nv_bfloat16, nvcuda::wmma::row_major> ah[2], al[2];
            #pragma unroll
            for (int i = 0; i < 2; i++) {
                int r = wm * 32 + i * 16;
                nvcuda::wmma::load_matrix_sync(ah[i], sAh + r * RS + ks * 16, RS);
                nvcuda::wmma::load_matrix_sync(al[i], sAl + r * RS + ks * 16, RS);
            }
            #pragma unroll
            for (int j = 0; j < NT; j++) {
                int nn = wn * (BN / 2) + j * 16;
                nvcuda::wmma::fragment<nvcuda::wmma::matrix_b, 16, 16, 16,
                                       __nv_bfloat16, nvcuda::wmma::col_major> bh, bl;
                nvcuda::wmma::load_matrix_sync(bh, sBh + nn * RS + ks * 16, RS);
                nvcuda::wmma::load_matrix_sync(bl, sBl + nn * RS + ks * 16, RS);
                #pragma unroll
                for (int i = 0; i < 2; i++) {
                    nvcuda::wmma::mma_sync(acc[i][j], ah[i], bh, acc[i][j]);
                    nvcuda::wmma::mma_sync(acc[i][j], ah[i], bl, acc[i][j]);
                    nvcuda::wmma::mma_sync(acc[i][j], al[i], bh, acc[i][j]);
                }
            }
        }
        __syncthreads();
    }
    #pragma unroll
    for (int i = 0; i < 2; i++) {
        #pragma unroll
        for (int j = 0; j < NT; j++) {
            int row = m0 + wm * 32 + i * 16;
            int col = n0 + wn * (BN / 2) + j * 16;
            nvcuda::wmma::store_matrix_sync(C + (long)row * ldc + col, acc[i][j],
                                            ldc, nvcuda::wmma::mem_row_major);
        }
    }
}

// ---------------- GEMM wrapper kernels ----------------------------------------
__global__ __launch_bounds__(256) void k_tc_w1()
{
    int z = blockIdx.z;
    tc_core<128, false>(g_hblk + z * 256, (const float*)0, (const float*)0, 512,
                        g_W1T_h + z * 256, g_W1T_l + z * 256, 512,
                        g_partC + (long)z * PC1_OFF, 512, 256,
                        blockIdx.y * 128, blockIdx.x * 128);
}
__global__ __launch_bounds__(256) void k_tc_comb()
{
    int z = blockIdx.z;
    tc_core<128, false>(g_bt + z * 256, (const float*)0, (const float*)0, 512,
                        g_combT_h + z * 256, g_combT_l + z * 256, 512,
                        g_partC + (long)z * PC1_OFF, 2048, 256,
                        blockIdx.y * 128, blockIdx.x * 128);
}
__global__ __launch_bounds__(256) void k_tc_uk(const float* __restrict__ bq)
{
    int h = blockIdx.z;
    tc_core<128, true>(g_partC + h * 64, g_partC + PC1_OFF + h * 64, bq + h * 64, 2048,
                       g_Wk_h + h * 64, g_Wk_l + h * 64, 512,
                       g_uK + h * 512, 4096, 64,
                       blockIdx.y * 128, blockIdx.x * 128);
}
__global__ __launch_bounds__(256) void k_tc_mraw()
{
    int z = blockIdx.z;
    int h = z >> 2;
    int ks = z & 3;
    tc_core<64, false>(g_ctx + h * 512 + (long)ks * 128, (const float*)0, (const float*)0, 4096,
                       g_WvT_h + (long)(h * 64) * 512 + ks * 128,
                       g_WvT_l + (long)(h * 64) * 512 + ks * 128, 512,
                       g_partM + ks * PM_OFF + h * 64, 512, 128,
                       blockIdx.y * 128, 0);
}
__global__ __launch_bounds__(256) void k_tc_gi()
{
    int z = blockIdx.z;
    tc_core<128, false>(g_mt + z * 256, (const float*)0, (const float*)0, 512,
                        g_Wih_h + z * 256, g_Wih_l + z * 256, 512,
                        g_partG + (long)z * PG1_OFF, 1536, 256,
                        blockIdx.y * 128, blockIdx.x * 128);
}

// ---------------- weight prep: transpose + bf16 hi/lo split --------------------
__global__ __launch_bounds__(256) void k_prep(
    const float* __restrict__ Wk, const float* __restrict__ W_ih,
    const float* __restrict__ W_hh, const float* __restrict__ Wq,
    const float* __restrict__ Wv, const float* __restrict__ W1)
{
    __shared__ float t[32][33];
    int job = blockIdx.z;
    int bx = blockIdx.x * 32;
    int by = blockIdx.y * 32;
    int lx = threadIdx.x & 31;
    int wy = threadIdx.x >> 5;
    if (job <= 2) {
        const float* src;
        __nv_bfloat16* dh;
        __nv_bfloat16* dl;
        int nrows;
        if (job == 0)      { src = Wk;   dh = g_Wk_h;  dl = g_Wk_l;  nrows = 512;  }
        else if (job == 1) { src = W_ih; dh = g_Wih_h; dl = g_Wih_l; nrows = 1536; }
        else               { src = W_hh; dh = g_combT_h + 512*512;
                             dl = g_combT_l + 512*512; nrows = 1536; }
        if (by >= nrows) return;
        for (int j = wy; j < 32; j += 8) {
            long o = (long)(by + j) * 512 + bx + lx;
            float v = src[o];
            __nv_bfloat16 hh = __float2bfloat16(v);
            dh[o] = hh;
            dl[o] = __float2bfloat16(v - __bfloat162float(hh));
        }
    } else {
        if (blockIdx.y >= 16) return;
        const float* src;
        __nv_bfloat16* dh;
        __nv_bfloat16* dl;
        if (job == 3)      { src = Wq; dh = g_combT_h; dl = g_combT_l; }
        else if (job == 4) { src = Wv; dh = g_WvT_h;   dl = g_WvT_l;   }
        else               { src = W1; dh = g_W1T_h;   dl = g_W1T_l;   }
        for (int j = wy; j < 32; j += 8)
            t[j][lx] = src[(long)(by + j) * 512 + bx + lx];
        __syncthreads();
        for (int j = wy; j < 32; j += 8) {
            float v = t[lx][j];
            long o = (long)(bx + j) * 512 + by + lx;
            __nv_bfloat16 hh = __float2bfloat16(v);
            dh[o] = hh;
            dl[o] = __float2bfloat16(v - __bfloat162float(hh));
        }
    }
}

// ---------------- preamble -----------------------------------------------------
__global__ __launch_bounds__(512) void k_build_hblk(
    const float* __restrict__ emb, const int* __restrict__ stc,
    const int* __restrict__ off, const int* __restrict__ sep)
{
    int b = blockIdx.x;
    int o = off[b], len = stc[b];
    int sA = sep[b * 2], sB2 = sep[b * 2 + 1];
    int idx = (sA < o ? 1 : 0) + (sB2 < o ? 1 : 0);
    int pidx = idx - 1; pidx = pidx < 0 ? 0 : (pidx > 1 ? 1 : pidx);
    int prev = (pidx == 0) ? sA : sB2;
    int left = (idx > 0) ? prev + 1 : 0;
    int nidx = idx > 1 ? 1 : idx;
    int nxt = (nidx == 0) ? sA : sB2;
    int right = (idx < 2) ? nxt : len;
    int start = (o - 2 > left) ? o - 2 : left;
    int end = (o + 2 < right) ? o + 2 : right;
    int t = threadIdx.x;
    #pragma unroll
    for (int l = 0; l < L_; l++) {
        int ind = start + l;
        bool v = ind < end;
        int ic = ind < 0 ? 0 : (ind > S_ - 1 ? S_ - 1 : ind);
        g_hblk[(b * L_ + l) * D_ + t] = v ? emb[((long)b * S_ + ic) * D_ + t] : 0.f;
        if (t == 0) g_valid[b * L_ + l] = v ? 1.f : 0.f;
    }
}

__global__ __launch_bounds__(256) void k_a(const float* __restrict__ W2)
{
    int m = blockIdx.x, t = threadIdx.x;
    float t0 = tanhf(g_partC[(long)m * 512 + t] + g_partC[PC1_OFF + (long)m * 512 + t]);
    float t1 = tanhf(g_partC[(long)m * 512 + t + 256] + g_partC[PC1_OFF + (long)m * 512 + t + 256]);
    float v = t0 * W2[t] + t1 * W2[t + 256];
    __shared__ float red[32];
    v = blockSum(v, red);
    if (t == 0) g_a[m] = v;
}

__global__ __launch_bounds__(512) void k_s1()
{
    int l = blockIdx.x, t = threadIdx.x;
    __shared__ float red[32];
    float v = g_a[t * L_ + l];
    float mx = blockMax(v, red);
    float e = expf(v - mx);
    float s = blockSum(e, red);
    g_s1[t * L_ + l] = e / s;
}

__global__ __launch_bounds__(512) void k_b0(
    const float* __restrict__ ln_g, const float* __restrict__ ln_b,
    const float* __restrict__ pe)
{
    int b = blockIdx.x, t = threadIdx.x;
    __shared__ float sc[4];
    __shared__ float red[32];
    if (t == 0) {
        float vals[4], mx = -3.0e38f;
        #pragma unroll
        for (int l = 0; l < 4; l++) {
            float v = (g_valid[b * 4 + l] > 0.5f) ? g_s1[b * 4 + l] : -1e9f;
            vals[l] = v; mx = fmaxf(mx, v);
        }
        float s = 0.f;
        #pragma unroll
        for (int l = 0; l < 4; l++) { float e = expf(vals[l] - mx); sc[l] = e; s += e; }
        #pragma unroll
        for (int l = 0; l < 4; l++) sc[l] /= s;
    }
    __syncthreads();
    float x = sc[0] * g_hblk[(b * 4 + 0) * D_ + t] + sc[1] * g_hblk[(b * 4 + 1) * D_ + t]
            + sc[2] * g_hblk[(b * 4 + 2) * D_ + t] + sc[3] * g_hblk[(b * 4 + 3) * D_ + t]
            + pe[t];
    float mean = blockSum(x, red) * (1.f / 512.f);
    float d = x - mean;
    float var = blockSum(d * d, red) * (1.f / 512.f);
    g_bt[b * D_ + t] = d * rsqrtf(var + 1e-5f) * ln_g[t] + ln_b[t];
}

__global__ __launch_bounds__(128) void k_buildH(
    const float* __restrict__ emb, const float* __restrict__ pe,
    const float* __restrict__ seg_emb, const float* __restrict__ ln_g,
    const float* __restrict__ ln_b, const int* __restrict__ stc,
    const int* __restrict__ off)
{
    int b = blockIdx.y, s = blockIdx.x;
    if (s >= stc[b]) return;
    int pos = off[b];
    int ip = (s < pos) ? (pos - s) : (s + 1 - pos);
    ip = ip < 0 ? 0 : (ip > S_ ? S_ : ip);
    int sg = (s >= pos) ? 1 : 0;
    int t = threadIdx.x;
    __shared__ float red[32];
    float4 e = *(const float4*)(emb + ((long)b * S_ + s) * D_ + t * 4);
    float4 p = *(const float4*)(pe + (long)ip * D_ + t * 4);
    float4 g = *(const float4*)(seg_emb + sg * D_ + t * 4);
    float x0 = e.x + p.x + g.x, x1 = e.y + p.y + g.y;
    float x2 = e.z + p.z + g.z, x3 = e.w + p.w + g.w;
    float mean = blockSum(x0 + x1 + x2 + x3, red) * (1.f / 512.f);
    float d0 = x0 - mean, d1 = x1 - mean, d2 = x2 - mean, d3 = x3 - mean;
    float var = blockSum(d0 * d0 + d1 * d1 + d2 * d2 + d3 * d3, red) * (1.f / 512.f);
    float inv = rsqrtf(var + 1e-5f);
    float4 gg = *(const float4*)(ln_g + t * 4);
    float4 bb = *(const float4*)(ln_b + t * 4);
    float4 o;
    o.x = d0 * inv * gg.x + bb.x; o.y = d1 * inv * gg.y + bb.y;
    o.z = d2 * inv * gg.z + bb.z; o.w = d3 * inv * gg.w + bb.w;
    *(float4*)(g_H + ((long)b * S_ + s) * D_ + t * 4) = o;
}

// ---------------- fused attention (256 thr, per-batch CTA) --------------------
__global__ __launch_bounds__(256) void k_attn(
    const float* __restrict__ bk, const float* __restrict__ bq,
    const int* __restrict__ stc)
{
    int b = blockIdx.x;
    int tid = threadIdx.x, lane = tid & 31, warp = tid >> 5;   // 8 warps
    extern __shared__ float sm[];
    float* uKs = sm;                    // 8*512
    float* Hs  = sm + NH_ * D_;         // 32*512
    float* ps  = Hs + CH * D_;          // 32*8  [s][h]
    float* cKs = ps + CH * NH_;         // 8
    float* pss = cKs + NH_;             // 8
    int len = stc[b];
    {
        const float4* src = (const float4*)(g_uK + (long)b * NH_ * D_);
        float4* dst = (float4*)uKs;
        #pragma unroll
        for (int i = 0; i < 4; i++) dst[i * 256 + tid] = src[i * 256 + tid];
    }
    {
        int j0 = warp * 64 + lane, j1 = j0 + 32;
        float q0 = g_partC[(long)b * 2048 + j0] + g_partC[PC1_OFF + (long)b * 2048 + j0] + bq[j0];
        float q1 = g_partC[(long)b * 2048 + j1] + g_partC[PC1_OFF + (long)b * 2048 + j1] + bq[j1];
        float v = bk[j0] * q0 + bk[j1] * q1;
        v = warpSum(v);
        if (lane == 0) { cKs[warp] = v; pss[warp] = 0.f; }
    }
    float creg[16] = {0.f,0.f,0.f,0.f,0.f,0.f,0.f,0.f,0.f,0.f,0.f,0.f,0.f,0.f,0.f,0.f};
    __syncthreads();
    int nch = (len + CH - 1) / CH;
    for (int c = 0; c < nch; c++) {
        int s0 = c * CH;
        for (int r = warp; r < CH; r += 8) {
            int s = s0 + r;
            float4* dst = (float4*)(Hs + r * D_);
            if (s < len) {
                const float4* src = (const float4*)(g_H + ((long)b * S_ + s) * D_);
                #pragma unroll
                for (int i = 0; i < 4; i++) dst[i * 32 + lane] = src[i * 32 + lane];
            } else {
                float4 z = make_float4(0.f, 0.f, 0.f, 0.f);
                #pragma unroll
                for (int i = 0; i < 4; i++) dst[i * 32 + lane] = z;
            }
        }
        ps[tid] = 0.f;
        __syncthreads();
        #pragma unroll
        for (int pass = 0; pass < 2; pass++) {
            int hb = pass * 4;
            float4 u[4][4];
            #pragma unroll
            for (int hh = 0; hh < 4; hh++) {
                #pragma unroll
                for (int i = 0; i < 4; i++)
                    u[hh][i] = *(const float4*)(uKs + (hb + hh) * D_ + (i * 32 + lane) * 4);
            }
            #pragma unroll
            for (int rr = 0; rr < 4; rr++) {
                int r = warp * 4 + rr;
                float4 h4[4];
                #pragma unroll
                for (int i = 0; i < 4; i++)
                    h4[i] = *(const float4*)(Hs + r * D_ + (i * 32 + lane) * 4);
                float acc[4];
                #pragma unroll
                for (int hh = 0; hh < 4; hh++) {
                    acc[hh] = DOT4(u[hh][0], h4[0]) + DOT4(u[hh][1], h4[1])
                            + DOT4(u[hh][2], h4[2]) + DOT4(u[hh][3], h4[3]);
                    acc[hh] = warpSum(acc[hh]);
                }
                if (lane == 0) {
                    int s = s0 + r;
                    if (s < len) {
                        #pragma unroll
                        for (int hh = 0; hh < 4; hh++)
                            ps[r * NH_ + hb + hh] = sigm(0.125f * (acc[hh] + cKs[hb + hh]));
                    }
                }
            }
        }
        __syncthreads();
        #pragma unroll 4
        for (int r = 0; r < CH; r++) {
            float hv0 = Hs[r * D_ + tid];
            float hv1 = Hs[r * D_ + tid + 256];
            float4 p0 = *(const float4*)(ps + r * NH_);
            float4 p1 = *(const float4*)(ps + r * NH_ + 4);
            creg[0] += p0.x * hv0; creg[1] += p0.y * hv0;
            creg[2] += p0.z * hv0; creg[3] += p0.w * hv0;
            creg[4] += p1.x * hv0; creg[5] += p1.y * hv0;
            creg[6] += p1.z * hv0; creg[7] += p1.w * hv0;
            creg[8]  += p0.x * hv1; creg[9]  += p0.y * hv1;
            creg[10] += p0.z * hv1; creg[11] += p0.w * hv1;
            creg[12] += p1.x * hv1; creg[13] += p1.y * hv1;
            creg[14] += p1.z * hv1; creg[15] += p1.w * hv1;
        }
        {
            float v = ps[lane * NH_ + warp];
            v = warpSum(v);
            if (lane == 0) pss[warp] += v;
        }
        __syncthreads();
    }
    #pragma unroll
    for (int h = 0; h < NH_; h++) {
        g_ctx[((long)b * NH_ + h) * D_ + tid]       = creg[h];
        g_ctx[((long)b * NH_ + h) * D_ + tid + 256] = creg[8 + h];
    }
    if (tid < NH_) g_psum[b * NH_ + tid] = pss[tid];
}

// ---------------- small per-iter kernels --------------------------------------
__global__ __launch_bounds__(512) void k_ln_mt(
    const float* __restrict__ bv, const float* __restrict__ lng_g,
    const float* __restrict__ lng_b)
{
    int b = blockIdx.x, t = threadIdx.x;
    __shared__ float red[32];
    long o = (long)b * 512 + t;
    float x = g_partM[o] + g_partM[PM_OFF + o] + g_partM[2 * PM_OFF + o]
            + g_partM[3 * PM_OFF + o] + g_psum[b * NH_ + (t >> 6)] * bv[t];
    float mean = blockSum(x, red) * (1.f / 512.f);
    float d = x - mean;
    float var = blockSum(d * d, red) * (1.f / 512.f);
    g_mt[b * D_ + t] = d * rsqrtf(var + 1e-5f) * lng_g[t] + lng_b[t];
}

__global__ __launch_bounds__(512) void k_gru(
    const float* __restrict__ b_ih, const float* __restrict__ b_hh,
    float* __restrict__ out, int last)
{
    int b = blockIdx.x, t = threadIdx.x;
    const float* G0 = g_partG + (long)b * 1536;
    const float* G1 = g_partG + PG1_OFF + (long)b * 1536;
    const float* C0 = g_partC + (long)b * 2048 + 512;
    const float* C1 = g_partC + PC1_OFF + (long)b * 2048 + 512;
    float ir = G0[t]        + G1[t]        + b_ih[t];
    float iz = G0[t + 512]  + G1[t + 512]  + b_ih[t + 512];
    float in = G0[t + 1024] + G1[t + 1024] + b_ih[t + 1024];
    float hr = C0[t]        + C1[t]        + b_hh[t];
    float hz = C0[t + 512]  + C1[t + 512]  + b_hh[t + 512];
    float hn = C0[t + 1024] + C1[t + 1024] + b_hh[t + 1024];
    float r = sigm(ir + hr);
    float z = sigm(iz + hz);
    float n = tanhf(in + r * hn);
    float old = g_bt[b * D_ + t];
    float nv = (1.f - z) * n + z * old;
    g_bt[b * D_ + t] = nv;
    if (last) out[b * 512 + t] = nv;
}

// ---------------- launch --------------------------------------------------------
extern "C" void kernel_launch(void* const* d_in, const int* in_sizes, int n_in,
                              void* d_out, int out_size)
{
    const float* emb   = (const float*)d_in[0];
    const int*   stc   = (const int*)  d_in[1];
    const int*   off   = (const int*)  d_in[2];
    const int*   sep   = (const int*)  d_in[3];
    const float* W1    = (const float*)d_in[4];
    const float* W2    = (const float*)d_in[5];
    const float* ln_g  = (const float*)d_in[6];
    const float* ln_b  = (const float*)d_in[7];
    const float* lng_g = (const float*)d_in[8];
    const float* lng_b = (const float*)d_in[9];
    const float* Wq    = (const float*)d_in[10];
    const float* bq    = (const float*)d_in[11];
    const float* Wk    = (const float*)d_in[12];
    const float* bk    = (const float*)d_in[13];
    const float* Wv    = (const float*)d_in[14];
    const float* bv    = (const float*)d_in[15];
    const float* W_ih  = (const float*)d_in[16];
    const float* W_hh  = (const float*)d_in[17];
    const float* b_ih  = (const float*)d_in[18];
    const float* b_hh  = (const float*)d_in[19];
    const float* seg   = (const float*)d_in[20];
    const float* pe    = (const float*)d_in[21];
    float* out = (float*)d_out;

    const int ATTN_SMEM = (NH_*D_ + CH*D_ + CH*NH_ + 2*NH_) * 4;
    cudaFuncSetAttribute(k_attn, cudaFuncAttributeMaxDynamicSharedMemorySize, ATTN_SMEM);

    // ---- preamble ----
    k_prep<<<dim3(16, 48, 6), 256>>>(Wk, W_ih, W_hh, Wq, Wv, W1);
    k_build_hblk<<<B_, 512>>>(emb, stc, off, sep);
    k_tc_w1<<<dim3(4, 16, 2), 256>>>();
    k_a<<<2048, 256>>>(W2);
    k_s1<<<L_, 512>>>();
    k_b0<<<B_, 512>>>(ln_g, ln_b, pe);
    k_buildH<<<dim3(S_, B_), 128>>>(emb, pe, seg, ln_g, ln_b, stc, off);

    // ---- 3 GRU iterations ----
    for (int it = 0; it < 3; it++) {
        k_tc_comb<<<dim3(16, 4, 2), 256>>>();
        k_tc_uk<<<dim3(4, 4, 8), 256>>>(bq);
        k_attn<<<B_, 256, ATTN_SMEM>>>(bk, bq, stc);
        k_tc_mraw<<<dim3(1, 4, 32), 256>>>();
        k_ln_mt<<<B_, 512>>>(bv, lng_g, lng_b);
        k_tc_gi<<<dim3(12, 4, 2), 256>>>();
        k_gru<<<B_, 512>>>(b_ih, b_hh, out, it == 2 ? 1 : 0);
    }
    (void)in_sizes; (void)n_in; (void)out_size;
}

// round 8
// speedup vs baseline: 2.3504x; 1.0551x over previous
#include <cuda_runtime.h>
#include <cuda_bf16.h>
#include <cuda_fp16.h>
#include <mma.h>
#include <math.h>

#define B_  512
#define S_  200
#define D_  512
#define NH_ 8
#define L_  4
#define CH  32

// ---------------- scratch (device globals) ----------------------------------
__device__ float g_hblk[B_*L_*D_];
__device__ float g_valid[B_*L_];
__device__ float g_a[B_*L_];
__device__ float g_s1[B_*L_];
__device__ float g_bt[B_*D_];
__device__ __half g_Hh[B_*S_*D_];        // 105 MB (fp16 H)
__device__ float g_uK[B_*NH_*D_];
__device__ float g_ctx[B_*NH_*D_];
__device__ float g_psum[B_*NH_];
__device__ float g_mt[B_*D_];
__device__ float g_partC[2*B_*2048];     // comb / W1 split-K partials
__device__ float g_partM[4*B_*D_];       // mraw split-K partials
__device__ float g_partG[2*B_*1536];     // gi split-K partials

// bf16 hi/lo split weights, [N][K] layout (K contiguous)
__device__ __nv_bfloat16 g_combT_h[2048*512];
__device__ __nv_bfloat16 g_combT_l[2048*512];
__device__ __nv_bfloat16 g_Wih_h[1536*512];
__device__ __nv_bfloat16 g_Wih_l[1536*512];
__device__ __nv_bfloat16 g_Wk_h[512*512];
__device__ __nv_bfloat16 g_Wk_l[512*512];
__device__ __nv_bfloat16 g_WvT_h[512*512];
__device__ __nv_bfloat16 g_WvT_l[512*512];
__device__ __nv_bfloat16 g_W1T_h[512*512];
__device__ __nv_bfloat16 g_W1T_l[512*512];

#define PC1_OFF 1048576L   // 512*2048
#define PM_OFF  262144L    // 512*512
#define PG1_OFF 786432L    // 512*1536

// ---------------- helpers ----------------------------------------------------
__device__ __forceinline__ float warpSum(float v) {
    #pragma unroll
    for (int o = 16; o; o >>= 1) v += __shfl_down_sync(0xffffffffu, v, o);
    return v;
}
__device__ __forceinline__ float warpMax(float v) {
    #pragma unroll
    for (int o = 16; o; o >>= 1) v = fmaxf(v, __shfl_down_sync(0xffffffffu, v, o));
    return v;
}
__device__ __forceinline__ float blockSum(float v, float* red) {
    int lane = threadIdx.x & 31, w = threadIdx.x >> 5;
    v = warpSum(v);
    if (lane == 0) red[w] = v;
    __syncthreads();
    float r = 0.f;
    if (threadIdx.x < (blockDim.x >> 5)) r = red[threadIdx.x];
    if (w == 0) r = warpSum(r);
    if (threadIdx.x == 0) red[0] = r;
    __syncthreads();
    r = red[0];
    __syncthreads();
    return r;
}
__device__ __forceinline__ float blockMax(float v, float* red) {
    int lane = threadIdx.x & 31, w = threadIdx.x >> 5;
    v = warpMax(v);
    if (lane == 0) red[w] = v;
    __syncthreads();
    float r = -3.0e38f;
    if (threadIdx.x < (blockDim.x >> 5)) r = red[threadIdx.x];
    if (w == 0) r = warpMax(r);
    if (threadIdx.x == 0) red[0] = r;
    __syncthreads();
    r = red[0];
    __syncthreads();
    return r;
}
__device__ __forceinline__ float sigm(float x) { return 1.f / (1.f + expf(-x)); }
#define DOT4(u, h) ((u).x*(h).x + (u).y*(h).y + (u).z*(h).z + (u).w*(h).w)

// ---------------- WMMA tensor GEMM core (register-prefetch pipeline) -----------
// C[128 x BN] tile of A[M,Kd](fp32) @ B^T where B is bf16 hi/lo in [N][K] layout.
// 3-product bf16 split: AhBh + AhBl + AlBh, fp32 accumulate.
// If COMPOSE: A = A0 + A1 + Abias[k].
template <int BN, bool COMPOSE>
__device__ __forceinline__ void tc_core(
    const float* A0, const float* A1, const float* Ab, int lda,
    const __nv_bfloat16* Bh, const __nv_bfloat16* Bl, int ldb,
    float* C, int ldc, int Kd, int m0, int n0)
{
    const int RS = 40;        // smem row stride in bf16 elems (80 B)
    const int NT = BN / 32;   // 16-wide n tiles per warp (4 or 2)
    const int BL = BN / 64;   // B prefetch regs per thread (2 or 1)

    __shared__ __align__(32) __nv_bfloat16 sAh[128 * RS];
    __shared__ __align__(32) __nv_bfloat16 sAl[128 * RS];
    __shared__ __align__(32) __nv_bfloat16 sBh[BN * RS];
    __shared__ __align__(32) __nv_bfloat16 sBl[BN * RS];

    int tid = threadIdx.x;
    int warp = tid >> 5;
    int wm = warp & 3;
    int wn = warp >> 2;

    nvcuda::wmma::fragment<nvcuda::wmma::accumulator, 16, 16, 16, float> acc[2][NT];
    #pragma unroll
    for (int i = 0; i < 2; i++) {
        #pragma unroll
        for (int j = 0; j < NT; j++) {
            nvcuda::wmma::fill_fragment(acc[i][j], 0.0f);
        }
    }

    float4 va[4];
    uint4 vbh[2], vbl[2];

    // ---- prefetch chunk 0 into registers ----
    #pragma unroll
    for (int i = 0; i < 4; i++) {
        int idx = tid + i * 256;
        int row = idx >> 3;
        int q = idx & 7;
        float4 v = *(const float4*)(A0 + (long)(m0 + row) * lda + q * 4);
        if (COMPOSE) {
            float4 v1 = *(const float4*)(A1 + (long)(m0 + row) * lda + q * 4);
            float4 bi = *(const float4*)(Ab + q * 4);
            v.x += v1.x + bi.x; v.y += v1.y + bi.y;
            v.z += v1.z + bi.z; v.w += v1.w + bi.w;
        }
        va[i] = v;
    }
    #pragma unroll
    for (int i = 0; i < BL; i++) {
        int c = tid + i * 256;
        int row = c >> 2;
        int q = c & 3;
        vbh[i] = *(const uint4*)(Bh + (long)(n0 + row) * ldb + q * 8);
        vbl[i] = *(const uint4*)(Bl + (long)(n0 + row) * ldb + q * 8);
    }
    // ---- store stage 0 ----
    #pragma unroll
    for (int i = 0; i < 4; i++) {
        int idx = tid + i * 256;
        int row = idx >> 3;
        int q = idx & 7;
        float4 v = va[i];
        __nv_bfloat16 h0 = __float2bfloat16(v.x);
        __nv_bfloat16 h1 = __float2bfloat16(v.y);
        __nv_bfloat16 h2 = __float2bfloat16(v.z);
        __nv_bfloat16 h3 = __float2bfloat16(v.w);
        int o = row * RS + q * 4;
        sAh[o + 0] = h0; sAh[o + 1] = h1; sAh[o + 2] = h2; sAh[o + 3] = h3;
        sAl[o + 0] = __float2bfloat16(v.x - __bfloat162float(h0));
        sAl[o + 1] = __float2bfloat16(v.y - __bfloat162float(h1));
        sAl[o + 2] = __float2bfloat16(v.z - __bfloat162float(h2));
        sAl[o + 3] = __float2bfloat16(v.w - __bfloat162float(h3));
    }
    #pragma unroll
    for (int i = 0; i < BL; i++) {
        int c = tid + i * 256;
        int row = c >> 2;
        int q = c & 3;
        *(uint4*)(sBh + row * RS + q * 8) = vbh[i];
        *(uint4*)(sBl + row * RS + q * 8) = vbl[i];
    }
    __syncthreads();

    int nch = Kd >> 5;
    for (int c = 0; c < nch; c++) {
        int kn = (c + 1) * 32;
        if (c + 1 < nch) {
            // prefetch next chunk into registers (overlaps MMA below)
            #pragma unroll
            for (int i = 0; i < 4; i++) {
                int idx = tid + i * 256;
                int row = idx >> 3;
                int q = idx & 7;
                float4 v = *(const float4*)(A0 + (long)(m0 + row) * lda + kn + q * 4);
                if (COMPOSE) {
                    float4 v1 = *(const float4*)(A1 + (long)(m0 + row) * lda + kn + q * 4);
                    float4 bi = *(const float4*)(Ab + kn + q * 4);
                    v.x += v1.x + bi.x; v.y += v1.y + bi.y;
                    v.z += v1.z + bi.z; v.w += v1.w + bi.w;
                }
                va[i] = v;
            }
            #pragma unroll
            for (int i = 0; i < BL; i++) {
                int cc = tid + i * 256;
                int row = cc >> 2;
                int q = cc & 3;
                vbh[i] = *(const uint4*)(Bh + (long)(n0 + row) * ldb + kn + q * 8);
                vbl[i] = *(const uint4*)(Bl + (long)(n0 + row) * ldb + kn + q * 8);
            }
        }
        // ---- compute current chunk from smem ----
        #pragma unroll
        for (int ks = 0; ks < 2; ks++) {
            nvcuda::wmma::fragment<nvcuda::wmma::matrix_a, 16, 16, 16,
                                   __nv_bfloat16, nvcuda::wmma::row_major> ah[2], al[2];
            #pragma unroll
            for (int i = 0; i < 2; i++) {
                int r = wm * 32 + i * 16;
                nvcuda::wmma::load_matrix_sync(ah[i], sAh + r * RS + ks * 16, RS);
                nvcuda::wmma::load_matrix_sync(al[i], sAl + r * RS + ks * 16, RS);
            }
            #pragma unroll
            for (int j = 0; j < NT; j++) {
                int nn = wn * (BN / 2) + j * 16;
                nvcuda::wmma::fragment<nvcuda::wmma::matrix_b, 16, 16, 16,
                                       __nv_bfloat16, nvcuda::wmma::col_major> bh, bl;
                nvcuda::wmma::load_matrix_sync(bh, sBh + nn * RS + ks * 16, RS);
                nvcuda::wmma::load_matrix_sync(bl, sBl + nn * RS + ks * 16, RS);
                #pragma unroll
                for (int i = 0; i < 2; i++) {
                    nvcuda::wmma::mma_sync(acc[i][j], ah[i], bh, acc[i][j]);
                    nvcuda::wmma::mma_sync(acc[i][j], ah[i], bl, acc[i][j]);
                    nvcuda::wmma::mma_sync(acc[i][j], al[i], bh, acc[i][j]);
                }
            }
        }
        __syncthreads();
        if (c + 1 < nch) {
            // ---- store next stage from registers ----
            #pragma unroll
            for (int i = 0; i < 4; i++) {
                int idx = tid + i * 256;
                int row = idx >> 3;
                int q = idx & 7;
                float4 v = va[i];
                __nv_bfloat16 h0 = __float2bfloat16(v.x);
                __nv_bfloat16 h1 = __float2bfloat16(v.y);
                __nv_bfloat16 h2 = __float2bfloat16(v.z);
                __nv_bfloat16 h3 = __float2bfloat16(v.w);
                int o = row * RS + q * 4;
                sAh[o + 0] = h0; sAh[o + 1] = h1; sAh[o + 2] = h2; sAh[o + 3] = h3;
                sAl[o + 0] = __float2bfloat16(v.x - __bfloat162float(h0));
                sAl[o + 1] = __float2bfloat16(v.y - __bfloat162float(h1));
                sAl[o + 2] = __float2bfloat16(v.z - __bfloat162float(h2));
                sAl[o + 3] = __float2bfloat16(v.w - __bfloat162float(h3));
            }
            #pragma unroll
            for (int i = 0; i < BL; i++) {
                int cc = tid + i * 256;
                int row = cc >> 2;
                int q = cc & 3;
                *(uint4*)(sBh + row * RS + q * 8) = vbh[i];
                *(uint4*)(sBl + row * RS + q * 8) = vbl[i];
            }
        }
        __syncthreads();
    }
    #pragma unroll
    for (int i = 0; i < 2; i++) {
        #pragma unroll
        for (int j = 0; j < NT; j++) {
            int row = m0 + wm * 32 + i * 16;
            int col = n0 + wn * (BN / 2) + j * 16;
            nvcuda::wmma::store_matrix_sync(C + (long)row * ldc + col, acc[i][j],
                                            ldc, nvcuda::wmma::mem_row_major);
        }
    }
}

// ---------------- GEMM wrapper kernels ----------------------------------------
__global__ __launch_bounds__(256) void k_tc_w1()
{
    int z = blockIdx.z;
    tc_core<128, false>(g_hblk + z * 256, (const float*)0, (const float*)0, 512,
                        g_W1T_h + z * 256, g_W1T_l + z * 256, 512,
                        g_partC + (long)z * PC1_OFF, 512, 256,
                        blockIdx.y * 128, blockIdx.x * 128);
}
__global__ __launch_bounds__(256) void k_tc_comb()
{
    int z = blockIdx.z;
    tc_core<128, false>(g_bt + z * 256, (const float*)0, (const float*)0, 512,
                        g_combT_h + z * 256, g_combT_l + z * 256, 512,
                        g_partC + (long)z * PC1_OFF, 2048, 256,
                        blockIdx.y * 128, blockIdx.x * 128);
}
__global__ __launch_bounds__(256) void k_tc_uk(const float* __restrict__ bq)
{
    int h = blockIdx.z;
    tc_core<128, true>(g_partC + h * 64, g_partC + PC1_OFF + h * 64, bq + h * 64, 2048,
                       g_Wk_h + h * 64, g_Wk_l + h * 64, 512,
                       g_uK + h * 512, 4096, 64,
                       blockIdx.y * 128, blockIdx.x * 128);
}
__global__ __launch_bounds__(256) void k_tc_mraw()
{
    int z = blockIdx.z;
    int h = z >> 2;
    int ks = z & 3;
    tc_core<64, false>(g_ctx + h * 512 + (long)ks * 128, (const float*)0, (const float*)0, 4096,
                       g_WvT_h + (long)(h * 64) * 512 + ks * 128,
                       g_WvT_l + (long)(h * 64) * 512 + ks * 128, 512,
                       g_partM + ks * PM_OFF + h * 64, 512, 128,
                       blockIdx.y * 128, 0);
}
__global__ __launch_bounds__(256) void k_tc_gi()
{
    int z = blockIdx.z;
    tc_core<128, false>(g_mt + z * 256, (const float*)0, (const float*)0, 512,
                        g_Wih_h + z * 256, g_Wih_l + z * 256, 512,
                        g_partG + (long)z * PG1_OFF, 1536, 256,
                        blockIdx.y * 128, blockIdx.x * 128);
}

// ---------------- weight prep: transpose + bf16 hi/lo split --------------------
__global__ __launch_bounds__(256) void k_prep(
    const float* __restrict__ Wk, const float* __restrict__ W_ih,
    const float* __restrict__ W_hh, const float* __restrict__ Wq,
    const float* __restrict__ Wv, const float* __restrict__ W1)
{
    __shared__ float t[32][33];
    int job = blockIdx.z;
    int bx = blockIdx.x * 32;
    int by = blockIdx.y * 32;
    int lx = threadIdx.x & 31;
    int wy = threadIdx.x >> 5;
    if (job <= 2) {
        const float* src;
        __nv_bfloat16* dh;
        __nv_bfloat16* dl;
        int nrows;
        if (job == 0)      { src = Wk;   dh = g_Wk_h;  dl = g_Wk_l;  nrows = 512;  }
        else if (job == 1) { src = W_ih; dh = g_Wih_h; dl = g_Wih_l; nrows = 1536; }
        else               { src = W_hh; dh = g_combT_h + 512*512;
                             dl = g_combT_l + 512*512; nrows = 1536; }
        if (by >= nrows) return;
        for (int j = wy; j < 32; j += 8) {
            long o = (long)(by + j) * 512 + bx + lx;
            float v = src[o];
            __nv_bfloat16 hh = __float2bfloat16(v);
            dh[o] = hh;
            dl[o] = __float2bfloat16(v - __bfloat162float(hh));
        }
    } else {
        if (blockIdx.y >= 16) return;
        const float* src;
        __nv_bfloat16* dh;
        __nv_bfloat16* dl;
        if (job == 3)      { src = Wq; dh = g_combT_h; dl = g_combT_l; }
        else if (job == 4) { src = Wv; dh = g_WvT_h;   dl = g_WvT_l;   }
        else               { src = W1; dh = g_W1T_h;   dl = g_W1T_l;   }
        for (int j = wy; j < 32; j += 8)
            t[j][lx] = src[(long)(by + j) * 512 + bx + lx];
        __syncthreads();
        for (int j = wy; j < 32; j += 8) {
            float v = t[lx][j];
            long o = (long)(bx + j) * 512 + by + lx;
            __nv_bfloat16 hh = __float2bfloat16(v);
            dh[o] = hh;
            dl[o] = __float2bfloat16(v - __bfloat162float(hh));
        }
    }
}

// ---------------- preamble -----------------------------------------------------
__global__ __launch_bounds__(512) void k_build_hblk(
    const float* __restrict__ emb, const int* __restrict__ stc,
    const int* __restrict__ off, const int* __restrict__ sep)
{
    int b = blockIdx.x;
    int o = off[b], len = stc[b];
    int sA = sep[b * 2], sB2 = sep[b * 2 + 1];
    int idx = (sA < o ? 1 : 0) + (sB2 < o ? 1 : 0);
    int pidx = idx - 1; pidx = pidx < 0 ? 0 : (pidx > 1 ? 1 : pidx);
    int prev = (pidx == 0) ? sA : sB2;
    int left = (idx > 0) ? prev + 1 : 0;
    int nidx = idx > 1 ? 1 : idx;
    int nxt = (nidx == 0) ? sA : sB2;
    int right = (idx < 2) ? nxt : len;
    int start = (o - 2 > left) ? o - 2 : left;
    int end = (o + 2 < right) ? o + 2 : right;
    int t = threadIdx.x;
    #pragma unroll
    for (int l = 0; l < L_; l++) {
        int ind = start + l;
        bool v = ind < end;
        int ic = ind < 0 ? 0 : (ind > S_ - 1 ? S_ - 1 : ind);
        g_hblk[(b * L_ + l) * D_ + t] = v ? emb[((long)b * S_ + ic) * D_ + t] : 0.f;
        if (t == 0) g_valid[b * L_ + l] = v ? 1.f : 0.f;
    }
}

__global__ __launch_bounds__(256) void k_a(const float* __restrict__ W2)
{
    int m = blockIdx.x, t = threadIdx.x;
    float t0 = tanhf(g_partC[(long)m * 512 + t] + g_partC[PC1_OFF + (long)m * 512 + t]);
    float t1 = tanhf(g_partC[(long)m * 512 + t + 256] + g_partC[PC1_OFF + (long)m * 512 + t + 256]);
    float v = t0 * W2[t] + t1 * W2[t + 256];
    __shared__ float red[32];
    v = blockSum(v, red);
    if (t == 0) g_a[m] = v;
}

__global__ __launch_bounds__(512) void k_s1()
{
    int l = blockIdx.x, t = threadIdx.x;
    __shared__ float red[32];
    float v = g_a[t * L_ + l];
    float mx = blockMax(v, red);
    float e = expf(v - mx);
    float s = blockSum(e, red);
    g_s1[t * L_ + l] = e / s;
}

__global__ __launch_bounds__(512) void k_b0(
    const float* __restrict__ ln_g, const float* __restrict__ ln_b,
    const float* __restrict__ pe)
{
    int b = blockIdx.x, t = threadIdx.x;
    __shared__ float sc[4];
    __shared__ float red[32];
    if (t == 0) {
        float vals[4], mx = -3.0e38f;
        #pragma unroll
        for (int l = 0; l < 4; l++) {
            float v = (g_valid[b * 4 + l] > 0.5f) ? g_s1[b * 4 + l] : -1e9f;
            vals[l] = v; mx = fmaxf(mx, v);
        }
        float s = 0.f;
        #pragma unroll
        for (int l = 0; l < 4; l++) { float e = expf(vals[l] - mx); sc[l] = e; s += e; }
        #pragma unroll
        for (int l = 0; l < 4; l++) sc[l] /= s;
    }
    __syncthreads();
    float x = sc[0] * g_hblk[(b * 4 + 0) * D_ + t] + sc[1] * g_hblk[(b * 4 + 1) * D_ + t]
            + sc[2] * g_hblk[(b * 4 + 2) * D_ + t] + sc[3] * g_hblk[(b * 4 + 3) * D_ + t]
            + pe[t];
    float mean = blockSum(x, red) * (1.f / 512.f);
    float d = x - mean;
    float var = blockSum(d * d, red) * (1.f / 512.f);
    g_bt[b * D_ + t] = d * rsqrtf(var + 1e-5f) * ln_g[t] + ln_b[t];
}

__global__ __launch_bounds__(128) void k_buildH(
    const float* __restrict__ emb, const float* __restrict__ pe,
    const float* __restrict__ seg_emb, const float* __restrict__ ln_g,
    const float* __restrict__ ln_b, const int* __restrict__ stc,
    const int* __restrict__ off)
{
    int b = blockIdx.y, s = blockIdx.x;
    if (s >= stc[b]) return;
    int pos = off[b];
    int ip = (s < pos) ? (pos - s) : (s + 1 - pos);
    ip = ip < 0 ? 0 : (ip > S_ ? S_ : ip);
    int sg = (s >= pos) ? 1 : 0;
    int t = threadIdx.x;
    __shared__ float red[32];
    float4 e = *(const float4*)(emb + ((long)b * S_ + s) * D_ + t * 4);
    float4 p = *(const float4*)(pe + (long)ip * D_ + t * 4);
    float4 g = *(const float4*)(seg_emb + sg * D_ + t * 4);
    float x0 = e.x + p.x + g.x, x1 = e.y + p.y + g.y;
    float x2 = e.z + p.z + g.z, x3 = e.w + p.w + g.w;
    float mean = blockSum(x0 + x1 + x2 + x3, red) * (1.f / 512.f);
    float d0 = x0 - mean, d1 = x1 - mean, d2 = x2 - mean, d3 = x3 - mean;
    float var = blockSum(d0 * d0 + d1 * d1 + d2 * d2 + d3 * d3, red) * (1.f / 512.f);
    float inv = rsqrtf(var + 1e-5f);
    float4 gg = *(const float4*)(ln_g + t * 4);
    float4 bb = *(const float4*)(ln_b + t * 4);
    float o0 = d0 * inv * gg.x + bb.x;
    float o1 = d1 * inv * gg.y + bb.y;
    float o2 = d2 * inv * gg.z + bb.z;
    float o3 = d3 * inv * gg.w + bb.w;
    __half2 ha = __floats2half2_rn(o0, o1);
    __half2 hb = __floats2half2_rn(o2, o3);
    __half2* dst = (__half2*)(g_Hh + ((long)b * S_ + s) * D_) + t * 2;
    dst[0] = ha;
    dst[1] = hb;
}

// ---------------- fused attention (256 thr, per-batch CTA) --------------------
__global__ __launch_bounds__(256) void k_attn(
    const float* __restrict__ bk, const float* __restrict__ bq,
    const int* __restrict__ stc)
{
    int b = blockIdx.x;
    int tid = threadIdx.x, lane = tid & 31, warp = tid >> 5;   // 8 warps
    extern __shared__ float sm[];
    float* uKs = sm;                    // 8*512
    float* Hs  = sm + NH_ * D_;         // 32*512
    float* ps  = Hs + CH * D_;          // 32*8  [s][h]
    float* cKs = ps + CH * NH_;         // 8
    float* pss = cKs + NH_;             // 8
    int len = stc[b];
    {
        const float4* src = (const float4*)(g_uK + (long)b * NH_ * D_);
        float4* dst = (float4*)uKs;
        #pragma unroll
        for (int i = 0; i < 4; i++) dst[i * 256 + tid] = src[i * 256 + tid];
    }
    {
        int j0 = warp * 64 + lane, j1 = j0 + 32;
        float q0 = g_partC[(long)b * 2048 + j0] + g_partC[PC1_OFF + (long)b * 2048 + j0] + bq[j0];
        float q1 = g_partC[(long)b * 2048 + j1] + g_partC[PC1_OFF + (long)b * 2048 + j1] + bq[j1];
        float v = bk[j0] * q0 + bk[j1] * q1;
        v = warpSum(v);
        if (lane == 0) { cKs[warp] = v; pss[warp] = 0.f; }
    }
    float creg[16] = {0.f,0.f,0.f,0.f,0.f,0.f,0.f,0.f,0.f,0.f,0.f,0.f,0.f,0.f,0.f,0.f};
    __syncthreads();
    int nch = (len + CH - 1) / CH;
    for (int c = 0; c < nch; c++) {
        int s0 = c * CH;
        for (int r = warp; r < CH; r += 8) {
            int s = s0 + r;
            float4* dst = (float4*)(Hs + r * D_);
            if (s < len) {
                const uint4* src = (const uint4*)(g_Hh + ((long)b * S_ + s) * D_);
                #pragma unroll
                for (int i = 0; i < 2; i++) {
                    uint4 v = src[i * 32 + lane];
                    __half2 h0 = *(__half2*)&v.x;
                    __half2 h1 = *(__half2*)&v.y;
                    __half2 h2 = *(__half2*)&v.z;
                    __half2 h3 = *(__half2*)&v.w;
                    float2 f0 = __half22float2(h0);
                    float2 f1 = __half22float2(h1);
                    float2 f2 = __half22float2(h2);
                    float2 f3 = __half22float2(h3);
                    float4 o0; o0.x = f0.x; o0.y = f0.y; o0.z = f1.x; o0.w = f1.y;
                    float4 o1; o1.x = f2.x; o1.y = f2.y; o1.z = f3.x; o1.w = f3.y;
                    dst[(i * 32 + lane) * 2]     = o0;
                    dst[(i * 32 + lane) * 2 + 1] = o1;
                }
            } else {
                float4 z = make_float4(0.f, 0.f, 0.f, 0.f);
                #pragma unroll
                for (int i = 0; i < 4; i++) dst[i * 32 + lane] = z;
            }
        }
        ps[tid] = 0.f;
        __syncthreads();
        #pragma unroll
        for (int pass = 0; pass < 2; pass++) {
            int hb = pass * 4;
            float4 u[4][4];
            #pragma unroll
            for (int hh = 0; hh < 4; hh++) {
                #pragma unroll
                for (int i = 0; i < 4; i++)
                    u[hh][i] = *(const float4*)(uKs + (hb + hh) * D_ + (i * 32 + lane) * 4);
            }
            #pragma unroll
            for (int rr = 0; rr < 4; rr++) {
                int r = warp * 4 + rr;
                float4 h4[4];
                #pragma unroll
                for (int i = 0; i < 4; i++)
                    h4[i] = *(const float4*)(Hs + r * D_ + (i * 32 + lane) * 4);
                float acc[4];
                #pragma unroll
                for (int hh = 0; hh < 4; hh++) {
                    acc[hh] = DOT4(u[hh][0], h4[0]) + DOT4(u[hh][1], h4[1])
                            + DOT4(u[hh][2], h4[2]) + DOT4(u[hh][3], h4[3]);
                    acc[hh] = warpSum(acc[hh]);
                }
                if (lane == 0) {
                    int s = s0 + r;
                    if (s < len) {
                        #pragma unroll
                        for (int hh = 0; hh < 4; hh++)
                            ps[r * NH_ + hb + hh] = sigm(0.125f * (acc[hh] + cKs[hb + hh]));
                    }
                }
            }
        }
        __syncthreads();
        #pragma unroll 4
        for (int r = 0; r < CH; r++) {
            float hv0 = Hs[r * D_ + tid];
            float hv1 = Hs[r * D_ + tid + 256];
            float4 p0 = *(const float4*)(ps + r * NH_);
            float4 p1 = *(const float4*)(ps + r * NH_ + 4);
            creg[0] += p0.x * hv0; creg[1] += p0.y * hv0;
            creg[2] += p0.z * hv0; creg[3] += p0.w * hv0;
            creg[4] += p1.x * hv0; creg[5] += p1.y * hv0;
            creg[6] += p1.z * hv0; creg[7] += p1.w * hv0;
            creg[8]  += p0.x * hv1; creg[9]  += p0.y * hv1;
            creg[10] += p0.z * hv1; creg[11] += p0.w * hv1;
            creg[12] += p1.x * hv1; creg[13] += p1.y * hv1;
            creg[14] += p1.z * hv1; creg[15] += p1.w * hv1;
        }
        {
            float v = ps[lane * NH_ + warp];
            v = warpSum(v);
            if (lane == 0) pss[warp] += v;
        }
        __syncthreads();
    }
    #pragma unroll
    for (int h = 0; h < NH_; h++) {
        g_ctx[((long)b * NH_ + h) * D_ + tid]       = creg[h];
        g_ctx[((long)b * NH_ + h) * D_ + tid + 256] = creg[8 + h];
    }
    if (tid < NH_) g_psum[b * NH_ + tid] = pss[tid];
}

// ---------------- small per-iter kernels --------------------------------------
__global__ __launch_bounds__(512) void k_ln_mt(
    const float* __restrict__ bv, const float* __restrict__ lng_g,
    const float* __restrict__ lng_b)
{
    int b = blockIdx.x, t = threadIdx.x;
    __shared__ float red[32];
    long o = (long)b * 512 + t;
    float x = g_partM[o] + g_partM[PM_OFF + o] + g_partM[2 * PM_OFF + o]
            + g_partM[3 * PM_OFF + o] + g_psum[b * NH_ + (t >> 6)] * bv[t];
    float mean = blockSum(x, red) * (1.f / 512.f);
    float d = x - mean;
    float var = blockSum(d * d, red) * (1.f / 512.f);
    g_mt[b * D_ + t] = d * rsqrtf(var + 1e-5f) * lng_g[t] + lng_b[t];
}

__global__ __launch_bounds__(512) void k_gru(
    const float* __restrict__ b_ih, const float* __restrict__ b_hh,
    float* __restrict__ out, int last)
{
    int b = blockIdx.x, t = threadIdx.x;
    const float* G0 = g_partG + (long)b * 1536;
    const float* G1 = g_partG + PG1_OFF + (long)b * 1536;
    const float* C0 = g_partC + (long)b * 2048 + 512;
    const float* C1 = g_partC + PC1_OFF + (long)b * 2048 + 512;
    float ir = G0[t]        + G1[t]        + b_ih[t];
    float iz = G0[t + 512]  + G1[t + 512]  + b_ih[t + 512];
    float in = G0[t + 1024] + G1[t + 1024] + b_ih[t + 1024];
    float hr = C0[t]        + C1[t]        + b_hh[t];
    float hz = C0[t + 512]  + C1[t + 512]  + b_hh[t + 512];
    float hn = C0[t + 1024] + C1[t + 1024] + b_hh[t + 1024];
    float r = sigm(ir + hr);
    float z = sigm(iz + hz);
    float n = tanhf(in + r * hn);
    float old = g_bt[b * D_ + t];
    float nv = (1.f - z) * n + z * old;
    g_bt[b * D_ + t] = nv;
    if (last) out[b * 512 + t] = nv;
}

// ---------------- launch --------------------------------------------------------
extern "C" void kernel_launch(void* const* d_in, const int* in_sizes, int n_in,
                              void* d_out, int out_size)
{
    const float* emb   = (const float*)d_in[0];
    const int*   stc   = (const int*)  d_in[1];
    const int*   off   = (const int*)  d_in[2];
    const int*   sep   = (const int*)  d_in[3];
    const float* W1    = (const float*)d_in[4];
    const float* W2    = (const float*)d_in[5];
    const float* ln_g  = (const float*)d_in[6];
    const float* ln_b  = (const float*)d_in[7];
    const float* lng_g = (const float*)d_in[8];
    const float* lng_b = (const float*)d_in[9];
    const float* Wq    = (const float*)d_in[10];
    const float* bq    = (const float*)d_in[11];
    const float* Wk    = (const float*)d_in[12];
    const float* bk    = (const float*)d_in[13];
    const float* Wv    = (const float*)d_in[14];
    const float* bv    = (const float*)d_in[15];
    const float* W_ih  = (const float*)d_in[16];
    const float* W_hh  = (const float*)d_in[17];
    const float* b_ih  = (const float*)d_in[18];
    const float* b_hh  = (const float*)d_in[19];
    const float* seg   = (const float*)d_in[20];
    const float* pe    = (const float*)d_in[21];
    float* out = (float*)d_out;

    const int ATTN_SMEM = (NH_*D_ + CH*D_ + CH*NH_ + 2*NH_) * 4;
    cudaFuncSetAttribute(k_attn, cudaFuncAttributeMaxDynamicSharedMemorySize, ATTN_SMEM);

    // ---- preamble ----
    k_prep<<<dim3(16, 48, 6), 256>>>(Wk, W_ih, W_hh, Wq, Wv, W1);
    k_build_hblk<<<B_, 512>>>(emb, stc, off, sep);
    k_tc_w1<<<dim3(4, 16, 2), 256>>>();
    k_a<<<2048, 256>>>(W2);
    k_s1<<<L_, 512>>>();
    k_b0<<<B_, 512>>>(ln_g, ln_b, pe);
    k_buildH<<<dim3(S_, B_), 128>>>(emb, pe, seg, ln_g, ln_b, stc, off);

    // ---- 3 GRU iterations ----
    for (int it = 0; it < 3; it++) {
        k_tc_comb<<<dim3(16, 4, 2), 256>>>();
        k_tc_uk<<<dim3(4, 4, 8), 256>>>(bq);
        k_attn<<<B_, 256, ATTN_SMEM>>>(bk, bq, stc);
        k_tc_mraw<<<dim3(1, 4, 32), 256>>>();
        k_ln_mt<<<B_, 512>>>(bv, lng_g, lng_b);
        k_tc_gi<<<dim3(12, 4, 2), 256>>>();
        k_gru<<<B_, 512>>>(b_ih, b_hh, out, it == 2 ? 1 : 0);
    }
    (void)in_sizes; (void)n_in; (void)out_size;
}

// round 9
// speedup vs baseline: 2.4218x; 1.0304x over previous
#include <cuda_runtime.h>
#include <cuda_bf16.h>
#include <cuda_fp16.h>
#include <mma.h>
#include <math.h>

#define B_  512
#define S_  200
#define D_  512
#define NH_ 8
#define L_  4
#define CH  32

// ---------------- scratch (device globals) ----------------------------------
__device__ float g_hblk[B_*L_*D_];
__device__ float g_valid[B_*L_];
__device__ float g_a[B_*L_];
__device__ float g_s1[B_*L_];
__device__ float g_bt[B_*D_];
__device__ __half g_Hh[B_*S_*D_];        // 105 MB (fp16 H)
__device__ float g_uK[B_*NH_*D_];
__device__ float g_ctx[B_*NH_*D_];
__device__ float g_psum[B_*NH_];
__device__ float g_mt[B_*D_];
__device__ float g_partC[2*B_*2048];     // comb / W1 split-K partials
__device__ float g_partM[4*B_*D_];       // mraw split-K partials
__device__ float g_partG[2*B_*1536];     // gi split-K partials

// bf16 hi/lo split weights, [N][K] layout (K contiguous)
__device__ __nv_bfloat16 g_combT_h[2048*512];
__device__ __nv_bfloat16 g_combT_l[2048*512];
__device__ __nv_bfloat16 g_Wih_h[1536*512];
__device__ __nv_bfloat16 g_Wih_l[1536*512];
__device__ __nv_bfloat16 g_Wk_h[512*512];
__device__ __nv_bfloat16 g_Wk_l[512*512];
__device__ __nv_bfloat16 g_WvT_h[512*512];
__device__ __nv_bfloat16 g_WvT_l[512*512];
__device__ __nv_bfloat16 g_W1T_h[512*512];
__device__ __nv_bfloat16 g_W1T_l[512*512];

#define PC1_OFF 1048576L   // 512*2048
#define PM_OFF  262144L    // 512*512
#define PG1_OFF 786432L    // 512*1536

// dynamic smem sizes for tc kernels (2 stages x (A h/l + B h/l))
#define SMEM_TC128 81920
#define SMEM_TC64  61440

// ---------------- helpers ----------------------------------------------------
__device__ __forceinline__ float warpSum(float v) {
    #pragma unroll
    for (int o = 16; o; o >>= 1) v += __shfl_down_sync(0xffffffffu, v, o);
    return v;
}
__device__ __forceinline__ float warpAll(float v) {
    #pragma unroll
    for (int o = 16; o; o >>= 1) v += __shfl_xor_sync(0xffffffffu, v, o);
    return v;
}
__device__ __forceinline__ float warpMax(float v) {
    #pragma unroll
    for (int o = 16; o; o >>= 1) v = fmaxf(v, __shfl_down_sync(0xffffffffu, v, o));
    return v;
}
__device__ __forceinline__ float blockSum(float v, float* red) {
    int lane = threadIdx.x & 31, w = threadIdx.x >> 5;
    v = warpSum(v);
    if (lane == 0) red[w] = v;
    __syncthreads();
    float r = 0.f;
    if (threadIdx.x < (blockDim.x >> 5)) r = red[threadIdx.x];
    if (w == 0) r = warpSum(r);
    if (threadIdx.x == 0) red[0] = r;
    __syncthreads();
    r = red[0];
    __syncthreads();
    return r;
}
__device__ __forceinline__ float blockMax(float v, float* red) {
    int lane = threadIdx.x & 31, w = threadIdx.x >> 5;
    v = warpMax(v);
    if (lane == 0) red[w] = v;
    __syncthreads();
    float r = -3.0e38f;
    if (threadIdx.x < (blockDim.x >> 5)) r = red[threadIdx.x];
    if (w == 0) r = warpMax(r);
    if (threadIdx.x == 0) red[0] = r;
    __syncthreads();
    r = red[0];
    __syncthreads();
    return r;
}
__device__ __forceinline__ float sigm(float x) { return 1.f / (1.f + expf(-x)); }
#define DOT4(u, h) ((u).x*(h).x + (u).y*(h).y + (u).z*(h).z + (u).w*(h).w)

// ---------------- WMMA tensor GEMM core (reg prefetch + smem double buffer) ----
// C[128 x BN] tile of A[M,Kd](fp32) @ B^T where B is bf16 hi/lo in [N][K] layout.
// 3-product bf16 split: AhBh + AhBl + AlBh, fp32 accumulate.
// If COMPOSE: A = A0 + A1 + Abias[k].
// ONE __syncthreads per k-chunk: compute reads stage c&1 while stores target (c+1)&1.
template <int BN, bool COMPOSE>
__device__ __forceinline__ void tc_core(
    const float* A0, const float* A1, const float* Ab, int lda,
    const __nv_bfloat16* Bh, const __nv_bfloat16* Bl, int ldb,
    float* C, int ldc, int Kd, int m0, int n0)
{
    const int RS = 40;            // smem row stride in bf16 elems (80 B)
    const int NT = BN / 32;       // 16-wide n tiles per warp (4 or 2)
    const int BL = BN / 64;       // B prefetch regs per thread (2 or 1)
    const int AE = 128 * RS;      // elems per A buffer (h or l)
    const int BE = BN * RS;       // elems per B buffer (h or l)
    const int STG = 2 * AE + 2 * BE;

    extern __shared__ __nv_bfloat16 dsm[];

    int tid = threadIdx.x;
    int warp = tid >> 5;
    int wm = warp & 3;
    int wn = warp >> 2;

    nvcuda::wmma::fragment<nvcuda::wmma::accumulator, 16, 16, 16, float> acc[2][NT];
    #pragma unroll
    for (int i = 0; i < 2; i++) {
        #pragma unroll
        for (int j = 0; j < NT; j++) {
            nvcuda::wmma::fill_fragment(acc[i][j], 0.0f);
        }
    }

    float4 va[4];
    uint4 vbh[2], vbl[2];

    // ---- prefetch chunk 0 into registers ----
    #pragma unroll
    for (int i = 0; i < 4; i++) {
        int idx = tid + i * 256;
        int row = idx >> 3;
        int q = idx & 7;
        float4 v = *(const float4*)(A0 + (long)(m0 + row) * lda + q * 4);
        if (COMPOSE) {
            float4 v1 = *(const float4*)(A1 + (long)(m0 + row) * lda + q * 4);
            float4 bi = *(const float4*)(Ab + q * 4);
            v.x += v1.x + bi.x; v.y += v1.y + bi.y;
            v.z += v1.z + bi.z; v.w += v1.w + bi.w;
        }
        va[i] = v;
    }
    #pragma unroll
    for (int i = 0; i < BL; i++) {
        int c = tid + i * 256;
        int row = c >> 2;
        int q = c & 3;
        vbh[i] = *(const uint4*)(Bh + (long)(n0 + row) * ldb + q * 8);
        vbl[i] = *(const uint4*)(Bl + (long)(n0 + row) * ldb + q * 8);
    }
    // ---- store stage 0 ----
    {
        __nv_bfloat16* sAh = dsm;
        __nv_bfloat16* sAl = dsm + AE;
        __nv_bfloat16* sBh = dsm + 2 * AE;
        __nv_bfloat16* sBl = dsm + 2 * AE + BE;
        #pragma unroll
        for (int i = 0; i < 4; i++) {
            int idx = tid + i * 256;
            int row = idx >> 3;
            int q = idx & 7;
            float4 v = va[i];
            __nv_bfloat16 h0 = __float2bfloat16(v.x);
            __nv_bfloat16 h1 = __float2bfloat16(v.y);
            __nv_bfloat16 h2 = __float2bfloat16(v.z);
            __nv_bfloat16 h3 = __float2bfloat16(v.w);
            int o = row * RS + q * 4;
            sAh[o + 0] = h0; sAh[o + 1] = h1; sAh[o + 2] = h2; sAh[o + 3] = h3;
            sAl[o + 0] = __float2bfloat16(v.x - __bfloat162float(h0));
            sAl[o + 1] = __float2bfloat16(v.y - __bfloat162float(h1));
            sAl[o + 2] = __float2bfloat16(v.z - __bfloat162float(h2));
            sAl[o + 3] = __float2bfloat16(v.w - __bfloat162float(h3));
        }
        #pragma unroll
        for (int i = 0; i < BL; i++) {
            int c = tid + i * 256;
            int row = c >> 2;
            int q = c & 3;
            *(uint4*)(sBh + row * RS + q * 8) = vbh[i];
            *(uint4*)(sBl + row * RS + q * 8) = vbl[i];
        }
    }
    __syncthreads();

    int nch = Kd >> 5;
    for (int c = 0; c < nch; c++) {
        int kn = (c + 1) * 32;
        if (c + 1 < nch) {
            // prefetch next chunk into registers (overlaps MMA below)
            #pragma unroll
            for (int i = 0; i < 4; i++) {
                int idx = tid + i * 256;
                int row = idx >> 3;
                int q = idx & 7;
                float4 v = *(const float4*)(A0 + (long)(m0 + row) * lda + kn + q * 4);
                if (COMPOSE) {
                    float4 v1 = *(const float4*)(A1 + (long)(m0 + row) * lda + kn + q * 4);
                    float4 bi = *(const float4*)(Ab + kn + q * 4);
                    v.x += v1.x + bi.x; v.y += v1.y + bi.y;
                    v.z += v1.z + bi.z; v.w += v1.w + bi.w;
                }
                va[i] = v;
            }
            #pragma unroll
            for (int i = 0; i < BL; i++) {
                int cc = tid + i * 256;
                int row = cc >> 2;
                int q = cc & 3;
                vbh[i] = *(const uint4*)(Bh + (long)(n0 + row) * ldb + kn + q * 8);
                vbl[i] = *(const uint4*)(Bl + (long)(n0 + row) * ldb + kn + q * 8);
            }
        }
        // ---- compute current chunk from stage c&1 ----
        {
            __nv_bfloat16* base = dsm + (c & 1) * STG;
            __nv_bfloat16* sAh = base;
            __nv_bfloat16* sAl = base + AE;
            __nv_bfloat16* sBh = base + 2 * AE;
            __nv_bfloat16* sBl = base + 2 * AE + BE;
            #pragma unroll
            for (int ks = 0; ks < 2; ks++) {
                nvcuda::wmma::fragment<nvcuda::wmma::matrix_a, 16, 16, 16,
                                       __nv_bfloat16, nvcuda::wmma::row_major> ah[2], al[2];
                #pragma unroll
                for (int i = 0; i < 2; i++) {
                    int r = wm * 32 + i * 16;
                    nvcuda::wmma::load_matrix_sync(ah[i], sAh + r * RS + ks * 16, RS);
                    nvcuda::wmma::load_matrix_sync(al[i], sAl + r * RS + ks * 16, RS);
                }
                #pragma unroll
                for (int j = 0; j < NT; j++) {
                    int nn = wn * (BN / 2) + j * 16;
                    nvcuda::wmma::fragment<nvcuda::wmma::matrix_b, 16, 16, 16,
                                           __nv_bfloat16, nvcuda::wmma::col_major> bh, bl;
                    nvcuda::wmma::load_matrix_sync(bh, sBh + nn * RS + ks * 16, RS);
                    nvcuda::wmma::load_matrix_sync(bl, sBl + nn * RS + ks * 16, RS);
                    #pragma unroll
                    for (int i = 0; i < 2; i++) {
                        nvcuda::wmma::mma_sync(acc[i][j], ah[i], bh, acc[i][j]);
                        nvcuda::wmma::mma_sync(acc[i][j], ah[i], bl, acc[i][j]);
                        nvcuda::wmma::mma_sync(acc[i][j], al[i], bh, acc[i][j]);
                    }
                }
            }
        }
        // ---- store next stage into the OTHER buffer (no barrier needed first) ----
        if (c + 1 < nch) {
            __nv_bfloat16* base = dsm + ((c + 1) & 1) * STG;
            __nv_bfloat16* sAh = base;
            __nv_bfloat16* sAl = base + AE;
            __nv_bfloat16* sBh = base + 2 * AE;
            __nv_bfloat16* sBl = base + 2 * AE + BE;
            #pragma unroll
            for (int i = 0; i < 4; i++) {
                int idx = tid + i * 256;
                int row = idx >> 3;
                int q = idx & 7;
                float4 v = va[i];
                __nv_bfloat16 h0 = __float2bfloat16(v.x);
                __nv_bfloat16 h1 = __float2bfloat16(v.y);
                __nv_bfloat16 h2 = __float2bfloat16(v.z);
                __nv_bfloat16 h3 = __float2bfloat16(v.w);
                int o = row * RS + q * 4;
                sAh[o + 0] = h0; sAh[o + 1] = h1; sAh[o + 2] = h2; sAh[o + 3] = h3;
                sAl[o + 0] = __float2bfloat16(v.x - __bfloat162float(h0));
                sAl[o + 1] = __float2bfloat16(v.y - __bfloat162float(h1));
                sAl[o + 2] = __float2bfloat16(v.z - __bfloat162float(h2));
                sAl[o + 3] = __float2bfloat16(v.w - __bfloat162float(h3));
            }
            #pragma unroll
            for (int i = 0; i < BL; i++) {
                int cc = tid + i * 256;
                int row = cc >> 2;
                int q = cc & 3;
                *(uint4*)(sBh + row * RS + q * 8) = vbh[i];
                *(uint4*)(sBl + row * RS + q * 8) = vbl[i];
            }
        }
        __syncthreads();
    }
    #pragma unroll
    for (int i = 0; i < 2; i++) {
        #pragma unroll
        for (int j = 0; j < NT; j++) {
            int row = m0 + wm * 32 + i * 16;
            int col = n0 + wn * (BN / 2) + j * 16;
            nvcuda::wmma::store_matrix_sync(C + (long)row * ldc + col, acc[i][j],
                                            ldc, nvcuda::wmma::mem_row_major);
        }
    }
}

// ---------------- GEMM wrapper kernels ----------------------------------------
__global__ __launch_bounds__(256) void k_tc_w1()
{
    int z = blockIdx.z;
    tc_core<128, false>(g_hblk + z * 256, (const float*)0, (const float*)0, 512,
                        g_W1T_h + z * 256, g_W1T_l + z * 256, 512,
                        g_partC + (long)z * PC1_OFF, 512, 256,
                        blockIdx.y * 128, blockIdx.x * 128);
}
__global__ __launch_bounds__(256) void k_tc_comb()
{
    int z = blockIdx.z;
    tc_core<128, false>(g_bt + z * 256, (const float*)0, (const float*)0, 512,
                        g_combT_h + z * 256, g_combT_l + z * 256, 512,
                        g_partC + (long)z * PC1_OFF, 2048, 256,
                        blockIdx.y * 128, blockIdx.x * 128);
}
__global__ __launch_bounds__(256) void k_tc_uk(const float* __restrict__ bq)
{
    int h = blockIdx.z;
    tc_core<128, true>(g_partC + h * 64, g_partC + PC1_OFF + h * 64, bq + h * 64, 2048,
                       g_Wk_h + h * 64, g_Wk_l + h * 64, 512,
                       g_uK + h * 512, 4096, 64,
                       blockIdx.y * 128, blockIdx.x * 128);
}
__global__ __launch_bounds__(256) void k_tc_mraw()
{
    int z = blockIdx.z;
    int h = z >> 2;
    int ks = z & 3;
    tc_core<64, false>(g_ctx + h * 512 + (long)ks * 128, (const float*)0, (const float*)0, 4096,
                       g_WvT_h + (long)(h * 64) * 512 + ks * 128,
                       g_WvT_l + (long)(h * 64) * 512 + ks * 128, 512,
                       g_partM + ks * PM_OFF + h * 64, 512, 128,
                       blockIdx.y * 128, 0);
}
__global__ __launch_bounds__(256) void k_tc_gi()
{
    int z = blockIdx.z;
    tc_core<128, false>(g_mt + z * 256, (const float*)0, (const float*)0, 512,
                        g_Wih_h + z * 256, g_Wih_l + z * 256, 512,
                        g_partG + (long)z * PG1_OFF, 1536, 256,
                        blockIdx.y * 128, blockIdx.x * 128);
}

// ---------------- weight prep: transpose + bf16 hi/lo split --------------------
__global__ __launch_bounds__(256) void k_prep(
    const float* __restrict__ Wk, const float* __restrict__ W_ih,
    const float* __restrict__ W_hh, const float* __restrict__ Wq,
    const float* __restrict__ Wv, const float* __restrict__ W1)
{
    __shared__ float t[32][33];
    int job = blockIdx.z;
    int bx = blockIdx.x * 32;
    int by = blockIdx.y * 32;
    int lx = threadIdx.x & 31;
    int wy = threadIdx.x >> 5;
    if (job <= 2) {
        const float* src;
        __nv_bfloat16* dh;
        __nv_bfloat16* dl;
        int nrows;
        if (job == 0)      { src = Wk;   dh = g_Wk_h;  dl = g_Wk_l;  nrows = 512;  }
        else if (job == 1) { src = W_ih; dh = g_Wih_h; dl = g_Wih_l; nrows = 1536; }
        else               { src = W_hh; dh = g_combT_h + 512*512;
                             dl = g_combT_l + 512*512; nrows = 1536; }
        if (by >= nrows) return;
        for (int j = wy; j < 32; j += 8) {
            long o = (long)(by + j) * 512 + bx + lx;
            float v = src[o];
            __nv_bfloat16 hh = __float2bfloat16(v);
            dh[o] = hh;
            dl[o] = __float2bfloat16(v - __bfloat162float(hh));
        }
    } else {
        if (blockIdx.y >= 16) return;
        const float* src;
        __nv_bfloat16* dh;
        __nv_bfloat16* dl;
        if (job == 3)      { src = Wq; dh = g_combT_h; dl = g_combT_l; }
        else if (job == 4) { src = Wv; dh = g_WvT_h;   dl = g_WvT_l;   }
        else               { src = W1; dh = g_W1T_h;   dl = g_W1T_l;   }
        for (int j = wy; j < 32; j += 8)
            t[j][lx] = src[(long)(by + j) * 512 + bx + lx];
        __syncthreads();
        for (int j = wy; j < 32; j += 8) {
            float v = t[lx][j];
            long o = (long)(bx + j) * 512 + by + lx;
            __nv_bfloat16 hh = __float2bfloat16(v);
            dh[o] = hh;
            dl[o] = __float2bfloat16(v - __bfloat162float(hh));
        }
    }
}

// ---------------- preamble -----------------------------------------------------
__global__ __launch_bounds__(512) void k_build_hblk(
    const float* __restrict__ emb, const int* __restrict__ stc,
    const int* __restrict__ off, const int* __restrict__ sep)
{
    int b = blockIdx.x;
    int o = off[b], len = stc[b];
    int sA = sep[b * 2], sB2 = sep[b * 2 + 1];
    int idx = (sA < o ? 1 : 0) + (sB2 < o ? 1 : 0);
    int pidx = idx - 1; pidx = pidx < 0 ? 0 : (pidx > 1 ? 1 : pidx);
    int prev = (pidx == 0) ? sA : sB2;
    int left = (idx > 0) ? prev + 1 : 0;
    int nidx = idx > 1 ? 1 : idx;
    int nxt = (nidx == 0) ? sA : sB2;
    int right = (idx < 2) ? nxt : len;
    int start = (o - 2 > left) ? o - 2 : left;
    int end = (o + 2 < right) ? o + 2 : right;
    int t = threadIdx.x;
    #pragma unroll
    for (int l = 0; l < L_; l++) {
        int ind = start + l;
        bool v = ind < end;
        int ic = ind < 0 ? 0 : (ind > S_ - 1 ? S_ - 1 : ind);
        g_hblk[(b * L_ + l) * D_ + t] = v ? emb[((long)b * S_ + ic) * D_ + t] : 0.f;
        if (t == 0) g_valid[b * L_ + l] = v ? 1.f : 0.f;
    }
}

__global__ __launch_bounds__(256) void k_a(const float* __restrict__ W2)
{
    int m = blockIdx.x, t = threadIdx.x;
    float t0 = tanhf(g_partC[(long)m * 512 + t] + g_partC[PC1_OFF + (long)m * 512 + t]);
    float t1 = tanhf(g_partC[(long)m * 512 + t + 256] + g_partC[PC1_OFF + (long)m * 512 + t + 256]);
    float v = t0 * W2[t] + t1 * W2[t + 256];
    __shared__ float red[32];
    v = blockSum(v, red);
    if (t == 0) g_a[m] = v;
}

__global__ __launch_bounds__(512) void k_s1()
{
    int l = blockIdx.x, t = threadIdx.x;
    __shared__ float red[32];
    float v = g_a[t * L_ + l];
    float mx = blockMax(v, red);
    float e = expf(v - mx);
    float s = blockSum(e, red);
    g_s1[t * L_ + l] = e / s;
}

__global__ __launch_bounds__(512) void k_b0(
    const float* __restrict__ ln_g, const float* __restrict__ ln_b,
    const float* __restrict__ pe)
{
    int b = blockIdx.x, t = threadIdx.x;
    __shared__ float sc[4];
    __shared__ float red[32];
    if (t == 0) {
        float vals[4], mx = -3.0e38f;
        #pragma unroll
        for (int l = 0; l < 4; l++) {
            float v = (g_valid[b * 4 + l] > 0.5f) ? g_s1[b * 4 + l] : -1e9f;
            vals[l] = v; mx = fmaxf(mx, v);
        }
        float s = 0.f;
        #pragma unroll
        for (int l = 0; l < 4; l++) { float e = expf(vals[l] - mx); sc[l] = e; s += e; }
        #pragma unroll
        for (int l = 0; l < 4; l++) sc[l] /= s;
    }
    __syncthreads();
    float x = sc[0] * g_hblk[(b * 4 + 0) * D_ + t] + sc[1] * g_hblk[(b * 4 + 1) * D_ + t]
            + sc[2] * g_hblk[(b * 4 + 2) * D_ + t] + sc[3] * g_hblk[(b * 4 + 3) * D_ + t]
            + pe[t];
    float mean = blockSum(x, red) * (1.f / 512.f);
    float d = x - mean;
    float var = blockSum(d * d, red) * (1.f / 512.f);
    g_bt[b * D_ + t] = d * rsqrtf(var + 1e-5f) * ln_g[t] + ln_b[t];
}

// warp-per-row H build: 512 blocks x 256 threads, no block barriers in hot loop
__global__ __launch_bounds__(256) void k_buildH(
    const float* __restrict__ emb, const float* __restrict__ pe,
    const float* __restrict__ seg_emb, const float* __restrict__ ln_g,
    const float* __restrict__ ln_b, const int* __restrict__ stc,
    const int* __restrict__ off)
{
    __shared__ float s_seg[2][D_];
    __shared__ float s_g[D_];
    __shared__ float s_b[D_];
    int b = blockIdx.x;
    int tid = threadIdx.x, lane = tid & 31, warp = tid >> 5;
    for (int i = tid; i < D_; i += 256) {
        s_seg[0][i] = seg_emb[i];
        s_seg[1][i] = seg_emb[D_ + i];
        s_g[i] = ln_g[i];
        s_b[i] = ln_b[i];
    }
    int len = stc[b];
    int pos = off[b];
    __syncthreads();
    for (int s = warp; s < len; s += 8) {
        int ip = (s < pos) ? (pos - s) : (s + 1 - pos);
        ip = ip < 0 ? 0 : (ip > S_ ? S_ : ip);
        int sg = (s >= pos) ? 1 : 0;
        const float* er = emb + ((long)b * S_ + s) * D_;
        const float* pr = pe + (long)ip * D_;
        float x[16];
        float sum = 0.f;
        #pragma unroll
        for (int i = 0; i < 4; i++) {
            int base = i * 128 + lane * 4;
            float4 e = *(const float4*)(er + base);
            float4 p = *(const float4*)(pr + base);
            float v0 = e.x + p.x + s_seg[sg][base + 0];
            float v1 = e.y + p.y + s_seg[sg][base + 1];
            float v2 = e.z + p.z + s_seg[sg][base + 2];
            float v3 = e.w + p.w + s_seg[sg][base + 3];
            x[i*4+0] = v0; x[i*4+1] = v1; x[i*4+2] = v2; x[i*4+3] = v3;
            sum += v0 + v1 + v2 + v3;
        }
        float mean = warpAll(sum) * (1.f / 512.f);
        float vs = 0.f;
        #pragma unroll
        for (int i = 0; i < 16; i++) {
            float d = x[i] - mean;
            x[i] = d;
            vs += d * d;
        }
        float inv = rsqrtf(warpAll(vs) * (1.f / 512.f) + 1e-5f);
        __half* dr = g_Hh + ((long)b * S_ + s) * D_;
        #pragma unroll
        for (int i = 0; i < 4; i++) {
            int base = i * 128 + lane * 4;
            float o0 = x[i*4+0] * inv * s_g[base + 0] + s_b[base + 0];
            float o1 = x[i*4+1] * inv * s_g[base + 1] + s_b[base + 1];
            float o2 = x[i*4+2] * inv * s_g[base + 2] + s_b[base + 2];
            float o3 = x[i*4+3] * inv * s_g[base + 3] + s_b[base + 3];
            __half2 ha = __floats2half2_rn(o0, o1);
            __half2 hb = __floats2half2_rn(o2, o3);
            *(__half2*)(dr + base)     = ha;
            *(__half2*)(dr + base + 2) = hb;
        }
    }
}

// ---------------- fused attention (256 thr, per-batch CTA) --------------------
__global__ __launch_bounds__(256) void k_attn(
    const float* __restrict__ bk, const float* __restrict__ bq,
    const int* __restrict__ stc)
{
    int b = blockIdx.x;
    int tid = threadIdx.x, lane = tid & 31, warp = tid >> 5;   // 8 warps
    extern __shared__ float sm[];
    float* uKs = sm;                    // 8*512
    float* Hs  = sm + NH_ * D_;         // 32*512
    float* ps  = Hs + CH * D_;          // 32*8  [s][h]
    float* cKs = ps + CH * NH_;         // 8
    float* pss = cKs + NH_;             // 8
    int len = stc[b];
    {
        const float4* src = (const float4*)(g_uK + (long)b * NH_ * D_);
        float4* dst = (float4*)uKs;
        #pragma unroll
        for (int i = 0; i < 4; i++) dst[i * 256 + tid] = src[i * 256 + tid];
    }
    {
        int j0 = warp * 64 + lane, j1 = j0 + 32;
        float q0 = g_partC[(long)b * 2048 + j0] + g_partC[PC1_OFF + (long)b * 2048 + j0] + bq[j0];
        float q1 = g_partC[(long)b * 2048 + j1] + g_partC[PC1_OFF + (long)b * 2048 + j1] + bq[j1];
        float v = bk[j0] * q0 + bk[j1] * q1;
        v = warpSum(v);
        if (lane == 0) { cKs[warp] = v; pss[warp] = 0.f; }
    }
    float creg[16] = {0.f,0.f,0.f,0.f,0.f,0.f,0.f,0.f,0.f,0.f,0.f,0.f,0.f,0.f,0.f,0.f};
    __syncthreads();
    int nch = (len + CH - 1) / CH;
    for (int c = 0; c < nch; c++) {
        int s0 = c * CH;
        for (int r = warp; r < CH; r += 8) {
            int s = s0 + r;
            float4* dst = (float4*)(Hs + r * D_);
            if (s < len) {
                const uint4* src = (const uint4*)(g_Hh + ((long)b * S_ + s) * D_);
                #pragma unroll
                for (int i = 0; i < 2; i++) {
                    uint4 v = src[i * 32 + lane];
                    __half2 h0 = *(__half2*)&v.x;
                    __half2 h1 = *(__half2*)&v.y;
                    __half2 h2 = *(__half2*)&v.z;
                    __half2 h3 = *(__half2*)&v.w;
                    float2 f0 = __half22float2(h0);
                    float2 f1 = __half22float2(h1);
                    float2 f2 = __half22float2(h2);
                    float2 f3 = __half22float2(h3);
                    float4 o0; o0.x = f0.x; o0.y = f0.y; o0.z = f1.x; o0.w = f1.y;
                    float4 o1; o1.x = f2.x; o1.y = f2.y; o1.z = f3.x; o1.w = f3.y;
                    dst[(i * 32 + lane) * 2]     = o0;
                    dst[(i * 32 + lane) * 2 + 1] = o1;
                }
            } else {
                float4 z = make_float4(0.f, 0.f, 0.f, 0.f);
                #pragma unroll
                for (int i = 0; i < 4; i++) dst[i * 32 + lane] = z;
            }
        }
        ps[tid] = 0.f;
        __syncthreads();
        #pragma unroll
        for (int pass = 0; pass < 2; pass++) {
            int hb = pass * 4;
            float4 u[4][4];
            #pragma unroll
            for (int hh = 0; hh < 4; hh++) {
                #pragma unroll
                for (int i = 0; i < 4; i++)
                    u[hh][i] = *(const float4*)(uKs + (hb + hh) * D_ + (i * 32 + lane) * 4);
            }
            #pragma unroll
            for (int rr = 0; rr < 4; rr++) {
                int r = warp * 4 + rr;
                float4 h4[4];
                #pragma unroll
                for (int i = 0; i < 4; i++)
                    h4[i] = *(const float4*)(Hs + r * D_ + (i * 32 + lane) * 4);
                float acc[4];
                #pragma unroll
                for (int hh = 0; hh < 4; hh++) {
                    acc[hh] = DOT4(u[hh][0], h4[0]) + DOT4(u[hh][1], h4[1])
                            + DOT4(u[hh][2], h4[2]) + DOT4(u[hh][3], h4[3]);
                    acc[hh] = warpSum(acc[hh]);
                }
                if (lane == 0) {
                    int s = s0 + r;
                    if (s < len) {
                        #pragma unroll
                        for (int hh = 0; hh < 4; hh++)
                            ps[r * NH_ + hb + hh] = sigm(0.125f * (acc[hh] + cKs[hb + hh]));
                    }
                }
            }
        }
        __syncthreads();
        #pragma unroll 4
        for (int r = 0; r < CH; r++) {
            float hv0 = Hs[r * D_ + tid];
            float hv1 = Hs[r * D_ + tid + 256];
            float4 p0 = *(const float4*)(ps + r * NH_);
            float4 p1 = *(const float4*)(ps + r * NH_ + 4);
            creg[0] += p0.x * hv0; creg[1] += p0.y * hv0;
            creg[2] += p0.z * hv0; creg[3] += p0.w * hv0;
            creg[4] += p1.x * hv0; creg[5] += p1.y * hv0;
            creg[6] += p1.z * hv0; creg[7] += p1.w * hv0;
            creg[8]  += p0.x * hv1; creg[9]  += p0.y * hv1;
            creg[10] += p0.z * hv1; creg[11] += p0.w * hv1;
            creg[12] += p1.x * hv1; creg[13] += p1.y * hv1;
            creg[14] += p1.z * hv1; creg[15] += p1.w * hv1;
        }
        {
            float v = ps[lane * NH_ + warp];
            v = warpSum(v);
            if (lane == 0) pss[warp] += v;
        }
        __syncthreads();
    }
    #pragma unroll
    for (int h = 0; h < NH_; h++) {
        g_ctx[((long)b * NH_ + h) * D_ + tid]       = creg[h];
        g_ctx[((long)b * NH_ + h) * D_ + tid + 256] = creg[8 + h];
    }
    if (tid < NH_) g_psum[b * NH_ + tid] = pss[tid];
}

// ---------------- small per-iter kernels --------------------------------------
__global__ __launch_bounds__(512) void k_ln_mt(
    const float* __restrict__ bv, const float* __restrict__ lng_g,
    const float* __restrict__ lng_b)
{
    int b = blockIdx.x, t = threadIdx.x;
    __shared__ float red[32];
    long o = (long)b * 512 + t;
    float x = g_partM[o] + g_partM[PM_OFF + o] + g_partM[2 * PM_OFF + o]
            + g_partM[3 * PM_OFF + o] + g_psum[b * NH_ + (t >> 6)] * bv[t];
    float mean = blockSum(x, red) * (1.f / 512.f);
    float d = x - mean;
    float var = blockSum(d * d, red) * (1.f / 512.f);
    g_mt[b * D_ + t] = d * rsqrtf(var + 1e-5f) * lng_g[t] + lng_b[t];
}

__global__ __launch_bounds__(512) void k_gru(
    const float* __restrict__ b_ih, const float* __restrict__ b_hh,
    float* __restrict__ out, int last)
{
    int b = blockIdx.x, t = threadIdx.x;
    const float* G0 = g_partG + (long)b * 1536;
    const float* G1 = g_partG + PG1_OFF + (long)b * 1536;
    const float* C0 = g_partC + (long)b * 2048 + 512;
    const float* C1 = g_partC + PC1_OFF + (long)b * 2048 + 512;
    float ir = G0[t]        + G1[t]        + b_ih[t];
    float iz = G0[t + 512]  + G1[t + 512]  + b_ih[t + 512];
    float in = G0[t + 1024] + G1[t + 1024] + b_ih[t + 1024];
    float hr = C0[t]        + C1[t]        + b_hh[t];
    float hz = C0[t + 512]  + C1[t + 512]  + b_hh[t + 512];
    float hn = C0[t + 1024] + C1[t + 1024] + b_hh[t + 1024];
    float r = sigm(ir + hr);
    float z = sigm(iz + hz);
    float n = tanhf(in + r * hn);
    float old = g_bt[b * D_ + t];
    float nv = (1.f - z) * n + z * old;
    g_bt[b * D_ + t] = nv;
    if (last) out[b * 512 + t] = nv;
}

// ---------------- launch --------------------------------------------------------
extern "C" void kernel_launch(void* const* d_in, const int* in_sizes, int n_in,
                              void* d_out, int out_size)
{
    const float* emb   = (const float*)d_in[0];
    const int*   stc   = (const int*)  d_in[1];
    const int*   off   = (const int*)  d_in[2];
    const int*   sep   = (const int*)  d_in[3];
    const float* W1    = (const float*)d_in[4];
    const float* W2    = (const float*)d_in[5];
    const float* ln_g  = (const float*)d_in[6];
    const float* ln_b  = (const float*)d_in[7];
    const float* lng_g = (const float*)d_in[8];
    const float* lng_b = (const float*)d_in[9];
    const float* Wq    = (const float*)d_in[10];
    const float* bq    = (const float*)d_in[11];
    const float* Wk    = (const float*)d_in[12];
    const float* bk    = (const float*)d_in[13];
    const float* Wv    = (const float*)d_in[14];
    const float* bv    = (const float*)d_in[15];
    const float* W_ih  = (const float*)d_in[16];
    const float* W_hh  = (const float*)d_in[17];
    const float* b_ih  = (const float*)d_in[18];
    const float* b_hh  = (const float*)d_in[19];
    const float* seg   = (const float*)d_in[20];
    const float* pe    = (const float*)d_in[21];
    float* out = (float*)d_out;

    const int ATTN_SMEM = (NH_*D_ + CH*D_ + CH*NH_ + 2*NH_) * 4;
    cudaFuncSetAttribute(k_attn, cudaFuncAttributeMaxDynamicSharedMemorySize, ATTN_SMEM);
    cudaFuncSetAttribute(k_tc_w1,   cudaFuncAttributeMaxDynamicSharedMemorySize, SMEM_TC128);
    cudaFuncSetAttribute(k_tc_comb, cudaFuncAttributeMaxDynamicSharedMemorySize, SMEM_TC128);
    cudaFuncSetAttribute(k_tc_uk,   cudaFuncAttributeMaxDynamicSharedMemorySize, SMEM_TC128);
    cudaFuncSetAttribute(k_tc_gi,   cudaFuncAttributeMaxDynamicSharedMemorySize, SMEM_TC128);
    cudaFuncSetAttribute(k_tc_mraw, cudaFuncAttributeMaxDynamicSharedMemorySize, SMEM_TC64);

    // ---- preamble ----
    k_prep<<<dim3(16, 48, 6), 256>>>(Wk, W_ih, W_hh, Wq, Wv, W1);
    k_build_hblk<<<B_, 512>>>(emb, stc, off, sep);
    k_tc_w1<<<dim3(4, 16, 2), 256, SMEM_TC128>>>();
    k_a<<<2048, 256>>>(W2);
    k_s1<<<L_, 512>>>();
    k_b0<<<B_, 512>>>(ln_g, ln_b, pe);
    k_buildH<<<B_, 256>>>(emb, pe, seg, ln_g, ln_b, stc, off);

    // ---- 3 GRU iterations ----
    for (int it = 0; it < 3; it++) {
        k_tc_comb<<<dim3(16, 4, 2), 256, SMEM_TC128>>>();
        k_tc_uk<<<dim3(4, 4, 8), 256, SMEM_TC128>>>(bq);
        k_attn<<<B_, 256, ATTN_SMEM>>>(bk, bq, stc);
        k_tc_mraw<<<dim3(1, 4, 32), 256, SMEM_TC64>>>();
        k_ln_mt<<<B_, 512>>>(bv, lng_g, lng_b);
        k_tc_gi<<<dim3(12, 4, 2), 256, SMEM_TC128>>>();
        k_gru<<<B_, 512>>>(b_ih, b_hh, out, it == 2 ? 1 : 0);
    }
    (void)in_sizes; (void)n_in; (void)out_size;
}

// round 10
// speedup vs baseline: 2.4789x; 1.0236x over previous
#include <cuda_runtime.h>
#include <cuda_bf16.h>
#include <cuda_fp16.h>
#include <mma.h>
#include <math.h>

#define B_  512
#define S_  200
#define D_  512
#define NH_ 8
#define L_  4
#define CH  32

// ---------------- scratch (device globals) ----------------------------------
__device__ float g_hblk[B_*L_*D_];
__device__ float g_valid[B_*L_];
__device__ float g_a[B_*L_];
__device__ float g_s1[B_*L_];
__device__ float g_bt[B_*D_];
__device__ __half g_Hh[B_*S_*D_];        // 105 MB (fp16 H)
__device__ float g_uK[B_*NH_*D_];
__device__ float g_ctx[B_*NH_*D_];
__device__ float g_psum[B_*NH_];
__device__ float g_mt[B_*D_];
__device__ float g_partC[2*B_*2048];     // comb / W1 split-K partials
__device__ float g_partM[4*B_*D_];       // mraw split-K partials
__device__ float g_partG[2*B_*1536];     // gi split-K partials

// bf16 hi/lo split weights, [N][K] layout (K contiguous)
__device__ __nv_bfloat16 g_combT_h[2048*512];
__device__ __nv_bfloat16 g_combT_l[2048*512];
__device__ __nv_bfloat16 g_Wih_h[1536*512];
__device__ __nv_bfloat16 g_Wih_l[1536*512];
__device__ __nv_bfloat16 g_Wk_h[512*512];
__device__ __nv_bfloat16 g_Wk_l[512*512];
__device__ __nv_bfloat16 g_WvT_h[512*512];
__device__ __nv_bfloat16 g_WvT_l[512*512];
__device__ __nv_bfloat16 g_W1T_h[512*512];
__device__ __nv_bfloat16 g_W1T_l[512*512];

#define PC1_OFF 1048576L   // 512*2048
#define PM_OFF  262144L    // 512*512
#define PG1_OFF 786432L    // 512*1536

// dynamic smem sizes for tc kernels (2 stages x (A h/l + B h/l))
#define SMEM_TC128 81920
#define SMEM_TC64  61440

// ---------------- helpers ----------------------------------------------------
__device__ __forceinline__ float warpSum(float v) {
    #pragma unroll
    for (int o = 16; o; o >>= 1) v += __shfl_down_sync(0xffffffffu, v, o);
    return v;
}
__device__ __forceinline__ float warpAll(float v) {
    #pragma unroll
    for (int o = 16; o; o >>= 1) v += __shfl_xor_sync(0xffffffffu, v, o);
    return v;
}
__device__ __forceinline__ float warpMax(float v) {
    #pragma unroll
    for (int o = 16; o; o >>= 1) v = fmaxf(v, __shfl_down_sync(0xffffffffu, v, o));
    return v;
}
__device__ __forceinline__ float blockSum(float v, float* red) {
    int lane = threadIdx.x & 31, w = threadIdx.x >> 5;
    v = warpSum(v);
    if (lane == 0) red[w] = v;
    __syncthreads();
    float r = 0.f;
    if (threadIdx.x < (blockDim.x >> 5)) r = red[threadIdx.x];
    if (w == 0) r = warpSum(r);
    if (threadIdx.x == 0) red[0] = r;
    __syncthreads();
    r = red[0];
    __syncthreads();
    return r;
}
__device__ __forceinline__ float blockMax(float v, float* red) {
    int lane = threadIdx.x & 31, w = threadIdx.x >> 5;
    v = warpMax(v);
    if (lane == 0) red[w] = v;
    __syncthreads();
    float r = -3.0e38f;
    if (threadIdx.x < (blockDim.x >> 5)) r = red[threadIdx.x];
    if (w == 0) r = warpMax(r);
    if (threadIdx.x == 0) red[0] = r;
    __syncthreads();
    r = red[0];
    __syncthreads();
    return r;
}
__device__ __forceinline__ float sigm(float x) { return 1.f / (1.f + expf(-x)); }
#define DOT4(u, h) ((u).x*(h).x + (u).y*(h).y + (u).z*(h).z + (u).w*(h).w)

// ---------------- WMMA tensor GEMM core (reg prefetch + smem double buffer) ----
template <int BN, bool COMPOSE>
__device__ __forceinline__ void tc_core(
    const float* A0, const float* A1, const float* Ab, int lda,
    const __nv_bfloat16* Bh, const __nv_bfloat16* Bl, int ldb,
    float* C, int ldc, int Kd, int m0, int n0)
{
    const int RS = 40;
    const int NT = BN / 32;
    const int BL = BN / 64;
    const int AE = 128 * RS;
    const int BE = BN * RS;
    const int STG = 2 * AE + 2 * BE;

    extern __shared__ __nv_bfloat16 dsm[];

    int tid = threadIdx.x;
    int warp = tid >> 5;
    int wm = warp & 3;
    int wn = warp >> 2;

    nvcuda::wmma::fragment<nvcuda::wmma::accumulator, 16, 16, 16, float> acc[2][NT];
    #pragma unroll
    for (int i = 0; i < 2; i++) {
        #pragma unroll
        for (int j = 0; j < NT; j++) {
            nvcuda::wmma::fill_fragment(acc[i][j], 0.0f);
        }
    }

    float4 va[4];
    uint4 vbh[2], vbl[2];

    #pragma unroll
    for (int i = 0; i < 4; i++) {
        int idx = tid + i * 256;
        int row = idx >> 3;
        int q = idx & 7;
        float4 v = *(const float4*)(A0 + (long)(m0 + row) * lda + q * 4);
        if (COMPOSE) {
            float4 v1 = *(const float4*)(A1 + (long)(m0 + row) * lda + q * 4);
            float4 bi = *(const float4*)(Ab + q * 4);
            v.x += v1.x + bi.x; v.y += v1.y + bi.y;
            v.z += v1.z + bi.z; v.w += v1.w + bi.w;
        }
        va[i] = v;
    }
    #pragma unroll
    for (int i = 0; i < BL; i++) {
        int c = tid + i * 256;
        int row = c >> 2;
        int q = c & 3;
        vbh[i] = *(const uint4*)(Bh + (long)(n0 + row) * ldb + q * 8);
        vbl[i] = *(const uint4*)(Bl + (long)(n0 + row) * ldb + q * 8);
    }
    {
        __nv_bfloat16* sAh = dsm;
        __nv_bfloat16* sAl = dsm + AE;
        __nv_bfloat16* sBh = dsm + 2 * AE;
        __nv_bfloat16* sBl = dsm + 2 * AE + BE;
        #pragma unroll
        for (int i = 0; i < 4; i++) {
            int idx = tid + i * 256;
            int row = idx >> 3;
            int q = idx & 7;
            float4 v = va[i];
            __nv_bfloat16 h0 = __float2bfloat16(v.x);
            __nv_bfloat16 h1 = __float2bfloat16(v.y);
            __nv_bfloat16 h2 = __float2bfloat16(v.z);
            __nv_bfloat16 h3 = __float2bfloat16(v.w);
            int o = row * RS + q * 4;
            sAh[o + 0] = h0; sAh[o + 1] = h1; sAh[o + 2] = h2; sAh[o + 3] = h3;
            sAl[o + 0] = __float2bfloat16(v.x - __bfloat162float(h0));
            sAl[o + 1] = __float2bfloat16(v.y - __bfloat162float(h1));
            sAl[o + 2] = __float2bfloat16(v.z - __bfloat162float(h2));
            sAl[o + 3] = __float2bfloat16(v.w - __bfloat162float(h3));
        }
        #pragma unroll
        for (int i = 0; i < BL; i++) {
            int c = tid + i * 256;
            int row = c >> 2;
            int q = c & 3;
            *(uint4*)(sBh + row * RS + q * 8) = vbh[i];
            *(uint4*)(sBl + row * RS + q * 8) = vbl[i];
        }
    }
    __syncthreads();

    int nch = Kd >> 5;
    for (int c = 0; c < nch; c++) {
        int kn = (c + 1) * 32;
        if (c + 1 < nch) {
            #pragma unroll
            for (int i = 0; i < 4; i++) {
                int idx = tid + i * 256;
                int row = idx >> 3;
                int q = idx & 7;
                float4 v = *(const float4*)(A0 + (long)(m0 + row) * lda + kn + q * 4);
                if (COMPOSE) {
                    float4 v1 = *(const float4*)(A1 + (long)(m0 + row) * lda + kn + q * 4);
                    float4 bi = *(const float4*)(Ab + kn + q * 4);
                    v.x += v1.x + bi.x; v.y += v1.y + bi.y;
                    v.z += v1.z + bi.z; v.w += v1.w + bi.w;
                }
                va[i] = v;
            }
            #pragma unroll
            for (int i = 0; i < BL; i++) {
                int cc = tid + i * 256;
                int row = cc >> 2;
                int q = cc & 3;
                vbh[i] = *(const uint4*)(Bh + (long)(n0 + row) * ldb + kn + q * 8);
                vbl[i] = *(const uint4*)(Bl + (long)(n0 + row) * ldb + kn + q * 8);
            }
        }
        {
            __nv_bfloat16* base = dsm + (c & 1) * STG;
            __nv_bfloat16* sAh = base;
            __nv_bfloat16* sAl = base + AE;
            __nv_bfloat16* sBh = base + 2 * AE;
            __nv_bfloat16* sBl = base + 2 * AE + BE;
            #pragma unroll
            for (int ks = 0; ks < 2; ks++) {
                nvcuda::wmma::fragment<nvcuda::wmma::matrix_a, 16, 16, 16,
                                       __nv_bfloat16, nvcuda::wmma::row_major> ah[2], al[2];
                #pragma unroll
                for (int i = 0; i < 2; i++) {
                    int r = wm * 32 + i * 16;
                    nvcuda::wmma::load_matrix_sync(ah[i], sAh + r * RS + ks * 16, RS);
                    nvcuda::wmma::load_matrix_sync(al[i], sAl + r * RS + ks * 16, RS);
                }
                #pragma unroll
                for (int j = 0; j < NT; j++) {
                    int nn = wn * (BN / 2) + j * 16;
                    nvcuda::wmma::fragment<nvcuda::wmma::matrix_b, 16, 16, 16,
                                           __nv_bfloat16, nvcuda::wmma::col_major> bh, bl;
                    nvcuda::wmma::load_matrix_sync(bh, sBh + nn * RS + ks * 16, RS);
                    nvcuda::wmma::load_matrix_sync(bl, sBl + nn * RS + ks * 16, RS);
                    #pragma unroll
                    for (int i = 0; i < 2; i++) {
                        nvcuda::wmma::mma_sync(acc[i][j], ah[i], bh, acc[i][j]);
                        nvcuda::wmma::mma_sync(acc[i][j], ah[i], bl, acc[i][j]);
                        nvcuda::wmma::mma_sync(acc[i][j], al[i], bh, acc[i][j]);
                    }
                }
            }
        }
        if (c + 1 < nch) {
            __nv_bfloat16* base = dsm + ((c + 1) & 1) * STG;
            __nv_bfloat16* sAh = base;
            __nv_bfloat16* sAl = base + AE;
            __nv_bfloat16* sBh = base + 2 * AE;
            __nv_bfloat16* sBl = base + 2 * AE + BE;
            #pragma unroll
            for (int i = 0; i < 4; i++) {
                int idx = tid + i * 256;
                int row = idx >> 3;
                int q = idx & 7;
                float4 v = va[i];
                __nv_bfloat16 h0 = __float2bfloat16(v.x);
                __nv_bfloat16 h1 = __float2bfloat16(v.y);
                __nv_bfloat16 h2 = __float2bfloat16(v.z);
                __nv_bfloat16 h3 = __float2bfloat16(v.w);
                int o = row * RS + q * 4;
                sAh[o + 0] = h0; sAh[o + 1] = h1; sAh[o + 2] = h2; sAh[o + 3] = h3;
                sAl[o + 0] = __float2bfloat16(v.x - __bfloat162float(h0));
                sAl[o + 1] = __float2bfloat16(v.y - __bfloat162float(h1));
                sAl[o + 2] = __float2bfloat16(v.z - __bfloat162float(h2));
                sAl[o + 3] = __float2bfloat16(v.w - __bfloat162float(h3));
            }
            #pragma unroll
            for (int i = 0; i < BL; i++) {
                int cc = tid + i * 256;
                int row = cc >> 2;
                int q = cc & 3;
                *(uint4*)(sBh + row * RS + q * 8) = vbh[i];
                *(uint4*)(sBl + row * RS + q * 8) = vbl[i];
            }
        }
        __syncthreads();
    }
    #pragma unroll
    for (int i = 0; i < 2; i++) {
        #pragma unroll
        for (int j = 0; j < NT; j++) {
            int row = m0 + wm * 32 + i * 16;
            int col = n0 + wn * (BN / 2) + j * 16;
            nvcuda::wmma::store_matrix_sync(C + (long)row * ldc + col, acc[i][j],
                                            ldc, nvcuda::wmma::mem_row_major);
        }
    }
}

// ---------------- GEMM wrapper kernels ----------------------------------------
__global__ __launch_bounds__(256) void k_tc_w1()
{
    int z = blockIdx.z;
    tc_core<128, false>(g_hblk + z * 256, (const float*)0, (const float*)0, 512,
                        g_W1T_h + z * 256, g_W1T_l + z * 256, 512,
                        g_partC + (long)z * PC1_OFF, 512, 256,
                        blockIdx.y * 128, blockIdx.x * 128);
}
// q partials only (comb cols 0-511)
__global__ __launch_bounds__(256) void k_tc_q()
{
    int z = blockIdx.z;
    tc_core<128, false>(g_bt + z * 256, (const float*)0, (const float*)0, 512,
                        g_combT_h + z * 256, g_combT_l + z * 256, 512,
                        g_partC + (long)z * PC1_OFF, 2048, 256,
                        blockIdx.y * 128, blockIdx.x * 128);
}
// gh partials only (comb cols 512-2047) — runs on side stream
__global__ __launch_bounds__(256) void k_tc_gh()
{
    int z = blockIdx.z;
    tc_core<128, false>(g_bt + z * 256, (const float*)0, (const float*)0, 512,
                        g_combT_h + (long)512 * 512 + z * 256,
                        g_combT_l + (long)512 * 512 + z * 256, 512,
                        g_partC + (long)z * PC1_OFF + 512, 2048, 256,
                        blockIdx.y * 128, blockIdx.x * 128);
}
__global__ __launch_bounds__(256) void k_tc_uk(const float* __restrict__ bq)
{
    int h = blockIdx.z;
    tc_core<128, true>(g_partC + h * 64, g_partC + PC1_OFF + h * 64, bq + h * 64, 2048,
                       g_Wk_h + h * 64, g_Wk_l + h * 64, 512,
                       g_uK + h * 512, 4096, 64,
                       blockIdx.y * 128, blockIdx.x * 128);
}
__global__ __launch_bounds__(256) void k_tc_mraw()
{
    int z = blockIdx.z;
    int h = z >> 2;
    int ks = z & 3;
    tc_core<64, false>(g_ctx + h * 512 + (long)ks * 128, (const float*)0, (const float*)0, 4096,
                       g_WvT_h + (long)(h * 64) * 512 + ks * 128,
                       g_WvT_l + (long)(h * 64) * 512 + ks * 128, 512,
                       g_partM + ks * PM_OFF + h * 64, 512, 128,
                       blockIdx.y * 128, 0);
}
__global__ __launch_bounds__(256) void k_tc_gi()
{
    int z = blockIdx.z;
    tc_core<128, false>(g_mt + z * 256, (const float*)0, (const float*)0, 512,
                        g_Wih_h + z * 256, g_Wih_l + z * 256, 512,
                        g_partG + (long)z * PG1_OFF, 1536, 256,
                        blockIdx.y * 128, blockIdx.x * 128);
}

// ---------------- weight prep: transpose + bf16 hi/lo split --------------------
__global__ __launch_bounds__(256) void k_prep(
    const float* __restrict__ Wk, const float* __restrict__ W_ih,
    const float* __restrict__ W_hh, const float* __restrict__ Wq,
    const float* __restrict__ Wv, const float* __restrict__ W1)
{
    __shared__ float t[32][33];
    int job = blockIdx.z;
    int bx = blockIdx.x * 32;
    int by = blockIdx.y * 32;
    int lx = threadIdx.x & 31;
    int wy = threadIdx.x >> 5;
    if (job <= 2) {
        const float* src;
        __nv_bfloat16* dh;
        __nv_bfloat16* dl;
        int nrows;
        if (job == 0)      { src = Wk;   dh = g_Wk_h;  dl = g_Wk_l;  nrows = 512;  }
        else if (job == 1) { src = W_ih; dh = g_Wih_h; dl = g_Wih_l; nrows = 1536; }
        else               { src = W_hh; dh = g_combT_h + 512*512;
                             dl = g_combT_l + 512*512; nrows = 1536; }
        if (by >= nrows) return;
        for (int j = wy; j < 32; j += 8) {
            long o = (long)(by + j) * 512 + bx + lx;
            float v = src[o];
            __nv_bfloat16 hh = __float2bfloat16(v);
            dh[o] = hh;
            dl[o] = __float2bfloat16(v - __bfloat162float(hh));
        }
    } else {
        if (blockIdx.y >= 16) return;
        const float* src;
        __nv_bfloat16* dh;
        __nv_bfloat16* dl;
        if (job == 3)      { src = Wq; dh = g_combT_h; dl = g_combT_l; }
        else if (job == 4) { src = Wv; dh = g_WvT_h;   dl = g_WvT_l;   }
        else               { src = W1; dh = g_W1T_h;   dl = g_W1T_l;   }
        for (int j = wy; j < 32; j += 8)
            t[j][lx] = src[(long)(by + j) * 512 + bx + lx];
        __syncthreads();
        for (int j = wy; j < 32; j += 8) {
            float v = t[lx][j];
            long o = (long)(bx + j) * 512 + by + lx;
            __nv_bfloat16 hh = __float2bfloat16(v);
            dh[o] = hh;
            dl[o] = __float2bfloat16(v - __bfloat162float(hh));
        }
    }
}

// ---------------- preamble -----------------------------------------------------
__global__ __launch_bounds__(512) void k_build_hblk(
    const float* __restrict__ emb, const int* __restrict__ stc,
    const int* __restrict__ off, const int* __restrict__ sep)
{
    int b = blockIdx.x;
    int o = off[b], len = stc[b];
    int sA = sep[b * 2], sB2 = sep[b * 2 + 1];
    int idx = (sA < o ? 1 : 0) + (sB2 < o ? 1 : 0);
    int pidx = idx - 1; pidx = pidx < 0 ? 0 : (pidx > 1 ? 1 : pidx);
    int prev = (pidx == 0) ? sA : sB2;
    int left = (idx > 0) ? prev + 1 : 0;
    int nidx = idx > 1 ? 1 : idx;
    int nxt = (nidx == 0) ? sA : sB2;
    int right = (idx < 2) ? nxt : len;
    int start = (o - 2 > left) ? o - 2 : left;
    int end = (o + 2 < right) ? o + 2 : right;
    int t = threadIdx.x;
    #pragma unroll
    for (int l = 0; l < L_; l++) {
        int ind = start + l;
        bool v = ind < end;
        int ic = ind < 0 ? 0 : (ind > S_ - 1 ? S_ - 1 : ind);
        g_hblk[(b * L_ + l) * D_ + t] = v ? emb[((long)b * S_ + ic) * D_ + t] : 0.f;
        if (t == 0) g_valid[b * L_ + l] = v ? 1.f : 0.f;
    }
}

__global__ __launch_bounds__(256) void k_a(const float* __restrict__ W2)
{
    int m = blockIdx.x, t = threadIdx.x;
    float t0 = tanhf(g_partC[(long)m * 512 + t] + g_partC[PC1_OFF + (long)m * 512 + t]);
    float t1 = tanhf(g_partC[(long)m * 512 + t + 256] + g_partC[PC1_OFF + (long)m * 512 + t + 256]);
    float v = t0 * W2[t] + t1 * W2[t + 256];
    __shared__ float red[32];
    v = blockSum(v, red);
    if (t == 0) g_a[m] = v;
}

__global__ __launch_bounds__(512) void k_s1()
{
    int l = blockIdx.x, t = threadIdx.x;
    __shared__ float red[32];
    float v = g_a[t * L_ + l];
    float mx = blockMax(v, red);
    float e = expf(v - mx);
    float s = blockSum(e, red);
    g_s1[t * L_ + l] = e / s;
}

__global__ __launch_bounds__(512) void k_b0(
    const float* __restrict__ ln_g, const float* __restrict__ ln_b,
    const float* __restrict__ pe)
{
    int b = blockIdx.x, t = threadIdx.x;
    __shared__ float sc[4];
    __shared__ float red[32];
    if (t == 0) {
        float vals[4], mx = -3.0e38f;
        #pragma unroll
        for (int l = 0; l < 4; l++) {
            float v = (g_valid[b * 4 + l] > 0.5f) ? g_s1[b * 4 + l] : -1e9f;
            vals[l] = v; mx = fmaxf(mx, v);
        }
        float s = 0.f;
        #pragma unroll
        for (int l = 0; l < 4; l++) { float e = expf(vals[l] - mx); sc[l] = e; s += e; }
        #pragma unroll
        for (int l = 0; l < 4; l++) sc[l] /= s;
    }
    __syncthreads();
    float x = sc[0] * g_hblk[(b * 4 + 0) * D_ + t] + sc[1] * g_hblk[(b * 4 + 1) * D_ + t]
            + sc[2] * g_hblk[(b * 4 + 2) * D_ + t] + sc[3] * g_hblk[(b * 4 + 3) * D_ + t]
            + pe[t];
    float mean = blockSum(x, red) * (1.f / 512.f);
    float d = x - mean;
    float var = blockSum(d * d, red) * (1.f / 512.f);
    g_bt[b * D_ + t] = d * rsqrtf(var + 1e-5f) * ln_g[t] + ln_b[t];
}

// warp-per-row H build: 512 blocks x 256 threads, no block barriers in hot loop
__global__ __launch_bounds__(256) void k_buildH(
    const float* __restrict__ emb, const float* __restrict__ pe,
    const float* __restrict__ seg_emb, const float* __restrict__ ln_g,
    const float* __restrict__ ln_b, const int* __restrict__ stc,
    const int* __restrict__ off)
{
    __shared__ float s_seg[2][D_];
    __shared__ float s_g[D_];
    __shared__ float s_b[D_];
    int b = blockIdx.x;
    int tid = threadIdx.x, lane = tid & 31, warp = tid >> 5;
    for (int i = tid; i < D_; i += 256) {
        s_seg[0][i] = seg_emb[i];
        s_seg[1][i] = seg_emb[D_ + i];
        s_g[i] = ln_g[i];
        s_b[i] = ln_b[i];
    }
    int len = stc[b];
    int pos = off[b];
    __syncthreads();
    for (int s = warp; s < len; s += 8) {
        int ip = (s < pos) ? (pos - s) : (s + 1 - pos);
        ip = ip < 0 ? 0 : (ip > S_ ? S_ : ip);
        int sg = (s >= pos) ? 1 : 0;
        const float* er = emb + ((long)b * S_ + s) * D_;
        const float* pr = pe + (long)ip * D_;
        float x[16];
        float sum = 0.f;
        #pragma unroll
        for (int i = 0; i < 4; i++) {
            int base = i * 128 + lane * 4;
            float4 e = *(const float4*)(er + base);
            float4 p = *(const float4*)(pr + base);
            float v0 = e.x + p.x + s_seg[sg][base + 0];
            float v1 = e.y + p.y + s_seg[sg][base + 1];
            float v2 = e.z + p.z + s_seg[sg][base + 2];
            float v3 = e.w + p.w + s_seg[sg][base + 3];
            x[i*4+0] = v0; x[i*4+1] = v1; x[i*4+2] = v2; x[i*4+3] = v3;
            sum += v0 + v1 + v2 + v3;
        }
        float mean = warpAll(sum) * (1.f / 512.f);
        float vs = 0.f;
        #pragma unroll
        for (int i = 0; i < 16; i++) {
            float d = x[i] - mean;
            x[i] = d;
            vs += d * d;
        }
        float inv = rsqrtf(warpAll(vs) * (1.f / 512.f) + 1e-5f);
        __half* dr = g_Hh + ((long)b * S_ + s) * D_;
        #pragma unroll
        for (int i = 0; i < 4; i++) {
            int base = i * 128 + lane * 4;
            float o0 = x[i*4+0] * inv * s_g[base + 0] + s_b[base + 0];
            float o1 = x[i*4+1] * inv * s_g[base + 1] + s_b[base + 1];
            float o2 = x[i*4+2] * inv * s_g[base + 2] + s_b[base + 2];
            float o3 = x[i*4+3] * inv * s_g[base + 3] + s_b[base + 3];
            __half2 ha = __floats2half2_rn(o0, o1);
            __half2 hb = __floats2half2_rn(o2, o3);
            *(__half2*)(dr + base)     = ha;
            *(__half2*)(dr + base + 2) = hb;
        }
    }
}

// ---------------- fused attention (256 thr, per-batch CTA) --------------------
__global__ __launch_bounds__(256) void k_attn(
    const float* __restrict__ bk, const float* __restrict__ bq,
    const int* __restrict__ stc)
{
    int b = blockIdx.x;
    int tid = threadIdx.x, lane = tid & 31, warp = tid >> 5;   // 8 warps
    extern __shared__ float sm[];
    float* uKs = sm;                    // 8*512
    float* Hs  = sm + NH_ * D_;         // 32*512
    float* ps  = Hs + CH * D_;          // 32*8  [s][h]
    float* cKs = ps + CH * NH_;         // 8
    float* pss = cKs + NH_;             // 8
    int len = stc[b];
    {
        const float4* src = (const float4*)(g_uK + (long)b * NH_ * D_);
        float4* dst = (float4*)uKs;
        #pragma unroll
        for (int i = 0; i < 4; i++) dst[i * 256 + tid] = src[i * 256 + tid];
    }
    {
        int j0 = warp * 64 + lane, j1 = j0 + 32;
        float q0 = g_partC[(long)b * 2048 + j0] + g_partC[PC1_OFF + (long)b * 2048 + j0] + bq[j0];
        float q1 = g_partC[(long)b * 2048 + j1] + g_partC[PC1_OFF + (long)b * 2048 + j1] + bq[j1];
        float v = bk[j0] * q0 + bk[j1] * q1;
        v = warpSum(v);
        if (lane == 0) { cKs[warp] = v; pss[warp] = 0.f; }
    }
    float creg[16] = {0.f,0.f,0.f,0.f,0.f,0.f,0.f,0.f,0.f,0.f,0.f,0.f,0.f,0.f,0.f,0.f};
    __syncthreads();
    int nch = (len + CH - 1) / CH;
    for (int c = 0; c < nch; c++) {
        int s0 = c * CH;
        for (int r = warp; r < CH; r += 8) {
            int s = s0 + r;
            float4* dst = (float4*)(Hs + r * D_);
            if (s < len) {
                const uint4* src = (const uint4*)(g_Hh + ((long)b * S_ + s) * D_);
                #pragma unroll
                for (int i = 0; i < 2; i++) {
                    uint4 v = src[i * 32 + lane];
                    __half2 h0 = *(__half2*)&v.x;
                    __half2 h1 = *(__half2*)&v.y;
                    __half2 h2 = *(__half2*)&v.z;
                    __half2 h3 = *(__half2*)&v.w;
                    float2 f0 = __half22float2(h0);
                    float2 f1 = __half22float2(h1);
                    float2 f2 = __half22float2(h2);
                    float2 f3 = __half22float2(h3);
                    float4 o0; o0.x = f0.x; o0.y = f0.y; o0.z = f1.x; o0.w = f1.y;
                    float4 o1; o1.x = f2.x; o1.y = f2.y; o1.z = f3.x; o1.w = f3.y;
                    dst[(i * 32 + lane) * 2]     = o0;
                    dst[(i * 32 + lane) * 2 + 1] = o1;
                }
            } else {
                float4 z = make_float4(0.f, 0.f, 0.f, 0.f);
                #pragma unroll
                for (int i = 0; i < 4; i++) dst[i * 32 + lane] = z;
            }
        }
        ps[tid] = 0.f;
        __syncthreads();
        #pragma unroll
        for (int pass = 0; pass < 2; pass++) {
            int hb = pass * 4;
            float4 u[4][4];
            #pragma unroll
            for (int hh = 0; hh < 4; hh++) {
                #pragma unroll
                for (int i = 0; i < 4; i++)
                    u[hh][i] = *(const float4*)(uKs + (hb + hh) * D_ + (i * 32 + lane) * 4);
            }
            #pragma unroll
            for (int rr = 0; rr < 4; rr++) {
                int r = warp * 4 + rr;
                float4 h4[4];
                #pragma unroll
                for (int i = 0; i < 4; i++)
                    h4[i] = *(const float4*)(Hs + r * D_ + (i * 32 + lane) * 4);
                float acc[4];
                #pragma unroll
                for (int hh = 0; hh < 4; hh++) {
                    acc[hh] = DOT4(u[hh][0], h4[0]) + DOT4(u[hh][1], h4[1])
                            + DOT4(u[hh][2], h4[2]) + DOT4(u[hh][3], h4[3]);
                    acc[hh] = warpSum(acc[hh]);
                }
                if (lane == 0) {
                    int s = s0 + r;
                    if (s < len) {
                        #pragma unroll
                        for (int hh = 0; hh < 4; hh++)
                            ps[r * NH_ + hb + hh] = sigm(0.125f * (acc[hh] + cKs[hb + hh]));
                    }
                }
            }
        }
        __syncthreads();
        #pragma unroll 4
        for (int r = 0; r < CH; r++) {
            float hv0 = Hs[r * D_ + tid];
            float hv1 = Hs[r * D_ + tid + 256];
            float4 p0 = *(const float4*)(ps + r * NH_);
            float4 p1 = *(const float4*)(ps + r * NH_ + 4);
            creg[0] += p0.x * hv0; creg[1] += p0.y * hv0;
            creg[2] += p0.z * hv0; creg[3] += p0.w * hv0;
            creg[4] += p1.x * hv0; creg[5] += p1.y * hv0;
            creg[6] += p1.z * hv0; creg[7] += p1.w * hv0;
            creg[8]  += p0.x * hv1; creg[9]  += p0.y * hv1;
            creg[10] += p0.z * hv1; creg[11] += p0.w * hv1;
            creg[12] += p1.x * hv1; creg[13] += p1.y * hv1;
            creg[14] += p1.z * hv1; creg[15] += p1.w * hv1;
        }
        {
            float v = ps[lane * NH_ + warp];
            v = warpSum(v);
            if (lane == 0) pss[warp] += v;
        }
        __syncthreads();
    }
    #pragma unroll
    for (int h = 0; h < NH_; h++) {
        g_ctx[((long)b * NH_ + h) * D_ + tid]       = creg[h];
        g_ctx[((long)b * NH_ + h) * D_ + tid + 256] = creg[8 + h];
    }
    if (tid < NH_) g_psum[b * NH_ + tid] = pss[tid];
}

// ---------------- small per-iter kernels --------------------------------------
__global__ __launch_bounds__(512) void k_ln_mt(
    const float* __restrict__ bv, const float* __restrict__ lng_g,
    const float* __restrict__ lng_b)
{
    int b = blockIdx.x, t = threadIdx.x;
    __shared__ float red[32];
    long o = (long)b * 512 + t;
    float x = g_partM[o] + g_partM[PM_OFF + o] + g_partM[2 * PM_OFF + o]
            + g_partM[3 * PM_OFF + o] + g_psum[b * NH_ + (t >> 6)] * bv[t];
    float mean = blockSum(x, red) * (1.f / 512.f);
    float d = x - mean;
    float var = blockSum(d * d, red) * (1.f / 512.f);
    g_mt[b * D_ + t] = d * rsqrtf(var + 1e-5f) * lng_g[t] + lng_b[t];
}

__global__ __launch_bounds__(512) void k_gru(
    const float* __restrict__ b_ih, const float* __restrict__ b_hh,
    float* __restrict__ out, int last)
{
    int b = blockIdx.x, t = threadIdx.x;
    const float* G0 = g_partG + (long)b * 1536;
    const float* G1 = g_partG + PG1_OFF + (long)b * 1536;
    const float* C0 = g_partC + (long)b * 2048 + 512;
    const float* C1 = g_partC + PC1_OFF + (long)b * 2048 + 512;
    float ir = G0[t]        + G1[t]        + b_ih[t];
    float iz = G0[t + 512]  + G1[t + 512]  + b_ih[t + 512];
    float in = G0[t + 1024] + G1[t + 1024] + b_ih[t + 1024];
    float hr = C0[t]        + C1[t]        + b_hh[t];
    float hz = C0[t + 512]  + C1[t + 512]  + b_hh[t + 512];
    float hn = C0[t + 1024] + C1[t + 1024] + b_hh[t + 1024];
    float r = sigm(ir + hr);
    float z = sigm(iz + hz);
    float n = tanhf(in + r * hn);
    float old = g_bt[b * D_ + t];
    float nv = (1.f - z) * n + z * old;
    g_bt[b * D_ + t] = nv;
    if (last) out[b * 512 + t] = nv;
}

// ---------------- launch --------------------------------------------------------
extern "C" void kernel_launch(void* const* d_in, const int* in_sizes, int n_in,
                              void* d_out, int out_size)
{
    const float* emb   = (const float*)d_in[0];
    const int*   stc   = (const int*)  d_in[1];
    const int*   off   = (const int*)  d_in[2];
    const int*   sep   = (const int*)  d_in[3];
    const float* W1    = (const float*)d_in[4];
    const float* W2    = (const float*)d_in[5];
    const float* ln_g  = (const float*)d_in[6];
    const float* ln_b  = (const float*)d_in[7];
    const float* lng_g = (const float*)d_in[8];
    const float* lng_b = (const float*)d_in[9];
    const float* Wq    = (const float*)d_in[10];
    const float* bq    = (const float*)d_in[11];
    const float* Wk    = (const float*)d_in[12];
    const float* bk    = (const float*)d_in[13];
    const float* Wv    = (const float*)d_in[14];
    const float* bv    = (const float*)d_in[15];
    const float* W_ih  = (const float*)d_in[16];
    const float* W_hh  = (const float*)d_in[17];
    const float* b_ih  = (const float*)d_in[18];
    const float* b_hh  = (const float*)d_in[19];
    const float* seg   = (const float*)d_in[20];
    const float* pe    = (const float*)d_in[21];
    float* out = (float*)d_out;

    const int ATTN_SMEM = (NH_*D_ + CH*D_ + CH*NH_ + 2*NH_) * 4;
    cudaFuncSetAttribute(k_attn, cudaFuncAttributeMaxDynamicSharedMemorySize, ATTN_SMEM);
    cudaFuncSetAttribute(k_tc_w1,   cudaFuncAttributeMaxDynamicSharedMemorySize, SMEM_TC128);
    cudaFuncSetAttribute(k_tc_q,    cudaFuncAttributeMaxDynamicSharedMemorySize, SMEM_TC128);
    cudaFuncSetAttribute(k_tc_gh,   cudaFuncAttributeMaxDynamicSharedMemorySize, SMEM_TC128);
    cudaFuncSetAttribute(k_tc_uk,   cudaFuncAttributeMaxDynamicSharedMemorySize, SMEM_TC128);
    cudaFuncSetAttribute(k_tc_gi,   cudaFuncAttributeMaxDynamicSharedMemorySize, SMEM_TC128);
    cudaFuncSetAttribute(k_tc_mraw, cudaFuncAttributeMaxDynamicSharedMemorySize, SMEM_TC64);

    // side stream + events (created fresh each call; never destroyed so an
    // in-flight graph capture is never invalidated — a few host handles leak
    // across the harness's ~2 calls, no device memory involved)
    cudaStream_t sB;
    cudaStreamCreateWithFlags(&sB, cudaStreamNonBlocking);
    cudaEvent_t evF, evH, evG;
    cudaEventCreateWithFlags(&evF, cudaEventDisableTiming);
    cudaEventCreateWithFlags(&evH, cudaEventDisableTiming);
    cudaEventCreateWithFlags(&evG, cudaEventDisableTiming);

    // ---- preamble: fork buildH onto side stream (depends only on inputs) ----
    cudaEventRecord(evF, 0);
    cudaStreamWaitEvent(sB, evF, 0);
    k_buildH<<<B_, 256, 0, sB>>>(emb, pe, seg, ln_g, ln_b, stc, off);
    cudaEventRecord(evH, sB);

    k_prep<<<dim3(16, 48, 6), 256>>>(Wk, W_ih, W_hh, Wq, Wv, W1);
    k_build_hblk<<<B_, 512>>>(emb, stc, off, sep);
    k_tc_w1<<<dim3(4, 16, 2), 256, SMEM_TC128>>>();
    k_a<<<2048, 256>>>(W2);
    k_s1<<<L_, 512>>>();
    k_b0<<<B_, 512>>>(ln_g, ln_b, pe);

    // ---- 3 GRU iterations ----
    for (int it = 0; it < 3; it++) {
        // fork gh GEMM (only consumed by k_gru) onto side stream
        cudaEventRecord(evF, 0);
        cudaStreamWaitEvent(sB, evF, 0);
        k_tc_gh<<<dim3(12, 4, 2), 256, SMEM_TC128, sB>>>();
        cudaEventRecord(evG, sB);

        // critical path
        k_tc_q<<<dim3(4, 4, 2), 256, SMEM_TC128>>>();
        k_tc_uk<<<dim3(4, 4, 8), 256, SMEM_TC128>>>(bq);
        if (it == 0) cudaStreamWaitEvent(0, evH, 0);   // attn needs H
        k_attn<<<B_, 256, ATTN_SMEM>>>(bk, bq, stc);
        k_tc_mraw<<<dim3(1, 4, 32), 256, SMEM_TC64>>>();
        k_ln_mt<<<B_, 512>>>(bv, lng_g, lng_b);
        k_tc_gi<<<dim3(12, 4, 2), 256, SMEM_TC128>>>();
        cudaStreamWaitEvent(0, evG, 0);                // gru needs gh
        k_gru<<<B_, 512>>>(b_ih, b_hh, out, it == 2 ? 1 : 0);
    }
    (void)in_sizes; (void)n_in; (void)out_size;
}

// round 11
// speedup vs baseline: 2.4889x; 1.0041x over previous
#include <cuda_runtime.h>
#include <cuda_bf16.h>
#include <cuda_fp16.h>
#include <cuda_pipeline.h>
#include <mma.h>
#include <math.h>

#define B_  512
#define S_  200
#define D_  512
#define NH_ 8
#define L_  4
#define CH  32

// ---------------- scratch (device globals) ----------------------------------
__device__ float g_hblk[B_*L_*D_];
__device__ float g_valid[B_*L_];
__device__ float g_a[B_*L_];
__device__ float g_s1[B_*L_];
__device__ float g_bt[B_*D_];
__device__ __half g_Hh[B_*S_*D_];        // 105 MB (fp16 H)
__device__ float g_uK[B_*NH_*D_];
__device__ float g_ctx[B_*NH_*D_];
__device__ float g_psum[B_*NH_];
__device__ float g_mt[B_*D_];
__device__ float g_partC[2*B_*2048];     // comb / W1 split-K partials
__device__ float g_partM[4*B_*D_];       // mraw split-K partials
__device__ float g_partG[2*B_*1536];     // gi split-K partials

// bf16 hi/lo split weights, [N][K] layout (K contiguous)
__device__ __nv_bfloat16 g_combT_h[2048*512];
__device__ __nv_bfloat16 g_combT_l[2048*512];
__device__ __nv_bfloat16 g_Wih_h[1536*512];
__device__ __nv_bfloat16 g_Wih_l[1536*512];
__device__ __nv_bfloat16 g_Wk_h[512*512];
__device__ __nv_bfloat16 g_Wk_l[512*512];
__device__ __nv_bfloat16 g_WvT_h[512*512];
__device__ __nv_bfloat16 g_WvT_l[512*512];
__device__ __nv_bfloat16 g_W1T_h[512*512];
__device__ __nv_bfloat16 g_W1T_l[512*512];

#define PC1_OFF 1048576L   // 512*2048
#define PM_OFF  262144L    // 512*512
#define PG1_OFF 786432L    // 512*1536

// dynamic smem: 2 stages x (A(64) h/l + B(BN) h/l) x RS(40) x 2B
#define SMEM_TCB128 61440
#define SMEM_TCB64  40960

// ---------------- helpers ----------------------------------------------------
__device__ __forceinline__ float warpSum(float v) {
    #pragma unroll
    for (int o = 16; o; o >>= 1) v += __shfl_down_sync(0xffffffffu, v, o);
    return v;
}
__device__ __forceinline__ float warpAll(float v) {
    #pragma unroll
    for (int o = 16; o; o >>= 1) v += __shfl_xor_sync(0xffffffffu, v, o);
    return v;
}
__device__ __forceinline__ float warpMax(float v) {
    #pragma unroll
    for (int o = 16; o; o >>= 1) v = fmaxf(v, __shfl_down_sync(0xffffffffu, v, o));
    return v;
}
__device__ __forceinline__ float blockSum(float v, float* red) {
    int lane = threadIdx.x & 31, w = threadIdx.x >> 5;
    v = warpSum(v);
    if (lane == 0) red[w] = v;
    __syncthreads();
    float r = 0.f;
    if (threadIdx.x < (blockDim.x >> 5)) r = red[threadIdx.x];
    if (w == 0) r = warpSum(r);
    if (threadIdx.x == 0) red[0] = r;
    __syncthreads();
    r = red[0];
    __syncthreads();
    return r;
}
__device__ __forceinline__ float blockMax(float v, float* red) {
    int lane = threadIdx.x & 31, w = threadIdx.x >> 5;
    v = warpMax(v);
    if (lane == 0) red[w] = v;
    __syncthreads();
    float r = -3.0e38f;
    if (threadIdx.x < (blockDim.x >> 5)) r = red[threadIdx.x];
    if (w == 0) r = warpMax(r);
    if (threadIdx.x == 0) red[0] = r;
    __syncthreads();
    r = red[0];
    __syncthreads();
    return r;
}
__device__ __forceinline__ float sigm(float x) { return 1.f / (1.f + expf(-x)); }
#define DOT4(u, h) ((u).x*(h).x + (u).y*(h).y + (u).z*(h).z + (u).w*(h).w)

// ---------------- WMMA tensor GEMM core v2 -------------------------------------
// BM=64 tile, 8 warps = 2(m) x 4(n). A: fp32 reg-prefetch + on-the-fly hi/lo
// split. B: cp.async (no register transit). Double-buffered smem, one barrier
// per k-chunk. 3-product bf16 split: AhBh + AhBl + AlBh, fp32 accumulate.
// If COMPOSE: A = A0 + A1 + Abias[k].
template <int BN, bool COMPOSE>
__device__ __forceinline__ void tc_core(
    const float* A0, const float* A1, const float* Ab, int lda,
    const __nv_bfloat16* Bh, const __nv_bfloat16* Bl, int ldb,
    float* C, int ldc, int Kd, int m0, int n0)
{
    const int RS = 40;
    const int NT = BN / 64;       // 16-wide n tiles per warp (2 or 1)
    const int BCH = BN / 64;      // 16B B chunks per thread per h/l
    const int AE = 64 * RS;
    const int BE = BN * RS;
    const int STG = 2 * AE + 2 * BE;

    extern __shared__ __align__(16) __nv_bfloat16 dsm[];

    int tid = threadIdx.x;
    int warp = tid >> 5;
    int wm = warp & 1;
    int wn = warp >> 1;

    nvcuda::wmma::fragment<nvcuda::wmma::accumulator, 16, 16, 16, float> acc[2][NT];
    #pragma unroll
    for (int i = 0; i < 2; i++) {
        #pragma unroll
        for (int j = 0; j < NT; j++) {
            nvcuda::wmma::fill_fragment(acc[i][j], 0.0f);
        }
    }

    float4 va[2];
    int arow = tid >> 3;         // 0..31 (x2 via +32)
    int aq = tid & 7;

    // ---- prologue: chunk 0 ----
    {
        __nv_bfloat16* sBh = dsm + 2 * AE;
        __nv_bfloat16* sBl = dsm + 2 * AE + BE;
        #pragma unroll
        for (int i = 0; i < BCH; i++) {
            int c = tid + i * 256;
            int row = c >> 2;
            int q = c & 3;
            __pipeline_memcpy_async(sBh + row * RS + q * 8,
                                    Bh + (long)(n0 + row) * ldb + q * 8, 16);
            __pipeline_memcpy_async(sBl + row * RS + q * 8,
                                    Bl + (long)(n0 + row) * ldb + q * 8, 16);
        }
        __pipeline_commit();
        #pragma unroll
        for (int i = 0; i < 2; i++) {
            int row = arow + i * 32;
            float4 v = *(const float4*)(A0 + (long)(m0 + row) * lda + aq * 4);
            if (COMPOSE) {
                float4 v1 = *(const float4*)(A1 + (long)(m0 + row) * lda + aq * 4);
                float4 bi = *(const float4*)(Ab + aq * 4);
                v.x += v1.x + bi.x; v.y += v1.y + bi.y;
                v.z += v1.z + bi.z; v.w += v1.w + bi.w;
            }
            va[i] = v;
        }
        __nv_bfloat16* sAh = dsm;
        __nv_bfloat16* sAl = dsm + AE;
        #pragma unroll
        for (int i = 0; i < 2; i++) {
            int row = arow + i * 32;
            float4 v = va[i];
            __nv_bfloat16 h0 = __float2bfloat16(v.x);
            __nv_bfloat16 h1 = __float2bfloat16(v.y);
            __nv_bfloat16 h2 = __float2bfloat16(v.z);
            __nv_bfloat16 h3 = __float2bfloat16(v.w);
            int o = row * RS + aq * 4;
            sAh[o + 0] = h0; sAh[o + 1] = h1; sAh[o + 2] = h2; sAh[o + 3] = h3;
            sAl[o + 0] = __float2bfloat16(v.x - __bfloat162float(h0));
            sAl[o + 1] = __float2bfloat16(v.y - __bfloat162float(h1));
            sAl[o + 2] = __float2bfloat16(v.z - __bfloat162float(h2));
            sAl[o + 3] = __float2bfloat16(v.w - __bfloat162float(h3));
        }
        __pipeline_wait_prior(0);
        __syncthreads();
    }

    int nch = Kd >> 5;
    for (int c = 0; c < nch; c++) {
        int kn = (c + 1) * 32;
        __nv_bfloat16* nxt = dsm + ((c + 1) & 1) * STG;
        if (c + 1 < nch) {
            // B next chunk via cp.async (overlaps compute)
            __nv_bfloat16* sBh = nxt + 2 * AE;
            __nv_bfloat16* sBl = nxt + 2 * AE + BE;
            #pragma unroll
            for (int i = 0; i < BCH; i++) {
                int cc = tid + i * 256;
                int row = cc >> 2;
                int q = cc & 3;
                __pipeline_memcpy_async(sBh + row * RS + q * 8,
                                        Bh + (long)(n0 + row) * ldb + kn + q * 8, 16);
                __pipeline_memcpy_async(sBl + row * RS + q * 8,
                                        Bl + (long)(n0 + row) * ldb + kn + q * 8, 16);
            }
            __pipeline_commit();
            // A next chunk into registers
            #pragma unroll
            for (int i = 0; i < 2; i++) {
                int row = arow + i * 32;
                float4 v = *(const float4*)(A0 + (long)(m0 + row) * lda + kn + aq * 4);
                if (COMPOSE) {
                    float4 v1 = *(const float4*)(A1 + (long)(m0 + row) * lda + kn + aq * 4);
                    float4 bi = *(const float4*)(Ab + kn + aq * 4);
                    v.x += v1.x + bi.x; v.y += v1.y + bi.y;
                    v.z += v1.z + bi.z; v.w += v1.w + bi.w;
                }
                va[i] = v;
            }
        }
        // ---- compute current chunk ----
        {
            __nv_bfloat16* base = dsm + (c & 1) * STG;
            __nv_bfloat16* sAh = base;
            __nv_bfloat16* sAl = base + AE;
            __nv_bfloat16* sBh = base + 2 * AE;
            __nv_bfloat16* sBl = base + 2 * AE + BE;
            #pragma unroll
            for (int ks = 0; ks < 2; ks++) {
                nvcuda::wmma::fragment<nvcuda::wmma::matrix_a, 16, 16, 16,
                                       __nv_bfloat16, nvcuda::wmma::row_major> ah[2], al[2];
                #pragma unroll
                for (int i = 0; i < 2; i++) {
                    int r = wm * 32 + i * 16;
                    nvcuda::wmma::load_matrix_sync(ah[i], sAh + r * RS + ks * 16, RS);
                    nvcuda::wmma::load_matrix_sync(al[i], sAl + r * RS + ks * 16, RS);
                }
                #pragma unroll
                for (int j = 0; j < NT; j++) {
                    int nn = wn * (BN / 4) + j * 16;
                    nvcuda::wmma::fragment<nvcuda::wmma::matrix_b, 16, 16, 16,
                                           __nv_bfloat16, nvcuda::wmma::col_major> bh, bl;
                    nvcuda::wmma::load_matrix_sync(bh, sBh + nn * RS + ks * 16, RS);
                    nvcuda::wmma::load_matrix_sync(bl, sBl + nn * RS + ks * 16, RS);
                    #pragma unroll
                    for (int i = 0; i < 2; i++) {
                        nvcuda::wmma::mma_sync(acc[i][j], ah[i], bh, acc[i][j]);
                        nvcuda::wmma::mma_sync(acc[i][j], ah[i], bl, acc[i][j]);
                        nvcuda::wmma::mma_sync(acc[i][j], al[i], bh, acc[i][j]);
                    }
                }
            }
        }
        // ---- store next A stage; wait B cp.async; barrier ----
        if (c + 1 < nch) {
            __nv_bfloat16* sAh = nxt;
            __nv_bfloat16* sAl = nxt + AE;
            #pragma unroll
            for (int i = 0; i < 2; i++) {
                int row = arow + i * 32;
                float4 v = va[i];
                __nv_bfloat16 h0 = __float2bfloat16(v.x);
                __nv_bfloat16 h1 = __float2bfloat16(v.y);
                __nv_bfloat16 h2 = __float2bfloat16(v.z);
                __nv_bfloat16 h3 = __float2bfloat16(v.w);
                int o = row * RS + aq * 4;
                sAh[o + 0] = h0; sAh[o + 1] = h1; sAh[o + 2] = h2; sAh[o + 3] = h3;
                sAl[o + 0] = __float2bfloat16(v.x - __bfloat162float(h0));
                sAl[o + 1] = __float2bfloat16(v.y - __bfloat162float(h1));
                sAl[o + 2] = __float2bfloat16(v.z - __bfloat162float(h2));
                sAl[o + 3] = __float2bfloat16(v.w - __bfloat162float(h3));
            }
            __pipeline_wait_prior(0);
        }
        __syncthreads();
    }
    #pragma unroll
    for (int i = 0; i < 2; i++) {
        #pragma unroll
        for (int j = 0; j < NT; j++) {
            int row = m0 + wm * 32 + i * 16;
            int col = n0 + wn * (BN / 4) + j * 16;
            nvcuda::wmma::store_matrix_sync(C + (long)row * ldc + col, acc[i][j],
                                            ldc, nvcuda::wmma::mem_row_major);
        }
    }
}

// ---------------- GEMM wrapper kernels (BM=64, 2 CTAs/SM) ----------------------
__global__ __launch_bounds__(256, 2) void k_tc_w1()
{
    int z = blockIdx.z;
    tc_core<128, false>(g_hblk + z * 256, (const float*)0, (const float*)0, 512,
                        g_W1T_h + z * 256, g_W1T_l + z * 256, 512,
                        g_partC + (long)z * PC1_OFF, 512, 256,
                        blockIdx.y * 64, blockIdx.x * 128);
}
__global__ __launch_bounds__(256, 2) void k_tc_q()
{
    int z = blockIdx.z;
    tc_core<128, false>(g_bt + z * 256, (const float*)0, (const float*)0, 512,
                        g_combT_h + z * 256, g_combT_l + z * 256, 512,
                        g_partC + (long)z * PC1_OFF, 2048, 256,
                        blockIdx.y * 64, blockIdx.x * 128);
}
__global__ __launch_bounds__(256, 2) void k_tc_gh()
{
    int z = blockIdx.z;
    tc_core<128, false>(g_bt + z * 256, (const float*)0, (const float*)0, 512,
                        g_combT_h + (long)512 * 512 + z * 256,
                        g_combT_l + (long)512 * 512 + z * 256, 512,
                        g_partC + (long)z * PC1_OFF + 512, 2048, 256,
                        blockIdx.y * 64, blockIdx.x * 128);
}
__global__ __launch_bounds__(256, 2) void k_tc_uk(const float* __restrict__ bq)
{
    int h = blockIdx.z;
    tc_core<128, true>(g_partC + h * 64, g_partC + PC1_OFF + h * 64, bq + h * 64, 2048,
                       g_Wk_h + h * 64, g_Wk_l + h * 64, 512,
                       g_uK + h * 512, 4096, 64,
                       blockIdx.y * 64, blockIdx.x * 128);
}
__global__ __launch_bounds__(256, 2) void k_tc_mraw()
{
    int z = blockIdx.z;
    int h = z >> 2;
    int ks = z & 3;
    tc_core<64, false>(g_ctx + h * 512 + (long)ks * 128, (const float*)0, (const float*)0, 4096,
                       g_WvT_h + (long)(h * 64) * 512 + ks * 128,
                       g_WvT_l + (long)(h * 64) * 512 + ks * 128, 512,
                       g_partM + ks * PM_OFF + h * 64, 512, 128,
                       blockIdx.y * 64, 0);
}
__global__ __launch_bounds__(256, 2) void k_tc_gi()
{
    int z = blockIdx.z;
    tc_core<128, false>(g_mt + z * 256, (const float*)0, (const float*)0, 512,
                        g_Wih_h + z * 256, g_Wih_l + z * 256, 512,
                        g_partG + (long)z * PG1_OFF, 1536, 256,
                        blockIdx.y * 64, blockIdx.x * 128);
}

// ---------------- weight prep: transpose + bf16 hi/lo split --------------------
__global__ __launch_bounds__(256) void k_prep(
    const float* __restrict__ Wk, const float* __restrict__ W_ih,
    const float* __restrict__ W_hh, const float* __restrict__ Wq,
    const float* __restrict__ Wv, const float* __restrict__ W1)
{
    __shared__ float t[32][33];
    int job = blockIdx.z;
    int bx = blockIdx.x * 32;
    int by = blockIdx.y * 32;
    int lx = threadIdx.x & 31;
    int wy = threadIdx.x >> 5;
    if (job <= 2) {
        const float* src;
        __nv_bfloat16* dh;
        __nv_bfloat16* dl;
        int nrows;
        if (job == 0)      { src = Wk;   dh = g_Wk_h;  dl = g_Wk_l;  nrows = 512;  }
        else if (job == 1) { src = W_ih; dh = g_Wih_h; dl = g_Wih_l; nrows = 1536; }
        else               { src = W_hh; dh = g_combT_h + 512*512;
                             dl = g_combT_l + 512*512; nrows = 1536; }
        if (by >= nrows) return;
        for (int j = wy; j < 32; j += 8) {
            long o = (long)(by + j) * 512 + bx + lx;
            float v = src[o];
            __nv_bfloat16 hh = __float2bfloat16(v);
            dh[o] = hh;
            dl[o] = __float2bfloat16(v - __bfloat162float(hh));
        }
    } else {
        if (blockIdx.y >= 16) return;
        const float* src;
        __nv_bfloat16* dh;
        __nv_bfloat16* dl;
        if (job == 3)      { src = Wq; dh = g_combT_h; dl = g_combT_l; }
        else if (job == 4) { src = Wv; dh = g_WvT_h;   dl = g_WvT_l;   }
        else               { src = W1; dh = g_W1T_h;   dl = g_W1T_l;   }
        for (int j = wy; j < 32; j += 8)
            t[j][lx] = src[(long)(by + j) * 512 + bx + lx];
        __syncthreads();
        for (int j = wy; j < 32; j += 8) {
            float v = t[lx][j];
            long o = (long)(bx + j) * 512 + by + lx;
            __nv_bfloat16 hh = __float2bfloat16(v);
            dh[o] = hh;
            dl[o] = __float2bfloat16(v - __bfloat162float(hh));
        }
    }
}

// ---------------- preamble -----------------------------------------------------
__global__ __launch_bounds__(512) void k_build_hblk(
    const float* __restrict__ emb, const int* __restrict__ stc,
    const int* __restrict__ off, const int* __restrict__ sep)
{
    int b = blockIdx.x;
    int o = off[b], len = stc[b];
    int sA = sep[b * 2], sB2 = sep[b * 2 + 1];
    int idx = (sA < o ? 1 : 0) + (sB2 < o ? 1 : 0);
    int pidx = idx - 1; pidx = pidx < 0 ? 0 : (pidx > 1 ? 1 : pidx);
    int prev = (pidx == 0) ? sA : sB2;
    int left = (idx > 0) ? prev + 1 : 0;
    int nidx = idx > 1 ? 1 : idx;
    int nxt = (nidx == 0) ? sA : sB2;
    int right = (idx < 2) ? nxt : len;
    int start = (o - 2 > left) ? o - 2 : left;
    int end = (o + 2 < right) ? o + 2 : right;
    int t = threadIdx.x;
    #pragma unroll
    for (int l = 0; l < L_; l++) {
        int ind = start + l;
        bool v = ind < end;
        int ic = ind < 0 ? 0 : (ind > S_ - 1 ? S_ - 1 : ind);
        g_hblk[(b * L_ + l) * D_ + t] = v ? emb[((long)b * S_ + ic) * D_ + t] : 0.f;
        if (t == 0) g_valid[b * L_ + l] = v ? 1.f : 0.f;
    }
}

__global__ __launch_bounds__(256) void k_a(const float* __restrict__ W2)
{
    int m = blockIdx.x, t = threadIdx.x;
    float t0 = tanhf(g_partC[(long)m * 512 + t] + g_partC[PC1_OFF + (long)m * 512 + t]);
    float t1 = tanhf(g_partC[(long)m * 512 + t + 256] + g_partC[PC1_OFF + (long)m * 512 + t + 256]);
    float v = t0 * W2[t] + t1 * W2[t + 256];
    __shared__ float red[32];
    v = blockSum(v, red);
    if (t == 0) g_a[m] = v;
}

__global__ __launch_bounds__(512) void k_s1()
{
    int l = blockIdx.x, t = threadIdx.x;
    __shared__ float red[32];
    float v = g_a[t * L_ + l];
    float mx = blockMax(v, red);
    float e = expf(v - mx);
    float s = blockSum(e, red);
    g_s1[t * L_ + l] = e / s;
}

__global__ __launch_bounds__(512) void k_b0(
    const float* __restrict__ ln_g, const float* __restrict__ ln_b,
    const float* __restrict__ pe)
{
    int b = blockIdx.x, t = threadIdx.x;
    __shared__ float sc[4];
    __shared__ float red[32];
    if (t == 0) {
        float vals[4], mx = -3.0e38f;
        #pragma unroll
        for (int l = 0; l < 4; l++) {
            float v = (g_valid[b * 4 + l] > 0.5f) ? g_s1[b * 4 + l] : -1e9f;
            vals[l] = v; mx = fmaxf(mx, v);
        }
        float s = 0.f;
        #pragma unroll
        for (int l = 0; l < 4; l++) { float e = expf(vals[l] - mx); sc[l] = e; s += e; }
        #pragma unroll
        for (int l = 0; l < 4; l++) sc[l] /= s;
    }
    __syncthreads();
    float x = sc[0] * g_hblk[(b * 4 + 0) * D_ + t] + sc[1] * g_hblk[(b * 4 + 1) * D_ + t]
            + sc[2] * g_hblk[(b * 4 + 2) * D_ + t] + sc[3] * g_hblk[(b * 4 + 3) * D_ + t]
            + pe[t];
    float mean = blockSum(x, red) * (1.f / 512.f);
    float d = x - mean;
    float var = blockSum(d * d, red) * (1.f / 512.f);
    g_bt[b * D_ + t] = d * rsqrtf(var + 1e-5f) * ln_g[t] + ln_b[t];
}

// warp-per-row H build: 512 blocks x 256 threads, no block barriers in hot loop
__global__ __launch_bounds__(256) void k_buildH(
    const float* __restrict__ emb, const float* __restrict__ pe,
    const float* __restrict__ seg_emb, const float* __restrict__ ln_g,
    const float* __restrict__ ln_b, const int* __restrict__ stc,
    const int* __restrict__ off)
{
    __shared__ float s_seg[2][D_];
    __shared__ float s_g[D_];
    __shared__ float s_b[D_];
    int b = blockIdx.x;
    int tid = threadIdx.x, lane = tid & 31, warp = tid >> 5;
    for (int i = tid; i < D_; i += 256) {
        s_seg[0][i] = seg_emb[i];
        s_seg[1][i] = seg_emb[D_ + i];
        s_g[i] = ln_g[i];
        s_b[i] = ln_b[i];
    }
    int len = stc[b];
    int pos = off[b];
    __syncthreads();
    for (int s = warp; s < len; s += 8) {
        int ip = (s < pos) ? (pos - s) : (s + 1 - pos);
        ip = ip < 0 ? 0 : (ip > S_ ? S_ : ip);
        int sg = (s >= pos) ? 1 : 0;
        const float* er = emb + ((long)b * S_ + s) * D_;
        const float* pr = pe + (long)ip * D_;
        float x[16];
        float sum = 0.f;
        #pragma unroll
        for (int i = 0; i < 4; i++) {
            int base = i * 128 + lane * 4;
            float4 e = *(const float4*)(er + base);
            float4 p = *(const float4*)(pr + base);
            float v0 = e.x + p.x + s_seg[sg][base + 0];
            float v1 = e.y + p.y + s_seg[sg][base + 1];
            float v2 = e.z + p.z + s_seg[sg][base + 2];
            float v3 = e.w + p.w + s_seg[sg][base + 3];
            x[i*4+0] = v0; x[i*4+1] = v1; x[i*4+2] = v2; x[i*4+3] = v3;
            sum += v0 + v1 + v2 + v3;
        }
        float mean = warpAll(sum) * (1.f / 512.f);
        float vs = 0.f;
        #pragma unroll
        for (int i = 0; i < 16; i++) {
            float d = x[i] - mean;
            x[i] = d;
            vs += d * d;
        }
        float inv = rsqrtf(warpAll(vs) * (1.f / 512.f) + 1e-5f);
        __half* dr = g_Hh + ((long)b * S_ + s) * D_;
        #pragma unroll
        for (int i = 0; i < 4; i++) {
            int base = i * 128 + lane * 4;
            float o0 = x[i*4+0] * inv * s_g[base + 0] + s_b[base + 0];
            float o1 = x[i*4+1] * inv * s_g[base + 1] + s_b[base + 1];
            float o2 = x[i*4+2] * inv * s_g[base + 2] + s_b[base + 2];
            float o3 = x[i*4+3] * inv * s_g[base + 3] + s_b[base + 3];
            __half2 ha = __floats2half2_rn(o0, o1);
            __half2 hb = __floats2half2_rn(o2, o3);
            *(__half2*)(dr + base)     = ha;
            *(__half2*)(dr + base + 2) = hb;
        }
    }
}

// ---------------- fused attention (256 thr, per-batch CTA) --------------------
__global__ __launch_bounds__(256) void k_attn(
    const float* __restrict__ bk, const float* __restrict__ bq,
    const int* __restrict__ stc)
{
    int b = blockIdx.x;
    int tid = threadIdx.x, lane = tid & 31, warp = tid >> 5;   // 8 warps
    extern __shared__ float sm[];
    float* uKs = sm;                    // 8*512
    float* Hs  = sm + NH_ * D_;         // 32*512
    float* ps  = Hs + CH * D_;          // 32*8  [s][h]
    float* cKs = ps + CH * NH_;         // 8
    float* pss = cKs + NH_;             // 8
    int len = stc[b];
    {
        const float4* src = (const float4*)(g_uK + (long)b * NH_ * D_);
        float4* dst = (float4*)uKs;
        #pragma unroll
        for (int i = 0; i < 4; i++) dst[i * 256 + tid] = src[i * 256 + tid];
    }
    {
        int j0 = warp * 64 + lane, j1 = j0 + 32;
        float q0 = g_partC[(long)b * 2048 + j0] + g_partC[PC1_OFF + (long)b * 2048 + j0] + bq[j0];
        float q1 = g_partC[(long)b * 2048 + j1] + g_partC[PC1_OFF + (long)b * 2048 + j1] + bq[j1];
        float v = bk[j0] * q0 + bk[j1] * q1;
        v = warpSum(v);
        if (lane == 0) { cKs[warp] = v; pss[warp] = 0.f; }
    }
    float creg[16] = {0.f,0.f,0.f,0.f,0.f,0.f,0.f,0.f,0.f,0.f,0.f,0.f,0.f,0.f,0.f,0.f};
    __syncthreads();
    int nch = (len + CH - 1) / CH;
    for (int c = 0; c < nch; c++) {
        int s0 = c * CH;
        for (int r = warp; r < CH; r += 8) {
            int s = s0 + r;
            float4* dst = (float4*)(Hs + r * D_);
            if (s < len) {
                const uint4* src = (const uint4*)(g_Hh + ((long)b * S_ + s) * D_);
                #pragma unroll
                for (int i = 0; i < 2; i++) {
                    uint4 v = src[i * 32 + lane];
                    __half2 h0 = *(__half2*)&v.x;
                    __half2 h1 = *(__half2*)&v.y;
                    __half2 h2 = *(__half2*)&v.z;
                    __half2 h3 = *(__half2*)&v.w;
                    float2 f0 = __half22float2(h0);
                    float2 f1 = __half22float2(h1);
                    float2 f2 = __half22float2(h2);
                    float2 f3 = __half22float2(h3);
                    float4 o0; o0.x = f0.x; o0.y = f0.y; o0.z = f1.x; o0.w = f1.y;
                    float4 o1; o1.x = f2.x; o1.y = f2.y; o1.z = f3.x; o1.w = f3.y;
                    dst[(i * 32 + lane) * 2]     = o0;
                    dst[(i * 32 + lane) * 2 + 1] = o1;
                }
            } else {
                float4 z = make_float4(0.f, 0.f, 0.f, 0.f);
                #pragma unroll
                for (int i = 0; i < 4; i++) dst[i * 32 + lane] = z;
            }
        }
        ps[tid] = 0.f;
        __syncthreads();
        #pragma unroll
        for (int pass = 0; pass < 2; pass++) {
            int hb = pass * 4;
            float4 u[4][4];
            #pragma unroll
            for (int hh = 0; hh < 4; hh++) {
                #pragma unroll
                for (int i = 0; i < 4; i++)
                    u[hh][i] = *(const float4*)(uKs + (hb + hh) * D_ + (i * 32 + lane) * 4);
            }
            #pragma unroll
            for (int rr = 0; rr < 4; rr++) {
                int r = warp * 4 + rr;
                float4 h4[4];
                #pragma unroll
                for (int i = 0; i < 4; i++)
                    h4[i] = *(const float4*)(Hs + r * D_ + (i * 32 + lane) * 4);
                float acc[4];
                #pragma unroll
                for (int hh = 0; hh < 4; hh++) {
                    acc[hh] = DOT4(u[hh][0], h4[0]) + DOT4(u[hh][1], h4[1])
                            + DOT4(u[hh][2], h4[2]) + DOT4(u[hh][3], h4[3]);
                    acc[hh] = warpSum(acc[hh]);
                }
                if (lane == 0) {
                    int s = s0 + r;
                    if (s < len) {
                        #pragma unroll
                        for (int hh = 0; hh < 4; hh++)
                            ps[r * NH_ + hb + hh] = sigm(0.125f * (acc[hh] + cKs[hb + hh]));
                    }
                }
            }
        }
        __syncthreads();
        #pragma unroll 4
        for (int r = 0; r < CH; r++) {
            float hv0 = Hs[r * D_ + tid];
            float hv1 = Hs[r * D_ + tid + 256];
            float4 p0 = *(const float4*)(ps + r * NH_);
            float4 p1 = *(const float4*)(ps + r * NH_ + 4);
            creg[0] += p0.x * hv0; creg[1] += p0.y * hv0;
            creg[2] += p0.z * hv0; creg[3] += p0.w * hv0;
            creg[4] += p1.x * hv0; creg[5] += p1.y * hv0;
            creg[6] += p1.z * hv0; creg[7] += p1.w * hv0;
            creg[8]  += p0.x * hv1; creg[9]  += p0.y * hv1;
            creg[10] += p0.z * hv1; creg[11] += p0.w * hv1;
            creg[12] += p1.x * hv1; creg[13] += p1.y * hv1;
            creg[14] += p1.z * hv1; creg[15] += p1.w * hv1;
        }
        {
            float v = ps[lane * NH_ + warp];
            v = warpSum(v);
            if (lane == 0) pss[warp] += v;
        }
        __syncthreads();
    }
    #pragma unroll
    for (int h = 0; h < NH_; h++) {
        g_ctx[((long)b * NH_ + h) * D_ + tid]       = creg[h];
        g_ctx[((long)b * NH_ + h) * D_ + tid + 256] = creg[8 + h];
    }
    if (tid < NH_) g_psum[b * NH_ + tid] = pss[tid];
}

// ---------------- small per-iter kernels --------------------------------------
__global__ __launch_bounds__(512) void k_ln_mt(
    const float* __restrict__ bv, const float* __restrict__ lng_g,
    const float* __restrict__ lng_b)
{
    int b = blockIdx.x, t = threadIdx.x;
    __shared__ float red[32];
    long o = (long)b * 512 + t;
    float x = g_partM[o] + g_partM[PM_OFF + o] + g_partM[2 * PM_OFF + o]
            + g_partM[3 * PM_OFF + o] + g_psum[b * NH_ + (t >> 6)] * bv[t];
    float mean = blockSum(x, red) * (1.f / 512.f);
    float d = x - mean;
    float var = blockSum(d * d, red) * (1.f / 512.f);
    g_mt[b * D_ + t] = d * rsqrtf(var + 1e-5f) * lng_g[t] + lng_b[t];
}

__global__ __launch_bounds__(512) void k_gru(
    const float* __restrict__ b_ih, const float* __restrict__ b_hh,
    float* __restrict__ out, int last)
{
    int b = blockIdx.x, t = threadIdx.x;
    const float* G0 = g_partG + (long)b * 1536;
    const float* G1 = g_partG + PG1_OFF + (long)b * 1536;
    const float* C0 = g_partC + (long)b * 2048 + 512;
    const float* C1 = g_partC + PC1_OFF + (long)b * 2048 + 512;
    float ir = G0[t]        + G1[t]        + b_ih[t];
    float iz = G0[t + 512]  + G1[t + 512]  + b_ih[t + 512];
    float in = G0[t + 1024] + G1[t + 1024] + b_ih[t + 1024];
    float hr = C0[t]        + C1[t]        + b_hh[t];
    float hz = C0[t + 512]  + C1[t + 512]  + b_hh[t + 512];
    float hn = C0[t + 1024] + C1[t + 1024] + b_hh[t + 1024];
    float r = sigm(ir + hr);
    float z = sigm(iz + hz);
    float n = tanhf(in + r * hn);
    float old = g_bt[b * D_ + t];
    float nv = (1.f - z) * n + z * old;
    g_bt[b * D_ + t] = nv;
    if (last) out[b * 512 + t] = nv;
}

// ---------------- launch --------------------------------------------------------
extern "C" void kernel_launch(void* const* d_in, const int* in_sizes, int n_in,
                              void* d_out, int out_size)
{
    const float* emb   = (const float*)d_in[0];
    const int*   stc   = (const int*)  d_in[1];
    const int*   off   = (const int*)  d_in[2];
    const int*   sep   = (const int*)  d_in[3];
    const float* W1    = (const float*)d_in[4];
    const float* W2    = (const float*)d_in[5];
    const float* ln_g  = (const float*)d_in[6];
    const float* ln_b  = (const float*)d_in[7];
    const float* lng_g = (const float*)d_in[8];
    const float* lng_b = (const float*)d_in[9];
    const float* Wq    = (const float*)d_in[10];
    const float* bq    = (const float*)d_in[11];
    const float* Wk    = (const float*)d_in[12];
    const float* bk    = (const float*)d_in[13];
    const float* Wv    = (const float*)d_in[14];
    const float* bv    = (const float*)d_in[15];
    const float* W_ih  = (const float*)d_in[16];
    const float* W_hh  = (const float*)d_in[17];
    const float* b_ih  = (const float*)d_in[18];
    const float* b_hh  = (const float*)d_in[19];
    const float* seg   = (const float*)d_in[20];
    const float* pe    = (const float*)d_in[21];
    float* out = (float*)d_out;

    const int ATTN_SMEM = (NH_*D_ + CH*D_ + CH*NH_ + 2*NH_) * 4;
    cudaFuncSetAttribute(k_attn, cudaFuncAttributeMaxDynamicSharedMemorySize, ATTN_SMEM);
    cudaFuncSetAttribute(k_tc_w1,   cudaFuncAttributeMaxDynamicSharedMemorySize, SMEM_TCB128);
    cudaFuncSetAttribute(k_tc_q,    cudaFuncAttributeMaxDynamicSharedMemorySize, SMEM_TCB128);
    cudaFuncSetAttribute(k_tc_gh,   cudaFuncAttributeMaxDynamicSharedMemorySize, SMEM_TCB128);
    cudaFuncSetAttribute(k_tc_uk,   cudaFuncAttributeMaxDynamicSharedMemorySize, SMEM_TCB128);
    cudaFuncSetAttribute(k_tc_gi,   cudaFuncAttributeMaxDynamicSharedMemorySize, SMEM_TCB128);
    cudaFuncSetAttribute(k_tc_mraw, cudaFuncAttributeMaxDynamicSharedMemorySize, SMEM_TCB64);

    // side stream + events (created fresh each call; never destroyed so an
    // in-flight graph capture is never invalidated)
    cudaStream_t sB;
    cudaStreamCreateWithFlags(&sB, cudaStreamNonBlocking);
    cudaEvent_t evF, evH, evG;
    cudaEventCreateWithFlags(&evF, cudaEventDisableTiming);
    cudaEventCreateWithFlags(&evH, cudaEventDisableTiming);
    cudaEventCreateWithFlags(&evG, cudaEventDisableTiming);

    // ---- preamble: fork buildH onto side stream (depends only on inputs) ----
    cudaEventRecord(evF, 0);
    cudaStreamWaitEvent(sB, evF, 0);
    k_buildH<<<B_, 256, 0, sB>>>(emb, pe, seg, ln_g, ln_b, stc, off);
    cudaEventRecord(evH, sB);

    k_prep<<<dim3(16, 48, 6), 256>>>(Wk, W_ih, W_hh, Wq, Wv, W1);
    k_build_hblk<<<B_, 512>>>(emb, stc, off, sep);
    k_tc_w1<<<dim3(4, 32, 2), 256, SMEM_TCB128>>>();
    k_a<<<2048, 256>>>(W2);
    k_s1<<<L_, 512>>>();
    k_b0<<<B_, 512>>>(ln_g, ln_b, pe);

    // ---- 3 GRU iterations ----
    for (int it = 0; it < 3; it++) {
        // fork gh GEMM (only consumed by k_gru) onto side stream
        cudaEventRecord(evF, 0);
        cudaStreamWaitEvent(sB, evF, 0);
        k_tc_gh<<<dim3(12, 8, 2), 256, SMEM_TCB128, sB>>>();
        cudaEventRecord(evG, sB);

        // critical path
        k_tc_q<<<dim3(4, 8, 2), 256, SMEM_TCB128>>>();
        k_tc_uk<<<dim3(4, 8, 8), 256, SMEM_TCB128>>>(bq);
        if (it == 0) cudaStreamWaitEvent(0, evH, 0);   // attn needs H
        k_attn<<<B_, 256, ATTN_SMEM>>>(bk, bq, stc);
        k_tc_mraw<<<dim3(1, 8, 32), 256, SMEM_TCB64>>>();
        k_ln_mt<<<B_, 512>>>(bv, lng_g, lng_b);
        k_tc_gi<<<dim3(12, 8, 2), 256, SMEM_TCB128>>>();
        cudaStreamWaitEvent(0, evG, 0);                // gru needs gh
        k_gru<<<B_, 512>>>(b_ih, b_hh, out, it == 2 ? 1 : 0);
    }
    (void)in_sizes; (void)n_in; (void)out_size;
}

// round 12
// speedup vs baseline: 2.5199x; 1.0124x over previous
#include <cuda_runtime.h>
#include <cuda_bf16.h>
#include <cuda_fp16.h>
#include <cuda_pipeline.h>
#include <mma.h>
#include <math.h>

#define B_  512
#define S_  200
#define D_  512
#define NH_ 8
#define L_  4
#define CH  32

// ---------------- scratch (device globals) ----------------------------------
__device__ float g_hblk[B_*L_*D_];
__device__ float g_valid[B_*L_];
__device__ float g_a[B_*L_];
__device__ float g_s1[B_*L_];
__device__ float g_bt[B_*D_];
__device__ __half g_Hh[B_*S_*D_];        // 105 MB (fp16 H)
__device__ float g_uK[B_*NH_*D_];
__device__ float g_ctx[B_*NH_*D_];
__device__ float g_psum[B_*NH_];
__device__ float g_mt[B_*D_];
__device__ float g_partC[2*B_*2048];     // comb / W1 split-K partials
__device__ float g_partM[4*B_*D_];       // mraw split-K partials
__device__ float g_partG[2*B_*1536];     // gi split-K partials

// bf16 hi/lo split weights, [N][K] layout (K contiguous)
__device__ __nv_bfloat16 g_combT_h[2048*512];
__device__ __nv_bfloat16 g_combT_l[2048*512];
__device__ __nv_bfloat16 g_Wih_h[1536*512];
__device__ __nv_bfloat16 g_Wih_l[1536*512];
__device__ __nv_bfloat16 g_Wk_h[512*512];
__device__ __nv_bfloat16 g_Wk_l[512*512];
__device__ __nv_bfloat16 g_WvT_h[512*512];
__device__ __nv_bfloat16 g_WvT_l[512*512];
__device__ __nv_bfloat16 g_W1T_h[512*512];
__device__ __nv_bfloat16 g_W1T_l[512*512];

#define PC1_OFF 1048576L   // 512*2048
#define PM_OFF  262144L    // 512*512
#define PG1_OFF 786432L    // 512*1536

// dynamic smem: 2 stages x (A(64) h/l + B(BN) h/l) x RS(40) x 2B
#define SMEM_TCB128 61440
#define SMEM_TCB64  40960

// PDL helpers: gridsync is a no-op when launched without the PDL attribute,
// so compute kernels call it unconditionally at their top.
__device__ __forceinline__ void pdl_sync() {
#if __CUDA_ARCH__ >= 900
    cudaGridDependencySynchronize();
    cudaTriggerProgrammaticLaunchCompletion();
#endif
}

// ---------------- helpers ----------------------------------------------------
__device__ __forceinline__ float warpSum(float v) {
    #pragma unroll
    for (int o = 16; o; o >>= 1) v += __shfl_down_sync(0xffffffffu, v, o);
    return v;
}
__device__ __forceinline__ float warpAll(float v) {
    #pragma unroll
    for (int o = 16; o; o >>= 1) v += __shfl_xor_sync(0xffffffffu, v, o);
    return v;
}
__device__ __forceinline__ float warpMax(float v) {
    #pragma unroll
    for (int o = 16; o; o >>= 1) v = fmaxf(v, __shfl_down_sync(0xffffffffu, v, o));
    return v;
}
__device__ __forceinline__ float blockSum(float v, float* red) {
    int lane = threadIdx.x & 31, w = threadIdx.x >> 5;
    v = warpSum(v);
    if (lane == 0) red[w] = v;
    __syncthreads();
    float r = 0.f;
    if (threadIdx.x < (blockDim.x >> 5)) r = red[threadIdx.x];
    if (w == 0) r = warpSum(r);
    if (threadIdx.x == 0) red[0] = r;
    __syncthreads();
    r = red[0];
    __syncthreads();
    return r;
}
__device__ __forceinline__ float blockMax(float v, float* red) {
    int lane = threadIdx.x & 31, w = threadIdx.x >> 5;
    v = warpMax(v);
    if (lane == 0) red[w] = v;
    __syncthreads();
    float r = -3.0e38f;
    if (threadIdx.x < (blockDim.x >> 5)) r = red[threadIdx.x];
    if (w == 0) r = warpMax(r);
    if (threadIdx.x == 0) red[0] = r;
    __syncthreads();
    r = red[0];
    __syncthreads();
    return r;
}
__device__ __forceinline__ float sigm(float x) { return 1.f / (1.f + expf(-x)); }
#define DOT4(u, h) ((u).x*(h).x + (u).y*(h).y + (u).z*(h).z + (u).w*(h).w)

// ---------------- WMMA tensor GEMM core v2 (unchanged math from R11) -----------
template <int BN, bool COMPOSE>
__device__ __forceinline__ void tc_core(
    const float* A0, const float* A1, const float* Ab, int lda,
    const __nv_bfloat16* Bh, const __nv_bfloat16* Bl, int ldb,
    float* C, int ldc, int Kd, int m0, int n0)
{
    const int RS = 40;
    const int NT = BN / 64;
    const int BCH = BN / 64;
    const int AE = 64 * RS;
    const int BE = BN * RS;
    const int STG = 2 * AE + 2 * BE;

    extern __shared__ __align__(16) __nv_bfloat16 dsm[];

    // PDL: wait for producers before ANY global read (B weights may be written
    // by k_prep in the preamble chain).
    pdl_sync();

    int tid = threadIdx.x;
    int warp = tid >> 5;
    int wm = warp & 1;
    int wn = warp >> 1;

    nvcuda::wmma::fragment<nvcuda::wmma::accumulator, 16, 16, 16, float> acc[2][NT];
    #pragma unroll
    for (int i = 0; i < 2; i++) {
        #pragma unroll
        for (int j = 0; j < NT; j++) {
            nvcuda::wmma::fill_fragment(acc[i][j], 0.0f);
        }
    }

    float4 va[2];
    int arow = tid >> 3;
    int aq = tid & 7;

    // ---- prologue: chunk 0 ----
    {
        __nv_bfloat16* sBh = dsm + 2 * AE;
        __nv_bfloat16* sBl = dsm + 2 * AE + BE;
        #pragma unroll
        for (int i = 0; i < BCH; i++) {
            int c = tid + i * 256;
            int row = c >> 2;
            int q = c & 3;
            __pipeline_memcpy_async(sBh + row * RS + q * 8,
                                    Bh + (long)(n0 + row) * ldb + q * 8, 16);
            __pipeline_memcpy_async(sBl + row * RS + q * 8,
                                    Bl + (long)(n0 + row) * ldb + q * 8, 16);
        }
        __pipeline_commit();
        #pragma unroll
        for (int i = 0; i < 2; i++) {
            int row = arow + i * 32;
            float4 v = *(const float4*)(A0 + (long)(m0 + row) * lda + aq * 4);
            if (COMPOSE) {
                float4 v1 = *(const float4*)(A1 + (long)(m0 + row) * lda + aq * 4);
                float4 bi = *(const float4*)(Ab + aq * 4);
                v.x += v1.x + bi.x; v.y += v1.y + bi.y;
                v.z += v1.z + bi.z; v.w += v1.w + bi.w;
            }
            va[i] = v;
        }
        __nv_bfloat16* sAh = dsm;
        __nv_bfloat16* sAl = dsm + AE;
        #pragma unroll
        for (int i = 0; i < 2; i++) {
            int row = arow + i * 32;
            float4 v = va[i];
            __nv_bfloat16 h0 = __float2bfloat16(v.x);
            __nv_bfloat16 h1 = __float2bfloat16(v.y);
            __nv_bfloat16 h2 = __float2bfloat16(v.z);
            __nv_bfloat16 h3 = __float2bfloat16(v.w);
            int o = row * RS + aq * 4;
            sAh[o + 0] = h0; sAh[o + 1] = h1; sAh[o + 2] = h2; sAh[o + 3] = h3;
            sAl[o + 0] = __float2bfloat16(v.x - __bfloat162float(h0));
            sAl[o + 1] = __float2bfloat16(v.y - __bfloat162float(h1));
            sAl[o + 2] = __float2bfloat16(v.z - __bfloat162float(h2));
            sAl[o + 3] = __float2bfloat16(v.w - __bfloat162float(h3));
        }
        __pipeline_wait_prior(0);
        __syncthreads();
    }

    int nch = Kd >> 5;
    for (int c = 0; c < nch; c++) {
        int kn = (c + 1) * 32;
        __nv_bfloat16* nxt = dsm + ((c + 1) & 1) * STG;
        if (c + 1 < nch) {
            __nv_bfloat16* sBh = nxt + 2 * AE;
            __nv_bfloat16* sBl = nxt + 2 * AE + BE;
            #pragma unroll
            for (int i = 0; i < BCH; i++) {
                int cc = tid + i * 256;
                int row = cc >> 2;
                int q = cc & 3;
                __pipeline_memcpy_async(sBh + row * RS + q * 8,
                                        Bh + (long)(n0 + row) * ldb + kn + q * 8, 16);
                __pipeline_memcpy_async(sBl + row * RS + q * 8,
                                        Bl + (long)(n0 + row) * ldb + kn + q * 8, 16);
            }
            __pipeline_commit();
            #pragma unroll
            for (int i = 0; i < 2; i++) {
                int row = arow + i * 32;
                float4 v = *(const float4*)(A0 + (long)(m0 + row) * lda + kn + aq * 4);
                if (COMPOSE) {
                    float4 v1 = *(const float4*)(A1 + (long)(m0 + row) * lda + kn + aq * 4);
                    float4 bi = *(const float4*)(Ab + kn + aq * 4);
                    v.x += v1.x + bi.x; v.y += v1.y + bi.y;
                    v.z += v1.z + bi.z; v.w += v1.w + bi.w;
                }
                va[i] = v;
            }
        }
        {
            __nv_bfloat16* base = dsm + (c & 1) * STG;
            __nv_bfloat16* sAh = base;
            __nv_bfloat16* sAl = base + AE;
            __nv_bfloat16* sBh = base + 2 * AE;
            __nv_bfloat16* sBl = base + 2 * AE + BE;
            #pragma unroll
            for (int ks = 0; ks < 2; ks++) {
                nvcuda::wmma::fragment<nvcuda::wmma::matrix_a, 16, 16, 16,
                                       __nv_bfloat16, nvcuda::wmma::row_major> ah[2], al[2];
                #pragma unroll
                for (int i = 0; i < 2; i++) {
                    int r = wm * 32 + i * 16;
                    nvcuda::wmma::load_matrix_sync(ah[i], sAh + r * RS + ks * 16, RS);
                    nvcuda::wmma::load_matrix_sync(al[i], sAl + r * RS + ks * 16, RS);
                }
                #pragma unroll
                for (int j = 0; j < NT; j++) {
                    int nn = wn * (BN / 4) + j * 16;
                    nvcuda::wmma::fragment<nvcuda::wmma::matrix_b, 16, 16, 16,
                                           __nv_bfloat16, nvcuda::wmma::col_major> bh, bl;
                    nvcuda::wmma::load_matrix_sync(bh, sBh + nn * RS + ks * 16, RS);
                    nvcuda::wmma::load_matrix_sync(bl, sBl + nn * RS + ks * 16, RS);
                    #pragma unroll
                    for (int i = 0; i < 2; i++) {
                        nvcuda::wmma::mma_sync(acc[i][j], ah[i], bh, acc[i][j]);
                        nvcuda::wmma::mma_sync(acc[i][j], ah[i], bl, acc[i][j]);
                        nvcuda::wmma::mma_sync(acc[i][j], al[i], bh, acc[i][j]);
                    }
                }
            }
        }
        if (c + 1 < nch) {
            __nv_bfloat16* sAh = nxt;
            __nv_bfloat16* sAl = nxt + AE;
            #pragma unroll
            for (int i = 0; i < 2; i++) {
                int row = arow + i * 32;
                float4 v = va[i];
                __nv_bfloat16 h0 = __float2bfloat16(v.x);
                __nv_bfloat16 h1 = __float2bfloat16(v.y);
                __nv_bfloat16 h2 = __float2bfloat16(v.z);
                __nv_bfloat16 h3 = __float2bfloat16(v.w);
                int o = row * RS + aq * 4;
                sAh[o + 0] = h0; sAh[o + 1] = h1; sAh[o + 2] = h2; sAh[o + 3] = h3;
                sAl[o + 0] = __float2bfloat16(v.x - __bfloat162float(h0));
                sAl[o + 1] = __float2bfloat16(v.y - __bfloat162float(h1));
                sAl[o + 2] = __float2bfloat16(v.z - __bfloat162float(h2));
                sAl[o + 3] = __float2bfloat16(v.w - __bfloat162float(h3));
            }
            __pipeline_wait_prior(0);
        }
        __syncthreads();
    }
    #pragma unroll
    for (int i = 0; i < 2; i++) {
        #pragma unroll
        for (int j = 0; j < NT; j++) {
            int row = m0 + wm * 32 + i * 16;
            int col = n0 + wn * (BN / 4) + j * 16;
            nvcuda::wmma::store_matrix_sync(C + (long)row * ldc + col, acc[i][j],
                                            ldc, nvcuda::wmma::mem_row_major);
        }
    }
}

// ---------------- GEMM wrapper kernels (BM=64, 2 CTAs/SM) ----------------------
__global__ __launch_bounds__(256, 2) void k_tc_w1()
{
    int z = blockIdx.z;
    tc_core<128, false>(g_hblk + z * 256, (const float*)0, (const float*)0, 512,
                        g_W1T_h + z * 256, g_W1T_l + z * 256, 512,
                        g_partC + (long)z * PC1_OFF, 512, 256,
                        blockIdx.y * 64, blockIdx.x * 128);
}
__global__ __launch_bounds__(256, 2) void k_tc_q()
{
    int z = blockIdx.z;
    tc_core<128, false>(g_bt + z * 256, (const float*)0, (const float*)0, 512,
                        g_combT_h + z * 256, g_combT_l + z * 256, 512,
                        g_partC + (long)z * PC1_OFF, 2048, 256,
                        blockIdx.y * 64, blockIdx.x * 128);
}
__global__ __launch_bounds__(256, 2) void k_tc_gh()
{
    int z = blockIdx.z;
    tc_core<128, false>(g_bt + z * 256, (const float*)0, (const float*)0, 512,
                        g_combT_h + (long)512 * 512 + z * 256,
                        g_combT_l + (long)512 * 512 + z * 256, 512,
                        g_partC + (long)z * PC1_OFF + 512, 2048, 256,
                        blockIdx.y * 64, blockIdx.x * 128);
}
__global__ __launch_bounds__(256, 2) void k_tc_uk(const float* __restrict__ bq)
{
    int h = blockIdx.z;
    tc_core<128, true>(g_partC + h * 64, g_partC + PC1_OFF + h * 64, bq + h * 64, 2048,
                       g_Wk_h + h * 64, g_Wk_l + h * 64, 512,
                       g_uK + h * 512, 4096, 64,
                       blockIdx.y * 64, blockIdx.x * 128);
}
__global__ __launch_bounds__(256, 2) void k_tc_mraw()
{
    int z = blockIdx.z;
    int h = z >> 2;
    int ks = z & 3;
    tc_core<64, false>(g_ctx + h * 512 + (long)ks * 128, (const float*)0, (const float*)0, 4096,
                       g_WvT_h + (long)(h * 64) * 512 + ks * 128,
                       g_WvT_l + (long)(h * 64) * 512 + ks * 128, 512,
                       g_partM + ks * PM_OFF + h * 64, 512, 128,
                       blockIdx.y * 64, 0);
}
__global__ __launch_bounds__(256, 2) void k_tc_gi()
{
    int z = blockIdx.z;
    tc_core<128, false>(g_mt + z * 256, (const float*)0, (const float*)0, 512,
                        g_Wih_h + z * 256, g_Wih_l + z * 256, 512,
                        g_partG + (long)z * PG1_OFF, 1536, 256,
                        blockIdx.y * 64, blockIdx.x * 128);
}

// ---------------- weight prep: transpose + bf16 hi/lo split --------------------
__global__ __launch_bounds__(256) void k_prep(
    const float* __restrict__ Wk, const float* __restrict__ W_ih,
    const float* __restrict__ W_hh, const float* __restrict__ Wq,
    const float* __restrict__ Wv, const float* __restrict__ W1)
{
    __shared__ float t[32][33];
    int job = blockIdx.z;
    int bx = blockIdx.x * 32;
    int by = blockIdx.y * 32;
    int lx = threadIdx.x & 31;
    int wy = threadIdx.x >> 5;
    if (job <= 2) {
        const float* src;
        __nv_bfloat16* dh;
        __nv_bfloat16* dl;
        int nrows;
        if (job == 0)      { src = Wk;   dh = g_Wk_h;  dl = g_Wk_l;  nrows = 512;  }
        else if (job == 1) { src = W_ih; dh = g_Wih_h; dl = g_Wih_l; nrows = 1536; }
        else               { src = W_hh; dh = g_combT_h + 512*512;
                             dl = g_combT_l + 512*512; nrows = 1536; }
        if (by >= nrows) return;
        for (int j = wy; j < 32; j += 8) {
            long o = (long)(by + j) * 512 + bx + lx;
            float v = src[o];
            __nv_bfloat16 hh = __float2bfloat16(v);
            dh[o] = hh;
            dl[o] = __float2bfloat16(v - __bfloat162float(hh));
        }
    } else {
        if (blockIdx.y >= 16) return;
        const float* src;
        __nv_bfloat16* dh;
        __nv_bfloat16* dl;
        if (job == 3)      { src = Wq; dh = g_combT_h; dl = g_combT_l; }
        else if (job == 4) { src = Wv; dh = g_WvT_h;   dl = g_WvT_l;   }
        else               { src = W1; dh = g_W1T_h;   dl = g_W1T_l;   }
        for (int j = wy; j < 32; j += 8)
            t[j][lx] = src[(long)(by + j) * 512 + bx + lx];
        __syncthreads();
        for (int j = wy; j < 32; j += 8) {
            float v = t[lx][j];
            long o = (long)(bx + j) * 512 + by + lx;
            __nv_bfloat16 hh = __float2bfloat16(v);
            dh[o] = hh;
            dl[o] = __float2bfloat16(v - __bfloat162float(hh));
        }
    }
}

// ---------------- preamble -----------------------------------------------------
__global__ __launch_bounds__(512) void k_build_hblk(
    const float* __restrict__ emb, const int* __restrict__ stc,
    const int* __restrict__ off, const int* __restrict__ sep)
{
    pdl_sync();
    int b = blockIdx.x;
    int o = off[b], len = stc[b];
    int sA = sep[b * 2], sB2 = sep[b * 2 + 1];
    int idx = (sA < o ? 1 : 0) + (sB2 < o ? 1 : 0);
    int pidx = idx - 1; pidx = pidx < 0 ? 0 : (pidx > 1 ? 1 : pidx);
    int prev = (pidx == 0) ? sA : sB2;
    int left = (idx > 0) ? prev + 1 : 0;
    int nidx = idx > 1 ? 1 : idx;
    int nxt = (nidx == 0) ? sA : sB2;
    int right = (idx < 2) ? nxt : len;
    int start = (o - 2 > left) ? o - 2 : left;
    int end = (o + 2 < right) ? o + 2 : right;
    int t = threadIdx.x;
    #pragma unroll
    for (int l = 0; l < L_; l++) {
        int ind = start + l;
        bool v = ind < end;
        int ic = ind < 0 ? 0 : (ind > S_ - 1 ? S_ - 1 : ind);
        g_hblk[(b * L_ + l) * D_ + t] = v ? emb[((long)b * S_ + ic) * D_ + t] : 0.f;
        if (t == 0) g_valid[b * L_ + l] = v ? 1.f : 0.f;
    }
}

__global__ __launch_bounds__(256) void k_a(const float* __restrict__ W2)
{
    pdl_sync();
    int m = blockIdx.x, t = threadIdx.x;
    float t0 = tanhf(g_partC[(long)m * 512 + t] + g_partC[PC1_OFF + (long)m * 512 + t]);
    float t1 = tanhf(g_partC[(long)m * 512 + t + 256] + g_partC[PC1_OFF + (long)m * 512 + t + 256]);
    float v = t0 * W2[t] + t1 * W2[t + 256];
    __shared__ float red[32];
    v = blockSum(v, red);
    if (t == 0) g_a[m] = v;
}

__global__ __launch_bounds__(512) void k_s1()
{
    pdl_sync();
    int l = blockIdx.x, t = threadIdx.x;
    __shared__ float red[32];
    float v = g_a[t * L_ + l];
    float mx = blockMax(v, red);
    float e = expf(v - mx);
    float s = blockSum(e, red);
    g_s1[t * L_ + l] = e / s;
}

__global__ __launch_bounds__(512) void k_b0(
    const float* __restrict__ ln_g, const float* __restrict__ ln_b,
    const float* __restrict__ pe)
{
    pdl_sync();
    int b = blockIdx.x, t = threadIdx.x;
    __shared__ float sc[4];
    __shared__ float red[32];
    if (t == 0) {
        float vals[4], mx = -3.0e38f;
        #pragma unroll
        for (int l = 0; l < 4; l++) {
            float v = (g_valid[b * 4 + l] > 0.5f) ? g_s1[b * 4 + l] : -1e9f;
            vals[l] = v; mx = fmaxf(mx, v);
        }
        float s = 0.f;
        #pragma unroll
        for (int l = 0; l < 4; l++) { float e = expf(vals[l] - mx); sc[l] = e; s += e; }
        #pragma unroll
        for (int l = 0; l < 4; l++) sc[l] /= s;
    }
    __syncthreads();
    float x = sc[0] * g_hblk[(b * 4 + 0) * D_ + t] + sc[1] * g_hblk[(b * 4 + 1) * D_ + t]
            + sc[2] * g_hblk[(b * 4 + 2) * D_ + t] + sc[3] * g_hblk[(b * 4 + 3) * D_ + t]
            + pe[t];
    float mean = blockSum(x, red) * (1.f / 512.f);
    float d = x - mean;
    float var = blockSum(d * d, red) * (1.f / 512.f);
    g_bt[b * D_ + t] = d * rsqrtf(var + 1e-5f) * ln_g[t] + ln_b[t];
}

// warp-per-row H build: 512 blocks x 256 threads, no block barriers in hot loop
__global__ __launch_bounds__(256) void k_buildH(
    const float* __restrict__ emb, const float* __restrict__ pe,
    const float* __restrict__ seg_emb, const float* __restrict__ ln_g,
    const float* __restrict__ ln_b, const int* __restrict__ stc,
    const int* __restrict__ off)
{
    __shared__ float s_seg[2][D_];
    __shared__ float s_g[D_];
    __shared__ float s_b[D_];
    int b = blockIdx.x;
    int tid = threadIdx.x, lane = tid & 31, warp = tid >> 5;
    for (int i = tid; i < D_; i += 256) {
        s_seg[0][i] = seg_emb[i];
        s_seg[1][i] = seg_emb[D_ + i];
        s_g[i] = ln_g[i];
        s_b[i] = ln_b[i];
    }
    int len = stc[b];
    int pos = off[b];
    __syncthreads();
    for (int s = warp; s < len; s += 8) {
        int ip = (s < pos) ? (pos - s) : (s + 1 - pos);
        ip = ip < 0 ? 0 : (ip > S_ ? S_ : ip);
        int sg = (s >= pos) ? 1 : 0;
        const float* er = emb + ((long)b * S_ + s) * D_;
        const float* pr = pe + (long)ip * D_;
        float x[16];
        float sum = 0.f;
        #pragma unroll
        for (int i = 0; i < 4; i++) {
            int base = i * 128 + lane * 4;
            float4 e = *(const float4*)(er + base);
            float4 p = *(const float4*)(pr + base);
            float v0 = e.x + p.x + s_seg[sg][base + 0];
            float v1 = e.y + p.y + s_seg[sg][base + 1];
            float v2 = e.z + p.z + s_seg[sg][base + 2];
            float v3 = e.w + p.w + s_seg[sg][base + 3];
            x[i*4+0] = v0; x[i*4+1] = v1; x[i*4+2] = v2; x[i*4+3] = v3;
            sum += v0 + v1 + v2 + v3;
        }
        float mean = warpAll(sum) * (1.f / 512.f);
        float vs = 0.f;
        #pragma unroll
        for (int i = 0; i < 16; i++) {
            float d = x[i] - mean;
            x[i] = d;
            vs += d * d;
        }
        float inv = rsqrtf(warpAll(vs) * (1.f / 512.f) + 1e-5f);
        __half* dr = g_Hh + ((long)b * S_ + s) * D_;
        #pragma unroll
        for (int i = 0; i < 4; i++) {
            int base = i * 128 + lane * 4;
            float o0 = x[i*4+0] * inv * s_g[base + 0] + s_b[base + 0];
            float o1 = x[i*4+1] * inv * s_g[base + 1] + s_b[base + 1];
            float o2 = x[i*4+2] * inv * s_g[base + 2] + s_b[base + 2];
            float o3 = x[i*4+3] * inv * s_g[base + 3] + s_b[base + 3];
            __half2 ha = __floats2half2_rn(o0, o1);
            __half2 hb = __floats2half2_rn(o2, o3);
            *(__half2*)(dr + base)     = ha;
            *(__half2*)(dr + base + 2) = hb;
        }
    }
}

// ---------------- fused attention (256 thr, per-batch CTA) --------------------
__global__ __launch_bounds__(256) void k_attn(
    const float* __restrict__ bk, const float* __restrict__ bq,
    const int* __restrict__ stc)
{
    pdl_sync();
    int b = blockIdx.x;
    int tid = threadIdx.x, lane = tid & 31, warp = tid >> 5;   // 8 warps
    extern __shared__ float sm[];
    float* uKs = sm;                    // 8*512
    float* Hs  = sm + NH_ * D_;         // 32*512
    float* ps  = Hs + CH * D_;          // 32*8  [s][h]
    float* cKs = ps + CH * NH_;         // 8
    float* pss = cKs + NH_;             // 8
    int len = stc[b];
    {
        const float4* src = (const float4*)(g_uK + (long)b * NH_ * D_);
        float4* dst = (float4*)uKs;
        #pragma unroll
        for (int i = 0; i < 4; i++) dst[i * 256 + tid] = src[i * 256 + tid];
    }
    {
        int j0 = warp * 64 + lane, j1 = j0 + 32;
        float q0 = g_partC[(long)b * 2048 + j0] + g_partC[PC1_OFF + (long)b * 2048 + j0] + bq[j0];
        float q1 = g_partC[(long)b * 2048 + j1] + g_partC[PC1_OFF + (long)b * 2048 + j1] + bq[j1];
        float v = bk[j0] * q0 + bk[j1] * q1;
        v = warpSum(v);
        if (lane == 0) { cKs[warp] = v; pss[warp] = 0.f; }
    }
    float creg[16] = {0.f,0.f,0.f,0.f,0.f,0.f,0.f,0.f,0.f,0.f,0.f,0.f,0.f,0.f,0.f,0.f};
    __syncthreads();
    int nch = (len + CH - 1) / CH;
    for (int c = 0; c < nch; c++) {
        int s0 = c * CH;
        for (int r = warp; r < CH; r += 8) {
            int s = s0 + r;
            float4* dst = (float4*)(Hs + r * D_);
            if (s < len) {
                const uint4* src = (const uint4*)(g_Hh + ((long)b * S_ + s) * D_);
                #pragma unroll
                for (int i = 0; i < 2; i++) {
                    uint4 v = src[i * 32 + lane];
                    __half2 h0 = *(__half2*)&v.x;
                    __half2 h1 = *(__half2*)&v.y;
                    __half2 h2 = *(__half2*)&v.z;
                    __half2 h3 = *(__half2*)&v.w;
                    float2 f0 = __half22float2(h0);
                    float2 f1 = __half22float2(h1);
                    float2 f2 = __half22float2(h2);
                    float2 f3 = __half22float2(h3);
                    float4 o0; o0.x = f0.x; o0.y = f0.y; o0.z = f1.x; o0.w = f1.y;
                    float4 o1; o1.x = f2.x; o1.y = f2.y; o1.z = f3.x; o1.w = f3.y;
                    dst[(i * 32 + lane) * 2]     = o0;
                    dst[(i * 32 + lane) * 2 + 1] = o1;
                }
            } else {
                float4 z = make_float4(0.f, 0.f, 0.f, 0.f);
                #pragma unroll
                for (int i = 0; i < 4; i++) dst[i * 32 + lane] = z;
            }
        }
        ps[tid] = 0.f;
        __syncthreads();
        #pragma unroll
        for (int pass = 0; pass < 2; pass++) {
            int hb = pass * 4;
            float4 u[4][4];
            #pragma unroll
            for (int hh = 0; hh < 4; hh++) {
                #pragma unroll
                for (int i = 0; i < 4; i++)
                    u[hh][i] = *(const float4*)(uKs + (hb + hh) * D_ + (i * 32 + lane) * 4);
            }
            #pragma unroll
            for (int rr = 0; rr < 4; rr++) {
                int r = warp * 4 + rr;
                float4 h4[4];
                #pragma unroll
                for (int i = 0; i < 4; i++)
                    h4[i] = *(const float4*)(Hs + r * D_ + (i * 32 + lane) * 4);
                float acc[4];
                #pragma unroll
                for (int hh = 0; hh < 4; hh++) {
                    acc[hh] = DOT4(u[hh][0], h4[0]) + DOT4(u[hh][1], h4[1])
                            + DOT4(u[hh][2], h4[2]) + DOT4(u[hh][3], h4[3]);
                    acc[hh] = warpSum(acc[hh]);
                }
                if (lane == 0) {
                    int s = s0 + r;
                    if (s < len) {
                        #pragma unroll
                        for (int hh = 0; hh < 4; hh++)
                            ps[r * NH_ + hb + hh] = sigm(0.125f * (acc[hh] + cKs[hb + hh]));
                    }
                }
            }
        }
        __syncthreads();
        #pragma unroll 4
        for (int r = 0; r < CH; r++) {
            float hv0 = Hs[r * D_ + tid];
            float hv1 = Hs[r * D_ + tid + 256];
            float4 p0 = *(const float4*)(ps + r * NH_);
            float4 p1 = *(const float4*)(ps + r * NH_ + 4);
            creg[0] += p0.x * hv0; creg[1] += p0.y * hv0;
            creg[2] += p0.z * hv0; creg[3] += p0.w * hv0;
            creg[4] += p1.x * hv0; creg[5] += p1.y * hv0;
            creg[6] += p1.z * hv0; creg[7] += p1.w * hv0;
            creg[8]  += p0.x * hv1; creg[9]  += p0.y * hv1;
            creg[10] += p0.z * hv1; creg[11] += p0.w * hv1;
            creg[12] += p1.x * hv1; creg[13] += p1.y * hv1;
            creg[14] += p1.z * hv1; creg[15] += p1.w * hv1;
        }
        {
            float v = ps[lane * NH_ + warp];
            v = warpSum(v);
            if (lane == 0) pss[warp] += v;
        }
        __syncthreads();
    }
    #pragma unroll
    for (int h = 0; h < NH_; h++) {
        g_ctx[((long)b * NH_ + h) * D_ + tid]       = creg[h];
        g_ctx[((long)b * NH_ + h) * D_ + tid + 256] = creg[8 + h];
    }
    if (tid < NH_) g_psum[b * NH_ + tid] = pss[tid];
}

// ---------------- small per-iter kernels --------------------------------------
__global__ __launch_bounds__(512) void k_ln_mt(
    const float* __restrict__ bv, const float* __restrict__ lng_g,
    const float* __restrict__ lng_b)
{
    pdl_sync();
    int b = blockIdx.x, t = threadIdx.x;
    __shared__ float red[32];
    long o = (long)b * 512 + t;
    float x = g_partM[o] + g_partM[PM_OFF + o] + g_partM[2 * PM_OFF + o]
            + g_partM[3 * PM_OFF + o] + g_psum[b * NH_ + (t >> 6)] * bv[t];
    float mean = blockSum(x, red) * (1.f / 512.f);
    float d = x - mean;
    float var = blockSum(d * d, red) * (1.f / 512.f);
    g_mt[b * D_ + t] = d * rsqrtf(var + 1e-5f) * lng_g[t] + lng_b[t];
}

__global__ __launch_bounds__(512) void k_gru(
    const float* __restrict__ b_ih, const float* __restrict__ b_hh,
    float* __restrict__ out, int last)
{
    int b = blockIdx.x, t = threadIdx.x;
    const float* G0 = g_partG + (long)b * 1536;
    const float* G1 = g_partG + PG1_OFF + (long)b * 1536;
    const float* C0 = g_partC + (long)b * 2048 + 512;
    const float* C1 = g_partC + PC1_OFF + (long)b * 2048 + 512;
    float ir = G0[t]        + G1[t]        + b_ih[t];
    float iz = G0[t + 512]  + G1[t + 512]  + b_ih[t + 512];
    float in = G0[t + 1024] + G1[t + 1024] + b_ih[t + 1024];
    float hr = C0[t]        + C1[t]        + b_hh[t];
    float hz = C0[t + 512]  + C1[t + 512]  + b_hh[t + 512];
    float hn = C0[t + 1024] + C1[t + 1024] + b_hh[t + 1024];
    float r = sigm(ir + hr);
    float z = sigm(iz + hz);
    float n = tanhf(in + r * hn);
    float old = g_bt[b * D_ + t];
    float nv = (1.f - z) * n + z * old;
    g_bt[b * D_ + t] = nv;
    if (last) out[b * 512 + t] = nv;
}

// ---------------- launch --------------------------------------------------------
extern "C" void kernel_launch(void* const* d_in, const int* in_sizes, int n_in,
                              void* d_out, int out_size)
{
    const float* emb   = (const float*)d_in[0];
    const int*   stc   = (const int*)  d_in[1];
    const int*   off   = (const int*)  d_in[2];
    const int*   sep   = (const int*)  d_in[3];
    const float* W1    = (const float*)d_in[4];
    const float* W2    = (const float*)d_in[5];
    const float* ln_g  = (const float*)d_in[6];
    const float* ln_b  = (const float*)d_in[7];
    const float* lng_g = (const float*)d_in[8];
    const float* lng_b = (const float*)d_in[9];
    const float* Wq    = (const float*)d_in[10];
    const float* bq    = (const float*)d_in[11];
    const float* Wk    = (const float*)d_in[12];
    const float* bk    = (const float*)d_in[13];
    const float* Wv    = (const float*)d_in[14];
    const float* bv    = (const float*)d_in[15];
    const float* W_ih  = (const float*)d_in[16];
    const float* W_hh  = (const float*)d_in[17];
    const float* b_ih  = (const float*)d_in[18];
    const float* b_hh  = (const float*)d_in[19];
    const float* seg   = (const float*)d_in[20];
    const float* pe    = (const float*)d_in[21];
    float* out = (float*)d_out;

    const int ATTN_SMEM = (NH_*D_ + CH*D_ + CH*NH_ + 2*NH_) * 4;
    cudaFuncSetAttribute(k_attn, cudaFuncAttributeMaxDynamicSharedMemorySize, ATTN_SMEM);
    cudaFuncSetAttribute(k_tc_w1,   cudaFuncAttributeMaxDynamicSharedMemorySize, SMEM_TCB128);
    cudaFuncSetAttribute(k_tc_q,    cudaFuncAttributeMaxDynamicSharedMemorySize, SMEM_TCB128);
    cudaFuncSetAttribute(k_tc_gh,   cudaFuncAttributeMaxDynamicSharedMemorySize, SMEM_TCB128);
    cudaFuncSetAttribute(k_tc_uk,   cudaFuncAttributeMaxDynamicSharedMemorySize, SMEM_TCB128);
    cudaFuncSetAttribute(k_tc_gi,   cudaFuncAttributeMaxDynamicSharedMemorySize, SMEM_TCB128);
    cudaFuncSetAttribute(k_tc_mraw, cudaFuncAttributeMaxDynamicSharedMemorySize, SMEM_TCB64);

    // side stream + events (created fresh each call; never destroyed so an
    // in-flight graph capture is never invalidated)
    cudaStream_t sB;
    cudaStreamCreateWithFlags(&sB, cudaStreamNonBlocking);
    cudaEvent_t evF, evH, evG;
    cudaEventCreateWithFlags(&evF, cudaEventDisableTiming);
    cudaEventCreateWithFlags(&evH, cudaEventDisableTiming);
    cudaEventCreateWithFlags(&evG, cudaEventDisableTiming);

    // PDL launch attribute (applies to stream-0 chain kernels; correctness is
    // carried by cudaGridDependencySynchronize() at each kernel's top)
    cudaLaunchAttribute pdlAttr[1];
    pdlAttr[0].id = cudaLaunchAttributeProgrammaticStreamSerialization;
    pdlAttr[0].val.programmaticStreamSerializationAllowed = 1;
    auto mkcfg = [&](dim3 g, dim3 b, size_t smem) {
        cudaLaunchConfig_t c;
        c.gridDim = g; c.blockDim = b; c.dynamicSmemBytes = smem;
        c.stream = 0; c.attrs = pdlAttr; c.numAttrs = 1;
        return c;
    };

    // ---- preamble: fork buildH onto side stream (depends only on inputs) ----
    cudaEventRecord(evF, 0);
    cudaStreamWaitEvent(sB, evF, 0);
    k_buildH<<<B_, 256, 0, sB>>>(emb, pe, seg, ln_g, ln_b, stc, off);
    cudaEventRecord(evH, sB);

    k_prep<<<dim3(16, 48, 6), 256>>>(Wk, W_ih, W_hh, Wq, Wv, W1);
    {
        cudaLaunchConfig_t c = mkcfg(dim3(B_, 1, 1), dim3(512, 1, 1), 0);
        cudaLaunchKernelEx(&c, k_build_hblk, emb, stc, off, sep);
    }
    {
        cudaLaunchConfig_t c = mkcfg(dim3(4, 32, 2), dim3(256, 1, 1), SMEM_TCB128);
        cudaLaunchKernelEx(&c, k_tc_w1);
    }
    {
        cudaLaunchConfig_t c = mkcfg(dim3(2048, 1, 1), dim3(256, 1, 1), 0);
        cudaLaunchKernelEx(&c, k_a, W2);
    }
    {
        cudaLaunchConfig_t c = mkcfg(dim3(L_, 1, 1), dim3(512, 1, 1), 0);
        cudaLaunchKernelEx(&c, k_s1);
    }
    {
        cudaLaunchConfig_t c = mkcfg(dim3(B_, 1, 1), dim3(512, 1, 1), 0);
        cudaLaunchKernelEx(&c, k_b0, ln_g, ln_b, pe);
    }

    // ---- 3 GRU iterations ----
    for (int it = 0; it < 3; it++) {
        // fork gh GEMM (only consumed by k_gru) onto side stream
        cudaEventRecord(evF, 0);
        cudaStreamWaitEvent(sB, evF, 0);
        k_tc_gh<<<dim3(12, 8, 2), 256, SMEM_TCB128, sB>>>();
        cudaEventRecord(evG, sB);

        // critical path (PDL chain)
        {
            cudaLaunchConfig_t c = mkcfg(dim3(4, 8, 2), dim3(256, 1, 1), SMEM_TCB128);
            cudaLaunchKernelEx(&c, k_tc_q);
        }
        {
            cudaLaunchConfig_t c = mkcfg(dim3(4, 8, 8), dim3(256, 1, 1), SMEM_TCB128);
            cudaLaunchKernelEx(&c, k_tc_uk, bq);
        }
        if (it == 0) {
            cudaStreamWaitEvent(0, evH, 0);   // attn needs H (normal launch)
            k_attn<<<B_, 256, ATTN_SMEM>>>(bk, bq, stc);
        } else {
            cudaLaunchConfig_t c = mkcfg(dim3(B_, 1, 1), dim3(256, 1, 1), ATTN_SMEM);
            cudaLaunchKernelEx(&c, k_attn, bk, bq, stc);
        }
        {
            cudaLaunchConfig_t c = mkcfg(dim3(1, 8, 32), dim3(256, 1, 1), SMEM_TCB64);
            cudaLaunchKernelEx(&c, k_tc_mraw);
        }
        {
            cudaLaunchConfig_t c = mkcfg(dim3(B_, 1, 1), dim3(512, 1, 1), 0);
            cudaLaunchKernelEx(&c, k_ln_mt, bv, lng_g, lng_b);
        }
        {
            cudaLaunchConfig_t c = mkcfg(dim3(12, 8, 2), dim3(256, 1, 1), SMEM_TCB128);
            cudaLaunchKernelEx(&c, k_tc_gi);
        }
        cudaStreamWaitEvent(0, evG, 0);                // gru needs gh (normal launch)
        k_gru<<<B_, 512>>>(b_ih, b_hh, out, it == 2 ? 1 : 0);
    }
    (void)in_sizes; (void)n_in; (void)out_size;
}

// round 13
// speedup vs baseline: 4.4471x; 1.7648x over previous
#include <cuda_runtime.h>
#include <cuda_bf16.h>
#include <cuda_fp16.h>
#include <cuda_pipeline.h>
#include <mma.h>
#include <math.h>

#define B_  512
#define S_  200
#define D_  512
#define NH_ 8
#define L_  4
#define CH  32

// ---------------- scratch (device globals) ----------------------------------
__device__ float g_hblk[B_*L_*D_];
__device__ float g_valid[B_*L_];
__device__ float g_a[B_*L_];
__device__ float g_s1[B_*L_];
__device__ float g_bt[B_*D_];
__device__ __half g_Hh[B_*S_*D_];        // 105 MB (fp16 H)
__device__ float g_uK[B_*NH_*D_];
__device__ float g_ctx[B_*NH_*D_];
__device__ float g_psum[B_*NH_];
__device__ float g_mt[B_*D_];
__device__ float g_partC[2*B_*2048];     // comb / W1 split-K partials
__device__ float g_partM[4*B_*D_];       // mraw split-K partials
__device__ float g_partG[2*B_*1536];     // gi split-K partials

// bf16 hi/lo split weights, [N][K] layout (K contiguous)
__device__ __nv_bfloat16 g_combT_h[2048*512];
__device__ __nv_bfloat16 g_combT_l[2048*512];
__device__ __nv_bfloat16 g_Wih_h[1536*512];
__device__ __nv_bfloat16 g_Wih_l[1536*512];
__device__ __nv_bfloat16 g_Wk_h[512*512];
__device__ __nv_bfloat16 g_Wk_l[512*512];
__device__ __nv_bfloat16 g_WvT_h[512*512];
__device__ __nv_bfloat16 g_WvT_l[512*512];
__device__ __nv_bfloat16 g_W1T_h[512*512];
__device__ __nv_bfloat16 g_W1T_l[512*512];

#define PC1_OFF 1048576L   // 512*2048
#define PM_OFF  262144L    // 512*512
#define PG1_OFF 786432L    // 512*1536

// dynamic smem: 2 stages x (A(64) h/l + B(BN) h/l) x RS(40) x 2B
#define SMEM_TCB128 61440
#define SMEM_TCB64  40960

// attention v2 smem layout (bytes)
#define AHS_ROW   520                       // halfs per Hs/uK row (512 + 8 pad)
#define AOFF_HS   0                         // 32 x 520 half = 33280
#define AOFF_UKH  33280                     // 16 x 520 half = 16640
#define AOFF_UKL  49920                     // 16 x 520 half = 16640
#define AOFF_SC   66560                     // 8 x 256 float = 8192
#define AOFF_PS   74752                     // 32 x 8 float  = 1024
#define AOFF_CK   75776                     // 8 float
#define AOFF_PSS  75808                     // 8 float
#define ATTN_SMEM_V2 75904

// PDL helpers
__device__ __forceinline__ void pdl_sync() {
#if __CUDA_ARCH__ >= 900
    cudaGridDependencySynchronize();
    cudaTriggerProgrammaticLaunchCompletion();
#endif
}

// ---------------- helpers ----------------------------------------------------
__device__ __forceinline__ float warpSum(float v) {
    #pragma unroll
    for (int o = 16; o; o >>= 1) v += __shfl_down_sync(0xffffffffu, v, o);
    return v;
}
__device__ __forceinline__ float warpAll(float v) {
    #pragma unroll
    for (int o = 16; o; o >>= 1) v += __shfl_xor_sync(0xffffffffu, v, o);
    return v;
}
__device__ __forceinline__ float warpMax(float v) {
    #pragma unroll
    for (int o = 16; o; o >>= 1) v = fmaxf(v, __shfl_down_sync(0xffffffffu, v, o));
    return v;
}
__device__ __forceinline__ float blockSum(float v, float* red) {
    int lane = threadIdx.x & 31, w = threadIdx.x >> 5;
    v = warpSum(v);
    if (lane == 0) red[w] = v;
    __syncthreads();
    float r = 0.f;
    if (threadIdx.x < (blockDim.x >> 5)) r = red[threadIdx.x];
    if (w == 0) r = warpSum(r);
    if (threadIdx.x == 0) red[0] = r;
    __syncthreads();
    r = red[0];
    __syncthreads();
    return r;
}
__device__ __forceinline__ float blockMax(float v, float* red) {
    int lane = threadIdx.x & 31, w = threadIdx.x >> 5;
    v = warpMax(v);
    if (lane == 0) red[w] = v;
    __syncthreads();
    float r = -3.0e38f;
    if (threadIdx.x < (blockDim.x >> 5)) r = red[threadIdx.x];
    if (w == 0) r = warpMax(r);
    if (threadIdx.x == 0) red[0] = r;
    __syncthreads();
    r = red[0];
    __syncthreads();
    return r;
}
__device__ __forceinline__ float sigm(float x) { return 1.f / (1.f + expf(-x)); }
#define DOT4(u, h) ((u).x*(h).x + (u).y*(h).y + (u).z*(h).z + (u).w*(h).w)

// ---------------- WMMA tensor GEMM core v2 (unchanged from R12) ----------------
template <int BN, bool COMPOSE>
__device__ __forceinline__ void tc_core(
    const float* A0, const float* A1, const float* Ab, int lda,
    const __nv_bfloat16* Bh, const __nv_bfloat16* Bl, int ldb,
    float* C, int ldc, int Kd, int m0, int n0)
{
    const int RS = 40;
    const int NT = BN / 64;
    const int BCH = BN / 64;
    const int AE = 64 * RS;
    const int BE = BN * RS;
    const int STG = 2 * AE + 2 * BE;

    extern __shared__ __align__(16) __nv_bfloat16 dsm[];

    pdl_sync();

    int tid = threadIdx.x;
    int warp = tid >> 5;
    int wm = warp & 1;
    int wn = warp >> 1;

    nvcuda::wmma::fragment<nvcuda::wmma::accumulator, 16, 16, 16, float> acc[2][NT];
    #pragma unroll
    for (int i = 0; i < 2; i++) {
        #pragma unroll
        for (int j = 0; j < NT; j++) {
            nvcuda::wmma::fill_fragment(acc[i][j], 0.0f);
        }
    }

    float4 va[2];
    int arow = tid >> 3;
    int aq = tid & 7;

    {
        __nv_bfloat16* sBh = dsm + 2 * AE;
        __nv_bfloat16* sBl = dsm + 2 * AE + BE;
        #pragma unroll
        for (int i = 0; i < BCH; i++) {
            int c = tid + i * 256;
            int row = c >> 2;
            int q = c & 3;
            __pipeline_memcpy_async(sBh + row * RS + q * 8,
                                    Bh + (long)(n0 + row) * ldb + q * 8, 16);
            __pipeline_memcpy_async(sBl + row * RS + q * 8,
                                    Bl + (long)(n0 + row) * ldb + q * 8, 16);
        }
        __pipeline_commit();
        #pragma unroll
        for (int i = 0; i < 2; i++) {
            int row = arow + i * 32;
            float4 v = *(const float4*)(A0 + (long)(m0 + row) * lda + aq * 4);
            if (COMPOSE) {
                float4 v1 = *(const float4*)(A1 + (long)(m0 + row) * lda + aq * 4);
                float4 bi = *(const float4*)(Ab + aq * 4);
                v.x += v1.x + bi.x; v.y += v1.y + bi.y;
                v.z += v1.z + bi.z; v.w += v1.w + bi.w;
            }
            va[i] = v;
        }
        __nv_bfloat16* sAh = dsm;
        __nv_bfloat16* sAl = dsm + AE;
        #pragma unroll
        for (int i = 0; i < 2; i++) {
            int row = arow + i * 32;
            float4 v = va[i];
            __nv_bfloat16 h0 = __float2bfloat16(v.x);
            __nv_bfloat16 h1 = __float2bfloat16(v.y);
            __nv_bfloat16 h2 = __float2bfloat16(v.z);
            __nv_bfloat16 h3 = __float2bfloat16(v.w);
            int o = row * RS + aq * 4;
            sAh[o + 0] = h0; sAh[o + 1] = h1; sAh[o + 2] = h2; sAh[o + 3] = h3;
            sAl[o + 0] = __float2bfloat16(v.x - __bfloat162float(h0));
            sAl[o + 1] = __float2bfloat16(v.y - __bfloat162float(h1));
            sAl[o + 2] = __float2bfloat16(v.z - __bfloat162float(h2));
            sAl[o + 3] = __float2bfloat16(v.w - __bfloat162float(h3));
        }
        __pipeline_wait_prior(0);
        __syncthreads();
    }

    int nch = Kd >> 5;
    for (int c = 0; c < nch; c++) {
        int kn = (c + 1) * 32;
        __nv_bfloat16* nxt = dsm + ((c + 1) & 1) * STG;
        if (c + 1 < nch) {
            __nv_bfloat16* sBh = nxt + 2 * AE;
            __nv_bfloat16* sBl = nxt + 2 * AE + BE;
            #pragma unroll
            for (int i = 0; i < BCH; i++) {
                int cc = tid + i * 256;
                int row = cc >> 2;
                int q = cc & 3;
                __pipeline_memcpy_async(sBh + row * RS + q * 8,
                                        Bh + (long)(n0 + row) * ldb + kn + q * 8, 16);
                __pipeline_memcpy_async(sBl + row * RS + q * 8,
                                        Bl + (long)(n0 + row) * ldb + kn + q * 8, 16);
            }
            __pipeline_commit();
            #pragma unroll
            for (int i = 0; i < 2; i++) {
                int row = arow + i * 32;
                float4 v = *(const float4*)(A0 + (long)(m0 + row) * lda + kn + aq * 4);
                if (COMPOSE) {
                    float4 v1 = *(const float4*)(A1 + (long)(m0 + row) * lda + kn + aq * 4);
                    float4 bi = *(const float4*)(Ab + kn + aq * 4);
                    v.x += v1.x + bi.x; v.y += v1.y + bi.y;
                    v.z += v1.z + bi.z; v.w += v1.w + bi.w;
                }
                va[i] = v;
            }
        }
        {
            __nv_bfloat16* base = dsm + (c & 1) * STG;
            __nv_bfloat16* sAh = base;
            __nv_bfloat16* sAl = base + AE;
            __nv_bfloat16* sBh = base + 2 * AE;
            __nv_bfloat16* sBl = base + 2 * AE + BE;
            #pragma unroll
            for (int ks = 0; ks < 2; ks++) {
                nvcuda::wmma::fragment<nvcuda::wmma::matrix_a, 16, 16, 16,
                                       __nv_bfloat16, nvcuda::wmma::row_major> ah[2], al[2];
                #pragma unroll
                for (int i = 0; i < 2; i++) {
                    int r = wm * 32 + i * 16;
                    nvcuda::wmma::load_matrix_sync(ah[i], sAh + r * RS + ks * 16, RS);
                    nvcuda::wmma::load_matrix_sync(al[i], sAl + r * RS + ks * 16, RS);
                }
                #pragma unroll
                for (int j = 0; j < NT; j++) {
                    int nn = wn * (BN / 4) + j * 16;
                    nvcuda::wmma::fragment<nvcuda::wmma::matrix_b, 16, 16, 16,
                                           __nv_bfloat16, nvcuda::wmma::col_major> bh, bl;
                    nvcuda::wmma::load_matrix_sync(bh, sBh + nn * RS + ks * 16, RS);
                    nvcuda::wmma::load_matrix_sync(bl, sBl + nn * RS + ks * 16, RS);
                    #pragma unroll
                    for (int i = 0; i < 2; i++) {
                        nvcuda::wmma::mma_sync(acc[i][j], ah[i], bh, acc[i][j]);
                        nvcuda::wmma::mma_sync(acc[i][j], ah[i], bl, acc[i][j]);
                        nvcuda::wmma::mma_sync(acc[i][j], al[i], bh, acc[i][j]);
                    }
                }
            }
        }
        if (c + 1 < nch) {
            __nv_bfloat16* sAh = nxt;
            __nv_bfloat16* sAl = nxt + AE;
            #pragma unroll
            for (int i = 0; i < 2; i++) {
                int row = arow + i * 32;
                float4 v = va[i];
                __nv_bfloat16 h0 = __float2bfloat16(v.x);
                __nv_bfloat16 h1 = __float2bfloat16(v.y);
                __nv_bfloat16 h2 = __float2bfloat16(v.z);
                __nv_bfloat16 h3 = __float2bfloat16(v.w);
                int o = row * RS + aq * 4;
                sAh[o + 0] = h0; sAh[o + 1] = h1; sAh[o + 2] = h2; sAh[o + 3] = h3;
                sAl[o + 0] = __float2bfloat16(v.x - __bfloat162float(h0));
                sAl[o + 1] = __float2bfloat16(v.y - __bfloat162float(h1));
                sAl[o + 2] = __float2bfloat16(v.z - __bfloat162float(h2));
                sAl[o + 3] = __float2bfloat16(v.w - __bfloat162float(h3));
            }
            __pipeline_wait_prior(0);
        }
        __syncthreads();
    }
    #pragma unroll
    for (int i = 0; i < 2; i++) {
        #pragma unroll
        for (int j = 0; j < NT; j++) {
            int row = m0 + wm * 32 + i * 16;
            int col = n0 + wn * (BN / 4) + j * 16;
            nvcuda::wmma::store_matrix_sync(C + (long)row * ldc + col, acc[i][j],
                                            ldc, nvcuda::wmma::mem_row_major);
        }
    }
}

// ---------------- GEMM wrapper kernels (BM=64, 2 CTAs/SM) ----------------------
__global__ __launch_bounds__(256, 2) void k_tc_w1()
{
    int z = blockIdx.z;
    tc_core<128, false>(g_hblk + z * 256, (const float*)0, (const float*)0, 512,
                        g_W1T_h + z * 256, g_W1T_l + z * 256, 512,
                        g_partC + (long)z * PC1_OFF, 512, 256,
                        blockIdx.y * 64, blockIdx.x * 128);
}
__global__ __launch_bounds__(256, 2) void k_tc_q()
{
    int z = blockIdx.z;
    tc_core<128, false>(g_bt + z * 256, (const float*)0, (const float*)0, 512,
                        g_combT_h + z * 256, g_combT_l + z * 256, 512,
                        g_partC + (long)z * PC1_OFF, 2048, 256,
                        blockIdx.y * 64, blockIdx.x * 128);
}
__global__ __launch_bounds__(256, 2) void k_tc_gh()
{
    int z = blockIdx.z;
    tc_core<128, false>(g_bt + z * 256, (const float*)0, (const float*)0, 512,
                        g_combT_h + (long)512 * 512 + z * 256,
                        g_combT_l + (long)512 * 512 + z * 256, 512,
                        g_partC + (long)z * PC1_OFF + 512, 2048, 256,
                        blockIdx.y * 64, blockIdx.x * 128);
}
__global__ __launch_bounds__(256, 2) void k_tc_uk(const float* __restrict__ bq)
{
    int h = blockIdx.z;
    tc_core<128, true>(g_partC + h * 64, g_partC + PC1_OFF + h * 64, bq + h * 64, 2048,
                       g_Wk_h + h * 64, g_Wk_l + h * 64, 512,
                       g_uK + h * 512, 4096, 64,
                       blockIdx.y * 64, blockIdx.x * 128);
}
__global__ __launch_bounds__(256, 2) void k_tc_mraw()
{
    int z = blockIdx.z;
    int h = z >> 2;
    int ks = z & 3;
    tc_core<64, false>(g_ctx + h * 512 + (long)ks * 128, (const float*)0, (const float*)0, 4096,
                       g_WvT_h + (long)(h * 64) * 512 + ks * 128,
                       g_WvT_l + (long)(h * 64) * 512 + ks * 128, 512,
                       g_partM + ks * PM_OFF + h * 64, 512, 128,
                       blockIdx.y * 64, 0);
}
__global__ __launch_bounds__(256, 2) void k_tc_gi()
{
    int z = blockIdx.z;
    tc_core<128, false>(g_mt + z * 256, (const float*)0, (const float*)0, 512,
                        g_Wih_h + z * 256, g_Wih_l + z * 256, 512,
                        g_partG + (long)z * PG1_OFF, 1536, 256,
                        blockIdx.y * 64, blockIdx.x * 128);
}

// ---------------- weight prep ---------------------------------------------------
__global__ __launch_bounds__(256) void k_prep(
    const float* __restrict__ Wk, const float* __restrict__ W_ih,
    const float* __restrict__ W_hh, const float* __restrict__ Wq,
    const float* __restrict__ Wv, const float* __restrict__ W1)
{
    __shared__ float t[32][33];
    int job = blockIdx.z;
    int bx = blockIdx.x * 32;
    int by = blockIdx.y * 32;
    int lx = threadIdx.x & 31;
    int wy = threadIdx.x >> 5;
    if (job <= 2) {
        const float* src;
        __nv_bfloat16* dh;
        __nv_bfloat16* dl;
        int nrows;
        if (job == 0)      { src = Wk;   dh = g_Wk_h;  dl = g_Wk_l;  nrows = 512;  }
        else if (job == 1) { src = W_ih; dh = g_Wih_h; dl = g_Wih_l; nrows = 1536; }
        else               { src = W_hh; dh = g_combT_h + 512*512;
                             dl = g_combT_l + 512*512; nrows = 1536; }
        if (by >= nrows) return;
        for (int j = wy; j < 32; j += 8) {
            long o = (long)(by + j) * 512 + bx + lx;
            float v = src[o];
            __nv_bfloat16 hh = __float2bfloat16(v);
            dh[o] = hh;
            dl[o] = __float2bfloat16(v - __bfloat162float(hh));
        }
    } else {
        if (blockIdx.y >= 16) return;
        const float* src;
        __nv_bfloat16* dh;
        __nv_bfloat16* dl;
        if (job == 3)      { src = Wq; dh = g_combT_h; dl = g_combT_l; }
        else if (job == 4) { src = Wv; dh = g_WvT_h;   dl = g_WvT_l;   }
        else               { src = W1; dh = g_W1T_h;   dl = g_W1T_l;   }
        for (int j = wy; j < 32; j += 8)
            t[j][lx] = src[(long)(by + j) * 512 + bx + lx];
        __syncthreads();
        for (int j = wy; j < 32; j += 8) {
            float v = t[lx][j];
            long o = (long)(bx + j) * 512 + by + lx;
            __nv_bfloat16 hh = __float2bfloat16(v);
            dh[o] = hh;
            dl[o] = __float2bfloat16(v - __bfloat162float(hh));
        }
    }
}

// ---------------- preamble -----------------------------------------------------
__global__ __launch_bounds__(512) void k_build_hblk(
    const float* __restrict__ emb, const int* __restrict__ stc,
    const int* __restrict__ off, const int* __restrict__ sep)
{
    pdl_sync();
    int b = blockIdx.x;
    int o = off[b], len = stc[b];
    int sA = sep[b * 2], sB2 = sep[b * 2 + 1];
    int idx = (sA < o ? 1 : 0) + (sB2 < o ? 1 : 0);
    int pidx = idx - 1; pidx = pidx < 0 ? 0 : (pidx > 1 ? 1 : pidx);
    int prev = (pidx == 0) ? sA : sB2;
    int left = (idx > 0) ? prev + 1 : 0;
    int nidx = idx > 1 ? 1 : idx;
    int nxt = (nidx == 0) ? sA : sB2;
    int right = (idx < 2) ? nxt : len;
    int start = (o - 2 > left) ? o - 2 : left;
    int end = (o + 2 < right) ? o + 2 : right;
    int t = threadIdx.x;
    #pragma unroll
    for (int l = 0; l < L_; l++) {
        int ind = start + l;
        bool v = ind < end;
        int ic = ind < 0 ? 0 : (ind > S_ - 1 ? S_ - 1 : ind);
        g_hblk[(b * L_ + l) * D_ + t] = v ? emb[((long)b * S_ + ic) * D_ + t] : 0.f;
        if (t == 0) g_valid[b * L_ + l] = v ? 1.f : 0.f;
    }
}

__global__ __launch_bounds__(256) void k_a(const float* __restrict__ W2)
{
    pdl_sync();
    int m = blockIdx.x, t = threadIdx.x;
    float t0 = tanhf(g_partC[(long)m * 512 + t] + g_partC[PC1_OFF + (long)m * 512 + t]);
    float t1 = tanhf(g_partC[(long)m * 512 + t + 256] + g_partC[PC1_OFF + (long)m * 512 + t + 256]);
    float v = t0 * W2[t] + t1 * W2[t + 256];
    __shared__ float red[32];
    v = blockSum(v, red);
    if (t == 0) g_a[m] = v;
}

__global__ __launch_bounds__(512) void k_s1()
{
    pdl_sync();
    int l = blockIdx.x, t = threadIdx.x;
    __shared__ float red[32];
    float v = g_a[t * L_ + l];
    float mx = blockMax(v, red);
    float e = expf(v - mx);
    float s = blockSum(e, red);
    g_s1[t * L_ + l] = e / s;
}

__global__ __launch_bounds__(512) void k_b0(
    const float* __restrict__ ln_g, const float* __restrict__ ln_b,
    const float* __restrict__ pe)
{
    pdl_sync();
    int b = blockIdx.x, t = threadIdx.x;
    __shared__ float sc[4];
    __shared__ float red[32];
    if (t == 0) {
        float vals[4], mx = -3.0e38f;
        #pragma unroll
        for (int l = 0; l < 4; l++) {
            float v = (g_valid[b * 4 + l] > 0.5f) ? g_s1[b * 4 + l] : -1e9f;
            vals[l] = v; mx = fmaxf(mx, v);
        }
        float s = 0.f;
        #pragma unroll
        for (int l = 0; l < 4; l++) { float e = expf(vals[l] - mx); sc[l] = e; s += e; }
        #pragma unroll
        for (int l = 0; l < 4; l++) sc[l] /= s;
    }
    __syncthreads();
    float x = sc[0] * g_hblk[(b * 4 + 0) * D_ + t] + sc[1] * g_hblk[(b * 4 + 1) * D_ + t]
            + sc[2] * g_hblk[(b * 4 + 2) * D_ + t] + sc[3] * g_hblk[(b * 4 + 3) * D_ + t]
            + pe[t];
    float mean = blockSum(x, red) * (1.f / 512.f);
    float d = x - mean;
    float var = blockSum(d * d, red) * (1.f / 512.f);
    g_bt[b * D_ + t] = d * rsqrtf(var + 1e-5f) * ln_g[t] + ln_b[t];
}

// warp-per-row H build
__global__ __launch_bounds__(256) void k_buildH(
    const float* __restrict__ emb, const float* __restrict__ pe,
    const float* __restrict__ seg_emb, const float* __restrict__ ln_g,
    const float* __restrict__ ln_b, const int* __restrict__ stc,
    const int* __restrict__ off)
{
    __shared__ float s_seg[2][D_];
    __shared__ float s_g[D_];
    __shared__ float s_b[D_];
    int b = blockIdx.x;
    int tid = threadIdx.x, lane = tid & 31, warp = tid >> 5;
    for (int i = tid; i < D_; i += 256) {
        s_seg[0][i] = seg_emb[i];
        s_seg[1][i] = seg_emb[D_ + i];
        s_g[i] = ln_g[i];
        s_b[i] = ln_b[i];
    }
    int len = stc[b];
    int pos = off[b];
    __syncthreads();
    for (int s = warp; s < len; s += 8) {
        int ip = (s < pos) ? (pos - s) : (s + 1 - pos);
        ip = ip < 0 ? 0 : (ip > S_ ? S_ : ip);
        int sg = (s >= pos) ? 1 : 0;
        const float* er = emb + ((long)b * S_ + s) * D_;
        const float* pr = pe + (long)ip * D_;
        float x[16];
        float sum = 0.f;
        #pragma unroll
        for (int i = 0; i < 4; i++) {
            int base = i * 128 + lane * 4;
            float4 e = *(const float4*)(er + base);
            float4 p = *(const float4*)(pr + base);
            float v0 = e.x + p.x + s_seg[sg][base + 0];
            float v1 = e.y + p.y + s_seg[sg][base + 1];
            float v2 = e.z + p.z + s_seg[sg][base + 2];
            float v3 = e.w + p.w + s_seg[sg][base + 3];
            x[i*4+0] = v0; x[i*4+1] = v1; x[i*4+2] = v2; x[i*4+3] = v3;
            sum += v0 + v1 + v2 + v3;
        }
        float mean = warpAll(sum) * (1.f / 512.f);
        float vs = 0.f;
        #pragma unroll
        for (int i = 0; i < 16; i++) {
            float d = x[i] - mean;
            x[i] = d;
            vs += d * d;
        }
        float inv = rsqrtf(warpAll(vs) * (1.f / 512.f) + 1e-5f);
        __half* dr = g_Hh + ((long)b * S_ + s) * D_;
        #pragma unroll
        for (int i = 0; i < 4; i++) {
            int base = i * 128 + lane * 4;
            float o0 = x[i*4+0] * inv * s_g[base + 0] + s_b[base + 0];
            float o1 = x[i*4+1] * inv * s_g[base + 1] + s_b[base + 1];
            float o2 = x[i*4+2] * inv * s_g[base + 2] + s_b[base + 2];
            float o3 = x[i*4+3] * inv * s_g[base + 3] + s_b[base + 3];
            __half2 ha = __floats2half2_rn(o0, o1);
            __half2 hb = __floats2half2_rn(o2, o3);
            *(__half2*)(dr + base)     = ha;
            *(__half2*)(dr + base + 2) = hb;
        }
    }
}

// ---------------- fused attention v2: WMMA scores, half H ----------------------
__global__ __launch_bounds__(256) void k_attn(
    const float* __restrict__ bk, const float* __restrict__ bq,
    const int* __restrict__ stc)
{
    pdl_sync();
    int b = blockIdx.x;
    int tid = threadIdx.x, lane = tid & 31, warp = tid >> 5;   // 8 warps
    extern __shared__ __align__(16) char asm_[];
    __half* Hs  = (__half*)(asm_ + AOFF_HS);    // 32 x 520 half
    __half* uKh = (__half*)(asm_ + AOFF_UKH);   // 16 x 520 half (rows 8..15 zero)
    __half* uKl = (__half*)(asm_ + AOFF_UKL);
    float* scb  = (float*)(asm_ + AOFF_SC);     // 8 x 256 (warp partials)
    float* ps   = (float*)(asm_ + AOFF_PS);     // 32 x 8
    float* cKs  = (float*)(asm_ + AOFF_CK);
    float* pss  = (float*)(asm_ + AOFF_PSS);
    int len = stc[b];

    // stage uK -> half hi/lo (rows 0..7), zero rows 8..15
    {
        const float* src = g_uK + (long)b * NH_ * D_;
        #pragma unroll
        for (int i = 0; i < 16; i++) {
            int idx = tid + i * 256;            // 0..4095
            int h = idx >> 9, k = idx & 511;
            float v = src[idx];
            __half hh = __float2half(v);
            uKh[h * AHS_ROW + k] = hh;
            uKl[h * AHS_ROW + k] = __float2half(v - __half2float(hh));
        }
        // zero pad rows 8..15 (full 520 incl pad cols)
        for (int i = tid; i < 8 * AHS_ROW; i += 256) {
            uKh[8 * AHS_ROW + i] = __float2half(0.f);
            uKl[8 * AHS_ROW + i] = __float2half(0.f);
        }
    }
    // cK[h] = bk_h . q_h (q composed from comb partials + bq)
    {
        int j0 = warp * 64 + lane, j1 = j0 + 32;
        float q0 = g_partC[(long)b * 2048 + j0] + g_partC[PC1_OFF + (long)b * 2048 + j0] + bq[j0];
        float q1 = g_partC[(long)b * 2048 + j1] + g_partC[PC1_OFF + (long)b * 2048 + j1] + bq[j1];
        float v = bk[j0] * q0 + bk[j1] * q1;
        v = warpSum(v);
        if (lane == 0) { cKs[warp] = v; pss[warp] = 0.f; }
    }
    float creg[16] = {0.f,0.f,0.f,0.f,0.f,0.f,0.f,0.f,0.f,0.f,0.f,0.f,0.f,0.f,0.f,0.f};
    __syncthreads();

    int nch = (len + CH - 1) / CH;
    int wm = warp & 1;          // m-tile (16 rows)
    int wq = warp >> 1;         // k quarter (8 k-tiles)
    for (int c = 0; c < nch; c++) {
        int s0 = c * CH;
        // stage H chunk as raw half rows (zero past len)
        for (int r = warp; r < CH; r += 8) {
            int s = s0 + r;
            uint4* dst = (uint4*)(Hs + r * AHS_ROW);    // 1040B row stride, 16B aligned
            if (s < len) {
                const uint4* src = (const uint4*)(g_Hh + ((long)b * S_ + s) * D_);
                dst[lane] = src[lane];
                dst[lane + 32] = src[lane + 32];
            } else {
                uint4 z; z.x = 0; z.y = 0; z.z = 0; z.w = 0;
                dst[lane] = z;
                dst[lane + 32] = z;
            }
        }
        __syncthreads();
        // scores via WMMA: (32 x 512 half) @ (512 x 16 half), k split 4 ways
        {
            nvcuda::wmma::fragment<nvcuda::wmma::accumulator, 16, 16, 16, float> sacc;
            nvcuda::wmma::fill_fragment(sacc, 0.0f);
            #pragma unroll
            for (int kt = 0; kt < 8; kt++) {
                int k0 = (wq * 8 + kt) * 16;
                nvcuda::wmma::fragment<nvcuda::wmma::matrix_a, 16, 16, 16,
                                       __half, nvcuda::wmma::row_major> af;
                nvcuda::wmma::fragment<nvcuda::wmma::matrix_b, 16, 16, 16,
                                       __half, nvcuda::wmma::col_major> bfh, bfl;
                nvcuda::wmma::load_matrix_sync(af, Hs + wm * 16 * AHS_ROW + k0, AHS_ROW);
                nvcuda::wmma::load_matrix_sync(bfh, uKh + k0, AHS_ROW);
                nvcuda::wmma::load_matrix_sync(bfl, uKl + k0, AHS_ROW);
                nvcuda::wmma::mma_sync(sacc, af, bfh, sacc);
                nvcuda::wmma::mma_sync(sacc, af, bfl, sacc);
            }
            nvcuda::wmma::store_matrix_sync(scb + warp * 256, sacc, 16,
                                            nvcuda::wmma::mem_row_major);
        }
        __syncthreads();
        // combine k-quarters + sigmoid -> ps
        {
            int r = tid >> 3, h = tid & 7;
            int m = r >> 4, rr = r & 15;
            float v = scb[(0 * 2 + m) * 256 + rr * 16 + h]
                    + scb[(1 * 2 + m) * 256 + rr * 16 + h]
                    + scb[(2 * 2 + m) * 256 + rr * 16 + h]
                    + scb[(3 * 2 + m) * 256 + rr * 16 + h];
            int s = s0 + r;
            ps[r * NH_ + h] = (s < len) ? sigm(0.125f * (v + cKs[h])) : 0.f;
        }
        __syncthreads();
        // ctx: thread owns dims tid and tid+256 (half reads)
        #pragma unroll 4
        for (int r = 0; r < CH; r++) {
            float hv0 = __half2float(Hs[r * AHS_ROW + tid]);
            float hv1 = __half2float(Hs[r * AHS_ROW + tid + 256]);
            float4 p0 = *(const float4*)(ps + r * NH_);
            float4 p1 = *(const float4*)(ps + r * NH_ + 4);
            creg[0] += p0.x * hv0; creg[1] += p0.y * hv0;
            creg[2] += p0.z * hv0; creg[3] += p0.w * hv0;
            creg[4] += p1.x * hv0; creg[5] += p1.y * hv0;
            creg[6] += p1.z * hv0; creg[7] += p1.w * hv0;
            creg[8]  += p0.x * hv1; creg[9]  += p0.y * hv1;
            creg[10] += p0.z * hv1; creg[11] += p0.w * hv1;
            creg[12] += p1.x * hv1; creg[13] += p1.y * hv1;
            creg[14] += p1.z * hv1; creg[15] += p1.w * hv1;
        }
        // psum
        {
            float v = ps[lane * NH_ + warp];
            v = warpSum(v);
            if (lane == 0) pss[warp] += v;
        }
        __syncthreads();
    }
    #pragma unroll
    for (int h = 0; h < NH_; h++) {
        g_ctx[((long)b * NH_ + h) * D_ + tid]       = creg[h];
        g_ctx[((long)b * NH_ + h) * D_ + tid + 256] = creg[8 + h];
    }
    if (tid < NH_) g_psum[b * NH_ + tid] = pss[tid];
}

// ---------------- small per-iter kernels --------------------------------------
__global__ __launch_bounds__(512) void k_ln_mt(
    const float* __restrict__ bv, const float* __restrict__ lng_g,
    const float* __restrict__ lng_b)
{
    pdl_sync();
    int b = blockIdx.x, t = threadIdx.x;
    __shared__ float red[32];
    long o = (long)b * 512 + t;
    float x = g_partM[o] + g_partM[PM_OFF + o] + g_partM[2 * PM_OFF + o]
            + g_partM[3 * PM_OFF + o] + g_psum[b * NH_ + (t >> 6)] * bv[t];
    float mean = blockSum(x, red) * (1.f / 512.f);
    float d = x - mean;
    float var = blockSum(d * d, red) * (1.f / 512.f);
    g_mt[b * D_ + t] = d * rsqrtf(var + 1e-5f) * lng_g[t] + lng_b[t];
}

__global__ __launch_bounds__(512) void k_gru(
    const float* __restrict__ b_ih, const float* __restrict__ b_hh,
    float* __restrict__ out, int last)
{
    int b = blockIdx.x, t = threadIdx.x;
    const float* G0 = g_partG + (long)b * 1536;
    const float* G1 = g_partG + PG1_OFF + (long)b * 1536;
    const float* C0 = g_partC + (long)b * 2048 + 512;
    const float* C1 = g_partC + PC1_OFF + (long)b * 2048 + 512;
    float ir = G0[t]        + G1[t]        + b_ih[t];
    float iz = G0[t + 512]  + G1[t + 512]  + b_ih[t + 512];
    float in = G0[t + 1024] + G1[t + 1024] + b_ih[t + 1024];
    float hr = C0[t]        + C1[t]        + b_hh[t];
    float hz = C0[t + 512]  + C1[t + 512]  + b_hh[t + 512];
    float hn = C0[t + 1024] + C1[t + 1024] + b_hh[t + 1024];
    float r = sigm(ir + hr);
    float z = sigm(iz + hz);
    float n = tanhf(in + r * hn);
    float old = g_bt[b * D_ + t];
    float nv = (1.f - z) * n + z * old;
    g_bt[b * D_ + t] = nv;
    if (last) out[b * 512 + t] = nv;
}

// ---------------- launch --------------------------------------------------------
extern "C" void kernel_launch(void* const* d_in, const int* in_sizes, int n_in,
                              void* d_out, int out_size)
{
    const float* emb   = (const float*)d_in[0];
    const int*   stc   = (const int*)  d_in[1];
    const int*   off   = (const int*)  d_in[2];
    const int*   sep   = (const int*)  d_in[3];
    const float* W1    = (const float*)d_in[4];
    const float* W2    = (const float*)d_in[5];
    const float* ln_g  = (const float*)d_in[6];
    const float* ln_b  = (const float*)d_in[7];
    const float* lng_g = (const float*)d_in[8];
    const float* lng_b = (const float*)d_in[9];
    const float* Wq    = (const float*)d_in[10];
    const float* bq    = (const float*)d_in[11];
    const float* Wk    = (const float*)d_in[12];
    const float* bk    = (const float*)d_in[13];
    const float* Wv    = (const float*)d_in[14];
    const float* bv    = (const float*)d_in[15];
    const float* W_ih  = (const float*)d_in[16];
    const float* W_hh  = (const float*)d_in[17];
    const float* b_ih  = (const float*)d_in[18];
    const float* b_hh  = (const float*)d_in[19];
    const float* seg   = (const float*)d_in[20];
    const float* pe    = (const float*)d_in[21];
    float* out = (float*)d_out;

    cudaFuncSetAttribute(k_attn, cudaFuncAttributeMaxDynamicSharedMemorySize, ATTN_SMEM_V2);
    cudaFuncSetAttribute(k_tc_w1,   cudaFuncAttributeMaxDynamicSharedMemorySize, SMEM_TCB128);
    cudaFuncSetAttribute(k_tc_q,    cudaFuncAttributeMaxDynamicSharedMemorySize, SMEM_TCB128);
    cudaFuncSetAttribute(k_tc_gh,   cudaFuncAttributeMaxDynamicSharedMemorySize, SMEM_TCB128);
    cudaFuncSetAttribute(k_tc_uk,   cudaFuncAttributeMaxDynamicSharedMemorySize, SMEM_TCB128);
    cudaFuncSetAttribute(k_tc_gi,   cudaFuncAttributeMaxDynamicSharedMemorySize, SMEM_TCB128);
    cudaFuncSetAttribute(k_tc_mraw, cudaFuncAttributeMaxDynamicSharedMemorySize, SMEM_TCB64);

    cudaStream_t sB;
    cudaStreamCreateWithFlags(&sB, cudaStreamNonBlocking);
    cudaEvent_t evF, evH, evG;
    cudaEventCreateWithFlags(&evF, cudaEventDisableTiming);
    cudaEventCreateWithFlags(&evH, cudaEventDisableTiming);
    cudaEventCreateWithFlags(&evG, cudaEventDisableTiming);

    cudaLaunchAttribute pdlAttr[1];
    pdlAttr[0].id = cudaLaunchAttributeProgrammaticStreamSerialization;
    pdlAttr[0].val.programmaticStreamSerializationAllowed = 1;
    auto mkcfg = [&](dim3 g, dim3 b, size_t smem) {
        cudaLaunchConfig_t c;
        c.gridDim = g; c.blockDim = b; c.dynamicSmemBytes = smem;
        c.stream = 0; c.attrs = pdlAttr; c.numAttrs = 1;
        return c;
    };

    // ---- preamble: fork buildH onto side stream ----
    cudaEventRecord(evF, 0);
    cudaStreamWaitEvent(sB, evF, 0);
    k_buildH<<<B_, 256, 0, sB>>>(emb, pe, seg, ln_g, ln_b, stc, off);
    cudaEventRecord(evH, sB);

    k_prep<<<dim3(16, 48, 6), 256>>>(Wk, W_ih, W_hh, Wq, Wv, W1);
    {
        cudaLaunchConfig_t c = mkcfg(dim3(B_, 1, 1), dim3(512, 1, 1), 0);
        cudaLaunchKernelEx(&c, k_build_hblk, emb, stc, off, sep);
    }
    {
        cudaLaunchConfig_t c = mkcfg(dim3(4, 32, 2), dim3(256, 1, 1), SMEM_TCB128);
        cudaLaunchKernelEx(&c, k_tc_w1);
    }
    {
        cudaLaunchConfig_t c = mkcfg(dim3(2048, 1, 1), dim3(256, 1, 1), 0);
        cudaLaunchKernelEx(&c, k_a, W2);
    }
    {
        cudaLaunchConfig_t c = mkcfg(dim3(L_, 1, 1), dim3(512, 1, 1), 0);
        cudaLaunchKernelEx(&c, k_s1);
    }
    {
        cudaLaunchConfig_t c = mkcfg(dim3(B_, 1, 1), dim3(512, 1, 1), 0);
        cudaLaunchKernelEx(&c, k_b0, ln_g, ln_b, pe);
    }

    // ---- 3 GRU iterations ----
    for (int it = 0; it < 3; it++) {
        cudaEventRecord(evF, 0);
        cudaStreamWaitEvent(sB, evF, 0);
        k_tc_gh<<<dim3(12, 8, 2), 256, SMEM_TCB128, sB>>>();
        cudaEventRecord(evG, sB);

        {
            cudaLaunchConfig_t c = mkcfg(dim3(4, 8, 2), dim3(256, 1, 1), SMEM_TCB128);
            cudaLaunchKernelEx(&c, k_tc_q);
        }
        {
            cudaLaunchConfig_t c = mkcfg(dim3(4, 8, 8), dim3(256, 1, 1), SMEM_TCB128);
            cudaLaunchKernelEx(&c, k_tc_uk, bq);
        }
        if (it == 0) {
            cudaStreamWaitEvent(0, evH, 0);
            k_attn<<<B_, 256, ATTN_SMEM_V2>>>(bk, bq, stc);
        } else {
            cudaLaunchConfig_t c = mkcfg(dim3(B_, 1, 1), dim3(256, 1, 1), ATTN_SMEM_V2);
            cudaLaunchKernelEx(&c, k_attn, bk, bq, stc);
        }
        {
            cudaLaunchConfig_t c = mkcfg(dim3(1, 8, 32), dim3(256, 1, 1), SMEM_TCB64);
            cudaLaunchKernelEx(&c, k_tc_mraw);
        }
        {
            cudaLaunchConfig_t c = mkcfg(dim3(B_, 1, 1), dim3(512, 1, 1), 0);
            cudaLaunchKernelEx(&c, k_ln_mt, bv, lng_g, lng_b);
        }
        {
            cudaLaunchConfig_t c = mkcfg(dim3(12, 8, 2), dim3(256, 1, 1), SMEM_TCB128);
            cudaLaunchKernelEx(&c, k_tc_gi);
        }
        cudaStreamWaitEvent(0, evG, 0);
        k_gru<<<B_, 512>>>(b_ih, b_hh, out, it == 2 ? 1 : 0);
    }
    (void)in_sizes; (void)n_in; (void)out_size;
}

// round 14
// speedup vs baseline: 4.5461x; 1.0223x over previous
#include <cuda_runtime.h>
#include <cuda_bf16.h>
#include <cuda_fp16.h>
#include <cuda_pipeline.h>
#include <mma.h>
#include <math.h>

#define B_  512
#define S_  200
#define D_  512
#define NH_ 8
#define L_  4
#define CH  32

// ---------------- scratch (device globals) ----------------------------------
__device__ float g_hblk[B_*L_*D_];
__device__ float g_valid[B_*L_];
__device__ float g_a[B_*L_];
__device__ float g_s1[B_*L_];
__device__ float g_bt[B_*D_];
__device__ __half g_Hh[B_*S_*D_];        // 105 MB (fp16 H)
__device__ float g_uK[B_*NH_*D_];
__device__ float g_ctx[B_*NH_*D_];
__device__ float g_psum[B_*NH_];
__device__ float g_mt[B_*D_];
__device__ float g_partC[2*B_*2048];     // comb / W1 split-K partials
__device__ float g_partM[4*B_*D_];       // mraw split-K partials
__device__ float g_partG[2*B_*1536];     // gi split-K partials

// bf16 hi/lo split weights, [N][K] layout (K contiguous)
__device__ __nv_bfloat16 g_combT_h[2048*512];
__device__ __nv_bfloat16 g_combT_l[2048*512];
__device__ __nv_bfloat16 g_Wih_h[1536*512];
__device__ __nv_bfloat16 g_Wih_l[1536*512];
__device__ __nv_bfloat16 g_Wk_h[512*512];
__device__ __nv_bfloat16 g_Wk_l[512*512];
__device__ __nv_bfloat16 g_WvT_h[512*512];
__device__ __nv_bfloat16 g_WvT_l[512*512];
__device__ __nv_bfloat16 g_W1T_h[512*512];
__device__ __nv_bfloat16 g_W1T_l[512*512];

#define PC1_OFF 1048576L   // 512*2048
#define PM_OFF  262144L    // 512*512
#define PG1_OFF 786432L    // 512*1536

// dynamic smem: 2 stages x (A(64) h/l + B(BN) h/l) x RS(40) x 2B
#define SMEM_TCB128 61440
#define SMEM_TCB64  40960

// attention v3 smem layout (bytes)
#define AHS_ROW   520                       // halfs per Hs/uK row (512 + 8 pad)
#define APT_ROW   40                        // halfs per psT row (32 + 8 pad)
#define AOFF_HS   0                         // 32 x 520 half = 33280
#define AOFF_UKH  33280                     // 16 x 520 half = 16640
#define AOFF_UKL  49920                     // 16 x 520 half = 16640
#define AOFF_SC   66560                     // 8 x 256 float = 8192
#define AOFF_PS   74752                     // 32 x 8 float  = 1024
#define AOFF_PTH  75776                     // 16 x 40 half  = 1280
#define AOFF_PTL  77056                     // 16 x 40 half  = 1280
#define AOFF_CK   78336                     // 8 float
#define AOFF_PSS  78368                     // 8 float
#define ATTN_SMEM_V3 78400

// PDL helpers
__device__ __forceinline__ void pdl_sync() {
#if __CUDA_ARCH__ >= 900
    cudaGridDependencySynchronize();
    cudaTriggerProgrammaticLaunchCompletion();
#endif
}

// ---------------- helpers ----------------------------------------------------
__device__ __forceinline__ float warpSum(float v) {
    #pragma unroll
    for (int o = 16; o; o >>= 1) v += __shfl_down_sync(0xffffffffu, v, o);
    return v;
}
__device__ __forceinline__ float warpAll(float v) {
    #pragma unroll
    for (int o = 16; o; o >>= 1) v += __shfl_xor_sync(0xffffffffu, v, o);
    return v;
}
__device__ __forceinline__ float warpMax(float v) {
    #pragma unroll
    for (int o = 16; o; o >>= 1) v = fmaxf(v, __shfl_down_sync(0xffffffffu, v, o));
    return v;
}
__device__ __forceinline__ float blockSum(float v, float* red) {
    int lane = threadIdx.x & 31, w = threadIdx.x >> 5;
    v = warpSum(v);
    if (lane == 0) red[w] = v;
    __syncthreads();
    float r = 0.f;
    if (threadIdx.x < (blockDim.x >> 5)) r = red[threadIdx.x];
    if (w == 0) r = warpSum(r);
    if (threadIdx.x == 0) red[0] = r;
    __syncthreads();
    r = red[0];
    __syncthreads();
    return r;
}
__device__ __forceinline__ float blockMax(float v, float* red) {
    int lane = threadIdx.x & 31, w = threadIdx.x >> 5;
    v = warpMax(v);
    if (lane == 0) red[w] = v;
    __syncthreads();
    float r = -3.0e38f;
    if (threadIdx.x < (blockDim.x >> 5)) r = red[threadIdx.x];
    if (w == 0) r = warpMax(r);
    if (threadIdx.x == 0) red[0] = r;
    __syncthreads();
    r = red[0];
    __syncthreads();
    return r;
}
__device__ __forceinline__ float sigm(float x) { return 1.f / (1.f + expf(-x)); }

// ---------------- WMMA tensor GEMM core v2 (unchanged from R13) ----------------
template <int BN, bool COMPOSE>
__device__ __forceinline__ void tc_core(
    const float* A0, const float* A1, const float* Ab, int lda,
    const __nv_bfloat16* Bh, const __nv_bfloat16* Bl, int ldb,
    float* C, int ldc, int Kd, int m0, int n0)
{
    const int RS = 40;
    const int NT = BN / 64;
    const int BCH = BN / 64;
    const int AE = 64 * RS;
    const int BE = BN * RS;
    const int STG = 2 * AE + 2 * BE;

    extern __shared__ __align__(16) __nv_bfloat16 dsm[];

    pdl_sync();

    int tid = threadIdx.x;
    int warp = tid >> 5;
    int wm = warp & 1;
    int wn = warp >> 1;

    nvcuda::wmma::fragment<nvcuda::wmma::accumulator, 16, 16, 16, float> acc[2][NT];
    #pragma unroll
    for (int i = 0; i < 2; i++) {
        #pragma unroll
        for (int j = 0; j < NT; j++) {
            nvcuda::wmma::fill_fragment(acc[i][j], 0.0f);
        }
    }

    float4 va[2];
    int arow = tid >> 3;
    int aq = tid & 7;

    {
        __nv_bfloat16* sBh = dsm + 2 * AE;
        __nv_bfloat16* sBl = dsm + 2 * AE + BE;
        #pragma unroll
        for (int i = 0; i < BCH; i++) {
            int c = tid + i * 256;
            int row = c >> 2;
            int q = c & 3;
            __pipeline_memcpy_async(sBh + row * RS + q * 8,
                                    Bh + (long)(n0 + row) * ldb + q * 8, 16);
            __pipeline_memcpy_async(sBl + row * RS + q * 8,
                                    Bl + (long)(n0 + row) * ldb + q * 8, 16);
        }
        __pipeline_commit();
        #pragma unroll
        for (int i = 0; i < 2; i++) {
            int row = arow + i * 32;
            float4 v = *(const float4*)(A0 + (long)(m0 + row) * lda + aq * 4);
            if (COMPOSE) {
                float4 v1 = *(const float4*)(A1 + (long)(m0 + row) * lda + aq * 4);
                float4 bi = *(const float4*)(Ab + aq * 4);
                v.x += v1.x + bi.x; v.y += v1.y + bi.y;
                v.z += v1.z + bi.z; v.w += v1.w + bi.w;
            }
            va[i] = v;
        }
        __nv_bfloat16* sAh = dsm;
        __nv_bfloat16* sAl = dsm + AE;
        #pragma unroll
        for (int i = 0; i < 2; i++) {
            int row = arow + i * 32;
            float4 v = va[i];
            __nv_bfloat16 h0 = __float2bfloat16(v.x);
            __nv_bfloat16 h1 = __float2bfloat16(v.y);
            __nv_bfloat16 h2 = __float2bfloat16(v.z);
            __nv_bfloat16 h3 = __float2bfloat16(v.w);
            int o = row * RS + aq * 4;
            sAh[o + 0] = h0; sAh[o + 1] = h1; sAh[o + 2] = h2; sAh[o + 3] = h3;
            sAl[o + 0] = __float2bfloat16(v.x - __bfloat162float(h0));
            sAl[o + 1] = __float2bfloat16(v.y - __bfloat162float(h1));
            sAl[o + 2] = __float2bfloat16(v.z - __bfloat162float(h2));
            sAl[o + 3] = __float2bfloat16(v.w - __bfloat162float(h3));
        }
        __pipeline_wait_prior(0);
        __syncthreads();
    }

    int nch = Kd >> 5;
    for (int c = 0; c < nch; c++) {
        int kn = (c + 1) * 32;
        __nv_bfloat16* nxt = dsm + ((c + 1) & 1) * STG;
        if (c + 1 < nch) {
            __nv_bfloat16* sBh = nxt + 2 * AE;
            __nv_bfloat16* sBl = nxt + 2 * AE + BE;
            #pragma unroll
            for (int i = 0; i < BCH; i++) {
                int cc = tid + i * 256;
                int row = cc >> 2;
                int q = cc & 3;
                __pipeline_memcpy_async(sBh + row * RS + q * 8,
                                        Bh + (long)(n0 + row) * ldb + kn + q * 8, 16);
                __pipeline_memcpy_async(sBl + row * RS + q * 8,
                                        Bl + (long)(n0 + row) * ldb + kn + q * 8, 16);
            }
            __pipeline_commit();
            #pragma unroll
            for (int i = 0; i < 2; i++) {
                int row = arow + i * 32;
                float4 v = *(const float4*)(A0 + (long)(m0 + row) * lda + kn + aq * 4);
                if (COMPOSE) {
                    float4 v1 = *(const float4*)(A1 + (long)(m0 + row) * lda + kn + aq * 4);
                    float4 bi = *(const float4*)(Ab + kn + aq * 4);
                    v.x += v1.x + bi.x; v.y += v1.y + bi.y;
                    v.z += v1.z + bi.z; v.w += v1.w + bi.w;
                }
                va[i] = v;
            }
        }
        {
            __nv_bfloat16* base = dsm + (c & 1) * STG;
            __nv_bfloat16* sAh = base;
            __nv_bfloat16* sAl = base + AE;
            __nv_bfloat16* sBh = base + 2 * AE;
            __nv_bfloat16* sBl = base + 2 * AE + BE;
            #pragma unroll
            for (int ks = 0; ks < 2; ks++) {
                nvcuda::wmma::fragment<nvcuda::wmma::matrix_a, 16, 16, 16,
                                       __nv_bfloat16, nvcuda::wmma::row_major> ah[2], al[2];
                #pragma unroll
                for (int i = 0; i < 2; i++) {
                    int r = wm * 32 + i * 16;
                    nvcuda::wmma::load_matrix_sync(ah[i], sAh + r * RS + ks * 16, RS);
                    nvcuda::wmma::load_matrix_sync(al[i], sAl + r * RS + ks * 16, RS);
                }
                #pragma unroll
                for (int j = 0; j < NT; j++) {
                    int nn = wn * (BN / 4) + j * 16;
                    nvcuda::wmma::fragment<nvcuda::wmma::matrix_b, 16, 16, 16,
                                           __nv_bfloat16, nvcuda::wmma::col_major> bh, bl;
                    nvcuda::wmma::load_matrix_sync(bh, sBh + nn * RS + ks * 16, RS);
                    nvcuda::wmma::load_matrix_sync(bl, sBl + nn * RS + ks * 16, RS);
                    #pragma unroll
                    for (int i = 0; i < 2; i++) {
                        nvcuda::wmma::mma_sync(acc[i][j], ah[i], bh, acc[i][j]);
                        nvcuda::wmma::mma_sync(acc[i][j], ah[i], bl, acc[i][j]);
                        nvcuda::wmma::mma_sync(acc[i][j], al[i], bh, acc[i][j]);
                    }
                }
            }
        }
        if (c + 1 < nch) {
            __nv_bfloat16* sAh = nxt;
            __nv_bfloat16* sAl = nxt + AE;
            #pragma unroll
            for (int i = 0; i < 2; i++) {
                int row = arow + i * 32;
                float4 v = va[i];
                __nv_bfloat16 h0 = __float2bfloat16(v.x);
                __nv_bfloat16 h1 = __float2bfloat16(v.y);
                __nv_bfloat16 h2 = __float2bfloat16(v.z);
                __nv_bfloat16 h3 = __float2bfloat16(v.w);
                int o = row * RS + aq * 4;
                sAh[o + 0] = h0; sAh[o + 1] = h1; sAh[o + 2] = h2; sAh[o + 3] = h3;
                sAl[o + 0] = __float2bfloat16(v.x - __bfloat162float(h0));
                sAl[o + 1] = __float2bfloat16(v.y - __bfloat162float(h1));
                sAl[o + 2] = __float2bfloat16(v.z - __bfloat162float(h2));
                sAl[o + 3] = __float2bfloat16(v.w - __bfloat162float(h3));
            }
            __pipeline_wait_prior(0);
        }
        __syncthreads();
    }
    #pragma unroll
    for (int i = 0; i < 2; i++) {
        #pragma unroll
        for (int j = 0; j < NT; j++) {
            int row = m0 + wm * 32 + i * 16;
            int col = n0 + wn * (BN / 4) + j * 16;
            nvcuda::wmma::store_matrix_sync(C + (long)row * ldc + col, acc[i][j],
                                            ldc, nvcuda::wmma::mem_row_major);
        }
    }
}

// ---------------- GEMM wrapper kernels (BM=64, 2 CTAs/SM) ----------------------
__global__ __launch_bounds__(256, 2) void k_tc_w1()
{
    int z = blockIdx.z;
    tc_core<128, false>(g_hblk + z * 256, (const float*)0, (const float*)0, 512,
                        g_W1T_h + z * 256, g_W1T_l + z * 256, 512,
                        g_partC + (long)z * PC1_OFF, 512, 256,
                        blockIdx.y * 64, blockIdx.x * 128);
}
__global__ __launch_bounds__(256, 2) void k_tc_q()
{
    int z = blockIdx.z;
    tc_core<128, false>(g_bt + z * 256, (const float*)0, (const float*)0, 512,
                        g_combT_h + z * 256, g_combT_l + z * 256, 512,
                        g_partC + (long)z * PC1_OFF, 2048, 256,
                        blockIdx.y * 64, blockIdx.x * 128);
}
__global__ __launch_bounds__(256, 2) void k_tc_gh()
{
    int z = blockIdx.z;
    tc_core<128, false>(g_bt + z * 256, (const float*)0, (const float*)0, 512,
                        g_combT_h + (long)512 * 512 + z * 256,
                        g_combT_l + (long)512 * 512 + z * 256, 512,
                        g_partC + (long)z * PC1_OFF + 512, 2048, 256,
                        blockIdx.y * 64, blockIdx.x * 128);
}
__global__ __launch_bounds__(256, 2) void k_tc_uk(const float* __restrict__ bq)
{
    int h = blockIdx.z;
    tc_core<128, true>(g_partC + h * 64, g_partC + PC1_OFF + h * 64, bq + h * 64, 2048,
                       g_Wk_h + h * 64, g_Wk_l + h * 64, 512,
                       g_uK + h * 512, 4096, 64,
                       blockIdx.y * 64, blockIdx.x * 128);
}
__global__ __launch_bounds__(256, 2) void k_tc_mraw()
{
    int z = blockIdx.z;
    int h = z >> 2;
    int ks = z & 3;
    tc_core<64, false>(g_ctx + h * 512 + (long)ks * 128, (const float*)0, (const float*)0, 4096,
                       g_WvT_h + (long)(h * 64) * 512 + ks * 128,
                       g_WvT_l + (long)(h * 64) * 512 + ks * 128, 512,
                       g_partM + ks * PM_OFF + h * 64, 512, 128,
                       blockIdx.y * 64, 0);
}
__global__ __launch_bounds__(256, 2) void k_tc_gi()
{
    int z = blockIdx.z;
    tc_core<128, false>(g_mt + z * 256, (const float*)0, (const float*)0, 512,
                        g_Wih_h + z * 256, g_Wih_l + z * 256, 512,
                        g_partG + (long)z * PG1_OFF, 1536, 256,
                        blockIdx.y * 64, blockIdx.x * 128);
}

// ---------------- weight prep ---------------------------------------------------
__global__ __launch_bounds__(256) void k_prep(
    const float* __restrict__ Wk, const float* __restrict__ W_ih,
    const float* __restrict__ W_hh, const float* __restrict__ Wq,
    const float* __restrict__ Wv, const float* __restrict__ W1)
{
    __shared__ float t[32][33];
    int job = blockIdx.z;
    int bx = blockIdx.x * 32;
    int by = blockIdx.y * 32;
    int lx = threadIdx.x & 31;
    int wy = threadIdx.x >> 5;
    if (job <= 2) {
        const float* src;
        __nv_bfloat16* dh;
        __nv_bfloat16* dl;
        int nrows;
        if (job == 0)      { src = Wk;   dh = g_Wk_h;  dl = g_Wk_l;  nrows = 512;  }
        else if (job == 1) { src = W_ih; dh = g_Wih_h; dl = g_Wih_l; nrows = 1536; }
        else               { src = W_hh; dh = g_combT_h + 512*512;
                             dl = g_combT_l + 512*512; nrows = 1536; }
        if (by >= nrows) return;
        for (int j = wy; j < 32; j += 8) {
            long o = (long)(by + j) * 512 + bx + lx;
            float v = src[o];
            __nv_bfloat16 hh = __float2bfloat16(v);
            dh[o] = hh;
            dl[o] = __float2bfloat16(v - __bfloat162float(hh));
        }
    } else {
        if (blockIdx.y >= 16) return;
        const float* src;
        __nv_bfloat16* dh;
        __nv_bfloat16* dl;
        if (job == 3)      { src = Wq; dh = g_combT_h; dl = g_combT_l; }
        else if (job == 4) { src = Wv; dh = g_WvT_h;   dl = g_WvT_l;   }
        else               { src = W1; dh = g_W1T_h;   dl = g_W1T_l;   }
        for (int j = wy; j < 32; j += 8)
            t[j][lx] = src[(long)(by + j) * 512 + bx + lx];
        __syncthreads();
        for (int j = wy; j < 32; j += 8) {
            float v = t[lx][j];
            long o = (long)(bx + j) * 512 + by + lx;
            __nv_bfloat16 hh = __float2bfloat16(v);
            dh[o] = hh;
            dl[o] = __float2bfloat16(v - __bfloat162float(hh));
        }
    }
}

// ---------------- preamble -----------------------------------------------------
__global__ __launch_bounds__(512) void k_build_hblk(
    const float* __restrict__ emb, const int* __restrict__ stc,
    const int* __restrict__ off, const int* __restrict__ sep)
{
    pdl_sync();
    int b = blockIdx.x;
    int o = off[b], len = stc[b];
    int sA = sep[b * 2], sB2 = sep[b * 2 + 1];
    int idx = (sA < o ? 1 : 0) + (sB2 < o ? 1 : 0);
    int pidx = idx - 1; pidx = pidx < 0 ? 0 : (pidx > 1 ? 1 : pidx);
    int prev = (pidx == 0) ? sA : sB2;
    int left = (idx > 0) ? prev + 1 : 0;
    int nidx = idx > 1 ? 1 : idx;
    int nxt = (nidx == 0) ? sA : sB2;
    int right = (idx < 2) ? nxt : len;
    int start = (o - 2 > left) ? o - 2 : left;
    int end = (o + 2 < right) ? o + 2 : right;
    int t = threadIdx.x;
    #pragma unroll
    for (int l = 0; l < L_; l++) {
        int ind = start + l;
        bool v = ind < end;
        int ic = ind < 0 ? 0 : (ind > S_ - 1 ? S_ - 1 : ind);
        g_hblk[(b * L_ + l) * D_ + t] = v ? emb[((long)b * S_ + ic) * D_ + t] : 0.f;
        if (t == 0) g_valid[b * L_ + l] = v ? 1.f : 0.f;
    }
}

__global__ __launch_bounds__(256) void k_a(const float* __restrict__ W2)
{
    pdl_sync();
    int m = blockIdx.x, t = threadIdx.x;
    float t0 = tanhf(g_partC[(long)m * 512 + t] + g_partC[PC1_OFF + (long)m * 512 + t]);
    float t1 = tanhf(g_partC[(long)m * 512 + t + 256] + g_partC[PC1_OFF + (long)m * 512 + t + 256]);
    float v = t0 * W2[t] + t1 * W2[t + 256];
    __shared__ float red[32];
    v = blockSum(v, red);
    if (t == 0) g_a[m] = v;
}

__global__ __launch_bounds__(512) void k_s1()
{
    pdl_sync();
    int l = blockIdx.x, t = threadIdx.x;
    __shared__ float red[32];
    float v = g_a[t * L_ + l];
    float mx = blockMax(v, red);
    float e = expf(v - mx);
    float s = blockSum(e, red);
    g_s1[t * L_ + l] = e / s;
}

__global__ __launch_bounds__(512) void k_b0(
    const float* __restrict__ ln_g, const float* __restrict__ ln_b,
    const float* __restrict__ pe)
{
    pdl_sync();
    int b = blockIdx.x, t = threadIdx.x;
    __shared__ float sc[4];
    __shared__ float red[32];
    if (t == 0) {
        float vals[4], mx = -3.0e38f;
        #pragma unroll
        for (int l = 0; l < 4; l++) {
            float v = (g_valid[b * 4 + l] > 0.5f) ? g_s1[b * 4 + l] : -1e9f;
            vals[l] = v; mx = fmaxf(mx, v);
        }
        float s = 0.f;
        #pragma unroll
        for (int l = 0; l < 4; l++) { float e = expf(vals[l] - mx); sc[l] = e; s += e; }
        #pragma unroll
        for (int l = 0; l < 4; l++) sc[l] /= s;
    }
    __syncthreads();
    float x = sc[0] * g_hblk[(b * 4 + 0) * D_ + t] + sc[1] * g_hblk[(b * 4 + 1) * D_ + t]
            + sc[2] * g_hblk[(b * 4 + 2) * D_ + t] + sc[3] * g_hblk[(b * 4 + 3) * D_ + t]
            + pe[t];
    float mean = blockSum(x, red) * (1.f / 512.f);
    float d = x - mean;
    float var = blockSum(d * d, red) * (1.f / 512.f);
    g_bt[b * D_ + t] = d * rsqrtf(var + 1e-5f) * ln_g[t] + ln_b[t];
}

// warp-per-row H build
__global__ __launch_bounds__(256) void k_buildH(
    const float* __restrict__ emb, const float* __restrict__ pe,
    const float* __restrict__ seg_emb, const float* __restrict__ ln_g,
    const float* __restrict__ ln_b, const int* __restrict__ stc,
    const int* __restrict__ off)
{
    __shared__ float s_seg[2][D_];
    __shared__ float s_g[D_];
    __shared__ float s_b[D_];
    int b = blockIdx.x;
    int tid = threadIdx.x, lane = tid & 31, warp = tid >> 5;
    for (int i = tid; i < D_; i += 256) {
        s_seg[0][i] = seg_emb[i];
        s_seg[1][i] = seg_emb[D_ + i];
        s_g[i] = ln_g[i];
        s_b[i] = ln_b[i];
    }
    int len = stc[b];
    int pos = off[b];
    __syncthreads();
    for (int s = warp; s < len; s += 8) {
        int ip = (s < pos) ? (pos - s) : (s + 1 - pos);
        ip = ip < 0 ? 0 : (ip > S_ ? S_ : ip);
        int sg = (s >= pos) ? 1 : 0;
        const float* er = emb + ((long)b * S_ + s) * D_;
        const float* pr = pe + (long)ip * D_;
        float x[16];
        float sum = 0.f;
        #pragma unroll
        for (int i = 0; i < 4; i++) {
            int base = i * 128 + lane * 4;
            float4 e = *(const float4*)(er + base);
            float4 p = *(const float4*)(pr + base);
            float v0 = e.x + p.x + s_seg[sg][base + 0];
            float v1 = e.y + p.y + s_seg[sg][base + 1];
            float v2 = e.z + p.z + s_seg[sg][base + 2];
            float v3 = e.w + p.w + s_seg[sg][base + 3];
            x[i*4+0] = v0; x[i*4+1] = v1; x[i*4+2] = v2; x[i*4+3] = v3;
            sum += v0 + v1 + v2 + v3;
        }
        float mean = warpAll(sum) * (1.f / 512.f);
        float vs = 0.f;
        #pragma unroll
        for (int i = 0; i < 16; i++) {
            float d = x[i] - mean;
            x[i] = d;
            vs += d * d;
        }
        float inv = rsqrtf(warpAll(vs) * (1.f / 512.f) + 1e-5f);
        __half* dr = g_Hh + ((long)b * S_ + s) * D_;
        #pragma unroll
        for (int i = 0; i < 4; i++) {
            int base = i * 128 + lane * 4;
            float o0 = x[i*4+0] * inv * s_g[base + 0] + s_b[base + 0];
            float o1 = x[i*4+1] * inv * s_g[base + 1] + s_b[base + 1];
            float o2 = x[i*4+2] * inv * s_g[base + 2] + s_b[base + 2];
            float o3 = x[i*4+3] * inv * s_g[base + 3] + s_b[base + 3];
            __half2 ha = __floats2half2_rn(o0, o1);
            __half2 hb = __floats2half2_rn(o2, o3);
            *(__half2*)(dr + base)     = ha;
            *(__half2*)(dr + base + 2) = hb;
        }
    }
}

// ---------------- fused attention v3: WMMA scores + WMMA ctx --------------------
__global__ __launch_bounds__(256) void k_attn(
    const float* __restrict__ bk, const float* __restrict__ bq,
    const int* __restrict__ stc)
{
    pdl_sync();
    int b = blockIdx.x;
    int tid = threadIdx.x, lane = tid & 31, warp = tid >> 5;   // 8 warps
    extern __shared__ __align__(16) char asm_[];
    __half* Hs   = (__half*)(asm_ + AOFF_HS);    // 32 x 520 half
    __half* uKh  = (__half*)(asm_ + AOFF_UKH);   // 16 x 520 half (rows 8..15 zero)
    __half* uKl  = (__half*)(asm_ + AOFF_UKL);
    float* scb   = (float*)(asm_ + AOFF_SC);     // 8 x 256 (warp scratch)
    float* ps    = (float*)(asm_ + AOFF_PS);     // 32 x 8
    __half* psTh = (__half*)(asm_ + AOFF_PTH);   // 16 x 40 half (rows 8..15 zero)
    __half* psTl = (__half*)(asm_ + AOFF_PTL);
    float* cKs   = (float*)(asm_ + AOFF_CK);
    float* pss   = (float*)(asm_ + AOFF_PSS);
    int len = stc[b];

    // stage uK -> half hi/lo (rows 0..7), zero rows 8..15; zero psT pad rows
    {
        const float* src = g_uK + (long)b * NH_ * D_;
        #pragma unroll
        for (int i = 0; i < 16; i++) {
            int idx = tid + i * 256;
            int h = idx >> 9, k = idx & 511;
            float v = src[idx];
            __half hh = __float2half(v);
            uKh[h * AHS_ROW + k] = hh;
            uKl[h * AHS_ROW + k] = __float2half(v - __half2float(hh));
        }
        for (int i = tid; i < 8 * AHS_ROW; i += 256) {
            uKh[8 * AHS_ROW + i] = __float2half(0.f);
            uKl[8 * AHS_ROW + i] = __float2half(0.f);
        }
        for (int i = tid; i < 8 * APT_ROW; i += 256) {
            psTh[8 * APT_ROW + i] = __float2half(0.f);
            psTl[8 * APT_ROW + i] = __float2half(0.f);
        }
    }
    // cK[h] = bk_h . q_h (q composed from comb partials + bq)
    {
        int j0 = warp * 64 + lane, j1 = j0 + 32;
        float q0 = g_partC[(long)b * 2048 + j0] + g_partC[PC1_OFF + (long)b * 2048 + j0] + bq[j0];
        float q1 = g_partC[(long)b * 2048 + j1] + g_partC[PC1_OFF + (long)b * 2048 + j1] + bq[j1];
        float v = bk[j0] * q0 + bk[j1] * q1;
        v = warpSum(v);
        if (lane == 0) { cKs[warp] = v; pss[warp] = 0.f; }
    }
    // persistent ctx accumulators: warp owns n-cols [warp*64, warp*64+64)
    nvcuda::wmma::fragment<nvcuda::wmma::accumulator, 16, 16, 16, float> cacc[4];
    #pragma unroll
    for (int j = 0; j < 4; j++) nvcuda::wmma::fill_fragment(cacc[j], 0.0f);
    __syncthreads();

    int nch = (len + CH - 1) / CH;
    int wm = warp & 1;          // score m-tile (16 rows)
    int wq = warp >> 1;         // score k quarter
    for (int c = 0; c < nch; c++) {
        int s0 = c * CH;
        // stage H chunk as raw half rows (zero past len)
        for (int r = warp; r < CH; r += 8) {
            int s = s0 + r;
            uint4* dst = (uint4*)(Hs + r * AHS_ROW);
            if (s < len) {
                const uint4* src = (const uint4*)(g_Hh + ((long)b * S_ + s) * D_);
                dst[lane] = src[lane];
                dst[lane + 32] = src[lane + 32];
            } else {
                uint4 z; z.x = 0; z.y = 0; z.z = 0; z.w = 0;
                dst[lane] = z;
                dst[lane + 32] = z;
            }
        }
        __syncthreads();
        // scores via WMMA: (32 x 512) @ (512 x 16), k split 4 ways
        {
            nvcuda::wmma::fragment<nvcuda::wmma::accumulator, 16, 16, 16, float> sacc;
            nvcuda::wmma::fill_fragment(sacc, 0.0f);
            #pragma unroll
            for (int kt = 0; kt < 8; kt++) {
                int k0 = (wq * 8 + kt) * 16;
                nvcuda::wmma::fragment<nvcuda::wmma::matrix_a, 16, 16, 16,
                                       __half, nvcuda::wmma::row_major> af;
                nvcuda::wmma::fragment<nvcuda::wmma::matrix_b, 16, 16, 16,
                                       __half, nvcuda::wmma::col_major> bfh, bfl;
                nvcuda::wmma::load_matrix_sync(af, Hs + wm * 16 * AHS_ROW + k0, AHS_ROW);
                nvcuda::wmma::load_matrix_sync(bfh, uKh + k0, AHS_ROW);
                nvcuda::wmma::load_matrix_sync(bfl, uKl + k0, AHS_ROW);
                nvcuda::wmma::mma_sync(sacc, af, bfh, sacc);
                nvcuda::wmma::mma_sync(sacc, af, bfl, sacc);
            }
            nvcuda::wmma::store_matrix_sync(scb + warp * 256, sacc, 16,
                                            nvcuda::wmma::mem_row_major);
        }
        __syncthreads();
        // combine k-quarters + sigmoid -> ps (psum) and psT hi/lo (ctx WMMA A)
        {
            int r = tid >> 3, h = tid & 7;
            int m = r >> 4, rr = r & 15;
            float v = scb[(0 * 2 + m) * 256 + rr * 16 + h]
                    + scb[(1 * 2 + m) * 256 + rr * 16 + h]
                    + scb[(2 * 2 + m) * 256 + rr * 16 + h]
                    + scb[(3 * 2 + m) * 256 + rr * 16 + h];
            int s = s0 + r;
            float p = (s < len) ? sigm(0.125f * (v + cKs[h])) : 0.f;
            ps[r * NH_ + h] = p;
            __half ph = __float2half(p);
            psTh[h * APT_ROW + r] = ph;
            psTl[h * APT_ROW + r] = __float2half(p - __half2float(ph));
        }
        __syncthreads();
        // ctx via WMMA: P^T(16x32 hi/lo) @ Hs(32x512), accumulate in cacc
        #pragma unroll
        for (int kt = 0; kt < 2; kt++) {
            nvcuda::wmma::fragment<nvcuda::wmma::matrix_a, 16, 16, 16,
                                   __half, nvcuda::wmma::row_major> pah, pal;
            nvcuda::wmma::load_matrix_sync(pah, psTh + kt * 16, APT_ROW);
            nvcuda::wmma::load_matrix_sync(pal, psTl + kt * 16, APT_ROW);
            #pragma unroll
            for (int j = 0; j < 4; j++) {
                nvcuda::wmma::fragment<nvcuda::wmma::matrix_b, 16, 16, 16,
                                       __half, nvcuda::wmma::row_major> hb;
                nvcuda::wmma::load_matrix_sync(hb, Hs + kt * 16 * AHS_ROW + warp * 64 + j * 16,
                                               AHS_ROW);
                nvcuda::wmma::mma_sync(cacc[j], pah, hb, cacc[j]);
                nvcuda::wmma::mma_sync(cacc[j], pal, hb, cacc[j]);
            }
        }
        // psum
        {
            float v = ps[lane * NH_ + warp];
            v = warpSum(v);
            if (lane == 0) pss[warp] += v;
        }
        __syncthreads();
    }
    // drain ctx accumulators: warp-local through its scb scratch
    #pragma unroll
    for (int j = 0; j < 4; j++) {
        nvcuda::wmma::store_matrix_sync(scb + warp * 256, cacc[j], 16,
                                        nvcuda::wmma::mem_row_major);
        __syncwarp();
        int h = lane >> 2;
        int cb = (lane & 3) * 4;
        float4 vv;
        vv.x = scb[warp * 256 + h * 16 + cb + 0];
        vv.y = scb[warp * 256 + h * 16 + cb + 1];
        vv.z = scb[warp * 256 + h * 16 + cb + 2];
        vv.w = scb[warp * 256 + h * 16 + cb + 3];
        *(float4*)&g_ctx[((long)b * NH_ + h) * D_ + warp * 64 + j * 16 + cb] = vv;
        __syncwarp();
    }
    if (tid < NH_) g_psum[b * NH_ + tid] = pss[tid];
}

// ---------------- small per-iter kernels --------------------------------------
__global__ __launch_bounds__(512) void k_ln_mt(
    const float* __restrict__ bv, const float* __restrict__ lng_g,
    const float* __restrict__ lng_b)
{
    pdl_sync();
    int b = blockIdx.x, t = threadIdx.x;
    __shared__ float red[32];
    long o = (long)b * 512 + t;
    float x = g_partM[o] + g_partM[PM_OFF + o] + g_partM[2 * PM_OFF + o]
            + g_partM[3 * PM_OFF + o] + g_psum[b * NH_ + (t >> 6)] * bv[t];
    float mean = blockSum(x, red) * (1.f / 512.f);
    float d = x - mean;
    float var = blockSum(d * d, red) * (1.f / 512.f);
    g_mt[b * D_ + t] = d * rsqrtf(var + 1e-5f) * lng_g[t] + lng_b[t];
}

__global__ __launch_bounds__(512) void k_gru(
    const float* __restrict__ b_ih, const float* __restrict__ b_hh,
    float* __restrict__ out, int last)
{
    int b = blockIdx.x, t = threadIdx.x;
    const float* G0 = g_partG + (long)b * 1536;
    const float* G1 = g_partG + PG1_OFF + (long)b * 1536;
    const float* C0 = g_partC + (long)b * 2048 + 512;
    const float* C1 = g_partC + PC1_OFF + (long)b * 2048 + 512;
    float ir = G0[t]        + G1[t]        + b_ih[t];
    float iz = G0[t + 512]  + G1[t + 512]  + b_ih[t + 512];
    float in = G0[t + 1024] + G1[t + 1024] + b_ih[t + 1024];
    float hr = C0[t]        + C1[t]        + b_hh[t];
    float hz = C0[t + 512]  + C1[t + 512]  + b_hh[t + 512];
    float hn = C0[t + 1024] + C1[t + 1024] + b_hh[t + 1024];
    float r = sigm(ir + hr);
    float z = sigm(iz + hz);
    float n = tanhf(in + r * hn);
    float old = g_bt[b * D_ + t];
    float nv = (1.f - z) * n + z * old;
    g_bt[b * D_ + t] = nv;
    if (last) out[b * 512 + t] = nv;
}

// ---------------- launch --------------------------------------------------------
extern "C" void kernel_launch(void* const* d_in, const int* in_sizes, int n_in,
                              void* d_out, int out_size)
{
    const float* emb   = (const float*)d_in[0];
    const int*   stc   = (const int*)  d_in[1];
    const int*   off   = (const int*)  d_in[2];
    const int*   sep   = (const int*)  d_in[3];
    const float* W1    = (const float*)d_in[4];
    const float* W2    = (const float*)d_in[5];
    const float* ln_g  = (const float*)d_in[6];
    const float* ln_b  = (const float*)d_in[7];
    const float* lng_g = (const float*)d_in[8];
    const float* lng_b = (const float*)d_in[9];
    const float* Wq    = (const float*)d_in[10];
    const float* bq    = (const float*)d_in[11];
    const float* Wk    = (const float*)d_in[12];
    const float* bk    = (const float*)d_in[13];
    const float* Wv    = (const float*)d_in[14];
    const float* bv    = (const float*)d_in[15];
    const float* W_ih  = (const float*)d_in[16];
    const float* W_hh  = (const float*)d_in[17];
    const float* b_ih  = (const float*)d_in[18];
    const float* b_hh  = (const float*)d_in[19];
    const float* seg   = (const float*)d_in[20];
    const float* pe    = (const float*)d_in[21];
    float* out = (float*)d_out;

    cudaFuncSetAttribute(k_attn, cudaFuncAttributeMaxDynamicSharedMemorySize, ATTN_SMEM_V3);
    cudaFuncSetAttribute(k_tc_w1,   cudaFuncAttributeMaxDynamicSharedMemorySize, SMEM_TCB128);
    cudaFuncSetAttribute(k_tc_q,    cudaFuncAttributeMaxDynamicSharedMemorySize, SMEM_TCB128);
    cudaFuncSetAttribute(k_tc_gh,   cudaFuncAttributeMaxDynamicSharedMemorySize, SMEM_TCB128);
    cudaFuncSetAttribute(k_tc_uk,   cudaFuncAttributeMaxDynamicSharedMemorySize, SMEM_TCB128);
    cudaFuncSetAttribute(k_tc_gi,   cudaFuncAttributeMaxDynamicSharedMemorySize, SMEM_TCB128);
    cudaFuncSetAttribute(k_tc_mraw, cudaFuncAttributeMaxDynamicSharedMemorySize, SMEM_TCB64);

    cudaStream_t sB;
    cudaStreamCreateWithFlags(&sB, cudaStreamNonBlocking);
    cudaEvent_t evF, evH, evG;
    cudaEventCreateWithFlags(&evF, cudaEventDisableTiming);
    cudaEventCreateWithFlags(&evH, cudaEventDisableTiming);
    cudaEventCreateWithFlags(&evG, cudaEventDisableTiming);

    cudaLaunchAttribute pdlAttr[1];
    pdlAttr[0].id = cudaLaunchAttributeProgrammaticStreamSerialization;
    pdlAttr[0].val.programmaticStreamSerializationAllowed = 1;
    auto mkcfg = [&](dim3 g, dim3 b, size_t smem) {
        cudaLaunchConfig_t c;
        c.gridDim = g; c.blockDim = b; c.dynamicSmemBytes = smem;
        c.stream = 0; c.attrs = pdlAttr; c.numAttrs = 1;
        return c;
    };

    // ---- preamble: fork buildH onto side stream ----
    cudaEventRecord(evF, 0);
    cudaStreamWaitEvent(sB, evF, 0);
    k_buildH<<<B_, 256, 0, sB>>>(emb, pe, seg, ln_g, ln_b, stc, off);
    cudaEventRecord(evH, sB);

    k_prep<<<dim3(16, 48, 6), 256>>>(Wk, W_ih, W_hh, Wq, Wv, W1);
    {
        cudaLaunchConfig_t c = mkcfg(dim3(B_, 1, 1), dim3(512, 1, 1), 0);
        cudaLaunchKernelEx(&c, k_build_hblk, emb, stc, off, sep);
    }
    {
        cudaLaunchConfig_t c = mkcfg(dim3(4, 32, 2), dim3(256, 1, 1), SMEM_TCB128);
        cudaLaunchKernelEx(&c, k_tc_w1);
    }
    {
        cudaLaunchConfig_t c = mkcfg(dim3(2048, 1, 1), dim3(256, 1, 1), 0);
        cudaLaunchKernelEx(&c, k_a, W2);
    }
    {
        cudaLaunchConfig_t c = mkcfg(dim3(L_, 1, 1), dim3(512, 1, 1), 0);
        cudaLaunchKernelEx(&c, k_s1);
    }
    {
        cudaLaunchConfig_t c = mkcfg(dim3(B_, 1, 1), dim3(512, 1, 1), 0);
        cudaLaunchKernelEx(&c, k_b0, ln_g, ln_b, pe);
    }

    // ---- 3 GRU iterations ----
    for (int it = 0; it < 3; it++) {
        cudaEventRecord(evF, 0);
        cudaStreamWaitEvent(sB, evF, 0);
        k_tc_gh<<<dim3(12, 8, 2), 256, SMEM_TCB128, sB>>>();
        cudaEventRecord(evG, sB);

        {
            cudaLaunchConfig_t c = mkcfg(dim3(4, 8, 2), dim3(256, 1, 1), SMEM_TCB128);
            cudaLaunchKernelEx(&c, k_tc_q);
        }
        {
            cudaLaunchConfig_t c = mkcfg(dim3(4, 8, 8), dim3(256, 1, 1), SMEM_TCB128);
            cudaLaunchKernelEx(&c, k_tc_uk, bq);
        }
        if (it == 0) {
            cudaStreamWaitEvent(0, evH, 0);
            k_attn<<<B_, 256, ATTN_SMEM_V3>>>(bk, bq, stc);
        } else {
            cudaLaunchConfig_t c = mkcfg(dim3(B_, 1, 1), dim3(256, 1, 1), ATTN_SMEM_V3);
            cudaLaunchKernelEx(&c, k_attn, bk, bq, stc);
        }
        {
            cudaLaunchConfig_t c = mkcfg(dim3(1, 8, 32), dim3(256, 1, 1), SMEM_TCB64);
            cudaLaunchKernelEx(&c, k_tc_mraw);
        }
        {
            cudaLaunchConfig_t c = mkcfg(dim3(B_, 1, 1), dim3(512, 1, 1), 0);
            cudaLaunchKernelEx(&c, k_ln_mt, bv, lng_g, lng_b);
        }
        {
            cudaLaunchConfig_t c = mkcfg(dim3(12, 8, 2), dim3(256, 1, 1), SMEM_TCB128);
            cudaLaunchKernelEx(&c, k_tc_gi);
        }
        cudaStreamWaitEvent(0, evG, 0);
        k_gru<<<B_, 512>>>(b_ih, b_hh, out, it == 2 ? 1 : 0);
    }
    (void)in_sizes; (void)n_in; (void)out_size;
}

// round 15
// speedup vs baseline: 5.0551x; 1.1120x over previous
#include <cuda_runtime.h>
#include <cuda_bf16.h>
#include <cuda_fp16.h>
#include <cuda_pipeline.h>
#include <mma.h>
#include <math.h>

#define B_  512
#define S_  200
#define D_  512
#define NH_ 8
#define L_  4
#define CH  32

// ---------------- scratch (device globals) ----------------------------------
__device__ float g_hblk[B_*L_*D_];
__device__ float g_valid[B_*L_];
__device__ float g_a[B_*L_];
__device__ float g_s1[B_*L_];
__device__ float g_bt[B_*D_];
__device__ __half g_Hh[B_*S_*D_];        // 105 MB (fp16 H)
__device__ float g_uK[B_*NH_*D_];
__device__ float g_ctx[B_*NH_*D_];
__device__ float g_psum[B_*NH_];
__device__ float g_mt[B_*D_];
__device__ float g_partC[2*B_*2048];     // comb / W1 split-K partials
__device__ float g_partM[4*B_*D_];       // mraw split-K partials
__device__ float g_partG[2*B_*1536];     // gi split-K partials

// bf16 hi/lo split weights, [N][K] layout (K contiguous)
__device__ __nv_bfloat16 g_combT_h[2048*512];
__device__ __nv_bfloat16 g_combT_l[2048*512];
__device__ __nv_bfloat16 g_Wih_h[1536*512];
__device__ __nv_bfloat16 g_Wih_l[1536*512];
__device__ __nv_bfloat16 g_Wk_h[512*512];
__device__ __nv_bfloat16 g_Wk_l[512*512];
__device__ __nv_bfloat16 g_WvT_h[512*512];
__device__ __nv_bfloat16 g_WvT_l[512*512];
__device__ __nv_bfloat16 g_W1T_h[512*512];
__device__ __nv_bfloat16 g_W1T_l[512*512];

#define PC1_OFF 1048576L   // 512*2048
#define PM_OFF  262144L    // 512*512
#define PG1_OFF 786432L    // 512*1536

// dynamic smem: 2 stages x (A(64) h/l + B(BN) h/l) x RS(40) x 2B
#define SMEM_TCB128 61440
#define SMEM_TCB64  40960

// attention v4 smem layout (bytes)
#define AHS_ROW   520                       // halfs per Hs row (512 + 8 pad)
#define APT_ROW   40                        // halfs per psT row (32 + 8 pad)
#define AOFF_HS   0                         // 32 x 520 half = 33280
#define AOFF_UKH  33280                     // 8 x 520 half = 8320
#define AOFF_UKL  41600                     // 8 x 520 half = 8320
#define AOFF_SC   49920                     // 8 x 256 float = 8192
#define AOFF_PS   58112                     // 32 x 8 float = 1024
#define AOFF_PTH  59136                     // 8 x 40 half = 640
#define AOFF_PTL  59776                     // 8 x 40 half = 640
#define AOFF_CK   60416                     // 8 float
#define AOFF_PSS  60448                     // 8 float
#define ATTN_SMEM_V4 60480

// PDL helpers
__device__ __forceinline__ void pdl_sync() {
#if __CUDA_ARCH__ >= 900
    cudaGridDependencySynchronize();
    cudaTriggerProgrammaticLaunchCompletion();
#endif
}

// ---------------- helpers ----------------------------------------------------
__device__ __forceinline__ float warpSum(float v) {
    #pragma unroll
    for (int o = 16; o; o >>= 1) v += __shfl_down_sync(0xffffffffu, v, o);
    return v;
}
__device__ __forceinline__ float warpAll(float v) {
    #pragma unroll
    for (int o = 16; o; o >>= 1) v += __shfl_xor_sync(0xffffffffu, v, o);
    return v;
}
__device__ __forceinline__ float warpMax(float v) {
    #pragma unroll
    for (int o = 16; o; o >>= 1) v = fmaxf(v, __shfl_down_sync(0xffffffffu, v, o));
    return v;
}
__device__ __forceinline__ float blockSum(float v, float* red) {
    int lane = threadIdx.x & 31, w = threadIdx.x >> 5;
    v = warpSum(v);
    if (lane == 0) red[w] = v;
    __syncthreads();
    float r = 0.f;
    if (threadIdx.x < (blockDim.x >> 5)) r = red[threadIdx.x];
    if (w == 0) r = warpSum(r);
    if (threadIdx.x == 0) red[0] = r;
    __syncthreads();
    r = red[0];
    __syncthreads();
    return r;
}
__device__ __forceinline__ float blockMax(float v, float* red) {
    int lane = threadIdx.x & 31, w = threadIdx.x >> 5;
    v = warpMax(v);
    if (lane == 0) red[w] = v;
    __syncthreads();
    float r = -3.0e38f;
    if (threadIdx.x < (blockDim.x >> 5)) r = red[threadIdx.x];
    if (w == 0) r = warpMax(r);
    if (threadIdx.x == 0) red[0] = r;
    __syncthreads();
    r = red[0];
    __syncthreads();
    return r;
}
__device__ __forceinline__ float sigm(float x) { return 1.f / (1.f + expf(-x)); }

// ---------------- WMMA tensor GEMM core v2 (unchanged from R14) ----------------
template <int BN, bool COMPOSE>
__device__ __forceinline__ void tc_core(
    const float* A0, const float* A1, const float* Ab, int lda,
    const __nv_bfloat16* Bh, const __nv_bfloat16* Bl, int ldb,
    float* C, int ldc, int Kd, int m0, int n0)
{
    const int RS = 40;
    const int NT = BN / 64;
    const int BCH = BN / 64;
    const int AE = 64 * RS;
    const int BE = BN * RS;
    const int STG = 2 * AE + 2 * BE;

    extern __shared__ __align__(16) __nv_bfloat16 dsm[];

    pdl_sync();

    int tid = threadIdx.x;
    int warp = tid >> 5;
    int wm = warp & 1;
    int wn = warp >> 1;

    nvcuda::wmma::fragment<nvcuda::wmma::accumulator, 16, 16, 16, float> acc[2][NT];
    #pragma unroll
    for (int i = 0; i < 2; i++) {
        #pragma unroll
        for (int j = 0; j < NT; j++) {
            nvcuda::wmma::fill_fragment(acc[i][j], 0.0f);
        }
    }

    float4 va[2];
    int arow = tid >> 3;
    int aq = tid & 7;

    {
        __nv_bfloat16* sBh = dsm + 2 * AE;
        __nv_bfloat16* sBl = dsm + 2 * AE + BE;
        #pragma unroll
        for (int i = 0; i < BCH; i++) {
            int c = tid + i * 256;
            int row = c >> 2;
            int q = c & 3;
            __pipeline_memcpy_async(sBh + row * RS + q * 8,
                                    Bh + (long)(n0 + row) * ldb + q * 8, 16);
            __pipeline_memcpy_async(sBl + row * RS + q * 8,
                                    Bl + (long)(n0 + row) * ldb + q * 8, 16);
        }
        __pipeline_commit();
        #pragma unroll
        for (int i = 0; i < 2; i++) {
            int row = arow + i * 32;
            float4 v = *(const float4*)(A0 + (long)(m0 + row) * lda + aq * 4);
            if (COMPOSE) {
                float4 v1 = *(const float4*)(A1 + (long)(m0 + row) * lda + aq * 4);
                float4 bi = *(const float4*)(Ab + aq * 4);
                v.x += v1.x + bi.x; v.y += v1.y + bi.y;
                v.z += v1.z + bi.z; v.w += v1.w + bi.w;
            }
            va[i] = v;
        }
        __nv_bfloat16* sAh = dsm;
        __nv_bfloat16* sAl = dsm + AE;
        #pragma unroll
        for (int i = 0; i < 2; i++) {
            int row = arow + i * 32;
            float4 v = va[i];
            __nv_bfloat16 h0 = __float2bfloat16(v.x);
            __nv_bfloat16 h1 = __float2bfloat16(v.y);
            __nv_bfloat16 h2 = __float2bfloat16(v.z);
            __nv_bfloat16 h3 = __float2bfloat16(v.w);
            int o = row * RS + aq * 4;
            sAh[o + 0] = h0; sAh[o + 1] = h1; sAh[o + 2] = h2; sAh[o + 3] = h3;
            sAl[o + 0] = __float2bfloat16(v.x - __bfloat162float(h0));
            sAl[o + 1] = __float2bfloat16(v.y - __bfloat162float(h1));
            sAl[o + 2] = __float2bfloat16(v.z - __bfloat162float(h2));
            sAl[o + 3] = __float2bfloat16(v.w - __bfloat162float(h3));
        }
        __pipeline_wait_prior(0);
        __syncthreads();
    }

    int nch = Kd >> 5;
    for (int c = 0; c < nch; c++) {
        int kn = (c + 1) * 32;
        __nv_bfloat16* nxt = dsm + ((c + 1) & 1) * STG;
        if (c + 1 < nch) {
            __nv_bfloat16* sBh = nxt + 2 * AE;
            __nv_bfloat16* sBl = nxt + 2 * AE + BE;
            #pragma unroll
            for (int i = 0; i < BCH; i++) {
                int cc = tid + i * 256;
                int row = cc >> 2;
                int q = cc & 3;
                __pipeline_memcpy_async(sBh + row * RS + q * 8,
                                        Bh + (long)(n0 + row) * ldb + kn + q * 8, 16);
                __pipeline_memcpy_async(sBl + row * RS + q * 8,
                                        Bl + (long)(n0 + row) * ldb + kn + q * 8, 16);
            }
            __pipeline_commit();
            #pragma unroll
            for (int i = 0; i < 2; i++) {
                int row = arow + i * 32;
                float4 v = *(const float4*)(A0 + (long)(m0 + row) * lda + kn + aq * 4);
                if (COMPOSE) {
                    float4 v1 = *(const float4*)(A1 + (long)(m0 + row) * lda + kn + aq * 4);
                    float4 bi = *(const float4*)(Ab + kn + aq * 4);
                    v.x += v1.x + bi.x; v.y += v1.y + bi.y;
                    v.z += v1.z + bi.z; v.w += v1.w + bi.w;
                }
                va[i] = v;
            }
        }
        {
            __nv_bfloat16* base = dsm + (c & 1) * STG;
            __nv_bfloat16* sAh = base;
            __nv_bfloat16* sAl = base + AE;
            __nv_bfloat16* sBh = base + 2 * AE;
            __nv_bfloat16* sBl = base + 2 * AE + BE;
            #pragma unroll
            for (int ks = 0; ks < 2; ks++) {
                nvcuda::wmma::fragment<nvcuda::wmma::matrix_a, 16, 16, 16,
                                       __nv_bfloat16, nvcuda::wmma::row_major> ah[2], al[2];
                #pragma unroll
                for (int i = 0; i < 2; i++) {
                    int r = wm * 32 + i * 16;
                    nvcuda::wmma::load_matrix_sync(ah[i], sAh + r * RS + ks * 16, RS);
                    nvcuda::wmma::load_matrix_sync(al[i], sAl + r * RS + ks * 16, RS);
                }
                #pragma unroll
                for (int j = 0; j < NT; j++) {
                    int nn = wn * (BN / 4) + j * 16;
                    nvcuda::wmma::fragment<nvcuda::wmma::matrix_b, 16, 16, 16,
                                           __nv_bfloat16, nvcuda::wmma::col_major> bh, bl;
                    nvcuda::wmma::load_matrix_sync(bh, sBh + nn * RS + ks * 16, RS);
                    nvcuda::wmma::load_matrix_sync(bl, sBl + nn * RS + ks * 16, RS);
                    #pragma unroll
                    for (int i = 0; i < 2; i++) {
                        nvcuda::wmma::mma_sync(acc[i][j], ah[i], bh, acc[i][j]);
                        nvcuda::wmma::mma_sync(acc[i][j], ah[i], bl, acc[i][j]);
                        nvcuda::wmma::mma_sync(acc[i][j], al[i], bh, acc[i][j]);
                    }
                }
            }
        }
        if (c + 1 < nch) {
            __nv_bfloat16* sAh = nxt;
            __nv_bfloat16* sAl = nxt + AE;
            #pragma unroll
            for (int i = 0; i < 2; i++) {
                int row = arow + i * 32;
                float4 v = va[i];
                __nv_bfloat16 h0 = __float2bfloat16(v.x);
                __nv_bfloat16 h1 = __float2bfloat16(v.y);
                __nv_bfloat16 h2 = __float2bfloat16(v.z);
                __nv_bfloat16 h3 = __float2bfloat16(v.w);
                int o = row * RS + aq * 4;
                sAh[o + 0] = h0; sAh[o + 1] = h1; sAh[o + 2] = h2; sAh[o + 3] = h3;
                sAl[o + 0] = __float2bfloat16(v.x - __bfloat162float(h0));
                sAl[o + 1] = __float2bfloat16(v.y - __bfloat162float(h1));
                sAl[o + 2] = __float2bfloat16(v.z - __bfloat162float(h2));
                sAl[o + 3] = __float2bfloat16(v.w - __bfloat162float(h3));
            }
            __pipeline_wait_prior(0);
        }
        __syncthreads();
    }
    #pragma unroll
    for (int i = 0; i < 2; i++) {
        #pragma unroll
        for (int j = 0; j < NT; j++) {
            int row = m0 + wm * 32 + i * 16;
            int col = n0 + wn * (BN / 4) + j * 16;
            nvcuda::wmma::store_matrix_sync(C + (long)row * ldc + col, acc[i][j],
                                            ldc, nvcuda::wmma::mem_row_major);
        }
    }
}

// ---------------- GEMM wrapper kernels (BM=64, 2 CTAs/SM) ----------------------
__global__ __launch_bounds__(256, 2) void k_tc_w1()
{
    int z = blockIdx.z;
    tc_core<128, false>(g_hblk + z * 256, (const float*)0, (const float*)0, 512,
                        g_W1T_h + z * 256, g_W1T_l + z * 256, 512,
                        g_partC + (long)z * PC1_OFF, 512, 256,
                        blockIdx.y * 64, blockIdx.x * 128);
}
__global__ __launch_bounds__(256, 2) void k_tc_q()
{
    int z = blockIdx.z;
    tc_core<128, false>(g_bt + z * 256, (const float*)0, (const float*)0, 512,
                        g_combT_h + z * 256, g_combT_l + z * 256, 512,
                        g_partC + (long)z * PC1_OFF, 2048, 256,
                        blockIdx.y * 64, blockIdx.x * 128);
}
__global__ __launch_bounds__(256, 2) void k_tc_gh()
{
    int z = blockIdx.z;
    tc_core<128, false>(g_bt + z * 256, (const float*)0, (const float*)0, 512,
                        g_combT_h + (long)512 * 512 + z * 256,
                        g_combT_l + (long)512 * 512 + z * 256, 512,
                        g_partC + (long)z * PC1_OFF + 512, 2048, 256,
                        blockIdx.y * 64, blockIdx.x * 128);
}
__global__ __launch_bounds__(256, 2) void k_tc_uk(const float* __restrict__ bq)
{
    int h = blockIdx.z;
    tc_core<128, true>(g_partC + h * 64, g_partC + PC1_OFF + h * 64, bq + h * 64, 2048,
                       g_Wk_h + h * 64, g_Wk_l + h * 64, 512,
                       g_uK + h * 512, 4096, 64,
                       blockIdx.y * 64, blockIdx.x * 128);
}
__global__ __launch_bounds__(256, 2) void k_tc_mraw()
{
    int z = blockIdx.z;
    int h = z >> 2;
    int ks = z & 3;
    tc_core<64, false>(g_ctx + h * 512 + (long)ks * 128, (const float*)0, (const float*)0, 4096,
                       g_WvT_h + (long)(h * 64) * 512 + ks * 128,
                       g_WvT_l + (long)(h * 64) * 512 + ks * 128, 512,
                       g_partM + ks * PM_OFF + h * 64, 512, 128,
                       blockIdx.y * 64, 0);
}
__global__ __launch_bounds__(256, 2) void k_tc_gi()
{
    int z = blockIdx.z;
    tc_core<128, false>(g_mt + z * 256, (const float*)0, (const float*)0, 512,
                        g_Wih_h + z * 256, g_Wih_l + z * 256, 512,
                        g_partG + (long)z * PG1_OFF, 1536, 256,
                        blockIdx.y * 64, blockIdx.x * 128);
}

// ---------------- weight prep (jbase selects job subset) -----------------------
__global__ __launch_bounds__(256) void k_prep(
    const float* __restrict__ Wk, const float* __restrict__ W_ih,
    const float* __restrict__ W_hh, const float* __restrict__ Wq,
    const float* __restrict__ Wv, const float* __restrict__ W1, int jbase)
{
    __shared__ float t[32][33];
    int job = blockIdx.z + jbase;
    int bx = blockIdx.x * 32;
    int by = blockIdx.y * 32;
    int lx = threadIdx.x & 31;
    int wy = threadIdx.x >> 5;
    if (job <= 2) {
        const float* src;
        __nv_bfloat16* dh;
        __nv_bfloat16* dl;
        int nrows;
        if (job == 0)      { src = Wk;   dh = g_Wk_h;  dl = g_Wk_l;  nrows = 512;  }
        else if (job == 1) { src = W_ih; dh = g_Wih_h; dl = g_Wih_l; nrows = 1536; }
        else               { src = W_hh; dh = g_combT_h + 512*512;
                             dl = g_combT_l + 512*512; nrows = 1536; }
        if (by >= nrows) return;
        for (int j = wy; j < 32; j += 8) {
            long o = (long)(by + j) * 512 + bx + lx;
            float v = src[o];
            __nv_bfloat16 hh = __float2bfloat16(v);
            dh[o] = hh;
            dl[o] = __float2bfloat16(v - __bfloat162float(hh));
        }
    } else {
        if (blockIdx.y >= 16) return;
        const float* src;
        __nv_bfloat16* dh;
        __nv_bfloat16* dl;
        if (job == 3)      { src = Wq; dh = g_combT_h; dl = g_combT_l; }
        else if (job == 4) { src = Wv; dh = g_WvT_h;   dl = g_WvT_l;   }
        else               { src = W1; dh = g_W1T_h;   dl = g_W1T_l;   }
        for (int j = wy; j < 32; j += 8)
            t[j][lx] = src[(long)(by + j) * 512 + bx + lx];
        __syncthreads();
        for (int j = wy; j < 32; j += 8) {
            float v = t[lx][j];
            long o = (long)(bx + j) * 512 + by + lx;
            __nv_bfloat16 hh = __float2bfloat16(v);
            dh[o] = hh;
            dl[o] = __float2bfloat16(v - __bfloat162float(hh));
        }
    }
}

// ---------------- preamble -----------------------------------------------------
__global__ __launch_bounds__(512) void k_build_hblk(
    const float* __restrict__ emb, const int* __restrict__ stc,
    const int* __restrict__ off, const int* __restrict__ sep)
{
    pdl_sync();
    int b = blockIdx.x;
    int o = off[b], len = stc[b];
    int sA = sep[b * 2], sB2 = sep[b * 2 + 1];
    int idx = (sA < o ? 1 : 0) + (sB2 < o ? 1 : 0);
    int pidx = idx - 1; pidx = pidx < 0 ? 0 : (pidx > 1 ? 1 : pidx);
    int prev = (pidx == 0) ? sA : sB2;
    int left = (idx > 0) ? prev + 1 : 0;
    int nidx = idx > 1 ? 1 : idx;
    int nxt = (nidx == 0) ? sA : sB2;
    int right = (idx < 2) ? nxt : len;
    int start = (o - 2 > left) ? o - 2 : left;
    int end = (o + 2 < right) ? o + 2 : right;
    int t = threadIdx.x;
    #pragma unroll
    for (int l = 0; l < L_; l++) {
        int ind = start + l;
        bool v = ind < end;
        int ic = ind < 0 ? 0 : (ind > S_ - 1 ? S_ - 1 : ind);
        g_hblk[(b * L_ + l) * D_ + t] = v ? emb[((long)b * S_ + ic) * D_ + t] : 0.f;
        if (t == 0) g_valid[b * L_ + l] = v ? 1.f : 0.f;
    }
}

__global__ __launch_bounds__(256) void k_a(const float* __restrict__ W2)
{
    pdl_sync();
    int m = blockIdx.x, t = threadIdx.x;
    float t0 = tanhf(g_partC[(long)m * 512 + t] + g_partC[PC1_OFF + (long)m * 512 + t]);
    float t1 = tanhf(g_partC[(long)m * 512 + t + 256] + g_partC[PC1_OFF + (long)m * 512 + t + 256]);
    float v = t0 * W2[t] + t1 * W2[t + 256];
    __shared__ float red[32];
    v = blockSum(v, red);
    if (t == 0) g_a[m] = v;
}

__global__ __launch_bounds__(512) void k_s1()
{
    pdl_sync();
    int l = blockIdx.x, t = threadIdx.x;
    __shared__ float red[32];
    float v = g_a[t * L_ + l];
    float mx = blockMax(v, red);
    float e = expf(v - mx);
    float s = blockSum(e, red);
    g_s1[t * L_ + l] = e / s;
}

__global__ __launch_bounds__(512) void k_b0(
    const float* __restrict__ ln_g, const float* __restrict__ ln_b,
    const float* __restrict__ pe)
{
    pdl_sync();
    int b = blockIdx.x, t = threadIdx.x;
    __shared__ float sc[4];
    __shared__ float red[32];
    if (t == 0) {
        float vals[4], mx = -3.0e38f;
        #pragma unroll
        for (int l = 0; l < 4; l++) {
            float v = (g_valid[b * 4 + l] > 0.5f) ? g_s1[b * 4 + l] : -1e9f;
            vals[l] = v; mx = fmaxf(mx, v);
        }
        float s = 0.f;
        #pragma unroll
        for (int l = 0; l < 4; l++) { float e = expf(vals[l] - mx); sc[l] = e; s += e; }
        #pragma unroll
        for (int l = 0; l < 4; l++) sc[l] /= s;
    }
    __syncthreads();
    float x = sc[0] * g_hblk[(b * 4 + 0) * D_ + t] + sc[1] * g_hblk[(b * 4 + 1) * D_ + t]
            + sc[2] * g_hblk[(b * 4 + 2) * D_ + t] + sc[3] * g_hblk[(b * 4 + 3) * D_ + t]
            + pe[t];
    float mean = blockSum(x, red) * (1.f / 512.f);
    float d = x - mean;
    float var = blockSum(d * d, red) * (1.f / 512.f);
    g_bt[b * D_ + t] = d * rsqrtf(var + 1e-5f) * ln_g[t] + ln_b[t];
}

// warp-per-row H build
__global__ __launch_bounds__(256) void k_buildH(
    const float* __restrict__ emb, const float* __restrict__ pe,
    const float* __restrict__ seg_emb, const float* __restrict__ ln_g,
    const float* __restrict__ ln_b, const int* __restrict__ stc,
    const int* __restrict__ off)
{
    __shared__ float s_seg[2][D_];
    __shared__ float s_g[D_];
    __shared__ float s_b[D_];
    int b = blockIdx.x;
    int tid = threadIdx.x, lane = tid & 31, warp = tid >> 5;
    for (int i = tid; i < D_; i += 256) {
        s_seg[0][i] = seg_emb[i];
        s_seg[1][i] = seg_emb[D_ + i];
        s_g[i] = ln_g[i];
        s_b[i] = ln_b[i];
    }
    int len = stc[b];
    int pos = off[b];
    __syncthreads();
    for (int s = warp; s < len; s += 8) {
        int ip = (s < pos) ? (pos - s) : (s + 1 - pos);
        ip = ip < 0 ? 0 : (ip > S_ ? S_ : ip);
        int sg = (s >= pos) ? 1 : 0;
        const float* er = emb + ((long)b * S_ + s) * D_;
        const float* pr = pe + (long)ip * D_;
        float x[16];
        float sum = 0.f;
        #pragma unroll
        for (int i = 0; i < 4; i++) {
            int base = i * 128 + lane * 4;
            float4 e = *(const float4*)(er + base);
            float4 p = *(const float4*)(pr + base);
            float v0 = e.x + p.x + s_seg[sg][base + 0];
            float v1 = e.y + p.y + s_seg[sg][base + 1];
            float v2 = e.z + p.z + s_seg[sg][base + 2];
            float v3 = e.w + p.w + s_seg[sg][base + 3];
            x[i*4+0] = v0; x[i*4+1] = v1; x[i*4+2] = v2; x[i*4+3] = v3;
            sum += v0 + v1 + v2 + v3;
        }
        float mean = warpAll(sum) * (1.f / 512.f);
        float vs = 0.f;
        #pragma unroll
        for (int i = 0; i < 16; i++) {
            float d = x[i] - mean;
            x[i] = d;
            vs += d * d;
        }
        float inv = rsqrtf(warpAll(vs) * (1.f / 512.f) + 1e-5f);
        __half* dr = g_Hh + ((long)b * S_ + s) * D_;
        #pragma unroll
        for (int i = 0; i < 4; i++) {
            int base = i * 128 + lane * 4;
            float o0 = x[i*4+0] * inv * s_g[base + 0] + s_b[base + 0];
            float o1 = x[i*4+1] * inv * s_g[base + 1] + s_b[base + 1];
            float o2 = x[i*4+2] * inv * s_g[base + 2] + s_b[base + 2];
            float o3 = x[i*4+3] * inv * s_g[base + 3] + s_b[base + 3];
            __half2 ha = __floats2half2_rn(o0, o1);
            __half2 hb = __floats2half2_rn(o2, o3);
            *(__half2*)(dr + base)     = ha;
            *(__half2*)(dr + base + 2) = hb;
        }
    }
}

// ---------------- fused attention v4: m32n8k16 scores + m8n32k16 ctx -----------
__global__ __launch_bounds__(256) void k_attn(
    const float* __restrict__ bk, const float* __restrict__ bq,
    const int* __restrict__ stc)
{
    pdl_sync();
    int b = blockIdx.x;
    int tid = threadIdx.x, lane = tid & 31, warp = tid >> 5;   // 8 warps
    extern __shared__ __align__(16) char asm_[];
    __half* Hs   = (__half*)(asm_ + AOFF_HS);    // 32 x 520 half
    __half* uKh  = (__half*)(asm_ + AOFF_UKH);   // 8 x 520 half
    __half* uKl  = (__half*)(asm_ + AOFF_UKL);
    float* scb   = (float*)(asm_ + AOFF_SC);     // 8 x 256 (warp scratch)
    float* ps    = (float*)(asm_ + AOFF_PS);     // 32 x 8
    __half* psTh = (__half*)(asm_ + AOFF_PTH);   // 8 x 40 half
    __half* psTl = (__half*)(asm_ + AOFF_PTL);
    float* cKs   = (float*)(asm_ + AOFF_CK);
    float* pss   = (float*)(asm_ + AOFF_PSS);
    int len = stc[b];

    // stage uK -> half hi/lo (8 rows)
    {
        const float* src = g_uK + (long)b * NH_ * D_;
        #pragma unroll
        for (int i = 0; i < 16; i++) {
            int idx = tid + i * 256;
            int h = idx >> 9, k = idx & 511;
            float v = src[idx];
            __half hh = __float2half(v);
            uKh[h * AHS_ROW + k] = hh;
            uKl[h * AHS_ROW + k] = __float2half(v - __half2float(hh));
        }
    }
    // cK[h] = bk_h . q_h (q composed from comb partials + bq)
    {
        int j0 = warp * 64 + lane, j1 = j0 + 32;
        float q0 = g_partC[(long)b * 2048 + j0] + g_partC[PC1_OFF + (long)b * 2048 + j0] + bq[j0];
        float q1 = g_partC[(long)b * 2048 + j1] + g_partC[PC1_OFF + (long)b * 2048 + j1] + bq[j1];
        float v = bk[j0] * q0 + bk[j1] * q1;
        v = warpSum(v);
        if (lane == 0) { cKs[warp] = v; pss[warp] = 0.f; }
    }
    // persistent ctx accumulators: warp owns n-cols [warp*64, warp*64+64)
    nvcuda::wmma::fragment<nvcuda::wmma::accumulator, 8, 32, 16, float> cacc[2];
    #pragma unroll
    for (int j = 0; j < 2; j++) nvcuda::wmma::fill_fragment(cacc[j], 0.0f);
    __syncthreads();

    int nch = (len + CH - 1) / CH;
    for (int c = 0; c < nch; c++) {
        int s0 = c * CH;
        // stage H chunk as raw half rows (zero past len)
        for (int r = warp; r < CH; r += 8) {
            int s = s0 + r;
            uint4* dst = (uint4*)(Hs + r * AHS_ROW);
            if (s < len) {
                const uint4* src = (const uint4*)(g_Hh + ((long)b * S_ + s) * D_);
                dst[lane] = src[lane];
                dst[lane + 32] = src[lane + 32];
            } else {
                uint4 z; z.x = 0; z.y = 0; z.z = 0; z.w = 0;
                dst[lane] = z;
                dst[lane + 32] = z;
            }
        }
        __syncthreads();
        // scores via WMMA m32n8k16: (32 x 512) @ (512 x 8), k split across warps
        {
            nvcuda::wmma::fragment<nvcuda::wmma::accumulator, 32, 8, 16, float> sacc;
            nvcuda::wmma::fill_fragment(sacc, 0.0f);
            #pragma unroll
            for (int kt = 0; kt < 4; kt++) {
                int k0 = (warp * 4 + kt) * 16;
                nvcuda::wmma::fragment<nvcuda::wmma::matrix_a, 32, 8, 16,
                                       __half, nvcuda::wmma::row_major> af;
                nvcuda::wmma::fragment<nvcuda::wmma::matrix_b, 32, 8, 16,
                                       __half, nvcuda::wmma::col_major> bfh, bfl;
                nvcuda::wmma::load_matrix_sync(af, Hs + k0, AHS_ROW);
                nvcuda::wmma::load_matrix_sync(bfh, uKh + k0, AHS_ROW);
                nvcuda::wmma::load_matrix_sync(bfl, uKl + k0, AHS_ROW);
                nvcuda::wmma::mma_sync(sacc, af, bfh, sacc);
                nvcuda::wmma::mma_sync(sacc, af, bfl, sacc);
            }
            nvcuda::wmma::store_matrix_sync(scb + warp * 256, sacc, 8,
                                            nvcuda::wmma::mem_row_major);
        }
        __syncthreads();
        // combine warp partials + sigmoid -> ps and psT hi/lo
        {
            int r = tid >> 3, h = tid & 7;
            float v = 0.f;
            #pragma unroll
            for (int w = 0; w < 8; w++) v += scb[w * 256 + r * 8 + h];
            int s = s0 + r;
            float p = (s < len) ? sigm(0.125f * (v + cKs[h])) : 0.f;
            ps[r * NH_ + h] = p;
            __half ph = __float2half(p);
            psTh[h * APT_ROW + r] = ph;
            psTl[h * APT_ROW + r] = __float2half(p - __half2float(ph));
        }
        __syncthreads();
        // ctx via WMMA m8n32k16: P^T(8x32 hi/lo) @ Hs(32x512)
        #pragma unroll
        for (int kt = 0; kt < 2; kt++) {
            nvcuda::wmma::fragment<nvcuda::wmma::matrix_a, 8, 32, 16,
                                   __half, nvcuda::wmma::row_major> pah, pal;
            nvcuda::wmma::load_matrix_sync(pah, psTh + kt * 16, APT_ROW);
            nvcuda::wmma::load_matrix_sync(pal, psTl + kt * 16, APT_ROW);
            #pragma unroll
            for (int j = 0; j < 2; j++) {
                nvcuda::wmma::fragment<nvcuda::wmma::matrix_b, 8, 32, 16,
                                       __half, nvcuda::wmma::row_major> hb;
                nvcuda::wmma::load_matrix_sync(hb, Hs + kt * 16 * AHS_ROW + warp * 64 + j * 32,
                                               AHS_ROW);
                nvcuda::wmma::mma_sync(cacc[j], pah, hb, cacc[j]);
                nvcuda::wmma::mma_sync(cacc[j], pal, hb, cacc[j]);
            }
        }
        // psum
        {
            float v = ps[lane * NH_ + warp];
            v = warpSum(v);
            if (lane == 0) pss[warp] += v;
        }
        __syncthreads();
    }
    // drain ctx accumulators: warp-local through its scb scratch (8x32 each)
    #pragma unroll
    for (int j = 0; j < 2; j++) {
        nvcuda::wmma::store_matrix_sync(scb + warp * 256, cacc[j], 32,
                                        nvcuda::wmma::mem_row_major);
        __syncwarp();
        int h = lane >> 2;
        int cb = (lane & 3) * 8;
        float4 v0;
        v0.x = scb[warp * 256 + h * 32 + cb + 0];
        v0.y = scb[warp * 256 + h * 32 + cb + 1];
        v0.z = scb[warp * 256 + h * 32 + cb + 2];
        v0.w = scb[warp * 256 + h * 32 + cb + 3];
        float4 v1;
        v1.x = scb[warp * 256 + h * 32 + cb + 4];
        v1.y = scb[warp * 256 + h * 32 + cb + 5];
        v1.z = scb[warp * 256 + h * 32 + cb + 6];
        v1.w = scb[warp * 256 + h * 32 + cb + 7];
        long o = ((long)b * NH_ + h) * D_ + warp * 64 + j * 32 + cb;
        *(float4*)&g_ctx[o] = v0;
        *(float4*)&g_ctx[o + 4] = v1;
        __syncwarp();
    }
    if (tid < NH_) g_psum[b * NH_ + tid] = pss[tid];
}

// ---------------- small per-iter kernels --------------------------------------
__global__ __launch_bounds__(512) void k_ln_mt(
    const float* __restrict__ bv, const float* __restrict__ lng_g,
    const float* __restrict__ lng_b)
{
    pdl_sync();
    int b = blockIdx.x, t = threadIdx.x;
    __shared__ float red[32];
    long o = (long)b * 512 + t;
    float x = g_partM[o] + g_partM[PM_OFF + o] + g_partM[2 * PM_OFF + o]
            + g_partM[3 * PM_OFF + o] + g_psum[b * NH_ + (t >> 6)] * bv[t];
    float mean = blockSum(x, red) * (1.f / 512.f);
    float d = x - mean;
    float var = blockSum(d * d, red) * (1.f / 512.f);
    g_mt[b * D_ + t] = d * rsqrtf(var + 1e-5f) * lng_g[t] + lng_b[t];
}

__global__ __launch_bounds__(512) void k_gru(
    const float* __restrict__ b_ih, const float* __restrict__ b_hh,
    float* __restrict__ out, int last)
{
    int b = blockIdx.x, t = threadIdx.x;
    const float* G0 = g_partG + (long)b * 1536;
    const float* G1 = g_partG + PG1_OFF + (long)b * 1536;
    const float* C0 = g_partC + (long)b * 2048 + 512;
    const float* C1 = g_partC + PC1_OFF + (long)b * 2048 + 512;
    float ir = G0[t]        + G1[t]        + b_ih[t];
    float iz = G0[t + 512]  + G1[t + 512]  + b_ih[t + 512];
    float in = G0[t + 1024] + G1[t + 1024] + b_ih[t + 1024];
    float hr = C0[t]        + C1[t]        + b_hh[t];
    float hz = C0[t + 512]  + C1[t + 512]  + b_hh[t + 512];
    float hn = C0[t + 1024] + C1[t + 1024] + b_hh[t + 1024];
    float r = sigm(ir + hr);
    float z = sigm(iz + hz);
    float n = tanhf(in + r * hn);
    float old = g_bt[b * D_ + t];
    float nv = (1.f - z) * n + z * old;
    g_bt[b * D_ + t] = nv;
    if (last) out[b * 512 + t] = nv;
}

// ---------------- launch --------------------------------------------------------
extern "C" void kernel_launch(void* const* d_in, const int* in_sizes, int n_in,
                              void* d_out, int out_size)
{
    const float* emb   = (const float*)d_in[0];
    const int*   stc   = (const int*)  d_in[1];
    const int*   off   = (const int*)  d_in[2];
    const int*   sep   = (const int*)  d_in[3];
    const float* W1    = (const float*)d_in[4];
    const float* W2    = (const float*)d_in[5];
    const float* ln_g  = (const float*)d_in[6];
    const float* ln_b  = (const float*)d_in[7];
    const float* lng_g = (const float*)d_in[8];
    const float* lng_b = (const float*)d_in[9];
    const float* Wq    = (const float*)d_in[10];
    const float* bq    = (const float*)d_in[11];
    const float* Wk    = (const float*)d_in[12];
    const float* bk    = (const float*)d_in[13];
    const float* Wv    = (const float*)d_in[14];
    const float* bv    = (const float*)d_in[15];
    const float* W_ih  = (const float*)d_in[16];
    const float* W_hh  = (const float*)d_in[17];
    const float* b_ih  = (const float*)d_in[18];
    const float* b_hh  = (const float*)d_in[19];
    const float* seg   = (const float*)d_in[20];
    const float* pe    = (const float*)d_in[21];
    float* out = (float*)d_out;

    cudaFuncSetAttribute(k_attn, cudaFuncAttributeMaxDynamicSharedMemorySize, ATTN_SMEM_V4);
    cudaFuncSetAttribute(k_tc_w1,   cudaFuncAttributeMaxDynamicSharedMemorySize, SMEM_TCB128);
    cudaFuncSetAttribute(k_tc_q,    cudaFuncAttributeMaxDynamicSharedMemorySize, SMEM_TCB128);
    cudaFuncSetAttribute(k_tc_gh,   cudaFuncAttributeMaxDynamicSharedMemorySize, SMEM_TCB128);
    cudaFuncSetAttribute(k_tc_uk,   cudaFuncAttributeMaxDynamicSharedMemorySize, SMEM_TCB128);
    cudaFuncSetAttribute(k_tc_gi,   cudaFuncAttributeMaxDynamicSharedMemorySize, SMEM_TCB128);
    cudaFuncSetAttribute(k_tc_mraw, cudaFuncAttributeMaxDynamicSharedMemorySize, SMEM_TCB64);

    cudaStream_t sB;
    cudaStreamCreateWithFlags(&sB, cudaStreamNonBlocking);
    cudaEvent_t evF, evH, evG;
    cudaEventCreateWithFlags(&evF, cudaEventDisableTiming);
    cudaEventCreateWithFlags(&evH, cudaEventDisableTiming);
    cudaEventCreateWithFlags(&evG, cudaEventDisableTiming);

    cudaLaunchAttribute pdlAttr[1];
    pdlAttr[0].id = cudaLaunchAttributeProgrammaticStreamSerialization;
    pdlAttr[0].val.programmaticStreamSerializationAllowed = 1;
    auto mkcfg = [&](dim3 g, dim3 b, size_t smem) {
        cudaLaunchConfig_t c;
        c.gridDim = g; c.blockDim = b; c.dynamicSmemBytes = smem;
        c.stream = 0; c.attrs = pdlAttr; c.numAttrs = 1;
        return c;
    };

    // ---- preamble: side stream does non-critical weight prep + buildH ----
    cudaEventRecord(evF, 0);
    cudaStreamWaitEvent(sB, evF, 0);
    k_prep<<<dim3(16, 48, 5), 256, 0, sB>>>(Wk, W_ih, W_hh, Wq, Wv, W1, 0);
    k_buildH<<<B_, 256, 0, sB>>>(emb, pe, seg, ln_g, ln_b, stc, off);
    cudaEventRecord(evH, sB);

    // critical preamble chain: W1 split -> hblk -> W1 GEMM -> a -> s1 -> b0
    k_prep<<<dim3(16, 16, 1), 256>>>(Wk, W_ih, W_hh, Wq, Wv, W1, 5);
    {
        cudaLaunchConfig_t c = mkcfg(dim3(B_, 1, 1), dim3(512, 1, 1), 0);
        cudaLaunchKernelEx(&c, k_build_hblk, emb, stc, off, sep);
    }
    {
        cudaLaunchConfig_t c = mkcfg(dim3(4, 32, 2), dim3(256, 1, 1), SMEM_TCB128);
        cudaLaunchKernelEx(&c, k_tc_w1);
    }
    {
        cudaLaunchConfig_t c = mkcfg(dim3(2048, 1, 1), dim3(256, 1, 1), 0);
        cudaLaunchKernelEx(&c, k_a, W2);
    }
    {
        cudaLaunchConfig_t c = mkcfg(dim3(L_, 1, 1), dim3(512, 1, 1), 0);
        cudaLaunchKernelEx(&c, k_s1);
    }
    {
        cudaLaunchConfig_t c = mkcfg(dim3(B_, 1, 1), dim3(512, 1, 1), 0);
        cudaLaunchKernelEx(&c, k_b0, ln_g, ln_b, pe);
    }
    // join side stream: weights + H ready before first iteration GEMMs
    cudaStreamWaitEvent(0, evH, 0);

    // ---- 3 GRU iterations ----
    for (int it = 0; it < 3; it++) {
        cudaEventRecord(evF, 0);
        cudaStreamWaitEvent(sB, evF, 0);
        k_tc_gh<<<dim3(12, 8, 2), 256, SMEM_TCB128, sB>>>();
        cudaEventRecord(evG, sB);

        {
            cudaLaunchConfig_t c = mkcfg(dim3(4, 8, 2), dim3(256, 1, 1), SMEM_TCB128);
            cudaLaunchKernelEx(&c, k_tc_q);
        }
        {
            cudaLaunchConfig_t c = mkcfg(dim3(4, 8, 8), dim3(256, 1, 1), SMEM_TCB128);
            cudaLaunchKernelEx(&c, k_tc_uk, bq);
        }
        {
            cudaLaunchConfig_t c = mkcfg(dim3(B_, 1, 1), dim3(256, 1, 1), ATTN_SMEM_V4);
            cudaLaunchKernelEx(&c, k_attn, bk, bq, stc);
        }
        {
            cudaLaunchConfig_t c = mkcfg(dim3(1, 8, 32), dim3(256, 1, 1), SMEM_TCB64);
            cudaLaunchKernelEx(&c, k_tc_mraw);
        }
        {
            cudaLaunchConfig_t c = mkcfg(dim3(B_, 1, 1), dim3(512, 1, 1), 0);
            cudaLaunchKernelEx(&c, k_ln_mt, bv, lng_g, lng_b);
        }
        {
            cudaLaunchConfig_t c = mkcfg(dim3(12, 8, 2), dim3(256, 1, 1), SMEM_TCB128);
            cudaLaunchKernelEx(&c, k_tc_gi);
        }
        cudaStreamWaitEvent(0, evG, 0);
        k_gru<<<B_, 512>>>(b_ih, b_hh, out, it == 2 ? 1 : 0);
    }
    (void)in_sizes; (void)n_in; (void)out_size;
}